// round 1
// baseline (speedup 1.0000x reference)
#include <cuda_runtime.h>
#include <cuda_bf16.h>
#include <math.h>

// ---------------------------------------------------------------------------
// Problem constants
// ---------------------------------------------------------------------------
#define HS    3072
#define MLPD  12288
#define NH    24
#define HD    128
#define LTXT  512
#define LIMG  2048
#define LTOT  2560          // txt rows [0,512), img rows [512,2560)
#define QKVW  9216          // 3*HS

// ---------------------------------------------------------------------------
// Static device scratch (no allocations allowed)
// ---------------------------------------------------------------------------
__device__ float g_silu[HS];
__device__ float g_mod_img[6 * HS];
__device__ float g_mod_txt[6 * HS];
__device__ float g_x   [(size_t)LTOT * HS];       // modulated LN input
__device__ float g_qkv [(size_t)LTOT * QKVW];
__device__ float g_q   [(size_t)NH * LTOT * HD];
__device__ float g_k   [(size_t)NH * LTOT * HD];
__device__ float g_v   [(size_t)NH * LTOT * HD];
__device__ float g_scores[(size_t)NH * LTOT * LTOT]; // 629 MB
__device__ float g_attn[(size_t)LTOT * HS];
__device__ float g_x1  [(size_t)LTOT * HS];       // after first residual
__device__ float g_x2  [(size_t)LTOT * HS];       // second modulated LN
__device__ float g_h1  [(size_t)LTOT * MLPD];     // MLP hidden

// ---------------------------------------------------------------------------
// Small elementwise kernels
// ---------------------------------------------------------------------------
__global__ void silu_kernel(const float* __restrict__ v, float* __restrict__ o) {
    int i = blockIdx.x * 256 + threadIdx.x;
    if (i < HS) {
        float x = v[i];
        o[i] = x / (1.0f + expf(-x));
    }
}

// m[j] = silu(vec) . w[:,j] + b[j]   (w: HS x 6HS row-major)
__global__ void mod_gemv(const float* __restrict__ sv, const float* __restrict__ w,
                         const float* __restrict__ b, float* __restrict__ out) {
    __shared__ float ssv[HS];
    for (int i = threadIdx.x; i < HS; i += 256) ssv[i] = sv[i];
    __syncthreads();
    int j = blockIdx.x * 256 + threadIdx.x;
    float acc = 0.0f;
    #pragma unroll 4
    for (int i = 0; i < HS; i++)
        acc += ssv[i] * w[(size_t)i * (6 * HS) + j];
    out[j] = acc + b[j];
}

// LayerNorm + modulate: dst = shift + (1+scale) * LN(x) ; one block per row
__global__ void ln_mod(const float* __restrict__ x, float* __restrict__ dst,
                       const float* __restrict__ shift, const float* __restrict__ scale) {
    int row = blockIdx.x;
    int t = threadIdx.x;
    const float* xr = x + (size_t)row * HS;
    float v[12];
    float s = 0.0f;
    #pragma unroll
    for (int i = 0; i < 12; i++) { v[i] = xr[t + i * 256]; s += v[i]; }
    __shared__ float red[256];
    red[t] = s; __syncthreads();
    for (int o = 128; o > 0; o >>= 1) { if (t < o) red[t] += red[t + o]; __syncthreads(); }
    float mean = red[0] * (1.0f / HS);
    __syncthreads();
    float s2 = 0.0f;
    #pragma unroll
    for (int i = 0; i < 12; i++) { float d = v[i] - mean; s2 += d * d; }
    red[t] = s2; __syncthreads();
    for (int o = 128; o > 0; o >>= 1) { if (t < o) red[t] += red[t + o]; __syncthreads(); }
    float inv = rsqrtf(red[0] * (1.0f / HS) + 1e-6f);
    float* dr = dst + (size_t)row * HS;
    #pragma unroll
    for (int i = 0; i < 12; i++) {
        int c = t + i * 256;
        dr[c] = shift[c] + (1.0f + scale[c]) * (v[i] - mean) * inv;
    }
}

// Per-head RMS-norm(q,k) + RoPE + scatter to [h][l][d]; copy v.
__global__ void rms_rope(const float* __restrict__ qkv, const float* __restrict__ pe,
                         const float* __restrict__ tqs, const float* __restrict__ tks,
                         const float* __restrict__ iqs, const float* __restrict__ iks,
                         float* __restrict__ Q, float* __restrict__ Kp, float* __restrict__ Vp) {
    int l = blockIdx.x;
    int w = threadIdx.x >> 5, lane = threadIdx.x & 31;
    const float* qs = (l < LTXT) ? tqs : iqs;
    const float* ks = (l < LTXT) ? tks : iks;
    const float* row = qkv + (size_t)l * QKVW;
    const float* peb = pe + (size_t)l * 256 + lane * 8; // 2 rope pairs per lane
    float4 p0 = *(const float4*)(peb);
    float4 p1 = *(const float4*)(peb + 4);
    int d0 = lane * 4;
    float4 scq = *(const float4*)(qs + d0);
    float4 sck = *(const float4*)(ks + d0);

    for (int h = w; h < NH; h += 8) {
        // ---- Q
        float4 xq = *(const float4*)(row + h * HD + d0);
        float ss = xq.x*xq.x + xq.y*xq.y + xq.z*xq.z + xq.w*xq.w;
        #pragma unroll
        for (int o = 16; o > 0; o >>= 1) ss += __shfl_xor_sync(0xffffffffu, ss, o);
        float r = rsqrtf(ss * (1.0f / HD) + 1e-6f);
        float x0 = xq.x * r * scq.x, x1 = xq.y * r * scq.y;
        float x2 = xq.z * r * scq.z, x3 = xq.w * r * scq.w;
        float4 oq;
        oq.x = p0.x * x0 + p0.y * x1;
        oq.y = p0.z * x0 + p0.w * x1;
        oq.z = p1.x * x2 + p1.y * x3;
        oq.w = p1.z * x2 + p1.w * x3;
        *(float4*)(Q + ((size_t)h * LTOT + l) * HD + d0) = oq;
        // ---- K
        float4 xk = *(const float4*)(row + HS + h * HD + d0);
        float sk = xk.x*xk.x + xk.y*xk.y + xk.z*xk.z + xk.w*xk.w;
        #pragma unroll
        for (int o = 16; o > 0; o >>= 1) sk += __shfl_xor_sync(0xffffffffu, sk, o);
        float rk = rsqrtf(sk * (1.0f / HD) + 1e-6f);
        float y0 = xk.x * rk * sck.x, y1 = xk.y * rk * sck.y;
        float y2 = xk.z * rk * sck.z, y3 = xk.w * rk * sck.w;
        float4 ok;
        ok.x = p0.x * y0 + p0.y * y1;
        ok.y = p0.z * y0 + p0.w * y1;
        ok.z = p1.x * y2 + p1.y * y3;
        ok.w = p1.z * y2 + p1.w * y3;
        *(float4*)(Kp + ((size_t)h * LTOT + l) * HD + d0) = ok;
        // ---- V copy
        float4 xv = *(const float4*)(row + 2 * HS + h * HD + d0);
        *(float4*)(Vp + ((size_t)h * LTOT + l) * HD + d0) = xv;
    }
}

// Row softmax over 2560 columns (with scale), one block per row
__global__ void softmax2560(float* __restrict__ S, float scale) {
    size_t row = blockIdx.x;
    float* sr = S + row * (size_t)LTOT;
    int t = threadIdx.x;
    float v[10];
    float mx = -1e30f;
    #pragma unroll
    for (int i = 0; i < 10; i++) { v[i] = sr[t + i * 256] * scale; mx = fmaxf(mx, v[i]); }
    __shared__ float red[256];
    red[t] = mx; __syncthreads();
    for (int o = 128; o > 0; o >>= 1) { if (t < o) red[t] = fmaxf(red[t], red[t + o]); __syncthreads(); }
    mx = red[0]; __syncthreads();
    float s = 0.0f;
    #pragma unroll
    for (int i = 0; i < 10; i++) { v[i] = expf(v[i] - mx); s += v[i]; }
    red[t] = s; __syncthreads();
    for (int o = 128; o > 0; o >>= 1) { if (t < o) red[t] += red[t + o]; __syncthreads(); }
    float inv = 1.0f / red[0];
    #pragma unroll
    for (int i = 0; i < 10; i++) sr[t + i * 256] = v[i] * inv;
}

// ---------------------------------------------------------------------------
// 128x128x8 SGEMM, 256 threads, 8x8 per-thread tile.
// All M,N multiples of 128; K multiple of 8 (true for every GEMM here).
// EPI: 0 = C = acc+bias ; 1 = gelu(acc+bias) ; 2 = resid + gate*(acc+bias)
// ---------------------------------------------------------------------------
__device__ __forceinline__ float gelu_tanh(float x) {
    float x3 = x * x * x;
    return 0.5f * x * (1.0f + tanhf(0.7978845608028654f * (x + 0.044715f * x3)));
}

template <bool TRANSB, int EPI>
__global__ void __launch_bounds__(256)
sgemm128(const float* __restrict__ A, const float* __restrict__ B,
         const float* __restrict__ bias, float* __restrict__ C,
         int K, int lda, int ldb, int ldc,
         size_t sA, size_t sB, size_t sC,
         const float* __restrict__ gate, const float* __restrict__ resid, int ldres) {
    A += (size_t)blockIdx.z * sA;
    B += (size_t)blockIdx.z * sB;
    C += (size_t)blockIdx.z * sC;

    __shared__ float As[8][128];
    __shared__ float Bs[8][128];

    const int t  = threadIdx.x;
    const int tx = t & 15, ty = t >> 4;
    const int m0 = blockIdx.y * 128, n0 = blockIdx.x * 128;
    const int c_m = ty * 8, c_n = tx * 8;

    // load indices
    const int a_m = t >> 1, a_k = (t & 1) * 4;
    const int b_k = t >> 5, b_n = (t & 31) * 4;     // !TRANSB
    const int bt_n = t >> 1, bt_k = (t & 1) * 4;    // TRANSB

    float acc[8][8];
    #pragma unroll
    for (int i = 0; i < 8; i++)
        #pragma unroll
        for (int j = 0; j < 8; j++) acc[i][j] = 0.0f;

    const float* Ap = A + (size_t)(m0 + a_m) * lda + a_k;
    const float* Bp = TRANSB ? (B + (size_t)(n0 + bt_n) * ldb + bt_k)
                             : (B + (size_t)b_k * ldb + n0 + b_n);

    for (int k0 = 0; k0 < K; k0 += 8) {
        float4 av = *(const float4*)(Ap + k0);
        As[a_k + 0][a_m] = av.x; As[a_k + 1][a_m] = av.y;
        As[a_k + 2][a_m] = av.z; As[a_k + 3][a_m] = av.w;
        if (TRANSB) {
            float4 bv = *(const float4*)(Bp + k0);
            Bs[bt_k + 0][bt_n] = bv.x; Bs[bt_k + 1][bt_n] = bv.y;
            Bs[bt_k + 2][bt_n] = bv.z; Bs[bt_k + 3][bt_n] = bv.w;
        } else {
            float4 bv = *(const float4*)(Bp + (size_t)k0 * ldb);
            *(float4*)(&Bs[b_k][b_n]) = bv;
        }
        __syncthreads();
        #pragma unroll
        for (int kk = 0; kk < 8; kk++) {
            __align__(16) float a[8], b[8];
            *(float4*)&a[0] = *(const float4*)&As[kk][c_m];
            *(float4*)&a[4] = *(const float4*)&As[kk][c_m + 4];
            *(float4*)&b[0] = *(const float4*)&Bs[kk][c_n];
            *(float4*)&b[4] = *(const float4*)&Bs[kk][c_n + 4];
            #pragma unroll
            for (int i = 0; i < 8; i++)
                #pragma unroll
                for (int j = 0; j < 8; j++)
                    acc[i][j] += a[i] * b[j];
        }
        __syncthreads();
    }

    float bv[8], gv[8];
    #pragma unroll
    for (int j = 0; j < 8; j++) {
        bv[j] = bias ? bias[n0 + c_n + j] : 0.0f;
        gv[j] = (EPI == 2) ? gate[n0 + c_n + j] : 0.0f;
    }
    #pragma unroll
    for (int i = 0; i < 8; i++) {
        int m = m0 + c_m + i;
        float* Crow = C + (size_t)m * ldc + n0 + c_n;
        const float* Rrow = (EPI == 2) ? (resid + (size_t)m * ldres + n0 + c_n) : nullptr;
        #pragma unroll
        for (int j = 0; j < 8; j++) {
            float c = acc[i][j] + bv[j];
            if (EPI == 1) c = gelu_tanh(c);
            if (EPI == 2) c = Rrow[j] + gv[j] * c;
            Crow[j] = c;
        }
    }
}

// ---------------------------------------------------------------------------
// Host launcher
// ---------------------------------------------------------------------------
static void launch_gemm(int epi, bool transB,
                        const float* A, const float* B, const float* bias, float* C,
                        int M, int N, int K, int lda, int ldb, int ldc,
                        int batch, size_t sA, size_t sB, size_t sC,
                        const float* gate = nullptr, const float* resid = nullptr, int ldres = 0) {
    dim3 grid(N / 128, M / 128, batch);
    if (transB) {
        sgemm128<true, 0><<<grid, 256>>>(A, B, bias, C, K, lda, ldb, ldc, sA, sB, sC, gate, resid, ldres);
    } else if (epi == 0) {
        sgemm128<false, 0><<<grid, 256>>>(A, B, bias, C, K, lda, ldb, ldc, sA, sB, sC, gate, resid, ldres);
    } else if (epi == 1) {
        sgemm128<false, 1><<<grid, 256>>>(A, B, bias, C, K, lda, ldb, ldc, sA, sB, sC, gate, resid, ldres);
    } else {
        sgemm128<false, 2><<<grid, 256>>>(A, B, bias, C, K, lda, ldb, ldc, sA, sB, sC, gate, resid, ldres);
    }
}

extern "C" void kernel_launch(void* const* d_in, const int* in_sizes, int n_in,
                              void* d_out, int out_size) {
    const float* img        = (const float*)d_in[0];
    const float* txt        = (const float*)d_in[1];
    const float* vec        = (const float*)d_in[2];
    const float* pe         = (const float*)d_in[3];
    const float* img_mod_w  = (const float*)d_in[4];
    const float* img_mod_b  = (const float*)d_in[5];
    const float* img_qkv_w  = (const float*)d_in[6];
    const float* img_qkv_b  = (const float*)d_in[7];
    const float* img_q_s    = (const float*)d_in[8];
    const float* img_k_s    = (const float*)d_in[9];
    const float* img_proj_w = (const float*)d_in[10];
    const float* img_proj_b = (const float*)d_in[11];
    const float* img_mlp_w1 = (const float*)d_in[12];
    const float* img_mlp_b1 = (const float*)d_in[13];
    const float* img_mlp_w2 = (const float*)d_in[14];
    const float* img_mlp_b2 = (const float*)d_in[15];
    const float* txt_mod_w  = (const float*)d_in[16];
    const float* txt_mod_b  = (const float*)d_in[17];
    const float* txt_qkv_w  = (const float*)d_in[18];
    const float* txt_qkv_b  = (const float*)d_in[19];
    const float* txt_q_s    = (const float*)d_in[20];
    const float* txt_k_s    = (const float*)d_in[21];
    const float* txt_proj_w = (const float*)d_in[22];
    const float* txt_proj_b = (const float*)d_in[23];
    const float* txt_mlp_w1 = (const float*)d_in[24];
    const float* txt_mlp_b1 = (const float*)d_in[25];
    const float* txt_mlp_w2 = (const float*)d_in[26];
    const float* txt_mlp_b2 = (const float*)d_in[27];
    float* out = (float*)d_out;

    float *sv, *modi, *modt, *x, *qkvb, *q, *k, *v, *scores, *attn, *x1, *x2, *h1;
    cudaGetSymbolAddress((void**)&sv,     g_silu);
    cudaGetSymbolAddress((void**)&modi,   g_mod_img);
    cudaGetSymbolAddress((void**)&modt,   g_mod_txt);
    cudaGetSymbolAddress((void**)&x,      g_x);
    cudaGetSymbolAddress((void**)&qkvb,   g_qkv);
    cudaGetSymbolAddress((void**)&q,      g_q);
    cudaGetSymbolAddress((void**)&k,      g_k);
    cudaGetSymbolAddress((void**)&v,      g_v);
    cudaGetSymbolAddress((void**)&scores, g_scores);
    cudaGetSymbolAddress((void**)&attn,   g_attn);
    cudaGetSymbolAddress((void**)&x1,     g_x1);
    cudaGetSymbolAddress((void**)&x2,     g_x2);
    cudaGetSymbolAddress((void**)&h1,     g_h1);

    // 1. silu(vec)
    silu_kernel<<<HS / 256, 256>>>(vec, sv);

    // 2. modulation params
    mod_gemv<<<(6 * HS) / 256, 256>>>(sv, img_mod_w, img_mod_b, modi);
    mod_gemv<<<(6 * HS) / 256, 256>>>(sv, txt_mod_w, txt_mod_b, modt);

    // 3. LN + modulate (txt rows 0..511, img rows 512..2559)
    ln_mod<<<LTXT, 256>>>(txt, x,                       modt + 0 * HS, modt + 1 * HS);
    ln_mod<<<LIMG, 256>>>(img, x + (size_t)LTXT * HS,   modi + 0 * HS, modi + 1 * HS);

    // 4. QKV GEMMs
    launch_gemm(0, false, x, txt_qkv_w, txt_qkv_b, qkvb,
                LTXT, QKVW, HS, HS, QKVW, QKVW, 1, 0, 0, 0);
    launch_gemm(0, false, x + (size_t)LTXT * HS, img_qkv_w, img_qkv_b,
                qkvb + (size_t)LTXT * QKVW,
                LIMG, QKVW, HS, HS, QKVW, QKVW, 1, 0, 0, 0);

    // 5. RMS norm + RoPE + head-major scatter
    rms_rope<<<LTOT, 256>>>(qkvb, pe, txt_q_s, txt_k_s, img_q_s, img_k_s, q, k, v);

    // 6. scores = q @ k^T  (batched over heads, B transposed)
    launch_gemm(0, true, q, k, nullptr, scores,
                LTOT, LTOT, HD, HD, HD, LTOT,
                NH, (size_t)LTOT * HD, (size_t)LTOT * HD, (size_t)LTOT * LTOT);

    // 7. softmax with 1/sqrt(D)
    softmax2560<<<NH * LTOT, 256>>>(scores, 0.08838834764831845f);

    // 8. o = a @ v, written into [l][h*128+d]
    launch_gemm(0, false, scores, v, nullptr, attn,
                LTOT, HD, LTOT, LTOT, HD, HS,
                NH, (size_t)LTOT * LTOT, (size_t)LTOT * HD, (size_t)HD);

    // 9. proj + gated residual  -> x1
    launch_gemm(2, false, attn, txt_proj_w, txt_proj_b, x1,
                LTXT, HS, HS, HS, HS, HS, 1, 0, 0, 0,
                modt + 2 * HS, txt, HS);
    launch_gemm(2, false, attn + (size_t)LTXT * HS, img_proj_w, img_proj_b,
                x1 + (size_t)LTXT * HS,
                LIMG, HS, HS, HS, HS, HS, 1, 0, 0, 0,
                modi + 2 * HS, img, HS);

    // 10. second LN + modulate -> x2
    ln_mod<<<LTXT, 256>>>(x1, x2,                                   modt + 3 * HS, modt + 4 * HS);
    ln_mod<<<LIMG, 256>>>(x1 + (size_t)LTXT * HS, x2 + (size_t)LTXT * HS, modi + 3 * HS, modi + 4 * HS);

    // 11. MLP1 with fused GELU -> h1
    launch_gemm(1, false, x2, txt_mlp_w1, txt_mlp_b1, h1,
                LTXT, MLPD, HS, HS, MLPD, MLPD, 1, 0, 0, 0);
    launch_gemm(1, false, x2 + (size_t)LTXT * HS, img_mlp_w1, img_mlp_b1,
                h1 + (size_t)LTXT * MLPD,
                LIMG, MLPD, HS, HS, MLPD, MLPD, 1, 0, 0, 0);

    // 12. MLP2 with fused gated residual, written straight to d_out
    //     output layout: img (2048*3072) then txt (512*3072)
    launch_gemm(2, false, h1, txt_mlp_w2, txt_mlp_b2,
                out + (size_t)LIMG * HS,
                LTXT, HS, MLPD, MLPD, HS, HS, 1, 0, 0, 0,
                modt + 5 * HS, x1, HS);
    launch_gemm(2, false, h1 + (size_t)LTXT * MLPD, img_mlp_w2, img_mlp_b2,
                out,
                LIMG, HS, MLPD, MLPD, HS, HS, 1, 0, 0, 0,
                modi + 5 * HS, x1 + (size_t)LTXT * HS, HS);
}

// round 2
// speedup vs baseline: 1.0016x; 1.0016x over previous
#include <cuda_runtime.h>
#include <cuda_bf16.h>
#include <math.h>

// ---------------------------------------------------------------------------
// Problem constants
// ---------------------------------------------------------------------------
#define HS    3072
#define MLPD  12288
#define NH    24
#define HD    128
#define LTXT  512
#define LIMG  2048
#define LTOT  2560          // txt rows [0,512), img rows [512,2560)
#define QKVW  9216          // 3*HS

// ---------------------------------------------------------------------------
// Static device scratch (no allocations allowed)
// ---------------------------------------------------------------------------
__device__ float g_silu[HS];
__device__ float g_mod_img[6 * HS];
__device__ float g_mod_txt[6 * HS];
__device__ float g_x   [(size_t)LTOT * HS];       // modulated LN input
__device__ float g_qkv [(size_t)LTOT * QKVW];
__device__ float g_q   [(size_t)NH * LTOT * HD];
__device__ float g_k   [(size_t)NH * LTOT * HD];
__device__ float g_v   [(size_t)NH * LTOT * HD];
__device__ float g_scores[(size_t)NH * LTOT * LTOT]; // 629 MB
__device__ float g_attn[(size_t)LTOT * HS];
__device__ float g_x1  [(size_t)LTOT * HS];       // after first residual
__device__ float g_x2  [(size_t)LTOT * HS];       // second modulated LN
__device__ float g_h1  [(size_t)LTOT * MLPD];     // MLP hidden

// ---------------------------------------------------------------------------
// Small elementwise kernels
// ---------------------------------------------------------------------------
__global__ void silu_kernel(const float* __restrict__ v, float* __restrict__ o) {
    int i = blockIdx.x * 256 + threadIdx.x;
    if (i < HS) {
        float x = v[i];
        o[i] = x / (1.0f + expf(-x));
    }
}

// m[j] = silu(vec) . w[:,j] + b[j]   (w: HS x 6HS row-major)
__global__ void mod_gemv(const float* __restrict__ sv, const float* __restrict__ w,
                         const float* __restrict__ b, float* __restrict__ out) {
    __shared__ float ssv[HS];
    for (int i = threadIdx.x; i < HS; i += 256) ssv[i] = sv[i];
    __syncthreads();
    int j = blockIdx.x * 256 + threadIdx.x;
    float acc = 0.0f;
    #pragma unroll 4
    for (int i = 0; i < HS; i++)
        acc += ssv[i] * w[(size_t)i * (6 * HS) + j];
    out[j] = acc + b[j];
}

// LayerNorm + modulate: dst = shift + (1+scale) * LN(x) ; one block per row
__global__ void ln_mod(const float* __restrict__ x, float* __restrict__ dst,
                       const float* __restrict__ shift, const float* __restrict__ scale) {
    int row = blockIdx.x;
    int t = threadIdx.x;
    const float* xr = x + (size_t)row * HS;
    float v[12];
    float s = 0.0f;
    #pragma unroll
    for (int i = 0; i < 12; i++) { v[i] = xr[t + i * 256]; s += v[i]; }
    __shared__ float red[256];
    red[t] = s; __syncthreads();
    for (int o = 128; o > 0; o >>= 1) { if (t < o) red[t] += red[t + o]; __syncthreads(); }
    float mean = red[0] * (1.0f / HS);
    __syncthreads();
    float s2 = 0.0f;
    #pragma unroll
    for (int i = 0; i < 12; i++) { float d = v[i] - mean; s2 += d * d; }
    red[t] = s2; __syncthreads();
    for (int o = 128; o > 0; o >>= 1) { if (t < o) red[t] += red[t + o]; __syncthreads(); }
    float inv = rsqrtf(red[0] * (1.0f / HS) + 1e-6f);
    float* dr = dst + (size_t)row * HS;
    #pragma unroll
    for (int i = 0; i < 12; i++) {
        int c = t + i * 256;
        dr[c] = shift[c] + (1.0f + scale[c]) * (v[i] - mean) * inv;
    }
}

// Per-head RMS-norm(q,k) + RoPE + scatter to [h][l][d]; copy v.
__global__ void rms_rope(const float* __restrict__ qkv, const float* __restrict__ pe,
                         const float* __restrict__ tqs, const float* __restrict__ tks,
                         const float* __restrict__ iqs, const float* __restrict__ iks,
                         float* __restrict__ Q, float* __restrict__ Kp, float* __restrict__ Vp) {
    int l = blockIdx.x;
    int w = threadIdx.x >> 5, lane = threadIdx.x & 31;
    const float* qs = (l < LTXT) ? tqs : iqs;
    const float* ks = (l < LTXT) ? tks : iks;
    const float* row = qkv + (size_t)l * QKVW;
    const float* peb = pe + (size_t)l * 256 + lane * 8; // 2 rope pairs per lane
    float4 p0 = *(const float4*)(peb);
    float4 p1 = *(const float4*)(peb + 4);
    int d0 = lane * 4;
    float4 scq = *(const float4*)(qs + d0);
    float4 sck = *(const float4*)(ks + d0);

    for (int h = w; h < NH; h += 8) {
        // ---- Q
        float4 xq = *(const float4*)(row + h * HD + d0);
        float ss = xq.x*xq.x + xq.y*xq.y + xq.z*xq.z + xq.w*xq.w;
        #pragma unroll
        for (int o = 16; o > 0; o >>= 1) ss += __shfl_xor_sync(0xffffffffu, ss, o);
        float r = rsqrtf(ss * (1.0f / HD) + 1e-6f);
        float x0 = xq.x * r * scq.x, x1 = xq.y * r * scq.y;
        float x2 = xq.z * r * scq.z, x3 = xq.w * r * scq.w;
        float4 oq;
        oq.x = p0.x * x0 + p0.y * x1;
        oq.y = p0.z * x0 + p0.w * x1;
        oq.z = p1.x * x2 + p1.y * x3;
        oq.w = p1.z * x2 + p1.w * x3;
        *(float4*)(Q + ((size_t)h * LTOT + l) * HD + d0) = oq;
        // ---- K
        float4 xk = *(const float4*)(row + HS + h * HD + d0);
        float sk = xk.x*xk.x + xk.y*xk.y + xk.z*xk.z + xk.w*xk.w;
        #pragma unroll
        for (int o = 16; o > 0; o >>= 1) sk += __shfl_xor_sync(0xffffffffu, sk, o);
        float rk = rsqrtf(sk * (1.0f / HD) + 1e-6f);
        float y0 = xk.x * rk * sck.x, y1 = xk.y * rk * sck.y;
        float y2 = xk.z * rk * sck.z, y3 = xk.w * rk * sck.w;
        float4 ok;
        ok.x = p0.x * y0 + p0.y * y1;
        ok.y = p0.z * y0 + p0.w * y1;
        ok.z = p1.x * y2 + p1.y * y3;
        ok.w = p1.z * y2 + p1.w * y3;
        *(float4*)(Kp + ((size_t)h * LTOT + l) * HD + d0) = ok;
        // ---- V copy
        float4 xv = *(const float4*)(row + 2 * HS + h * HD + d0);
        *(float4*)(Vp + ((size_t)h * LTOT + l) * HD + d0) = xv;
    }
}

// Row softmax over 2560 columns (with scale), one block per row
__global__ void softmax2560(float* __restrict__ S, float scale) {
    size_t row = blockIdx.x;
    float* sr = S + row * (size_t)LTOT;
    int t = threadIdx.x;
    float v[10];
    float mx = -1e30f;
    #pragma unroll
    for (int i = 0; i < 10; i++) { v[i] = sr[t + i * 256] * scale; mx = fmaxf(mx, v[i]); }
    __shared__ float red[256];
    red[t] = mx; __syncthreads();
    for (int o = 128; o > 0; o >>= 1) { if (t < o) red[t] = fmaxf(red[t], red[t + o]); __syncthreads(); }
    mx = red[0]; __syncthreads();
    float s = 0.0f;
    #pragma unroll
    for (int i = 0; i < 10; i++) { v[i] = expf(v[i] - mx); s += v[i]; }
    red[t] = s; __syncthreads();
    for (int o = 128; o > 0; o >>= 1) { if (t < o) red[t] += red[t + o]; __syncthreads(); }
    float inv = 1.0f / red[0];
    #pragma unroll
    for (int i = 0; i < 10; i++) sr[t + i * 256] = v[i] * inv;
}

// ---------------------------------------------------------------------------
// 128x128x8 SGEMM, 256 threads, 8x8 per-thread tile.
// All M,N multiples of 128; K multiple of 8 (true for every GEMM here).
// EPI: 0 = C = acc+bias ; 1 = gelu(acc+bias) ; 2 = resid + gate*(acc+bias)
// ---------------------------------------------------------------------------
__device__ __forceinline__ float gelu_tanh(float x) {
    float x3 = x * x * x;
    return 0.5f * x * (1.0f + tanhf(0.7978845608028654f * (x + 0.044715f * x3)));
}

template <bool TRANSB, int EPI>
__global__ void __launch_bounds__(256)
sgemm128(const float* __restrict__ A, const float* __restrict__ B,
         const float* __restrict__ bias, float* __restrict__ C,
         int K, int lda, int ldb, int ldc,
         size_t sA, size_t sB, size_t sC,
         const float* __restrict__ gate, const float* __restrict__ resid, int ldres) {
    A += (size_t)blockIdx.z * sA;
    B += (size_t)blockIdx.z * sB;
    C += (size_t)blockIdx.z * sC;

    __shared__ float As[8][128];
    __shared__ float Bs[8][128];

    const int t  = threadIdx.x;
    const int tx = t & 15, ty = t >> 4;
    const int m0 = blockIdx.y * 128, n0 = blockIdx.x * 128;
    const int c_m = ty * 8, c_n = tx * 8;

    // load indices
    const int a_m = t >> 1, a_k = (t & 1) * 4;
    const int b_k = t >> 5, b_n = (t & 31) * 4;     // !TRANSB
    const int bt_n = t >> 1, bt_k = (t & 1) * 4;    // TRANSB

    float acc[8][8];
    #pragma unroll
    for (int i = 0; i < 8; i++)
        #pragma unroll
        for (int j = 0; j < 8; j++) acc[i][j] = 0.0f;

    const float* Ap = A + (size_t)(m0 + a_m) * lda + a_k;
    const float* Bp = TRANSB ? (B + (size_t)(n0 + bt_n) * ldb + bt_k)
                             : (B + (size_t)b_k * ldb + n0 + b_n);

    for (int k0 = 0; k0 < K; k0 += 8) {
        float4 av = *(const float4*)(Ap + k0);
        As[a_k + 0][a_m] = av.x; As[a_k + 1][a_m] = av.y;
        As[a_k + 2][a_m] = av.z; As[a_k + 3][a_m] = av.w;
        if (TRANSB) {
            float4 bv = *(const float4*)(Bp + k0);
            Bs[bt_k + 0][bt_n] = bv.x; Bs[bt_k + 1][bt_n] = bv.y;
            Bs[bt_k + 2][bt_n] = bv.z; Bs[bt_k + 3][bt_n] = bv.w;
        } else {
            float4 bv = *(const float4*)(Bp + (size_t)k0 * ldb);
            *(float4*)(&Bs[b_k][b_n]) = bv;
        }
        __syncthreads();
        #pragma unroll
        for (int kk = 0; kk < 8; kk++) {
            __align__(16) float a[8], b[8];
            *(float4*)&a[0] = *(const float4*)&As[kk][c_m];
            *(float4*)&a[4] = *(const float4*)&As[kk][c_m + 4];
            *(float4*)&b[0] = *(const float4*)&Bs[kk][c_n];
            *(float4*)&b[4] = *(const float4*)&Bs[kk][c_n + 4];
            #pragma unroll
            for (int i = 0; i < 8; i++)
                #pragma unroll
                for (int j = 0; j < 8; j++)
                    acc[i][j] += a[i] * b[j];
        }
        __syncthreads();
    }

    float bv[8], gv[8];
    #pragma unroll
    for (int j = 0; j < 8; j++) {
        bv[j] = bias ? bias[n0 + c_n + j] : 0.0f;
        gv[j] = (EPI == 2) ? gate[n0 + c_n + j] : 0.0f;
    }
    #pragma unroll
    for (int i = 0; i < 8; i++) {
        int m = m0 + c_m + i;
        float* Crow = C + (size_t)m * ldc + n0 + c_n;
        const float* Rrow = (EPI == 2) ? (resid + (size_t)m * ldres + n0 + c_n) : nullptr;
        #pragma unroll
        for (int j = 0; j < 8; j++) {
            float c = acc[i][j] + bv[j];
            if (EPI == 1) c = gelu_tanh(c);
            if (EPI == 2) c = Rrow[j] + gv[j] * c;
            Crow[j] = c;
        }
    }
}

// ---------------------------------------------------------------------------
// Host launcher
// ---------------------------------------------------------------------------
static void launch_gemm(int epi, bool transB,
                        const float* A, const float* B, const float* bias, float* C,
                        int M, int N, int K, int lda, int ldb, int ldc,
                        int batch, size_t sA, size_t sB, size_t sC,
                        const float* gate = nullptr, const float* resid = nullptr, int ldres = 0) {
    dim3 grid(N / 128, M / 128, batch);
    if (transB) {
        sgemm128<true, 0><<<grid, 256>>>(A, B, bias, C, K, lda, ldb, ldc, sA, sB, sC, gate, resid, ldres);
    } else if (epi == 0) {
        sgemm128<false, 0><<<grid, 256>>>(A, B, bias, C, K, lda, ldb, ldc, sA, sB, sC, gate, resid, ldres);
    } else if (epi == 1) {
        sgemm128<false, 1><<<grid, 256>>>(A, B, bias, C, K, lda, ldb, ldc, sA, sB, sC, gate, resid, ldres);
    } else {
        sgemm128<false, 2><<<grid, 256>>>(A, B, bias, C, K, lda, ldb, ldc, sA, sB, sC, gate, resid, ldres);
    }
}

extern "C" void kernel_launch(void* const* d_in, const int* in_sizes, int n_in,
                              void* d_out, int out_size) {
    const float* img        = (const float*)d_in[0];
    const float* txt        = (const float*)d_in[1];
    const float* vec        = (const float*)d_in[2];
    const float* pe         = (const float*)d_in[3];
    const float* img_mod_w  = (const float*)d_in[4];
    const float* img_mod_b  = (const float*)d_in[5];
    const float* img_qkv_w  = (const float*)d_in[6];
    const float* img_qkv_b  = (const float*)d_in[7];
    const float* img_q_s    = (const float*)d_in[8];
    const float* img_k_s    = (const float*)d_in[9];
    const float* img_proj_w = (const float*)d_in[10];
    const float* img_proj_b = (const float*)d_in[11];
    const float* img_mlp_w1 = (const float*)d_in[12];
    const float* img_mlp_b1 = (const float*)d_in[13];
    const float* img_mlp_w2 = (const float*)d_in[14];
    const float* img_mlp_b2 = (const float*)d_in[15];
    const float* txt_mod_w  = (const float*)d_in[16];
    const float* txt_mod_b  = (const float*)d_in[17];
    const float* txt_qkv_w  = (const float*)d_in[18];
    const float* txt_qkv_b  = (const float*)d_in[19];
    const float* txt_q_s    = (const float*)d_in[20];
    const float* txt_k_s    = (const float*)d_in[21];
    const float* txt_proj_w = (const float*)d_in[22];
    const float* txt_proj_b = (const float*)d_in[23];
    const float* txt_mlp_w1 = (const float*)d_in[24];
    const float* txt_mlp_b1 = (const float*)d_in[25];
    const float* txt_mlp_w2 = (const float*)d_in[26];
    const float* txt_mlp_b2 = (const float*)d_in[27];
    float* out = (float*)d_out;

    float *sv, *modi, *modt, *x, *qkvb, *q, *k, *v, *scores, *attn, *x1, *x2, *h1;
    cudaGetSymbolAddress((void**)&sv,     g_silu);
    cudaGetSymbolAddress((void**)&modi,   g_mod_img);
    cudaGetSymbolAddress((void**)&modt,   g_mod_txt);
    cudaGetSymbolAddress((void**)&x,      g_x);
    cudaGetSymbolAddress((void**)&qkvb,   g_qkv);
    cudaGetSymbolAddress((void**)&q,      g_q);
    cudaGetSymbolAddress((void**)&k,      g_k);
    cudaGetSymbolAddress((void**)&v,      g_v);
    cudaGetSymbolAddress((void**)&scores, g_scores);
    cudaGetSymbolAddress((void**)&attn,   g_attn);
    cudaGetSymbolAddress((void**)&x1,     g_x1);
    cudaGetSymbolAddress((void**)&x2,     g_x2);
    cudaGetSymbolAddress((void**)&h1,     g_h1);

    // 1. silu(vec)
    silu_kernel<<<HS / 256, 256>>>(vec, sv);

    // 2. modulation params
    mod_gemv<<<(6 * HS) / 256, 256>>>(sv, img_mod_w, img_mod_b, modi);
    mod_gemv<<<(6 * HS) / 256, 256>>>(sv, txt_mod_w, txt_mod_b, modt);

    // 3. LN + modulate (txt rows 0..511, img rows 512..2559)
    ln_mod<<<LTXT, 256>>>(txt, x,                       modt + 0 * HS, modt + 1 * HS);
    ln_mod<<<LIMG, 256>>>(img, x + (size_t)LTXT * HS,   modi + 0 * HS, modi + 1 * HS);

    // 4. QKV GEMMs
    launch_gemm(0, false, x, txt_qkv_w, txt_qkv_b, qkvb,
                LTXT, QKVW, HS, HS, QKVW, QKVW, 1, 0, 0, 0);
    launch_gemm(0, false, x + (size_t)LTXT * HS, img_qkv_w, img_qkv_b,
                qkvb + (size_t)LTXT * QKVW,
                LIMG, QKVW, HS, HS, QKVW, QKVW, 1, 0, 0, 0);

    // 5. RMS norm + RoPE + head-major scatter
    rms_rope<<<LTOT, 256>>>(qkvb, pe, txt_q_s, txt_k_s, img_q_s, img_k_s, q, k, v);

    // 6. scores = q @ k^T  (batched over heads, B transposed)
    launch_gemm(0, true, q, k, nullptr, scores,
                LTOT, LTOT, HD, HD, HD, LTOT,
                NH, (size_t)LTOT * HD, (size_t)LTOT * HD, (size_t)LTOT * LTOT);

    // 7. softmax with 1/sqrt(D)
    softmax2560<<<NH * LTOT, 256>>>(scores, 0.08838834764831845f);

    // 8. o = a @ v, written into [l][h*128+d]
    launch_gemm(0, false, scores, v, nullptr, attn,
                LTOT, HD, LTOT, LTOT, HD, HS,
                NH, (size_t)LTOT * LTOT, (size_t)LTOT * HD, (size_t)HD);

    // 9. proj + gated residual  -> x1
    launch_gemm(2, false, attn, txt_proj_w, txt_proj_b, x1,
                LTXT, HS, HS, HS, HS, HS, 1, 0, 0, 0,
                modt + 2 * HS, txt, HS);
    launch_gemm(2, false, attn + (size_t)LTXT * HS, img_proj_w, img_proj_b,
                x1 + (size_t)LTXT * HS,
                LIMG, HS, HS, HS, HS, HS, 1, 0, 0, 0,
                modi + 2 * HS, img, HS);

    // 10. second LN + modulate -> x2
    ln_mod<<<LTXT, 256>>>(x1, x2,                                   modt + 3 * HS, modt + 4 * HS);
    ln_mod<<<LIMG, 256>>>(x1 + (size_t)LTXT * HS, x2 + (size_t)LTXT * HS, modi + 3 * HS, modi + 4 * HS);

    // 11. MLP1 with fused GELU -> h1
    launch_gemm(1, false, x2, txt_mlp_w1, txt_mlp_b1, h1,
                LTXT, MLPD, HS, HS, MLPD, MLPD, 1, 0, 0, 0);
    launch_gemm(1, false, x2 + (size_t)LTXT * HS, img_mlp_w1, img_mlp_b1,
                h1 + (size_t)LTXT * MLPD,
                LIMG, MLPD, HS, HS, MLPD, MLPD, 1, 0, 0, 0);

    // 12. MLP2 with fused gated residual, written straight to d_out
    //     output layout: img (2048*3072) then txt (512*3072)
    launch_gemm(2, false, h1, txt_mlp_w2, txt_mlp_b2,
                out + (size_t)LIMG * HS,
                LTXT, HS, MLPD, MLPD, HS, HS, 1, 0, 0, 0,
                modt + 5 * HS, x1, HS);
    launch_gemm(2, false, h1 + (size_t)LTXT * MLPD, img_mlp_w2, img_mlp_b2,
                out,
                LIMG, HS, MLPD, MLPD, HS, HS, 1, 0, 0, 0,
                modi + 5 * HS, x1 + (size_t)LTXT * HS, HS);
}

// round 3
// speedup vs baseline: 2.3105x; 2.3067x over previous
#include <cuda_runtime.h>
#include <cuda_bf16.h>
#include <math.h>

// ---------------------------------------------------------------------------
// Problem constants
// ---------------------------------------------------------------------------
#define HS    3072
#define MLPD  12288
#define NH    24
#define HD    128
#define LTXT  512
#define LIMG  2048
#define LTOT  2560          // txt rows [0,512), img rows [512,2560)
#define QKVW  9216          // 3*HS

// ---------------------------------------------------------------------------
// Static device scratch (no allocations allowed)
// ---------------------------------------------------------------------------
__device__ float g_silu[HS];
__device__ float g_mod_img[6 * HS];
__device__ float g_mod_txt[6 * HS];
__device__ float g_x   [(size_t)LTOT * HS];       // modulated LN input
__device__ float g_qkv [(size_t)LTOT * QKVW];
__device__ float g_q   [(size_t)NH * LTOT * HD];
__device__ float g_k   [(size_t)NH * LTOT * HD];
__device__ float g_v   [(size_t)NH * LTOT * HD];
__device__ float g_scores[(size_t)NH * LTOT * LTOT];
__device__ float g_attn[(size_t)LTOT * HS];
__device__ float g_x1  [(size_t)LTOT * HS];       // after first residual
__device__ float g_x2  [(size_t)LTOT * HS];       // second modulated LN
__device__ float g_h1  [(size_t)LTOT * MLPD];     // MLP hidden

// ---------------------------------------------------------------------------
// Small elementwise kernels
// ---------------------------------------------------------------------------
__global__ void silu_kernel(const float* __restrict__ v, float* __restrict__ o) {
    int i = blockIdx.x * 256 + threadIdx.x;
    if (i < HS) {
        float x = v[i];
        o[i] = x / (1.0f + expf(-x));
    }
}

// m[j] = silu(vec) . w[:,j] + b[j]   (w: HS x 6HS row-major)
__global__ void mod_gemv(const float* __restrict__ sv, const float* __restrict__ w,
                         const float* __restrict__ b, float* __restrict__ out) {
    __shared__ float ssv[HS];
    for (int i = threadIdx.x; i < HS; i += 256) ssv[i] = sv[i];
    __syncthreads();
    int j = blockIdx.x * 256 + threadIdx.x;
    float acc = 0.0f;
    #pragma unroll 4
    for (int i = 0; i < HS; i++)
        acc += ssv[i] * w[(size_t)i * (6 * HS) + j];
    out[j] = acc + b[j];
}

// LayerNorm + modulate: dst = shift + (1+scale) * LN(x) ; one block per row
__global__ void ln_mod(const float* __restrict__ x, float* __restrict__ dst,
                       const float* __restrict__ shift, const float* __restrict__ scale) {
    int row = blockIdx.x;
    int t = threadIdx.x;
    const float* xr = x + (size_t)row * HS;
    float v[12];
    float s = 0.0f;
    #pragma unroll
    for (int i = 0; i < 12; i++) { v[i] = xr[t + i * 256]; s += v[i]; }
    __shared__ float red[256];
    red[t] = s; __syncthreads();
    for (int o = 128; o > 0; o >>= 1) { if (t < o) red[t] += red[t + o]; __syncthreads(); }
    float mean = red[0] * (1.0f / HS);
    __syncthreads();
    float s2 = 0.0f;
    #pragma unroll
    for (int i = 0; i < 12; i++) { float d = v[i] - mean; s2 += d * d; }
    red[t] = s2; __syncthreads();
    for (int o = 128; o > 0; o >>= 1) { if (t < o) red[t] += red[t + o]; __syncthreads(); }
    float inv = rsqrtf(red[0] * (1.0f / HS) + 1e-6f);
    float* dr = dst + (size_t)row * HS;
    #pragma unroll
    for (int i = 0; i < 12; i++) {
        int c = t + i * 256;
        dr[c] = shift[c] + (1.0f + scale[c]) * (v[i] - mean) * inv;
    }
}

// Per-head RMS-norm(q,k) + RoPE + scatter to [h][l][d]; copy v.
__global__ void rms_rope(const float* __restrict__ qkv, const float* __restrict__ pe,
                         const float* __restrict__ tqs, const float* __restrict__ tks,
                         const float* __restrict__ iqs, const float* __restrict__ iks,
                         float* __restrict__ Q, float* __restrict__ Kp, float* __restrict__ Vp) {
    int l = blockIdx.x;
    int w = threadIdx.x >> 5, lane = threadIdx.x & 31;
    const float* qs = (l < LTXT) ? tqs : iqs;
    const float* ks = (l < LTXT) ? tks : iks;
    const float* row = qkv + (size_t)l * QKVW;
    const float* peb = pe + (size_t)l * 256 + lane * 8; // 2 rope pairs per lane
    float4 p0 = *(const float4*)(peb);
    float4 p1 = *(const float4*)(peb + 4);
    int d0 = lane * 4;
    float4 scq = *(const float4*)(qs + d0);
    float4 sck = *(const float4*)(ks + d0);

    for (int h = w; h < NH; h += 8) {
        // ---- Q
        float4 xq = *(const float4*)(row + h * HD + d0);
        float ss = xq.x*xq.x + xq.y*xq.y + xq.z*xq.z + xq.w*xq.w;
        #pragma unroll
        for (int o = 16; o > 0; o >>= 1) ss += __shfl_xor_sync(0xffffffffu, ss, o);
        float r = rsqrtf(ss * (1.0f / HD) + 1e-6f);
        float x0 = xq.x * r * scq.x, x1 = xq.y * r * scq.y;
        float x2 = xq.z * r * scq.z, x3 = xq.w * r * scq.w;
        float4 oq;
        oq.x = p0.x * x0 + p0.y * x1;
        oq.y = p0.z * x0 + p0.w * x1;
        oq.z = p1.x * x2 + p1.y * x3;
        oq.w = p1.z * x2 + p1.w * x3;
        *(float4*)(Q + ((size_t)h * LTOT + l) * HD + d0) = oq;
        // ---- K
        float4 xk = *(const float4*)(row + HS + h * HD + d0);
        float sk = xk.x*xk.x + xk.y*xk.y + xk.z*xk.z + xk.w*xk.w;
        #pragma unroll
        for (int o = 16; o > 0; o >>= 1) sk += __shfl_xor_sync(0xffffffffu, sk, o);
        float rk = rsqrtf(sk * (1.0f / HD) + 1e-6f);
        float y0 = xk.x * rk * sck.x, y1 = xk.y * rk * sck.y;
        float y2 = xk.z * rk * sck.z, y3 = xk.w * rk * sck.w;
        float4 ok;
        ok.x = p0.x * y0 + p0.y * y1;
        ok.y = p0.z * y0 + p0.w * y1;
        ok.z = p1.x * y2 + p1.y * y3;
        ok.w = p1.z * y2 + p1.w * y3;
        *(float4*)(Kp + ((size_t)h * LTOT + l) * HD + d0) = ok;
        // ---- V copy
        float4 xv = *(const float4*)(row + 2 * HS + h * HD + d0);
        *(float4*)(Vp + ((size_t)h * LTOT + l) * HD + d0) = xv;
    }
}

// Row softmax over 2560 columns (with scale), one block per row
__global__ void softmax2560(float* __restrict__ S, float scale) {
    size_t row = blockIdx.x;
    float* sr = S + row * (size_t)LTOT;
    int t = threadIdx.x;
    float v[10];
    float mx = -1e30f;
    #pragma unroll
    for (int i = 0; i < 10; i++) { v[i] = sr[t + i * 256] * scale; mx = fmaxf(mx, v[i]); }
    __shared__ float red[256];
    red[t] = mx; __syncthreads();
    for (int o = 128; o > 0; o >>= 1) { if (t < o) red[t] = fmaxf(red[t], red[t + o]); __syncthreads(); }
    mx = red[0]; __syncthreads();
    float s = 0.0f;
    #pragma unroll
    for (int i = 0; i < 10; i++) { v[i] = expf(v[i] - mx); s += v[i]; }
    red[t] = s; __syncthreads();
    for (int o = 128; o > 0; o >>= 1) { if (t < o) red[t] += red[t + o]; __syncthreads(); }
    float inv = 1.0f / red[0];
    #pragma unroll
    for (int i = 0; i < 10; i++) sr[t + i * 256] = v[i] * inv;
}

// ---------------------------------------------------------------------------
// TF32 tensor-core GEMM: 128x128 block tile, 8 warps (2x4), 64x32 per warp,
// m16n8k8 mma, K-step 16, double-buffered smem.
// EPI: 0 = acc+bias ; 1 = gelu(acc+bias) ; 2 = resid + gate*(acc+bias)
// Requires: M%128==0, N%128==0, K%16==0.
// ---------------------------------------------------------------------------
__device__ __forceinline__ float gelu_tanh(float x) {
    float x3 = x * x * x;
    return 0.5f * x * (1.0f + tanhf(0.7978845608028654f * (x + 0.044715f * x3)));
}

__device__ __forceinline__ float to_tf32(float x) {
    unsigned int u;
    asm("cvt.rna.tf32.f32 %0, %1;" : "=r"(u) : "f"(x));
    return __uint_as_float(u);
}

__device__ __forceinline__ void mma_tf32(float c[4], const unsigned int a[4],
                                         const unsigned int b[2]) {
    asm volatile(
        "mma.sync.aligned.m16n8k8.row.col.f32.tf32.tf32.f32 "
        "{%0,%1,%2,%3}, {%4,%5,%6,%7}, {%8,%9}, {%0,%1,%2,%3};"
        : "+f"(c[0]), "+f"(c[1]), "+f"(c[2]), "+f"(c[3])
        : "r"(a[0]), "r"(a[1]), "r"(a[2]), "r"(a[3]), "r"(b[0]), "r"(b[1]));
}

template <bool TRANSB, int EPI>
__global__ void __launch_bounds__(256, 2)
mma_gemm(const float* __restrict__ A, const float* __restrict__ B,
         const float* __restrict__ bias, float* __restrict__ C,
         int K, int lda, int ldb, int ldc,
         size_t sA, size_t sB, size_t sC,
         const float* __restrict__ gate, const float* __restrict__ resid, int ldres) {
    A += (size_t)blockIdx.z * sA;
    B += (size_t)blockIdx.z * sB;
    C += (size_t)blockIdx.z * sC;

    __shared__ float As[2][16][132];
    __shared__ float Bs[2][16][132];

    const int t = threadIdx.x;
    const int wid = t >> 5, lane = t & 31;
    const int wm = wid >> 2, wn = wid & 3;
    const int gid = lane >> 2, tig = lane & 3;
    const int m0 = blockIdx.y * 128, n0 = blockIdx.x * 128;

    // global load indices
    const int a_m = t >> 1, a_k = (t & 1) * 4;        // A: 2 float4 per thread
    const int bt_n = t >> 1, bt_k = (t & 1) * 4;      // TRANSB
    const int b_k = t >> 5,  b_n = (t & 31) * 4;      // !TRANSB

    const float* Ap = A + (size_t)(m0 + a_m) * lda + a_k;
    const float* Bp = TRANSB ? B + (size_t)(n0 + bt_n) * ldb + bt_k
                             : B + (size_t)b_k * ldb + n0 + b_n;

    float c[4][4][4];
    #pragma unroll
    for (int i = 0; i < 4; i++)
        #pragma unroll
        for (int j = 0; j < 4; j++)
            #pragma unroll
            for (int r = 0; r < 4; r++) c[i][j][r] = 0.0f;

    const int nk = K / 16;
    float4 pa0, pa1, pb0, pb1;

    // prologue: load tile 0
    pa0 = *(const float4*)(Ap);
    pa1 = *(const float4*)(Ap + 8);
    if (TRANSB) {
        pb0 = *(const float4*)(Bp);
        pb1 = *(const float4*)(Bp + 8);
    } else {
        pb0 = *(const float4*)(Bp);
        pb1 = *(const float4*)(Bp + (size_t)8 * ldb);
    }
    // store tile 0 into buf 0
    {
        As[0][a_k + 0][a_m] = to_tf32(pa0.x); As[0][a_k + 1][a_m] = to_tf32(pa0.y);
        As[0][a_k + 2][a_m] = to_tf32(pa0.z); As[0][a_k + 3][a_m] = to_tf32(pa0.w);
        As[0][a_k + 8][a_m] = to_tf32(pa1.x); As[0][a_k + 9][a_m] = to_tf32(pa1.y);
        As[0][a_k +10][a_m] = to_tf32(pa1.z); As[0][a_k +11][a_m] = to_tf32(pa1.w);
        if (TRANSB) {
            Bs[0][bt_k + 0][bt_n] = to_tf32(pb0.x); Bs[0][bt_k + 1][bt_n] = to_tf32(pb0.y);
            Bs[0][bt_k + 2][bt_n] = to_tf32(pb0.z); Bs[0][bt_k + 3][bt_n] = to_tf32(pb0.w);
            Bs[0][bt_k + 8][bt_n] = to_tf32(pb1.x); Bs[0][bt_k + 9][bt_n] = to_tf32(pb1.y);
            Bs[0][bt_k +10][bt_n] = to_tf32(pb1.z); Bs[0][bt_k +11][bt_n] = to_tf32(pb1.w);
        } else {
            float4 q0 = make_float4(to_tf32(pb0.x), to_tf32(pb0.y), to_tf32(pb0.z), to_tf32(pb0.w));
            float4 q1 = make_float4(to_tf32(pb1.x), to_tf32(pb1.y), to_tf32(pb1.z), to_tf32(pb1.w));
            *(float4*)(&Bs[0][b_k][b_n])     = q0;
            *(float4*)(&Bs[0][b_k + 8][b_n]) = q1;
        }
    }
    __syncthreads();

    for (int kt = 0; kt < nk; kt++) {
        const int buf = kt & 1;
        const bool has_next = (kt + 1 < nk);
        if (has_next) {
            const int off = (kt + 1) * 16;
            pa0 = *(const float4*)(Ap + off);
            pa1 = *(const float4*)(Ap + off + 8);
            if (TRANSB) {
                pb0 = *(const float4*)(Bp + off);
                pb1 = *(const float4*)(Bp + off + 8);
            } else {
                pb0 = *(const float4*)(Bp + (size_t)off * ldb);
                pb1 = *(const float4*)(Bp + (size_t)(off + 8) * ldb);
            }
        }

        // compute on current buffer
        #pragma unroll
        for (int ks = 0; ks < 2; ks++) {
            const int kb = ks * 8;
            unsigned int af[4][4], bf[4][2];
            #pragma unroll
            for (int mt = 0; mt < 4; mt++) {
                const int bm = wm * 64 + mt * 16 + gid;
                af[mt][0] = __float_as_uint(As[buf][kb + tig    ][bm]);
                af[mt][1] = __float_as_uint(As[buf][kb + tig    ][bm + 8]);
                af[mt][2] = __float_as_uint(As[buf][kb + tig + 4][bm]);
                af[mt][3] = __float_as_uint(As[buf][kb + tig + 4][bm + 8]);
            }
            #pragma unroll
            for (int nt = 0; nt < 4; nt++) {
                const int bn = wn * 32 + nt * 8 + gid;
                bf[nt][0] = __float_as_uint(Bs[buf][kb + tig    ][bn]);
                bf[nt][1] = __float_as_uint(Bs[buf][kb + tig + 4][bn]);
            }
            #pragma unroll
            for (int mt = 0; mt < 4; mt++)
                #pragma unroll
                for (int nt = 0; nt < 4; nt++)
                    mma_tf32(c[mt][nt], af[mt], bf[nt]);
        }

        if (has_next) {
            const int nb = buf ^ 1;
            As[nb][a_k + 0][a_m] = to_tf32(pa0.x); As[nb][a_k + 1][a_m] = to_tf32(pa0.y);
            As[nb][a_k + 2][a_m] = to_tf32(pa0.z); As[nb][a_k + 3][a_m] = to_tf32(pa0.w);
            As[nb][a_k + 8][a_m] = to_tf32(pa1.x); As[nb][a_k + 9][a_m] = to_tf32(pa1.y);
            As[nb][a_k +10][a_m] = to_tf32(pa1.z); As[nb][a_k +11][a_m] = to_tf32(pa1.w);
            if (TRANSB) {
                Bs[nb][bt_k + 0][bt_n] = to_tf32(pb0.x); Bs[nb][bt_k + 1][bt_n] = to_tf32(pb0.y);
                Bs[nb][bt_k + 2][bt_n] = to_tf32(pb0.z); Bs[nb][bt_k + 3][bt_n] = to_tf32(pb0.w);
                Bs[nb][bt_k + 8][bt_n] = to_tf32(pb1.x); Bs[nb][bt_k + 9][bt_n] = to_tf32(pb1.y);
                Bs[nb][bt_k +10][bt_n] = to_tf32(pb1.z); Bs[nb][bt_k +11][bt_n] = to_tf32(pb1.w);
            } else {
                float4 q0 = make_float4(to_tf32(pb0.x), to_tf32(pb0.y), to_tf32(pb0.z), to_tf32(pb0.w));
                float4 q1 = make_float4(to_tf32(pb1.x), to_tf32(pb1.y), to_tf32(pb1.z), to_tf32(pb1.w));
                *(float4*)(&Bs[nb][b_k][b_n])     = q0;
                *(float4*)(&Bs[nb][b_k + 8][b_n]) = q1;
            }
        }
        __syncthreads();
    }

    // epilogue
    #pragma unroll
    for (int nt = 0; nt < 4; nt++) {
        const int col = n0 + wn * 32 + nt * 8 + tig * 2;
        const float bv0 = bias ? bias[col]     : 0.0f;
        const float bv1 = bias ? bias[col + 1] : 0.0f;
        float gv0 = 0.0f, gv1 = 0.0f;
        if (EPI == 2) { gv0 = gate[col]; gv1 = gate[col + 1]; }
        #pragma unroll
        for (int mt = 0; mt < 4; mt++) {
            const int row0 = m0 + wm * 64 + mt * 16 + gid;
            #pragma unroll
            for (int h = 0; h < 2; h++) {
                const int row = row0 + h * 8;
                float v0 = c[mt][nt][h * 2 + 0] + bv0;
                float v1 = c[mt][nt][h * 2 + 1] + bv1;
                if (EPI == 1) { v0 = gelu_tanh(v0); v1 = gelu_tanh(v1); }
                if (EPI == 2) {
                    const float* Rr = resid + (size_t)row * ldres + col;
                    v0 = Rr[0] + gv0 * v0;
                    v1 = Rr[1] + gv1 * v1;
                }
                *(float2*)(C + (size_t)row * ldc + col) = make_float2(v0, v1);
            }
        }
    }
}

// ---------------------------------------------------------------------------
// Host launcher
// ---------------------------------------------------------------------------
static void launch_gemm(int epi, bool transB,
                        const float* A, const float* B, const float* bias, float* C,
                        int M, int N, int K, int lda, int ldb, int ldc,
                        int batch, size_t sA, size_t sB, size_t sC,
                        const float* gate = nullptr, const float* resid = nullptr, int ldres = 0) {
    dim3 grid(N / 128, M / 128, batch);
    if (transB) {
        mma_gemm<true, 0><<<grid, 256>>>(A, B, bias, C, K, lda, ldb, ldc, sA, sB, sC, gate, resid, ldres);
    } else if (epi == 0) {
        mma_gemm<false, 0><<<grid, 256>>>(A, B, bias, C, K, lda, ldb, ldc, sA, sB, sC, gate, resid, ldres);
    } else if (epi == 1) {
        mma_gemm<false, 1><<<grid, 256>>>(A, B, bias, C, K, lda, ldb, ldc, sA, sB, sC, gate, resid, ldres);
    } else {
        mma_gemm<false, 2><<<grid, 256>>>(A, B, bias, C, K, lda, ldb, ldc, sA, sB, sC, gate, resid, ldres);
    }
}

extern "C" void kernel_launch(void* const* d_in, const int* in_sizes, int n_in,
                              void* d_out, int out_size) {
    const float* img        = (const float*)d_in[0];
    const float* txt        = (const float*)d_in[1];
    const float* vec        = (const float*)d_in[2];
    const float* pe         = (const float*)d_in[3];
    const float* img_mod_w  = (const float*)d_in[4];
    const float* img_mod_b  = (const float*)d_in[5];
    const float* img_qkv_w  = (const float*)d_in[6];
    const float* img_qkv_b  = (const float*)d_in[7];
    const float* img_q_s    = (const float*)d_in[8];
    const float* img_k_s    = (const float*)d_in[9];
    const float* img_proj_w = (const float*)d_in[10];
    const float* img_proj_b = (const float*)d_in[11];
    const float* img_mlp_w1 = (const float*)d_in[12];
    const float* img_mlp_b1 = (const float*)d_in[13];
    const float* img_mlp_w2 = (const float*)d_in[14];
    const float* img_mlp_b2 = (const float*)d_in[15];
    const float* txt_mod_w  = (const float*)d_in[16];
    const float* txt_mod_b  = (const float*)d_in[17];
    const float* txt_qkv_w  = (const float*)d_in[18];
    const float* txt_qkv_b  = (const float*)d_in[19];
    const float* txt_q_s    = (const float*)d_in[20];
    const float* txt_k_s    = (const float*)d_in[21];
    const float* txt_proj_w = (const float*)d_in[22];
    const float* txt_proj_b = (const float*)d_in[23];
    const float* txt_mlp_w1 = (const float*)d_in[24];
    const float* txt_mlp_b1 = (const float*)d_in[25];
    const float* txt_mlp_w2 = (const float*)d_in[26];
    const float* txt_mlp_b2 = (const float*)d_in[27];
    float* out = (float*)d_out;

    float *sv, *modi, *modt, *x, *qkvb, *q, *k, *v, *scores, *attn, *x1, *x2, *h1;
    cudaGetSymbolAddress((void**)&sv,     g_silu);
    cudaGetSymbolAddress((void**)&modi,   g_mod_img);
    cudaGetSymbolAddress((void**)&modt,   g_mod_txt);
    cudaGetSymbolAddress((void**)&x,      g_x);
    cudaGetSymbolAddress((void**)&qkvb,   g_qkv);
    cudaGetSymbolAddress((void**)&q,      g_q);
    cudaGetSymbolAddress((void**)&k,      g_k);
    cudaGetSymbolAddress((void**)&v,      g_v);
    cudaGetSymbolAddress((void**)&scores, g_scores);
    cudaGetSymbolAddress((void**)&attn,   g_attn);
    cudaGetSymbolAddress((void**)&x1,     g_x1);
    cudaGetSymbolAddress((void**)&x2,     g_x2);
    cudaGetSymbolAddress((void**)&h1,     g_h1);

    // 1. silu(vec)
    silu_kernel<<<HS / 256, 256>>>(vec, sv);

    // 2. modulation params
    mod_gemv<<<(6 * HS) / 256, 256>>>(sv, img_mod_w, img_mod_b, modi);
    mod_gemv<<<(6 * HS) / 256, 256>>>(sv, txt_mod_w, txt_mod_b, modt);

    // 3. LN + modulate (txt rows 0..511, img rows 512..2559)
    ln_mod<<<LTXT, 256>>>(txt, x,                       modt + 0 * HS, modt + 1 * HS);
    ln_mod<<<LIMG, 256>>>(img, x + (size_t)LTXT * HS,   modi + 0 * HS, modi + 1 * HS);

    // 4. QKV GEMMs
    launch_gemm(0, false, x, txt_qkv_w, txt_qkv_b, qkvb,
                LTXT, QKVW, HS, HS, QKVW, QKVW, 1, 0, 0, 0);
    launch_gemm(0, false, x + (size_t)LTXT * HS, img_qkv_w, img_qkv_b,
                qkvb + (size_t)LTXT * QKVW,
                LIMG, QKVW, HS, HS, QKVW, QKVW, 1, 0, 0, 0);

    // 5. RMS norm + RoPE + head-major scatter
    rms_rope<<<LTOT, 256>>>(qkvb, pe, txt_q_s, txt_k_s, img_q_s, img_k_s, q, k, v);

    // 6. scores = q @ k^T  (batched over heads, B transposed)
    launch_gemm(0, true, q, k, nullptr, scores,
                LTOT, LTOT, HD, HD, HD, LTOT,
                NH, (size_t)LTOT * HD, (size_t)LTOT * HD, (size_t)LTOT * LTOT);

    // 7. softmax with 1/sqrt(D)
    softmax2560<<<NH * LTOT, 256>>>(scores, 0.08838834764831845f);

    // 8. o = a @ v, written into [l][h*128+d]
    launch_gemm(0, false, scores, v, nullptr, attn,
                LTOT, HD, LTOT, LTOT, HD, HS,
                NH, (size_t)LTOT * LTOT, (size_t)LTOT * HD, (size_t)HD);

    // 9. proj + gated residual  -> x1
    launch_gemm(2, false, attn, txt_proj_w, txt_proj_b, x1,
                LTXT, HS, HS, HS, HS, HS, 1, 0, 0, 0,
                modt + 2 * HS, txt, HS);
    launch_gemm(2, false, attn + (size_t)LTXT * HS, img_proj_w, img_proj_b,
                x1 + (size_t)LTXT * HS,
                LIMG, HS, HS, HS, HS, HS, 1, 0, 0, 0,
                modi + 2 * HS, img, HS);

    // 10. second LN + modulate -> x2
    ln_mod<<<LTXT, 256>>>(x1, x2,                                   modt + 3 * HS, modt + 4 * HS);
    ln_mod<<<LIMG, 256>>>(x1 + (size_t)LTXT * HS, x2 + (size_t)LTXT * HS, modi + 3 * HS, modi + 4 * HS);

    // 11. MLP1 with fused GELU -> h1
    launch_gemm(1, false, x2, txt_mlp_w1, txt_mlp_b1, h1,
                LTXT, MLPD, HS, HS, MLPD, MLPD, 1, 0, 0, 0);
    launch_gemm(1, false, x2 + (size_t)LTXT * HS, img_mlp_w1, img_mlp_b1,
                h1 + (size_t)LTXT * MLPD,
                LIMG, MLPD, HS, HS, MLPD, MLPD, 1, 0, 0, 0);

    // 12. MLP2 with fused gated residual, written straight to d_out
    //     output layout: img (2048*3072) then txt (512*3072)
    launch_gemm(2, false, h1, txt_mlp_w2, txt_mlp_b2,
                out + (size_t)LIMG * HS,
                LTXT, HS, MLPD, MLPD, HS, HS, 1, 0, 0, 0,
                modt + 5 * HS, x1, HS);
    launch_gemm(2, false, h1 + (size_t)LTXT * MLPD, img_mlp_w2, img_mlp_b2,
                out,
                LIMG, HS, MLPD, MLPD, HS, HS, 1, 0, 0, 0,
                modi + 5 * HS, x1 + (size_t)LTXT * HS, HS);
}

// round 4
// speedup vs baseline: 2.3133x; 1.0012x over previous
#include <cuda_runtime.h>
#include <cuda_bf16.h>
#include <math.h>

// ---------------------------------------------------------------------------
// Problem constants
// ---------------------------------------------------------------------------
#define HS    3072
#define MLPD  12288
#define NH    24
#define HD    128
#define LTXT  512
#define LIMG  2048
#define LTOT  2560          // txt rows [0,512), img rows [512,2560)
#define QKVW  9216          // 3*HS

// ---------------------------------------------------------------------------
// Static device scratch (no allocations allowed)
// ---------------------------------------------------------------------------
__device__ float g_silu[HS];
__device__ float g_mod_img[6 * HS];
__device__ float g_mod_txt[6 * HS];
__device__ float g_x   [(size_t)LTOT * HS];       // modulated LN input
__device__ float g_qkv [(size_t)LTOT * QKVW];
__device__ float g_q   [(size_t)NH * LTOT * HD];
__device__ float g_k   [(size_t)NH * LTOT * HD];
__device__ float g_v   [(size_t)NH * LTOT * HD];
__device__ float g_scores[(size_t)NH * LTOT * LTOT];
__device__ float g_attn[(size_t)LTOT * HS];
__device__ float g_x1  [(size_t)LTOT * HS];       // after first residual
__device__ float g_x2  [(size_t)LTOT * HS];       // second modulated LN
__device__ float g_h1  [(size_t)LTOT * MLPD];     // MLP hidden

// ---------------------------------------------------------------------------
// Small elementwise kernels
// ---------------------------------------------------------------------------
__global__ void silu_kernel(const float* __restrict__ v, float* __restrict__ o) {
    int i = blockIdx.x * 256 + threadIdx.x;
    if (i < HS) {
        float x = v[i];
        o[i] = x / (1.0f + expf(-x));
    }
}

// m[j] = silu(vec) . w[:,j] + b[j]   (w: HS x 6HS row-major)
__global__ void mod_gemv(const float* __restrict__ sv, const float* __restrict__ w,
                         const float* __restrict__ b, float* __restrict__ out) {
    __shared__ float ssv[HS];
    for (int i = threadIdx.x; i < HS; i += 256) ssv[i] = sv[i];
    __syncthreads();
    int j = blockIdx.x * 256 + threadIdx.x;
    float acc = 0.0f;
    #pragma unroll 4
    for (int i = 0; i < HS; i++)
        acc += ssv[i] * w[(size_t)i * (6 * HS) + j];
    out[j] = acc + b[j];
}

// LayerNorm + modulate: dst = shift + (1+scale) * LN(x) ; one block per row
__global__ void ln_mod(const float* __restrict__ x, float* __restrict__ dst,
                       const float* __restrict__ shift, const float* __restrict__ scale) {
    int row = blockIdx.x;
    int t = threadIdx.x;
    const float* xr = x + (size_t)row * HS;
    float v[12];
    float s = 0.0f;
    #pragma unroll
    for (int i = 0; i < 12; i++) { v[i] = xr[t + i * 256]; s += v[i]; }
    __shared__ float red[256];
    red[t] = s; __syncthreads();
    for (int o = 128; o > 0; o >>= 1) { if (t < o) red[t] += red[t + o]; __syncthreads(); }
    float mean = red[0] * (1.0f / HS);
    __syncthreads();
    float s2 = 0.0f;
    #pragma unroll
    for (int i = 0; i < 12; i++) { float d = v[i] - mean; s2 += d * d; }
    red[t] = s2; __syncthreads();
    for (int o = 128; o > 0; o >>= 1) { if (t < o) red[t] += red[t + o]; __syncthreads(); }
    float inv = rsqrtf(red[0] * (1.0f / HS) + 1e-6f);
    float* dr = dst + (size_t)row * HS;
    #pragma unroll
    for (int i = 0; i < 12; i++) {
        int c = t + i * 256;
        dr[c] = shift[c] + (1.0f + scale[c]) * (v[i] - mean) * inv;
    }
}

// Per-head RMS-norm(q,k) + RoPE + scatter to [h][l][d]; copy v.
__global__ void rms_rope(const float* __restrict__ qkv, const float* __restrict__ pe,
                         const float* __restrict__ tqs, const float* __restrict__ tks,
                         const float* __restrict__ iqs, const float* __restrict__ iks,
                         float* __restrict__ Q, float* __restrict__ Kp, float* __restrict__ Vp) {
    int l = blockIdx.x;
    int w = threadIdx.x >> 5, lane = threadIdx.x & 31;
    const float* qs = (l < LTXT) ? tqs : iqs;
    const float* ks = (l < LTXT) ? tks : iks;
    const float* row = qkv + (size_t)l * QKVW;
    const float* peb = pe + (size_t)l * 256 + lane * 8; // 2 rope pairs per lane
    float4 p0 = *(const float4*)(peb);
    float4 p1 = *(const float4*)(peb + 4);
    int d0 = lane * 4;
    float4 scq = *(const float4*)(qs + d0);
    float4 sck = *(const float4*)(ks + d0);

    for (int h = w; h < NH; h += 8) {
        // ---- Q
        float4 xq = *(const float4*)(row + h * HD + d0);
        float ss = xq.x*xq.x + xq.y*xq.y + xq.z*xq.z + xq.w*xq.w;
        #pragma unroll
        for (int o = 16; o > 0; o >>= 1) ss += __shfl_xor_sync(0xffffffffu, ss, o);
        float r = rsqrtf(ss * (1.0f / HD) + 1e-6f);
        float x0 = xq.x * r * scq.x, x1 = xq.y * r * scq.y;
        float x2 = xq.z * r * scq.z, x3 = xq.w * r * scq.w;
        float4 oq;
        oq.x = p0.x * x0 + p0.y * x1;
        oq.y = p0.z * x0 + p0.w * x1;
        oq.z = p1.x * x2 + p1.y * x3;
        oq.w = p1.z * x2 + p1.w * x3;
        *(float4*)(Q + ((size_t)h * LTOT + l) * HD + d0) = oq;
        // ---- K
        float4 xk = *(const float4*)(row + HS + h * HD + d0);
        float sk = xk.x*xk.x + xk.y*xk.y + xk.z*xk.z + xk.w*xk.w;
        #pragma unroll
        for (int o = 16; o > 0; o >>= 1) sk += __shfl_xor_sync(0xffffffffu, sk, o);
        float rk = rsqrtf(sk * (1.0f / HD) + 1e-6f);
        float y0 = xk.x * rk * sck.x, y1 = xk.y * rk * sck.y;
        float y2 = xk.z * rk * sck.z, y3 = xk.w * rk * sck.w;
        float4 ok;
        ok.x = p0.x * y0 + p0.y * y1;
        ok.y = p0.z * y0 + p0.w * y1;
        ok.z = p1.x * y2 + p1.y * y3;
        ok.w = p1.z * y2 + p1.w * y3;
        *(float4*)(Kp + ((size_t)h * LTOT + l) * HD + d0) = ok;
        // ---- V copy
        float4 xv = *(const float4*)(row + 2 * HS + h * HD + d0);
        *(float4*)(Vp + ((size_t)h * LTOT + l) * HD + d0) = xv;
    }
}

// Row softmax over 2560 columns (with scale), one block per row
__global__ void softmax2560(float* __restrict__ S, float scale) {
    size_t row = blockIdx.x;
    float* sr = S + row * (size_t)LTOT;
    int t = threadIdx.x;
    float v[10];
    float mx = -1e30f;
    #pragma unroll
    for (int i = 0; i < 10; i++) { v[i] = sr[t + i * 256] * scale; mx = fmaxf(mx, v[i]); }
    __shared__ float red[256];
    red[t] = mx; __syncthreads();
    for (int o = 128; o > 0; o >>= 1) { if (t < o) red[t] = fmaxf(red[t], red[t + o]); __syncthreads(); }
    mx = red[0]; __syncthreads();
    float s = 0.0f;
    #pragma unroll
    for (int i = 0; i < 10; i++) { v[i] = expf(v[i] - mx); s += v[i]; }
    red[t] = s; __syncthreads();
    for (int o = 128; o > 0; o >>= 1) { if (t < o) red[t] += red[t + o]; __syncthreads(); }
    float inv = 1.0f / red[0];
    #pragma unroll
    for (int i = 0; i < 10; i++) sr[t + i * 256] = v[i] * inv;
}

// ---------------------------------------------------------------------------
// TF32 tensor-core GEMM: 128x128 block tile, 8 warps (2x4), 64x32 per warp,
// m16n8k8 mma, K-step 16, double-buffered smem.
// EPI: 0 = acc+bias ; 1 = gelu(acc+bias) ; 2 = resid + gate*(acc+bias)
// Requires: M%128==0, N%128==0, K%16==0.
// ---------------------------------------------------------------------------
__device__ __forceinline__ float gelu_tanh(float x) {
    float x3 = x * x * x;
    return 0.5f * x * (1.0f + tanhf(0.7978845608028654f * (x + 0.044715f * x3)));
}

__device__ __forceinline__ float to_tf32(float x) {
    unsigned int u;
    asm("cvt.rna.tf32.f32 %0, %1;" : "=r"(u) : "f"(x));
    return __uint_as_float(u);
}

__device__ __forceinline__ void mma_tf32(float c[4], const unsigned int a[4],
                                         const unsigned int b[2]) {
    asm volatile(
        "mma.sync.aligned.m16n8k8.row.col.f32.tf32.tf32.f32 "
        "{%0,%1,%2,%3}, {%4,%5,%6,%7}, {%8,%9}, {%0,%1,%2,%3};"
        : "+f"(c[0]), "+f"(c[1]), "+f"(c[2]), "+f"(c[3])
        : "r"(a[0]), "r"(a[1]), "r"(a[2]), "r"(a[3]), "r"(b[0]), "r"(b[1]));
}

template <bool TRANSB, int EPI>
__global__ void __launch_bounds__(256, 2)
mma_gemm(const float* __restrict__ A, const float* __restrict__ B,
         const float* __restrict__ bias, float* __restrict__ C,
         int K, int lda, int ldb, int ldc,
         size_t sA, size_t sB, size_t sC,
         const float* __restrict__ gate, const float* __restrict__ resid, int ldres) {
    A += (size_t)blockIdx.z * sA;
    B += (size_t)blockIdx.z * sB;
    C += (size_t)blockIdx.z * sC;

    __shared__ float As[2][16][132];
    __shared__ float Bs[2][16][132];

    const int t = threadIdx.x;
    const int wid = t >> 5, lane = t & 31;
    const int wm = wid >> 2, wn = wid & 3;
    const int gid = lane >> 2, tig = lane & 3;
    const int m0 = blockIdx.y * 128, n0 = blockIdx.x * 128;

    // global load indices
    const int a_m = t >> 1, a_k = (t & 1) * 4;        // A: 2 float4 per thread
    const int bt_n = t >> 1, bt_k = (t & 1) * 4;      // TRANSB
    const int b_k = t >> 5,  b_n = (t & 31) * 4;      // !TRANSB

    const float* Ap = A + (size_t)(m0 + a_m) * lda + a_k;
    const float* Bp = TRANSB ? B + (size_t)(n0 + bt_n) * ldb + bt_k
                             : B + (size_t)b_k * ldb + n0 + b_n;

    float c[4][4][4];
    #pragma unroll
    for (int i = 0; i < 4; i++)
        #pragma unroll
        for (int j = 0; j < 4; j++)
            #pragma unroll
            for (int r = 0; r < 4; r++) c[i][j][r] = 0.0f;

    const int nk = K / 16;
    float4 pa0, pa1, pb0, pb1;

    // prologue: load tile 0
    pa0 = *(const float4*)(Ap);
    pa1 = *(const float4*)(Ap + 8);
    if (TRANSB) {
        pb0 = *(const float4*)(Bp);
        pb1 = *(const float4*)(Bp + 8);
    } else {
        pb0 = *(const float4*)(Bp);
        pb1 = *(const float4*)(Bp + (size_t)8 * ldb);
    }
    // store tile 0 into buf 0
    {
        As[0][a_k + 0][a_m] = to_tf32(pa0.x); As[0][a_k + 1][a_m] = to_tf32(pa0.y);
        As[0][a_k + 2][a_m] = to_tf32(pa0.z); As[0][a_k + 3][a_m] = to_tf32(pa0.w);
        As[0][a_k + 8][a_m] = to_tf32(pa1.x); As[0][a_k + 9][a_m] = to_tf32(pa1.y);
        As[0][a_k +10][a_m] = to_tf32(pa1.z); As[0][a_k +11][a_m] = to_tf32(pa1.w);
        if (TRANSB) {
            Bs[0][bt_k + 0][bt_n] = to_tf32(pb0.x); Bs[0][bt_k + 1][bt_n] = to_tf32(pb0.y);
            Bs[0][bt_k + 2][bt_n] = to_tf32(pb0.z); Bs[0][bt_k + 3][bt_n] = to_tf32(pb0.w);
            Bs[0][bt_k + 8][bt_n] = to_tf32(pb1.x); Bs[0][bt_k + 9][bt_n] = to_tf32(pb1.y);
            Bs[0][bt_k +10][bt_n] = to_tf32(pb1.z); Bs[0][bt_k +11][bt_n] = to_tf32(pb1.w);
        } else {
            float4 q0 = make_float4(to_tf32(pb0.x), to_tf32(pb0.y), to_tf32(pb0.z), to_tf32(pb0.w));
            float4 q1 = make_float4(to_tf32(pb1.x), to_tf32(pb1.y), to_tf32(pb1.z), to_tf32(pb1.w));
            *(float4*)(&Bs[0][b_k][b_n])     = q0;
            *(float4*)(&Bs[0][b_k + 8][b_n]) = q1;
        }
    }
    __syncthreads();

    for (int kt = 0; kt < nk; kt++) {
        const int buf = kt & 1;
        const bool has_next = (kt + 1 < nk);
        if (has_next) {
            const int off = (kt + 1) * 16;
            pa0 = *(const float4*)(Ap + off);
            pa1 = *(const float4*)(Ap + off + 8);
            if (TRANSB) {
                pb0 = *(const float4*)(Bp + off);
                pb1 = *(const float4*)(Bp + off + 8);
            } else {
                pb0 = *(const float4*)(Bp + (size_t)off * ldb);
                pb1 = *(const float4*)(Bp + (size_t)(off + 8) * ldb);
            }
        }

        // compute on current buffer
        #pragma unroll
        for (int ks = 0; ks < 2; ks++) {
            const int kb = ks * 8;
            unsigned int af[4][4], bf[4][2];
            #pragma unroll
            for (int mt = 0; mt < 4; mt++) {
                const int bm = wm * 64 + mt * 16 + gid;
                af[mt][0] = __float_as_uint(As[buf][kb + tig    ][bm]);
                af[mt][1] = __float_as_uint(As[buf][kb + tig    ][bm + 8]);
                af[mt][2] = __float_as_uint(As[buf][kb + tig + 4][bm]);
                af[mt][3] = __float_as_uint(As[buf][kb + tig + 4][bm + 8]);
            }
            #pragma unroll
            for (int nt = 0; nt < 4; nt++) {
                const int bn = wn * 32 + nt * 8 + gid;
                bf[nt][0] = __float_as_uint(Bs[buf][kb + tig    ][bn]);
                bf[nt][1] = __float_as_uint(Bs[buf][kb + tig + 4][bn]);
            }
            #pragma unroll
            for (int mt = 0; mt < 4; mt++)
                #pragma unroll
                for (int nt = 0; nt < 4; nt++)
                    mma_tf32(c[mt][nt], af[mt], bf[nt]);
        }

        if (has_next) {
            const int nb = buf ^ 1;
            As[nb][a_k + 0][a_m] = to_tf32(pa0.x); As[nb][a_k + 1][a_m] = to_tf32(pa0.y);
            As[nb][a_k + 2][a_m] = to_tf32(pa0.z); As[nb][a_k + 3][a_m] = to_tf32(pa0.w);
            As[nb][a_k + 8][a_m] = to_tf32(pa1.x); As[nb][a_k + 9][a_m] = to_tf32(pa1.y);
            As[nb][a_k +10][a_m] = to_tf32(pa1.z); As[nb][a_k +11][a_m] = to_tf32(pa1.w);
            if (TRANSB) {
                Bs[nb][bt_k + 0][bt_n] = to_tf32(pb0.x); Bs[nb][bt_k + 1][bt_n] = to_tf32(pb0.y);
                Bs[nb][bt_k + 2][bt_n] = to_tf32(pb0.z); Bs[nb][bt_k + 3][bt_n] = to_tf32(pb0.w);
                Bs[nb][bt_k + 8][bt_n] = to_tf32(pb1.x); Bs[nb][bt_k + 9][bt_n] = to_tf32(pb1.y);
                Bs[nb][bt_k +10][bt_n] = to_tf32(pb1.z); Bs[nb][bt_k +11][bt_n] = to_tf32(pb1.w);
            } else {
                float4 q0 = make_float4(to_tf32(pb0.x), to_tf32(pb0.y), to_tf32(pb0.z), to_tf32(pb0.w));
                float4 q1 = make_float4(to_tf32(pb1.x), to_tf32(pb1.y), to_tf32(pb1.z), to_tf32(pb1.w));
                *(float4*)(&Bs[nb][b_k][b_n])     = q0;
                *(float4*)(&Bs[nb][b_k + 8][b_n]) = q1;
            }
        }
        __syncthreads();
    }

    // epilogue
    #pragma unroll
    for (int nt = 0; nt < 4; nt++) {
        const int col = n0 + wn * 32 + nt * 8 + tig * 2;
        const float bv0 = bias ? bias[col]     : 0.0f;
        const float bv1 = bias ? bias[col + 1] : 0.0f;
        float gv0 = 0.0f, gv1 = 0.0f;
        if (EPI == 2) { gv0 = gate[col]; gv1 = gate[col + 1]; }
        #pragma unroll
        for (int mt = 0; mt < 4; mt++) {
            const int row0 = m0 + wm * 64 + mt * 16 + gid;
            #pragma unroll
            for (int h = 0; h < 2; h++) {
                const int row = row0 + h * 8;
                float v0 = c[mt][nt][h * 2 + 0] + bv0;
                float v1 = c[mt][nt][h * 2 + 1] + bv1;
                if (EPI == 1) { v0 = gelu_tanh(v0); v1 = gelu_tanh(v1); }
                if (EPI == 2) {
                    const float* Rr = resid + (size_t)row * ldres + col;
                    v0 = Rr[0] + gv0 * v0;
                    v1 = Rr[1] + gv1 * v1;
                }
                *(float2*)(C + (size_t)row * ldc + col) = make_float2(v0, v1);
            }
        }
    }
}

// ---------------------------------------------------------------------------
// Host launcher
// ---------------------------------------------------------------------------
static void launch_gemm(int epi, bool transB,
                        const float* A, const float* B, const float* bias, float* C,
                        int M, int N, int K, int lda, int ldb, int ldc,
                        int batch, size_t sA, size_t sB, size_t sC,
                        const float* gate = nullptr, const float* resid = nullptr, int ldres = 0) {
    dim3 grid(N / 128, M / 128, batch);
    if (transB) {
        mma_gemm<true, 0><<<grid, 256>>>(A, B, bias, C, K, lda, ldb, ldc, sA, sB, sC, gate, resid, ldres);
    } else if (epi == 0) {
        mma_gemm<false, 0><<<grid, 256>>>(A, B, bias, C, K, lda, ldb, ldc, sA, sB, sC, gate, resid, ldres);
    } else if (epi == 1) {
        mma_gemm<false, 1><<<grid, 256>>>(A, B, bias, C, K, lda, ldb, ldc, sA, sB, sC, gate, resid, ldres);
    } else {
        mma_gemm<false, 2><<<grid, 256>>>(A, B, bias, C, K, lda, ldb, ldc, sA, sB, sC, gate, resid, ldres);
    }
}

extern "C" void kernel_launch(void* const* d_in, const int* in_sizes, int n_in,
                              void* d_out, int out_size) {
    const float* img        = (const float*)d_in[0];
    const float* txt        = (const float*)d_in[1];
    const float* vec        = (const float*)d_in[2];
    const float* pe         = (const float*)d_in[3];
    const float* img_mod_w  = (const float*)d_in[4];
    const float* img_mod_b  = (const float*)d_in[5];
    const float* img_qkv_w  = (const float*)d_in[6];
    const float* img_qkv_b  = (const float*)d_in[7];
    const float* img_q_s    = (const float*)d_in[8];
    const float* img_k_s    = (const float*)d_in[9];
    const float* img_proj_w = (const float*)d_in[10];
    const float* img_proj_b = (const float*)d_in[11];
    const float* img_mlp_w1 = (const float*)d_in[12];
    const float* img_mlp_b1 = (const float*)d_in[13];
    const float* img_mlp_w2 = (const float*)d_in[14];
    const float* img_mlp_b2 = (const float*)d_in[15];
    const float* txt_mod_w  = (const float*)d_in[16];
    const float* txt_mod_b  = (const float*)d_in[17];
    const float* txt_qkv_w  = (const float*)d_in[18];
    const float* txt_qkv_b  = (const float*)d_in[19];
    const float* txt_q_s    = (const float*)d_in[20];
    const float* txt_k_s    = (const float*)d_in[21];
    const float* txt_proj_w = (const float*)d_in[22];
    const float* txt_proj_b = (const float*)d_in[23];
    const float* txt_mlp_w1 = (const float*)d_in[24];
    const float* txt_mlp_b1 = (const float*)d_in[25];
    const float* txt_mlp_w2 = (const float*)d_in[26];
    const float* txt_mlp_b2 = (const float*)d_in[27];
    float* out = (float*)d_out;

    float *sv, *modi, *modt, *x, *qkvb, *q, *k, *v, *scores, *attn, *x1, *x2, *h1;
    cudaGetSymbolAddress((void**)&sv,     g_silu);
    cudaGetSymbolAddress((void**)&modi,   g_mod_img);
    cudaGetSymbolAddress((void**)&modt,   g_mod_txt);
    cudaGetSymbolAddress((void**)&x,      g_x);
    cudaGetSymbolAddress((void**)&qkvb,   g_qkv);
    cudaGetSymbolAddress((void**)&q,      g_q);
    cudaGetSymbolAddress((void**)&k,      g_k);
    cudaGetSymbolAddress((void**)&v,      g_v);
    cudaGetSymbolAddress((void**)&scores, g_scores);
    cudaGetSymbolAddress((void**)&attn,   g_attn);
    cudaGetSymbolAddress((void**)&x1,     g_x1);
    cudaGetSymbolAddress((void**)&x2,     g_x2);
    cudaGetSymbolAddress((void**)&h1,     g_h1);

    // 1. silu(vec)
    silu_kernel<<<HS / 256, 256>>>(vec, sv);

    // 2. modulation params
    mod_gemv<<<(6 * HS) / 256, 256>>>(sv, img_mod_w, img_mod_b, modi);
    mod_gemv<<<(6 * HS) / 256, 256>>>(sv, txt_mod_w, txt_mod_b, modt);

    // 3. LN + modulate (txt rows 0..511, img rows 512..2559)
    ln_mod<<<LTXT, 256>>>(txt, x,                       modt + 0 * HS, modt + 1 * HS);
    ln_mod<<<LIMG, 256>>>(img, x + (size_t)LTXT * HS,   modi + 0 * HS, modi + 1 * HS);

    // 4. QKV GEMMs
    launch_gemm(0, false, x, txt_qkv_w, txt_qkv_b, qkvb,
                LTXT, QKVW, HS, HS, QKVW, QKVW, 1, 0, 0, 0);
    launch_gemm(0, false, x + (size_t)LTXT * HS, img_qkv_w, img_qkv_b,
                qkvb + (size_t)LTXT * QKVW,
                LIMG, QKVW, HS, HS, QKVW, QKVW, 1, 0, 0, 0);

    // 5. RMS norm + RoPE + head-major scatter
    rms_rope<<<LTOT, 256>>>(qkvb, pe, txt_q_s, txt_k_s, img_q_s, img_k_s, q, k, v);

    // 6. scores = q @ k^T  (batched over heads, B transposed)
    launch_gemm(0, true, q, k, nullptr, scores,
                LTOT, LTOT, HD, HD, HD, LTOT,
                NH, (size_t)LTOT * HD, (size_t)LTOT * HD, (size_t)LTOT * LTOT);

    // 7. softmax with 1/sqrt(D)
    softmax2560<<<NH * LTOT, 256>>>(scores, 0.08838834764831845f);

    // 8. o = a @ v, written into [l][h*128+d]
    launch_gemm(0, false, scores, v, nullptr, attn,
                LTOT, HD, LTOT, LTOT, HD, HS,
                NH, (size_t)LTOT * LTOT, (size_t)LTOT * HD, (size_t)HD);

    // 9. proj + gated residual  -> x1
    launch_gemm(2, false, attn, txt_proj_w, txt_proj_b, x1,
                LTXT, HS, HS, HS, HS, HS, 1, 0, 0, 0,
                modt + 2 * HS, txt, HS);
    launch_gemm(2, false, attn + (size_t)LTXT * HS, img_proj_w, img_proj_b,
                x1 + (size_t)LTXT * HS,
                LIMG, HS, HS, HS, HS, HS, 1, 0, 0, 0,
                modi + 2 * HS, img, HS);

    // 10. second LN + modulate -> x2
    ln_mod<<<LTXT, 256>>>(x1, x2,                                   modt + 3 * HS, modt + 4 * HS);
    ln_mod<<<LIMG, 256>>>(x1 + (size_t)LTXT * HS, x2 + (size_t)LTXT * HS, modi + 3 * HS, modi + 4 * HS);

    // 11. MLP1 with fused GELU -> h1
    launch_gemm(1, false, x2, txt_mlp_w1, txt_mlp_b1, h1,
                LTXT, MLPD, HS, HS, MLPD, MLPD, 1, 0, 0, 0);
    launch_gemm(1, false, x2 + (size_t)LTXT * HS, img_mlp_w1, img_mlp_b1,
                h1 + (size_t)LTXT * MLPD,
                LIMG, MLPD, HS, HS, MLPD, MLPD, 1, 0, 0, 0);

    // 12. MLP2 with fused gated residual, written straight to d_out
    //     output layout: img (2048*3072) then txt (512*3072)
    launch_gemm(2, false, h1, txt_mlp_w2, txt_mlp_b2,
                out + (size_t)LIMG * HS,
                LTXT, HS, MLPD, MLPD, HS, HS, 1, 0, 0, 0,
                modt + 5 * HS, x1, HS);
    launch_gemm(2, false, h1 + (size_t)LTXT * MLPD, img_mlp_w2, img_mlp_b2,
                out,
                LIMG, HS, MLPD, MLPD, HS, HS, 1, 0, 0, 0,
                modi + 5 * HS, x1 + (size_t)LTXT * HS, HS);
}

// round 5
// speedup vs baseline: 2.4808x; 1.0724x over previous
#include <cuda_runtime.h>
#include <cuda_bf16.h>
#include <math.h>

// ---------------------------------------------------------------------------
// Problem constants
// ---------------------------------------------------------------------------
#define HS    3072
#define MLPD  12288
#define NH    24
#define HD    128
#define LTXT  512
#define LIMG  2048
#define LTOT  2560          // txt rows [0,512), img rows [512,2560)
#define QKVW  9216          // 3*HS

// ---------------------------------------------------------------------------
// Static device scratch (no allocations allowed)
// ---------------------------------------------------------------------------
__device__ float g_silu[HS];
__device__ float g_mod_img[6 * HS];
__device__ float g_mod_txt[6 * HS];
__device__ float g_x   [(size_t)LTOT * HS];       // modulated LN input
__device__ float g_qkv [(size_t)LTOT * QKVW];
__device__ float g_q   [(size_t)NH * LTOT * HD];
__device__ float g_k   [(size_t)NH * LTOT * HD];
__device__ float g_v   [(size_t)NH * LTOT * HD];
__device__ float g_attn[(size_t)LTOT * HS];
__device__ float g_x1  [(size_t)LTOT * HS];       // after first residual
__device__ float g_x2  [(size_t)LTOT * HS];       // second modulated LN
__device__ float g_h1  [(size_t)LTOT * MLPD];     // MLP hidden

// ---------------------------------------------------------------------------
// Small elementwise kernels
// ---------------------------------------------------------------------------
__global__ void silu_kernel(const float* __restrict__ v, float* __restrict__ o) {
    int i = blockIdx.x * 256 + threadIdx.x;
    if (i < HS) {
        float x = v[i];
        o[i] = x / (1.0f + expf(-x));
    }
}

// split-K modulation GEMV: grid = 6*HS/64 blocks, 256 threads
// block computes 64 outputs; 4 thread-groups split K; smem reduce.
__global__ void mod_gemv2(const float* __restrict__ sv, const float* __restrict__ w,
                          const float* __restrict__ b, float* __restrict__ out) {
    __shared__ float ssv[HS];
    __shared__ float red[4][64];
    for (int i = threadIdx.x; i < HS; i += 256) ssv[i] = sv[i];
    __syncthreads();
    const int jl = threadIdx.x & 63, kq = threadIdx.x >> 6;
    const int j = blockIdx.x * 64 + jl;
    const int i0 = kq * (HS / 4);
    float acc = 0.0f;
    #pragma unroll 8
    for (int i = 0; i < HS / 4; i++)
        acc += ssv[i0 + i] * w[(size_t)(i0 + i) * (6 * HS) + j];
    red[kq][jl] = acc;
    __syncthreads();
    if (threadIdx.x < 64) {
        int jj = blockIdx.x * 64 + threadIdx.x;
        out[jj] = red[0][threadIdx.x] + red[1][threadIdx.x] +
                  red[2][threadIdx.x] + red[3][threadIdx.x] + b[jj];
    }
}

// LayerNorm + modulate: dst = shift + (1+scale) * LN(x) ; one block per row
__global__ void ln_mod(const float* __restrict__ x, float* __restrict__ dst,
                       const float* __restrict__ shift, const float* __restrict__ scale) {
    int row = blockIdx.x;
    int t = threadIdx.x;
    const float* xr = x + (size_t)row * HS;
    float v[12];
    float s = 0.0f;
    #pragma unroll
    for (int i = 0; i < 12; i++) { v[i] = xr[t + i * 256]; s += v[i]; }
    __shared__ float red[256];
    red[t] = s; __syncthreads();
    for (int o = 128; o > 0; o >>= 1) { if (t < o) red[t] += red[t + o]; __syncthreads(); }
    float mean = red[0] * (1.0f / HS);
    __syncthreads();
    float s2 = 0.0f;
    #pragma unroll
    for (int i = 0; i < 12; i++) { float d = v[i] - mean; s2 += d * d; }
    red[t] = s2; __syncthreads();
    for (int o = 128; o > 0; o >>= 1) { if (t < o) red[t] += red[t + o]; __syncthreads(); }
    float inv = rsqrtf(red[0] * (1.0f / HS) + 1e-6f);
    float* dr = dst + (size_t)row * HS;
    #pragma unroll
    for (int i = 0; i < 12; i++) {
        int c = t + i * 256;
        dr[c] = shift[c] + (1.0f + scale[c]) * (v[i] - mean) * inv;
    }
}

// Per-head RMS-norm(q,k) + RoPE + scatter to [h][l][d]; copy v.
__global__ void rms_rope(const float* __restrict__ qkv, const float* __restrict__ pe,
                         const float* __restrict__ tqs, const float* __restrict__ tks,
                         const float* __restrict__ iqs, const float* __restrict__ iks,
                         float* __restrict__ Q, float* __restrict__ Kp, float* __restrict__ Vp) {
    int l = blockIdx.x;
    int w = threadIdx.x >> 5, lane = threadIdx.x & 31;
    const float* qs = (l < LTXT) ? tqs : iqs;
    const float* ks = (l < LTXT) ? tks : iks;
    const float* row = qkv + (size_t)l * QKVW;
    const float* peb = pe + (size_t)l * 256 + lane * 8; // 2 rope pairs per lane
    float4 p0 = *(const float4*)(peb);
    float4 p1 = *(const float4*)(peb + 4);
    int d0 = lane * 4;
    float4 scq = *(const float4*)(qs + d0);
    float4 sck = *(const float4*)(ks + d0);

    for (int h = w; h < NH; h += 8) {
        // ---- Q
        float4 xq = *(const float4*)(row + h * HD + d0);
        float ss = xq.x*xq.x + xq.y*xq.y + xq.z*xq.z + xq.w*xq.w;
        #pragma unroll
        for (int o = 16; o > 0; o >>= 1) ss += __shfl_xor_sync(0xffffffffu, ss, o);
        float r = rsqrtf(ss * (1.0f / HD) + 1e-6f);
        float x0 = xq.x * r * scq.x, x1 = xq.y * r * scq.y;
        float x2 = xq.z * r * scq.z, x3 = xq.w * r * scq.w;
        float4 oq;
        oq.x = p0.x * x0 + p0.y * x1;
        oq.y = p0.z * x0 + p0.w * x1;
        oq.z = p1.x * x2 + p1.y * x3;
        oq.w = p1.z * x2 + p1.w * x3;
        *(float4*)(Q + ((size_t)h * LTOT + l) * HD + d0) = oq;
        // ---- K
        float4 xk = *(const float4*)(row + HS + h * HD + d0);
        float sk = xk.x*xk.x + xk.y*xk.y + xk.z*xk.z + xk.w*xk.w;
        #pragma unroll
        for (int o = 16; o > 0; o >>= 1) sk += __shfl_xor_sync(0xffffffffu, sk, o);
        float rk = rsqrtf(sk * (1.0f / HD) + 1e-6f);
        float y0 = xk.x * rk * sck.x, y1 = xk.y * rk * sck.y;
        float y2 = xk.z * rk * sck.z, y3 = xk.w * rk * sck.w;
        float4 ok;
        ok.x = p0.x * y0 + p0.y * y1;
        ok.y = p0.z * y0 + p0.w * y1;
        ok.z = p1.x * y2 + p1.y * y3;
        ok.w = p1.z * y2 + p1.w * y3;
        *(float4*)(Kp + ((size_t)h * LTOT + l) * HD + d0) = ok;
        // ---- V copy
        float4 xv = *(const float4*)(row + 2 * HS + h * HD + d0);
        *(float4*)(Vp + ((size_t)h * LTOT + l) * HD + d0) = xv;
    }
}

// ---------------------------------------------------------------------------
// TF32 helpers
// ---------------------------------------------------------------------------
__device__ __forceinline__ float gelu_tanh(float x) {
    float x3 = x * x * x;
    return 0.5f * x * (1.0f + tanhf(0.7978845608028654f * (x + 0.044715f * x3)));
}

__device__ __forceinline__ float to_tf32(float x) {
    unsigned int u;
    asm("cvt.rna.tf32.f32 %0, %1;" : "=r"(u) : "f"(x));
    return __uint_as_float(u);
}

__device__ __forceinline__ void mma_tf32(float c[4], const unsigned int a[4],
                                         const unsigned int b[2]) {
    asm volatile(
        "mma.sync.aligned.m16n8k8.row.col.f32.tf32.tf32.f32 "
        "{%0,%1,%2,%3}, {%4,%5,%6,%7}, {%8,%9}, {%0,%1,%2,%3};"
        : "+f"(c[0]), "+f"(c[1]), "+f"(c[2]), "+f"(c[3])
        : "r"(a[0]), "r"(a[1]), "r"(a[2]), "r"(a[3]), "r"(b[0]), "r"(b[1]));
}

// ---------------------------------------------------------------------------
// Flash attention: 128 Q rows per CTA, 64-wide KV tiles, tf32 mma, online
// softmax. Grid (LTOT/128, NH), 256 threads (8 warps, 16 Q rows each).
// O written to [l][h*HD+d] (i.e. g_attn row-major HS).
// ---------------------------------------------------------------------------
#define FA_SCALE 0.08838834764831845f
#define SQ_PITCH 132
#define SK_PITCH 68
#define SV_PITCH 132
#define SP_PITCH 132
#define SQ_OFF 0
#define SK_OFF (128 * SQ_PITCH)
#define SV_OFF (SK_OFF + 128 * SK_PITCH)
#define SP_OFF (SV_OFF + 64 * SV_PITCH)
#define FA_SMEM_FLOATS (SP_OFF + 64 * SP_PITCH)
#define FA_SMEM_BYTES (FA_SMEM_FLOATS * 4)

__global__ void __launch_bounds__(256, 1)
flash_attn(const float* __restrict__ Q, const float* __restrict__ K,
           const float* __restrict__ V, float* __restrict__ O) {
    extern __shared__ float sm[];
    float* sQ = sm + SQ_OFF;
    float* sK = sm + SK_OFF;
    float* sV = sm + SV_OFF;
    float* sP = sm + SP_OFF;

    const int t = threadIdx.x;
    const int wid = t >> 5, lane = t & 31;
    const int gid = lane >> 2, tig = lane & 3;
    const int h = blockIdx.y;
    const int q0 = blockIdx.x * 128;
    const int m0 = wid * 16;

    const float* Qh = Q + ((size_t)h * LTOT + q0) * HD;
    const float* Kh = K + (size_t)h * LTOT * HD;
    const float* Vh = V + (size_t)h * LTOT * HD;

    // --- load Q tile transposed into sQ[d][row], pre-scaled, tf32 ---
    {
        int r = t >> 1;
        int dseg = (t & 1) * 64;
        const float* qr = Qh + (size_t)r * HD + dseg;
        #pragma unroll
        for (int i = 0; i < 16; i++) {
            float4 v4 = *(const float4*)(qr + i * 4);
            int d = dseg + i * 4;
            sQ[(d + 0) * SQ_PITCH + r] = to_tf32(v4.x * FA_SCALE);
            sQ[(d + 1) * SQ_PITCH + r] = to_tf32(v4.y * FA_SCALE);
            sQ[(d + 2) * SQ_PITCH + r] = to_tf32(v4.z * FA_SCALE);
            sQ[(d + 3) * SQ_PITCH + r] = to_tf32(v4.w * FA_SCALE);
        }
    }
    __syncthreads();

    // --- Q fragments register-resident for the whole KV loop ---
    unsigned int qf[16][4];
    #pragma unroll
    for (int kt = 0; kt < 16; kt++) {
        int kb = kt * 8;
        qf[kt][0] = __float_as_uint(sQ[(kb + tig)     * SQ_PITCH + m0 + gid]);
        qf[kt][1] = __float_as_uint(sQ[(kb + tig)     * SQ_PITCH + m0 + gid + 8]);
        qf[kt][2] = __float_as_uint(sQ[(kb + tig + 4) * SQ_PITCH + m0 + gid]);
        qf[kt][3] = __float_as_uint(sQ[(kb + tig + 4) * SQ_PITCH + m0 + gid + 8]);
    }

    float co[16][4];
    #pragma unroll
    for (int i = 0; i < 16; i++)
        #pragma unroll
        for (int j = 0; j < 4; j++) co[i][j] = 0.0f;
    float mrow0 = -1e30f, mrow1 = -1e30f, lrow0 = 0.0f, lrow1 = 0.0f;

    for (int kv = 0; kv < LTOT; kv += 64) {
        __syncthreads();   // previous iteration done with sK/sV
        // load K tile transposed: sK[d][c]
        {
            int c = t >> 2;
            int dseg = (t & 3) * 32;
            const float* kr = Kh + (size_t)(kv + c) * HD + dseg;
            #pragma unroll
            for (int i = 0; i < 8; i++) {
                float4 v4 = *(const float4*)(kr + i * 4);
                int d = dseg + i * 4;
                sK[(d + 0) * SK_PITCH + c] = to_tf32(v4.x);
                sK[(d + 1) * SK_PITCH + c] = to_tf32(v4.y);
                sK[(d + 2) * SK_PITCH + c] = to_tf32(v4.z);
                sK[(d + 3) * SK_PITCH + c] = to_tf32(v4.w);
            }
        }
        // load V tile: sV[c][d]
        {
            int c = t >> 2;
            int dseg = (t & 3) * 32;
            const float* vr = Vh + (size_t)(kv + c) * HD + dseg;
            #pragma unroll
            for (int i = 0; i < 8; i++) {
                float4 v4 = *(const float4*)(vr + i * 4);
                float4 q4 = make_float4(to_tf32(v4.x), to_tf32(v4.y),
                                        to_tf32(v4.z), to_tf32(v4.w));
                *(float4*)(sV + c * SV_PITCH + dseg + i * 4) = q4;
            }
        }
        __syncthreads();

        // --- S = Q @ K^T : 16x64 per warp ---
        float cs[8][4];
        #pragma unroll
        for (int i = 0; i < 8; i++)
            #pragma unroll
            for (int j = 0; j < 4; j++) cs[i][j] = 0.0f;
        #pragma unroll
        for (int kt = 0; kt < 16; kt++) {
            int kb = kt * 8;
            #pragma unroll
            for (int nt = 0; nt < 8; nt++) {
                unsigned int bf[2];
                bf[0] = __float_as_uint(sK[(kb + tig)     * SK_PITCH + nt * 8 + gid]);
                bf[1] = __float_as_uint(sK[(kb + tig + 4) * SK_PITCH + nt * 8 + gid]);
                mma_tf32(cs[nt], qf[kt], bf);
            }
        }

        // --- online softmax ---
        float rmax0 = -1e30f, rmax1 = -1e30f;
        #pragma unroll
        for (int nt = 0; nt < 8; nt++) {
            rmax0 = fmaxf(rmax0, fmaxf(cs[nt][0], cs[nt][1]));
            rmax1 = fmaxf(rmax1, fmaxf(cs[nt][2], cs[nt][3]));
        }
        rmax0 = fmaxf(rmax0, __shfl_xor_sync(0xffffffffu, rmax0, 1));
        rmax0 = fmaxf(rmax0, __shfl_xor_sync(0xffffffffu, rmax0, 2));
        rmax1 = fmaxf(rmax1, __shfl_xor_sync(0xffffffffu, rmax1, 1));
        rmax1 = fmaxf(rmax1, __shfl_xor_sync(0xffffffffu, rmax1, 2));
        float mn0 = fmaxf(mrow0, rmax0);
        float mn1 = fmaxf(mrow1, rmax1);
        float corr0 = __expf(mrow0 - mn0);
        float corr1 = __expf(mrow1 - mn1);
        mrow0 = mn0; mrow1 = mn1;

        float rs0 = 0.0f, rs1 = 0.0f;
        #pragma unroll
        for (int nt = 0; nt < 8; nt++) {
            cs[nt][0] = __expf(cs[nt][0] - mn0);
            cs[nt][1] = __expf(cs[nt][1] - mn0);
            cs[nt][2] = __expf(cs[nt][2] - mn1);
            cs[nt][3] = __expf(cs[nt][3] - mn1);
            rs0 += cs[nt][0] + cs[nt][1];
            rs1 += cs[nt][2] + cs[nt][3];
        }
        rs0 += __shfl_xor_sync(0xffffffffu, rs0, 1);
        rs0 += __shfl_xor_sync(0xffffffffu, rs0, 2);
        rs1 += __shfl_xor_sync(0xffffffffu, rs1, 1);
        rs1 += __shfl_xor_sync(0xffffffffu, rs1, 2);
        lrow0 = lrow0 * corr0 + rs0;
        lrow1 = lrow1 * corr1 + rs1;

        #pragma unroll
        for (int nt = 0; nt < 16; nt++) {
            co[nt][0] *= corr0; co[nt][1] *= corr0;
            co[nt][2] *= corr1; co[nt][3] *= corr1;
        }

        // --- store P transposed into sP[kvcol][row] (tf32) ---
        #pragma unroll
        for (int nt = 0; nt < 8; nt++) {
            int cb = nt * 8 + tig * 2;
            sP[(cb + 0) * SP_PITCH + m0 + gid]     = to_tf32(cs[nt][0]);
            sP[(cb + 1) * SP_PITCH + m0 + gid]     = to_tf32(cs[nt][1]);
            sP[(cb + 0) * SP_PITCH + m0 + gid + 8] = to_tf32(cs[nt][2]);
            sP[(cb + 1) * SP_PITCH + m0 + gid + 8] = to_tf32(cs[nt][3]);
        }
        __syncwarp();

        // --- O += P @ V ---
        #pragma unroll
        for (int kt = 0; kt < 8; kt++) {
            int kb = kt * 8;
            unsigned int af[4];
            af[0] = __float_as_uint(sP[(kb + tig)     * SP_PITCH + m0 + gid]);
            af[1] = __float_as_uint(sP[(kb + tig)     * SP_PITCH + m0 + gid + 8]);
            af[2] = __float_as_uint(sP[(kb + tig + 4) * SP_PITCH + m0 + gid]);
            af[3] = __float_as_uint(sP[(kb + tig + 4) * SP_PITCH + m0 + gid + 8]);
            #pragma unroll
            for (int nt = 0; nt < 16; nt++) {
                unsigned int bf[2];
                bf[0] = __float_as_uint(sV[(kb + tig)     * SV_PITCH + nt * 8 + gid]);
                bf[1] = __float_as_uint(sV[(kb + tig + 4) * SV_PITCH + nt * 8 + gid]);
                mma_tf32(co[nt], af, bf);
            }
        }
    }

    // --- epilogue: O /= l, write [l][h*HD+d] ---
    float inv0 = 1.0f / lrow0;
    float inv1 = 1.0f / lrow1;
    int row0 = q0 + m0 + gid;
    #pragma unroll
    for (int nt = 0; nt < 16; nt++) {
        int col = h * HD + nt * 8 + tig * 2;
        *(float2*)(O + (size_t)row0 * HS + col) =
            make_float2(co[nt][0] * inv0, co[nt][1] * inv0);
        *(float2*)(O + (size_t)(row0 + 8) * HS + col) =
            make_float2(co[nt][2] * inv1, co[nt][3] * inv1);
    }
}

// ---------------------------------------------------------------------------
// TF32 tensor-core GEMM: 128x128 block tile, 8 warps (2x4), 64x32 per warp,
// m16n8k8 mma, K-step 16, double-buffered smem.
// EPI: 0 = acc+bias ; 1 = gelu(acc+bias) ; 2 = resid + gate*(acc+bias)
// ---------------------------------------------------------------------------
template <bool TRANSB, int EPI>
__global__ void __launch_bounds__(256, 2)
mma_gemm(const float* __restrict__ A, const float* __restrict__ B,
         const float* __restrict__ bias, float* __restrict__ C,
         int K, int lda, int ldb, int ldc,
         size_t sA, size_t sB, size_t sC,
         const float* __restrict__ gate, const float* __restrict__ resid, int ldres) {
    A += (size_t)blockIdx.z * sA;
    B += (size_t)blockIdx.z * sB;
    C += (size_t)blockIdx.z * sC;

    __shared__ float As[2][16][132];
    __shared__ float Bs[2][16][132];

    const int t = threadIdx.x;
    const int wid = t >> 5, lane = t & 31;
    const int wm = wid >> 2, wn = wid & 3;
    const int gid = lane >> 2, tig = lane & 3;
    const int m0 = blockIdx.y * 128, n0 = blockIdx.x * 128;

    const int a_m = t >> 1, a_k = (t & 1) * 4;
    const int bt_n = t >> 1, bt_k = (t & 1) * 4;
    const int b_k = t >> 5,  b_n = (t & 31) * 4;

    const float* Ap = A + (size_t)(m0 + a_m) * lda + a_k;
    const float* Bp = TRANSB ? B + (size_t)(n0 + bt_n) * ldb + bt_k
                             : B + (size_t)b_k * ldb + n0 + b_n;

    float c[4][4][4];
    #pragma unroll
    for (int i = 0; i < 4; i++)
        #pragma unroll
        for (int j = 0; j < 4; j++)
            #pragma unroll
            for (int r = 0; r < 4; r++) c[i][j][r] = 0.0f;

    const int nk = K / 16;
    float4 pa0, pa1, pb0, pb1;

    pa0 = *(const float4*)(Ap);
    pa1 = *(const float4*)(Ap + 8);
    if (TRANSB) {
        pb0 = *(const float4*)(Bp);
        pb1 = *(const float4*)(Bp + 8);
    } else {
        pb0 = *(const float4*)(Bp);
        pb1 = *(const float4*)(Bp + (size_t)8 * ldb);
    }
    {
        As[0][a_k + 0][a_m] = to_tf32(pa0.x); As[0][a_k + 1][a_m] = to_tf32(pa0.y);
        As[0][a_k + 2][a_m] = to_tf32(pa0.z); As[0][a_k + 3][a_m] = to_tf32(pa0.w);
        As[0][a_k + 8][a_m] = to_tf32(pa1.x); As[0][a_k + 9][a_m] = to_tf32(pa1.y);
        As[0][a_k +10][a_m] = to_tf32(pa1.z); As[0][a_k +11][a_m] = to_tf32(pa1.w);
        if (TRANSB) {
            Bs[0][bt_k + 0][bt_n] = to_tf32(pb0.x); Bs[0][bt_k + 1][bt_n] = to_tf32(pb0.y);
            Bs[0][bt_k + 2][bt_n] = to_tf32(pb0.z); Bs[0][bt_k + 3][bt_n] = to_tf32(pb0.w);
            Bs[0][bt_k + 8][bt_n] = to_tf32(pb1.x); Bs[0][bt_k + 9][bt_n] = to_tf32(pb1.y);
            Bs[0][bt_k +10][bt_n] = to_tf32(pb1.z); Bs[0][bt_k +11][bt_n] = to_tf32(pb1.w);
        } else {
            float4 q0 = make_float4(to_tf32(pb0.x), to_tf32(pb0.y), to_tf32(pb0.z), to_tf32(pb0.w));
            float4 q1 = make_float4(to_tf32(pb1.x), to_tf32(pb1.y), to_tf32(pb1.z), to_tf32(pb1.w));
            *(float4*)(&Bs[0][b_k][b_n])     = q0;
            *(float4*)(&Bs[0][b_k + 8][b_n]) = q1;
        }
    }
    __syncthreads();

    for (int kt = 0; kt < nk; kt++) {
        const int buf = kt & 1;
        const bool has_next = (kt + 1 < nk);
        if (has_next) {
            const int off = (kt + 1) * 16;
            pa0 = *(const float4*)(Ap + off);
            pa1 = *(const float4*)(Ap + off + 8);
            if (TRANSB) {
                pb0 = *(const float4*)(Bp + off);
                pb1 = *(const float4*)(Bp + off + 8);
            } else {
                pb0 = *(const float4*)(Bp + (size_t)off * ldb);
                pb1 = *(const float4*)(Bp + (size_t)(off + 8) * ldb);
            }
        }

        #pragma unroll
        for (int ks = 0; ks < 2; ks++) {
            const int kb = ks * 8;
            unsigned int af[4][4], bf[4][2];
            #pragma unroll
            for (int mt = 0; mt < 4; mt++) {
                const int bm = wm * 64 + mt * 16 + gid;
                af[mt][0] = __float_as_uint(As[buf][kb + tig    ][bm]);
                af[mt][1] = __float_as_uint(As[buf][kb + tig    ][bm + 8]);
                af[mt][2] = __float_as_uint(As[buf][kb + tig + 4][bm]);
                af[mt][3] = __float_as_uint(As[buf][kb + tig + 4][bm + 8]);
            }
            #pragma unroll
            for (int nt = 0; nt < 4; nt++) {
                const int bn = wn * 32 + nt * 8 + gid;
                bf[nt][0] = __float_as_uint(Bs[buf][kb + tig    ][bn]);
                bf[nt][1] = __float_as_uint(Bs[buf][kb + tig + 4][bn]);
            }
            #pragma unroll
            for (int mt = 0; mt < 4; mt++)
                #pragma unroll
                for (int nt = 0; nt < 4; nt++)
                    mma_tf32(c[mt][nt], af[mt], bf[nt]);
        }

        if (has_next) {
            const int nb = buf ^ 1;
            As[nb][a_k + 0][a_m] = to_tf32(pa0.x); As[nb][a_k + 1][a_m] = to_tf32(pa0.y);
            As[nb][a_k + 2][a_m] = to_tf32(pa0.z); As[nb][a_k + 3][a_m] = to_tf32(pa0.w);
            As[nb][a_k + 8][a_m] = to_tf32(pa1.x); As[nb][a_k + 9][a_m] = to_tf32(pa1.y);
            As[nb][a_k +10][a_m] = to_tf32(pa1.z); As[nb][a_k +11][a_m] = to_tf32(pa1.w);
            if (TRANSB) {
                Bs[nb][bt_k + 0][bt_n] = to_tf32(pb0.x); Bs[nb][bt_k + 1][bt_n] = to_tf32(pb0.y);
                Bs[nb][bt_k + 2][bt_n] = to_tf32(pb0.z); Bs[nb][bt_k + 3][bt_n] = to_tf32(pb0.w);
                Bs[nb][bt_k + 8][bt_n] = to_tf32(pb1.x); Bs[nb][bt_k + 9][bt_n] = to_tf32(pb1.y);
                Bs[nb][bt_k +10][bt_n] = to_tf32(pb1.z); Bs[nb][bt_k +11][bt_n] = to_tf32(pb1.w);
            } else {
                float4 q0 = make_float4(to_tf32(pb0.x), to_tf32(pb0.y), to_tf32(pb0.z), to_tf32(pb0.w));
                float4 q1 = make_float4(to_tf32(pb1.x), to_tf32(pb1.y), to_tf32(pb1.z), to_tf32(pb1.w));
                *(float4*)(&Bs[nb][b_k][b_n])     = q0;
                *(float4*)(&Bs[nb][b_k + 8][b_n]) = q1;
            }
        }
        __syncthreads();
    }

    #pragma unroll
    for (int nt = 0; nt < 4; nt++) {
        const int col = n0 + wn * 32 + nt * 8 + tig * 2;
        const float bv0 = bias ? bias[col]     : 0.0f;
        const float bv1 = bias ? bias[col + 1] : 0.0f;
        float gv0 = 0.0f, gv1 = 0.0f;
        if (EPI == 2) { gv0 = gate[col]; gv1 = gate[col + 1]; }
        #pragma unroll
        for (int mt = 0; mt < 4; mt++) {
            const int row0 = m0 + wm * 64 + mt * 16 + gid;
            #pragma unroll
            for (int h = 0; h < 2; h++) {
                const int row = row0 + h * 8;
                float v0 = c[mt][nt][h * 2 + 0] + bv0;
                float v1 = c[mt][nt][h * 2 + 1] + bv1;
                if (EPI == 1) { v0 = gelu_tanh(v0); v1 = gelu_tanh(v1); }
                if (EPI == 2) {
                    const float* Rr = resid + (size_t)row * ldres + col;
                    v0 = Rr[0] + gv0 * v0;
                    v1 = Rr[1] + gv1 * v1;
                }
                *(float2*)(C + (size_t)row * ldc + col) = make_float2(v0, v1);
            }
        }
    }
}

// ---------------------------------------------------------------------------
// Host launcher
// ---------------------------------------------------------------------------
static void launch_gemm(int epi, bool transB,
                        const float* A, const float* B, const float* bias, float* C,
                        int M, int N, int K, int lda, int ldb, int ldc,
                        int batch, size_t sA, size_t sB, size_t sC,
                        const float* gate = nullptr, const float* resid = nullptr, int ldres = 0) {
    dim3 grid(N / 128, M / 128, batch);
    if (transB) {
        mma_gemm<true, 0><<<grid, 256>>>(A, B, bias, C, K, lda, ldb, ldc, sA, sB, sC, gate, resid, ldres);
    } else if (epi == 0) {
        mma_gemm<false, 0><<<grid, 256>>>(A, B, bias, C, K, lda, ldb, ldc, sA, sB, sC, gate, resid, ldres);
    } else if (epi == 1) {
        mma_gemm<false, 1><<<grid, 256>>>(A, B, bias, C, K, lda, ldb, ldc, sA, sB, sC, gate, resid, ldres);
    } else {
        mma_gemm<false, 2><<<grid, 256>>>(A, B, bias, C, K, lda, ldb, ldc, sA, sB, sC, gate, resid, ldres);
    }
}

extern "C" void kernel_launch(void* const* d_in, const int* in_sizes, int n_in,
                              void* d_out, int out_size) {
    const float* img        = (const float*)d_in[0];
    const float* txt        = (const float*)d_in[1];
    const float* vec        = (const float*)d_in[2];
    const float* pe         = (const float*)d_in[3];
    const float* img_mod_w  = (const float*)d_in[4];
    const float* img_mod_b  = (const float*)d_in[5];
    const float* img_qkv_w  = (const float*)d_in[6];
    const float* img_qkv_b  = (const float*)d_in[7];
    const float* img_q_s    = (const float*)d_in[8];
    const float* img_k_s    = (const float*)d_in[9];
    const float* img_proj_w = (const float*)d_in[10];
    const float* img_proj_b = (const float*)d_in[11];
    const float* img_mlp_w1 = (const float*)d_in[12];
    const float* img_mlp_b1 = (const float*)d_in[13];
    const float* img_mlp_w2 = (const float*)d_in[14];
    const float* img_mlp_b2 = (const float*)d_in[15];
    const float* txt_mod_w  = (const float*)d_in[16];
    const float* txt_mod_b  = (const float*)d_in[17];
    const float* txt_qkv_w  = (const float*)d_in[18];
    const float* txt_qkv_b  = (const float*)d_in[19];
    const float* txt_q_s    = (const float*)d_in[20];
    const float* txt_k_s    = (const float*)d_in[21];
    const float* txt_proj_w = (const float*)d_in[22];
    const float* txt_proj_b = (const float*)d_in[23];
    const float* txt_mlp_w1 = (const float*)d_in[24];
    const float* txt_mlp_b1 = (const float*)d_in[25];
    const float* txt_mlp_w2 = (const float*)d_in[26];
    const float* txt_mlp_b2 = (const float*)d_in[27];
    float* out = (float*)d_out;

    float *sv, *modi, *modt, *x, *qkvb, *q, *k, *v, *attn, *x1, *x2, *h1;
    cudaGetSymbolAddress((void**)&sv,     g_silu);
    cudaGetSymbolAddress((void**)&modi,   g_mod_img);
    cudaGetSymbolAddress((void**)&modt,   g_mod_txt);
    cudaGetSymbolAddress((void**)&x,      g_x);
    cudaGetSymbolAddress((void**)&qkvb,   g_qkv);
    cudaGetSymbolAddress((void**)&q,      g_q);
    cudaGetSymbolAddress((void**)&k,      g_k);
    cudaGetSymbolAddress((void**)&v,      g_v);
    cudaGetSymbolAddress((void**)&attn,   g_attn);
    cudaGetSymbolAddress((void**)&x1,     g_x1);
    cudaGetSymbolAddress((void**)&x2,     g_x2);
    cudaGetSymbolAddress((void**)&h1,     g_h1);

    // allow 166KB dynamic smem for flash_attn (idempotent)
    cudaFuncSetAttribute(flash_attn, cudaFuncAttributeMaxDynamicSharedMemorySize,
                         FA_SMEM_BYTES);

    // 1. silu(vec)
    silu_kernel<<<HS / 256, 256>>>(vec, sv);

    // 2. modulation params (split-K GEMV)
    mod_gemv2<<<(6 * HS) / 64, 256>>>(sv, img_mod_w, img_mod_b, modi);
    mod_gemv2<<<(6 * HS) / 64, 256>>>(sv, txt_mod_w, txt_mod_b, modt);

    // 3. LN + modulate (txt rows 0..511, img rows 512..2559)
    ln_mod<<<LTXT, 256>>>(txt, x,                       modt + 0 * HS, modt + 1 * HS);
    ln_mod<<<LIMG, 256>>>(img, x + (size_t)LTXT * HS,   modi + 0 * HS, modi + 1 * HS);

    // 4. QKV GEMMs
    launch_gemm(0, false, x, txt_qkv_w, txt_qkv_b, qkvb,
                LTXT, QKVW, HS, HS, QKVW, QKVW, 1, 0, 0, 0);
    launch_gemm(0, false, x + (size_t)LTXT * HS, img_qkv_w, img_qkv_b,
                qkvb + (size_t)LTXT * QKVW,
                LIMG, QKVW, HS, HS, QKVW, QKVW, 1, 0, 0, 0);

    // 5. RMS norm + RoPE + head-major scatter
    rms_rope<<<LTOT, 256>>>(qkvb, pe, txt_q_s, txt_k_s, img_q_s, img_k_s, q, k, v);

    // 6-8. fused flash attention -> attn [l][h*HD+d]
    {
        dim3 fgrid(LTOT / 128, NH);
        flash_attn<<<fgrid, 256, FA_SMEM_BYTES>>>(q, k, v, attn);
    }

    // 9. proj + gated residual  -> x1
    launch_gemm(2, false, attn, txt_proj_w, txt_proj_b, x1,
                LTXT, HS, HS, HS, HS, HS, 1, 0, 0, 0,
                modt + 2 * HS, txt, HS);
    launch_gemm(2, false, attn + (size_t)LTXT * HS, img_proj_w, img_proj_b,
                x1 + (size_t)LTXT * HS,
                LIMG, HS, HS, HS, HS, HS, 1, 0, 0, 0,
                modi + 2 * HS, img, HS);

    // 10. second LN + modulate -> x2
    ln_mod<<<LTXT, 256>>>(x1, x2,                                   modt + 3 * HS, modt + 4 * HS);
    ln_mod<<<LIMG, 256>>>(x1 + (size_t)LTXT * HS, x2 + (size_t)LTXT * HS, modi + 3 * HS, modi + 4 * HS);

    // 11. MLP1 with fused GELU -> h1
    launch_gemm(1, false, x2, txt_mlp_w1, txt_mlp_b1, h1,
                LTXT, MLPD, HS, HS, MLPD, MLPD, 1, 0, 0, 0);
    launch_gemm(1, false, x2 + (size_t)LTXT * HS, img_mlp_w1, img_mlp_b1,
                h1 + (size_t)LTXT * MLPD,
                LIMG, MLPD, HS, HS, MLPD, MLPD, 1, 0, 0, 0);

    // 12. MLP2 with fused gated residual, written straight to d_out
    //     output layout: img (2048*3072) then txt (512*3072)
    launch_gemm(2, false, h1, txt_mlp_w2, txt_mlp_b2,
                out + (size_t)LIMG * HS,
                LTXT, HS, MLPD, MLPD, HS, HS, 1, 0, 0, 0,
                modt + 5 * HS, x1, HS);
    launch_gemm(2, false, h1 + (size_t)LTXT * MLPD, img_mlp_w2, img_mlp_b2,
                out,
                LIMG, HS, MLPD, MLPD, HS, HS, 1, 0, 0, 0,
                modi + 5 * HS, x1 + (size_t)LTXT * HS, HS);
}

// round 6
// speedup vs baseline: 2.4815x; 1.0003x over previous
#include <cuda_runtime.h>
#include <cuda_bf16.h>
#include <math.h>

// ---------------------------------------------------------------------------
// Problem constants
// ---------------------------------------------------------------------------
#define HS    3072
#define MLPD  12288
#define NH    24
#define HD    128
#define LTXT  512
#define LIMG  2048
#define LTOT  2560          // txt rows [0,512), img rows [512,2560)
#define QKVW  9216          // 3*HS

// ---------------------------------------------------------------------------
// Static device scratch (no allocations allowed)
// ---------------------------------------------------------------------------
__device__ float g_silu[HS];
__device__ float g_mod_img[6 * HS];
__device__ float g_mod_txt[6 * HS];
__device__ float g_x   [(size_t)LTOT * HS];       // modulated LN input
__device__ float g_qkv [(size_t)LTOT * QKVW];
__device__ float g_q   [(size_t)NH * LTOT * HD];
__device__ float g_k   [(size_t)NH * LTOT * HD];
__device__ float g_v   [(size_t)NH * LTOT * HD];
__device__ float g_attn[(size_t)LTOT * HS];
__device__ float g_x1  [(size_t)LTOT * HS];       // after first residual
__device__ float g_x2  [(size_t)LTOT * HS];       // second modulated LN
__device__ float g_h1  [(size_t)LTOT * MLPD];     // MLP hidden

// ---------------------------------------------------------------------------
// Small elementwise kernels
// ---------------------------------------------------------------------------
__global__ void silu_kernel(const float* __restrict__ v, float* __restrict__ o) {
    int i = blockIdx.x * 256 + threadIdx.x;
    if (i < HS) {
        float x = v[i];
        o[i] = x / (1.0f + expf(-x));
    }
}

// split-K modulation GEMV: grid = 6*HS/64 blocks, 256 threads
// block computes 64 outputs; 4 thread-groups split K; smem reduce.
__global__ void mod_gemv2(const float* __restrict__ sv, const float* __restrict__ w,
                          const float* __restrict__ b, float* __restrict__ out) {
    __shared__ float ssv[HS];
    __shared__ float red[4][64];
    for (int i = threadIdx.x; i < HS; i += 256) ssv[i] = sv[i];
    __syncthreads();
    const int jl = threadIdx.x & 63, kq = threadIdx.x >> 6;
    const int j = blockIdx.x * 64 + jl;
    const int i0 = kq * (HS / 4);
    float acc = 0.0f;
    #pragma unroll 8
    for (int i = 0; i < HS / 4; i++)
        acc += ssv[i0 + i] * w[(size_t)(i0 + i) * (6 * HS) + j];
    red[kq][jl] = acc;
    __syncthreads();
    if (threadIdx.x < 64) {
        int jj = blockIdx.x * 64 + threadIdx.x;
        out[jj] = red[0][threadIdx.x] + red[1][threadIdx.x] +
                  red[2][threadIdx.x] + red[3][threadIdx.x] + b[jj];
    }
}

// LayerNorm + modulate: dst = shift + (1+scale) * LN(x) ; one block per row
__global__ void ln_mod(const float* __restrict__ x, float* __restrict__ dst,
                       const float* __restrict__ shift, const float* __restrict__ scale) {
    int row = blockIdx.x;
    int t = threadIdx.x;
    const float* xr = x + (size_t)row * HS;
    float v[12];
    float s = 0.0f;
    #pragma unroll
    for (int i = 0; i < 12; i++) { v[i] = xr[t + i * 256]; s += v[i]; }
    __shared__ float red[256];
    red[t] = s; __syncthreads();
    for (int o = 128; o > 0; o >>= 1) { if (t < o) red[t] += red[t + o]; __syncthreads(); }
    float mean = red[0] * (1.0f / HS);
    __syncthreads();
    float s2 = 0.0f;
    #pragma unroll
    for (int i = 0; i < 12; i++) { float d = v[i] - mean; s2 += d * d; }
    red[t] = s2; __syncthreads();
    for (int o = 128; o > 0; o >>= 1) { if (t < o) red[t] += red[t + o]; __syncthreads(); }
    float inv = rsqrtf(red[0] * (1.0f / HS) + 1e-6f);
    float* dr = dst + (size_t)row * HS;
    #pragma unroll
    for (int i = 0; i < 12; i++) {
        int c = t + i * 256;
        dr[c] = shift[c] + (1.0f + scale[c]) * (v[i] - mean) * inv;
    }
}

// Per-head RMS-norm(q,k) + RoPE + scatter to [h][l][d]; copy v.
__global__ void rms_rope(const float* __restrict__ qkv, const float* __restrict__ pe,
                         const float* __restrict__ tqs, const float* __restrict__ tks,
                         const float* __restrict__ iqs, const float* __restrict__ iks,
                         float* __restrict__ Q, float* __restrict__ Kp, float* __restrict__ Vp) {
    int l = blockIdx.x;
    int w = threadIdx.x >> 5, lane = threadIdx.x & 31;
    const float* qs = (l < LTXT) ? tqs : iqs;
    const float* ks = (l < LTXT) ? tks : iks;
    const float* row = qkv + (size_t)l * QKVW;
    const float* peb = pe + (size_t)l * 256 + lane * 8; // 2 rope pairs per lane
    float4 p0 = *(const float4*)(peb);
    float4 p1 = *(const float4*)(peb + 4);
    int d0 = lane * 4;
    float4 scq = *(const float4*)(qs + d0);
    float4 sck = *(const float4*)(ks + d0);

    for (int h = w; h < NH; h += 8) {
        // ---- Q
        float4 xq = *(const float4*)(row + h * HD + d0);
        float ss = xq.x*xq.x + xq.y*xq.y + xq.z*xq.z + xq.w*xq.w;
        #pragma unroll
        for (int o = 16; o > 0; o >>= 1) ss += __shfl_xor_sync(0xffffffffu, ss, o);
        float r = rsqrtf(ss * (1.0f / HD) + 1e-6f);
        float x0 = xq.x * r * scq.x, x1 = xq.y * r * scq.y;
        float x2 = xq.z * r * scq.z, x3 = xq.w * r * scq.w;
        float4 oq;
        oq.x = p0.x * x0 + p0.y * x1;
        oq.y = p0.z * x0 + p0.w * x1;
        oq.z = p1.x * x2 + p1.y * x3;
        oq.w = p1.z * x2 + p1.w * x3;
        *(float4*)(Q + ((size_t)h * LTOT + l) * HD + d0) = oq;
        // ---- K
        float4 xk = *(const float4*)(row + HS + h * HD + d0);
        float sk = xk.x*xk.x + xk.y*xk.y + xk.z*xk.z + xk.w*xk.w;
        #pragma unroll
        for (int o = 16; o > 0; o >>= 1) sk += __shfl_xor_sync(0xffffffffu, sk, o);
        float rk = rsqrtf(sk * (1.0f / HD) + 1e-6f);
        float y0 = xk.x * rk * sck.x, y1 = xk.y * rk * sck.y;
        float y2 = xk.z * rk * sck.z, y3 = xk.w * rk * sck.w;
        float4 ok;
        ok.x = p0.x * y0 + p0.y * y1;
        ok.y = p0.z * y0 + p0.w * y1;
        ok.z = p1.x * y2 + p1.y * y3;
        ok.w = p1.z * y2 + p1.w * y3;
        *(float4*)(Kp + ((size_t)h * LTOT + l) * HD + d0) = ok;
        // ---- V copy
        float4 xv = *(const float4*)(row + 2 * HS + h * HD + d0);
        *(float4*)(Vp + ((size_t)h * LTOT + l) * HD + d0) = xv;
    }
}

// ---------------------------------------------------------------------------
// TF32 helpers
// ---------------------------------------------------------------------------
__device__ __forceinline__ float gelu_tanh(float x) {
    float x3 = x * x * x;
    return 0.5f * x * (1.0f + tanhf(0.7978845608028654f * (x + 0.044715f * x3)));
}

__device__ __forceinline__ float to_tf32(float x) {
    unsigned int u;
    asm("cvt.rna.tf32.f32 %0, %1;" : "=r"(u) : "f"(x));
    return __uint_as_float(u);
}

__device__ __forceinline__ void mma_tf32(float c[4], const unsigned int a[4],
                                         const unsigned int b[2]) {
    asm volatile(
        "mma.sync.aligned.m16n8k8.row.col.f32.tf32.tf32.f32 "
        "{%0,%1,%2,%3}, {%4,%5,%6,%7}, {%8,%9}, {%0,%1,%2,%3};"
        : "+f"(c[0]), "+f"(c[1]), "+f"(c[2]), "+f"(c[3])
        : "r"(a[0]), "r"(a[1]), "r"(a[2]), "r"(a[3]), "r"(b[0]), "r"(b[1]));
}

// ---------------------------------------------------------------------------
// Flash attention: 128 Q rows per CTA, 64-wide KV tiles, tf32 mma, online
// softmax. Grid (LTOT/128, NH), 256 threads (8 warps, 16 Q rows each).
// O written to [l][h*HD+d] (i.e. g_attn row-major HS).
// ---------------------------------------------------------------------------
#define FA_SCALE 0.08838834764831845f
#define SQ_PITCH 132
#define SK_PITCH 68
#define SV_PITCH 132
#define SP_PITCH 132
#define SQ_OFF 0
#define SK_OFF (128 * SQ_PITCH)
#define SV_OFF (SK_OFF + 128 * SK_PITCH)
#define SP_OFF (SV_OFF + 64 * SV_PITCH)
#define FA_SMEM_FLOATS (SP_OFF + 64 * SP_PITCH)
#define FA_SMEM_BYTES (FA_SMEM_FLOATS * 4)

__global__ void __launch_bounds__(256, 1)
flash_attn(const float* __restrict__ Q, const float* __restrict__ K,
           const float* __restrict__ V, float* __restrict__ O) {
    extern __shared__ float sm[];
    float* sQ = sm + SQ_OFF;
    float* sK = sm + SK_OFF;
    float* sV = sm + SV_OFF;
    float* sP = sm + SP_OFF;

    const int t = threadIdx.x;
    const int wid = t >> 5, lane = t & 31;
    const int gid = lane >> 2, tig = lane & 3;
    const int h = blockIdx.y;
    const int q0 = blockIdx.x * 128;
    const int m0 = wid * 16;

    const float* Qh = Q + ((size_t)h * LTOT + q0) * HD;
    const float* Kh = K + (size_t)h * LTOT * HD;
    const float* Vh = V + (size_t)h * LTOT * HD;

    // --- load Q tile transposed into sQ[d][row], pre-scaled, tf32 ---
    {
        int r = t >> 1;
        int dseg = (t & 1) * 64;
        const float* qr = Qh + (size_t)r * HD + dseg;
        #pragma unroll
        for (int i = 0; i < 16; i++) {
            float4 v4 = *(const float4*)(qr + i * 4);
            int d = dseg + i * 4;
            sQ[(d + 0) * SQ_PITCH + r] = to_tf32(v4.x * FA_SCALE);
            sQ[(d + 1) * SQ_PITCH + r] = to_tf32(v4.y * FA_SCALE);
            sQ[(d + 2) * SQ_PITCH + r] = to_tf32(v4.z * FA_SCALE);
            sQ[(d + 3) * SQ_PITCH + r] = to_tf32(v4.w * FA_SCALE);
        }
    }
    __syncthreads();

    // --- Q fragments register-resident for the whole KV loop ---
    unsigned int qf[16][4];
    #pragma unroll
    for (int kt = 0; kt < 16; kt++) {
        int kb = kt * 8;
        qf[kt][0] = __float_as_uint(sQ[(kb + tig)     * SQ_PITCH + m0 + gid]);
        qf[kt][1] = __float_as_uint(sQ[(kb + tig)     * SQ_PITCH + m0 + gid + 8]);
        qf[kt][2] = __float_as_uint(sQ[(kb + tig + 4) * SQ_PITCH + m0 + gid]);
        qf[kt][3] = __float_as_uint(sQ[(kb + tig + 4) * SQ_PITCH + m0 + gid + 8]);
    }

    float co[16][4];
    #pragma unroll
    for (int i = 0; i < 16; i++)
        #pragma unroll
        for (int j = 0; j < 4; j++) co[i][j] = 0.0f;
    float mrow0 = -1e30f, mrow1 = -1e30f, lrow0 = 0.0f, lrow1 = 0.0f;

    for (int kv = 0; kv < LTOT; kv += 64) {
        __syncthreads();   // previous iteration done with sK/sV
        // load K tile transposed: sK[d][c]
        {
            int c = t >> 2;
            int dseg = (t & 3) * 32;
            const float* kr = Kh + (size_t)(kv + c) * HD + dseg;
            #pragma unroll
            for (int i = 0; i < 8; i++) {
                float4 v4 = *(const float4*)(kr + i * 4);
                int d = dseg + i * 4;
                sK[(d + 0) * SK_PITCH + c] = to_tf32(v4.x);
                sK[(d + 1) * SK_PITCH + c] = to_tf32(v4.y);
                sK[(d + 2) * SK_PITCH + c] = to_tf32(v4.z);
                sK[(d + 3) * SK_PITCH + c] = to_tf32(v4.w);
            }
        }
        // load V tile: sV[c][d]
        {
            int c = t >> 2;
            int dseg = (t & 3) * 32;
            const float* vr = Vh + (size_t)(kv + c) * HD + dseg;
            #pragma unroll
            for (int i = 0; i < 8; i++) {
                float4 v4 = *(const float4*)(vr + i * 4);
                float4 q4 = make_float4(to_tf32(v4.x), to_tf32(v4.y),
                                        to_tf32(v4.z), to_tf32(v4.w));
                *(float4*)(sV + c * SV_PITCH + dseg + i * 4) = q4;
            }
        }
        __syncthreads();

        // --- S = Q @ K^T : 16x64 per warp ---
        float cs[8][4];
        #pragma unroll
        for (int i = 0; i < 8; i++)
            #pragma unroll
            for (int j = 0; j < 4; j++) cs[i][j] = 0.0f;
        #pragma unroll
        for (int kt = 0; kt < 16; kt++) {
            int kb = kt * 8;
            #pragma unroll
            for (int nt = 0; nt < 8; nt++) {
                unsigned int bf[2];
                bf[0] = __float_as_uint(sK[(kb + tig)     * SK_PITCH + nt * 8 + gid]);
                bf[1] = __float_as_uint(sK[(kb + tig + 4) * SK_PITCH + nt * 8 + gid]);
                mma_tf32(cs[nt], qf[kt], bf);
            }
        }

        // --- online softmax ---
        float rmax0 = -1e30f, rmax1 = -1e30f;
        #pragma unroll
        for (int nt = 0; nt < 8; nt++) {
            rmax0 = fmaxf(rmax0, fmaxf(cs[nt][0], cs[nt][1]));
            rmax1 = fmaxf(rmax1, fmaxf(cs[nt][2], cs[nt][3]));
        }
        rmax0 = fmaxf(rmax0, __shfl_xor_sync(0xffffffffu, rmax0, 1));
        rmax0 = fmaxf(rmax0, __shfl_xor_sync(0xffffffffu, rmax0, 2));
        rmax1 = fmaxf(rmax1, __shfl_xor_sync(0xffffffffu, rmax1, 1));
        rmax1 = fmaxf(rmax1, __shfl_xor_sync(0xffffffffu, rmax1, 2));
        float mn0 = fmaxf(mrow0, rmax0);
        float mn1 = fmaxf(mrow1, rmax1);
        float corr0 = __expf(mrow0 - mn0);
        float corr1 = __expf(mrow1 - mn1);
        mrow0 = mn0; mrow1 = mn1;

        float rs0 = 0.0f, rs1 = 0.0f;
        #pragma unroll
        for (int nt = 0; nt < 8; nt++) {
            cs[nt][0] = __expf(cs[nt][0] - mn0);
            cs[nt][1] = __expf(cs[nt][1] - mn0);
            cs[nt][2] = __expf(cs[nt][2] - mn1);
            cs[nt][3] = __expf(cs[nt][3] - mn1);
            rs0 += cs[nt][0] + cs[nt][1];
            rs1 += cs[nt][2] + cs[nt][3];
        }
        rs0 += __shfl_xor_sync(0xffffffffu, rs0, 1);
        rs0 += __shfl_xor_sync(0xffffffffu, rs0, 2);
        rs1 += __shfl_xor_sync(0xffffffffu, rs1, 1);
        rs1 += __shfl_xor_sync(0xffffffffu, rs1, 2);
        lrow0 = lrow0 * corr0 + rs0;
        lrow1 = lrow1 * corr1 + rs1;

        #pragma unroll
        for (int nt = 0; nt < 16; nt++) {
            co[nt][0] *= corr0; co[nt][1] *= corr0;
            co[nt][2] *= corr1; co[nt][3] *= corr1;
        }

        // --- store P transposed into sP[kvcol][row] (tf32) ---
        #pragma unroll
        for (int nt = 0; nt < 8; nt++) {
            int cb = nt * 8 + tig * 2;
            sP[(cb + 0) * SP_PITCH + m0 + gid]     = to_tf32(cs[nt][0]);
            sP[(cb + 1) * SP_PITCH + m0 + gid]     = to_tf32(cs[nt][1]);
            sP[(cb + 0) * SP_PITCH + m0 + gid + 8] = to_tf32(cs[nt][2]);
            sP[(cb + 1) * SP_PITCH + m0 + gid + 8] = to_tf32(cs[nt][3]);
        }
        __syncwarp();

        // --- O += P @ V ---
        #pragma unroll
        for (int kt = 0; kt < 8; kt++) {
            int kb = kt * 8;
            unsigned int af[4];
            af[0] = __float_as_uint(sP[(kb + tig)     * SP_PITCH + m0 + gid]);
            af[1] = __float_as_uint(sP[(kb + tig)     * SP_PITCH + m0 + gid + 8]);
            af[2] = __float_as_uint(sP[(kb + tig + 4) * SP_PITCH + m0 + gid]);
            af[3] = __float_as_uint(sP[(kb + tig + 4) * SP_PITCH + m0 + gid + 8]);
            #pragma unroll
            for (int nt = 0; nt < 16; nt++) {
                unsigned int bf[2];
                bf[0] = __float_as_uint(sV[(kb + tig)     * SV_PITCH + nt * 8 + gid]);
                bf[1] = __float_as_uint(sV[(kb + tig + 4) * SV_PITCH + nt * 8 + gid]);
                mma_tf32(co[nt], af, bf);
            }
        }
    }

    // --- epilogue: O /= l, write [l][h*HD+d] ---
    float inv0 = 1.0f / lrow0;
    float inv1 = 1.0f / lrow1;
    int row0 = q0 + m0 + gid;
    #pragma unroll
    for (int nt = 0; nt < 16; nt++) {
        int col = h * HD + nt * 8 + tig * 2;
        *(float2*)(O + (size_t)row0 * HS + col) =
            make_float2(co[nt][0] * inv0, co[nt][1] * inv0);
        *(float2*)(O + (size_t)(row0 + 8) * HS + col) =
            make_float2(co[nt][2] * inv1, co[nt][3] * inv1);
    }
}

// ---------------------------------------------------------------------------
// TF32 tensor-core GEMM: 128x128 block tile, 8 warps (2x4), 64x32 per warp,
// m16n8k8 mma, K-step 16, double-buffered smem.
// EPI: 0 = acc+bias ; 1 = gelu(acc+bias) ; 2 = resid + gate*(acc+bias)
// ---------------------------------------------------------------------------
template <bool TRANSB, int EPI>
__global__ void __launch_bounds__(256, 2)
mma_gemm(const float* __restrict__ A, const float* __restrict__ B,
         const float* __restrict__ bias, float* __restrict__ C,
         int K, int lda, int ldb, int ldc,
         size_t sA, size_t sB, size_t sC,
         const float* __restrict__ gate, const float* __restrict__ resid, int ldres) {
    A += (size_t)blockIdx.z * sA;
    B += (size_t)blockIdx.z * sB;
    C += (size_t)blockIdx.z * sC;

    __shared__ float As[2][16][132];
    __shared__ float Bs[2][16][132];

    const int t = threadIdx.x;
    const int wid = t >> 5, lane = t & 31;
    const int wm = wid >> 2, wn = wid & 3;
    const int gid = lane >> 2, tig = lane & 3;
    const int m0 = blockIdx.y * 128, n0 = blockIdx.x * 128;

    const int a_m = t >> 1, a_k = (t & 1) * 4;
    const int bt_n = t >> 1, bt_k = (t & 1) * 4;
    const int b_k = t >> 5,  b_n = (t & 31) * 4;

    const float* Ap = A + (size_t)(m0 + a_m) * lda + a_k;
    const float* Bp = TRANSB ? B + (size_t)(n0 + bt_n) * ldb + bt_k
                             : B + (size_t)b_k * ldb + n0 + b_n;

    float c[4][4][4];
    #pragma unroll
    for (int i = 0; i < 4; i++)
        #pragma unroll
        for (int j = 0; j < 4; j++)
            #pragma unroll
            for (int r = 0; r < 4; r++) c[i][j][r] = 0.0f;

    const int nk = K / 16;
    float4 pa0, pa1, pb0, pb1;

    pa0 = *(const float4*)(Ap);
    pa1 = *(const float4*)(Ap + 8);
    if (TRANSB) {
        pb0 = *(const float4*)(Bp);
        pb1 = *(const float4*)(Bp + 8);
    } else {
        pb0 = *(const float4*)(Bp);
        pb1 = *(const float4*)(Bp + (size_t)8 * ldb);
    }
    {
        As[0][a_k + 0][a_m] = to_tf32(pa0.x); As[0][a_k + 1][a_m] = to_tf32(pa0.y);
        As[0][a_k + 2][a_m] = to_tf32(pa0.z); As[0][a_k + 3][a_m] = to_tf32(pa0.w);
        As[0][a_k + 8][a_m] = to_tf32(pa1.x); As[0][a_k + 9][a_m] = to_tf32(pa1.y);
        As[0][a_k +10][a_m] = to_tf32(pa1.z); As[0][a_k +11][a_m] = to_tf32(pa1.w);
        if (TRANSB) {
            Bs[0][bt_k + 0][bt_n] = to_tf32(pb0.x); Bs[0][bt_k + 1][bt_n] = to_tf32(pb0.y);
            Bs[0][bt_k + 2][bt_n] = to_tf32(pb0.z); Bs[0][bt_k + 3][bt_n] = to_tf32(pb0.w);
            Bs[0][bt_k + 8][bt_n] = to_tf32(pb1.x); Bs[0][bt_k + 9][bt_n] = to_tf32(pb1.y);
            Bs[0][bt_k +10][bt_n] = to_tf32(pb1.z); Bs[0][bt_k +11][bt_n] = to_tf32(pb1.w);
        } else {
            float4 q0 = make_float4(to_tf32(pb0.x), to_tf32(pb0.y), to_tf32(pb0.z), to_tf32(pb0.w));
            float4 q1 = make_float4(to_tf32(pb1.x), to_tf32(pb1.y), to_tf32(pb1.z), to_tf32(pb1.w));
            *(float4*)(&Bs[0][b_k][b_n])     = q0;
            *(float4*)(&Bs[0][b_k + 8][b_n]) = q1;
        }
    }
    __syncthreads();

    for (int kt = 0; kt < nk; kt++) {
        const int buf = kt & 1;
        const bool has_next = (kt + 1 < nk);
        if (has_next) {
            const int off = (kt + 1) * 16;
            pa0 = *(const float4*)(Ap + off);
            pa1 = *(const float4*)(Ap + off + 8);
            if (TRANSB) {
                pb0 = *(const float4*)(Bp + off);
                pb1 = *(const float4*)(Bp + off + 8);
            } else {
                pb0 = *(const float4*)(Bp + (size_t)off * ldb);
                pb1 = *(const float4*)(Bp + (size_t)(off + 8) * ldb);
            }
        }

        #pragma unroll
        for (int ks = 0; ks < 2; ks++) {
            const int kb = ks * 8;
            unsigned int af[4][4], bf[4][2];
            #pragma unroll
            for (int mt = 0; mt < 4; mt++) {
                const int bm = wm * 64 + mt * 16 + gid;
                af[mt][0] = __float_as_uint(As[buf][kb + tig    ][bm]);
                af[mt][1] = __float_as_uint(As[buf][kb + tig    ][bm + 8]);
                af[mt][2] = __float_as_uint(As[buf][kb + tig + 4][bm]);
                af[mt][3] = __float_as_uint(As[buf][kb + tig + 4][bm + 8]);
            }
            #pragma unroll
            for (int nt = 0; nt < 4; nt++) {
                const int bn = wn * 32 + nt * 8 + gid;
                bf[nt][0] = __float_as_uint(Bs[buf][kb + tig    ][bn]);
                bf[nt][1] = __float_as_uint(Bs[buf][kb + tig + 4][bn]);
            }
            #pragma unroll
            for (int mt = 0; mt < 4; mt++)
                #pragma unroll
                for (int nt = 0; nt < 4; nt++)
                    mma_tf32(c[mt][nt], af[mt], bf[nt]);
        }

        if (has_next) {
            const int nb = buf ^ 1;
            As[nb][a_k + 0][a_m] = to_tf32(pa0.x); As[nb][a_k + 1][a_m] = to_tf32(pa0.y);
            As[nb][a_k + 2][a_m] = to_tf32(pa0.z); As[nb][a_k + 3][a_m] = to_tf32(pa0.w);
            As[nb][a_k + 8][a_m] = to_tf32(pa1.x); As[nb][a_k + 9][a_m] = to_tf32(pa1.y);
            As[nb][a_k +10][a_m] = to_tf32(pa1.z); As[nb][a_k +11][a_m] = to_tf32(pa1.w);
            if (TRANSB) {
                Bs[nb][bt_k + 0][bt_n] = to_tf32(pb0.x); Bs[nb][bt_k + 1][bt_n] = to_tf32(pb0.y);
                Bs[nb][bt_k + 2][bt_n] = to_tf32(pb0.z); Bs[nb][bt_k + 3][bt_n] = to_tf32(pb0.w);
                Bs[nb][bt_k + 8][bt_n] = to_tf32(pb1.x); Bs[nb][bt_k + 9][bt_n] = to_tf32(pb1.y);
                Bs[nb][bt_k +10][bt_n] = to_tf32(pb1.z); Bs[nb][bt_k +11][bt_n] = to_tf32(pb1.w);
            } else {
                float4 q0 = make_float4(to_tf32(pb0.x), to_tf32(pb0.y), to_tf32(pb0.z), to_tf32(pb0.w));
                float4 q1 = make_float4(to_tf32(pb1.x), to_tf32(pb1.y), to_tf32(pb1.z), to_tf32(pb1.w));
                *(float4*)(&Bs[nb][b_k][b_n])     = q0;
                *(float4*)(&Bs[nb][b_k + 8][b_n]) = q1;
            }
        }
        __syncthreads();
    }

    #pragma unroll
    for (int nt = 0; nt < 4; nt++) {
        const int col = n0 + wn * 32 + nt * 8 + tig * 2;
        const float bv0 = bias ? bias[col]     : 0.0f;
        const float bv1 = bias ? bias[col + 1] : 0.0f;
        float gv0 = 0.0f, gv1 = 0.0f;
        if (EPI == 2) { gv0 = gate[col]; gv1 = gate[col + 1]; }
        #pragma unroll
        for (int mt = 0; mt < 4; mt++) {
            const int row0 = m0 + wm * 64 + mt * 16 + gid;
            #pragma unroll
            for (int h = 0; h < 2; h++) {
                const int row = row0 + h * 8;
                float v0 = c[mt][nt][h * 2 + 0] + bv0;
                float v1 = c[mt][nt][h * 2 + 1] + bv1;
                if (EPI == 1) { v0 = gelu_tanh(v0); v1 = gelu_tanh(v1); }
                if (EPI == 2) {
                    const float* Rr = resid + (size_t)row * ldres + col;
                    v0 = Rr[0] + gv0 * v0;
                    v1 = Rr[1] + gv1 * v1;
                }
                *(float2*)(C + (size_t)row * ldc + col) = make_float2(v0, v1);
            }
        }
    }
}

// ---------------------------------------------------------------------------
// Host launcher
// ---------------------------------------------------------------------------
static void launch_gemm(int epi, bool transB,
                        const float* A, const float* B, const float* bias, float* C,
                        int M, int N, int K, int lda, int ldb, int ldc,
                        int batch, size_t sA, size_t sB, size_t sC,
                        const float* gate = nullptr, const float* resid = nullptr, int ldres = 0) {
    dim3 grid(N / 128, M / 128, batch);
    if (transB) {
        mma_gemm<true, 0><<<grid, 256>>>(A, B, bias, C, K, lda, ldb, ldc, sA, sB, sC, gate, resid, ldres);
    } else if (epi == 0) {
        mma_gemm<false, 0><<<grid, 256>>>(A, B, bias, C, K, lda, ldb, ldc, sA, sB, sC, gate, resid, ldres);
    } else if (epi == 1) {
        mma_gemm<false, 1><<<grid, 256>>>(A, B, bias, C, K, lda, ldb, ldc, sA, sB, sC, gate, resid, ldres);
    } else {
        mma_gemm<false, 2><<<grid, 256>>>(A, B, bias, C, K, lda, ldb, ldc, sA, sB, sC, gate, resid, ldres);
    }
}

extern "C" void kernel_launch(void* const* d_in, const int* in_sizes, int n_in,
                              void* d_out, int out_size) {
    const float* img        = (const float*)d_in[0];
    const float* txt        = (const float*)d_in[1];
    const float* vec        = (const float*)d_in[2];
    const float* pe         = (const float*)d_in[3];
    const float* img_mod_w  = (const float*)d_in[4];
    const float* img_mod_b  = (const float*)d_in[5];
    const float* img_qkv_w  = (const float*)d_in[6];
    const float* img_qkv_b  = (const float*)d_in[7];
    const float* img_q_s    = (const float*)d_in[8];
    const float* img_k_s    = (const float*)d_in[9];
    const float* img_proj_w = (const float*)d_in[10];
    const float* img_proj_b = (const float*)d_in[11];
    const float* img_mlp_w1 = (const float*)d_in[12];
    const float* img_mlp_b1 = (const float*)d_in[13];
    const float* img_mlp_w2 = (const float*)d_in[14];
    const float* img_mlp_b2 = (const float*)d_in[15];
    const float* txt_mod_w  = (const float*)d_in[16];
    const float* txt_mod_b  = (const float*)d_in[17];
    const float* txt_qkv_w  = (const float*)d_in[18];
    const float* txt_qkv_b  = (const float*)d_in[19];
    const float* txt_q_s    = (const float*)d_in[20];
    const float* txt_k_s    = (const float*)d_in[21];
    const float* txt_proj_w = (const float*)d_in[22];
    const float* txt_proj_b = (const float*)d_in[23];
    const float* txt_mlp_w1 = (const float*)d_in[24];
    const float* txt_mlp_b1 = (const float*)d_in[25];
    const float* txt_mlp_w2 = (const float*)d_in[26];
    const float* txt_mlp_b2 = (const float*)d_in[27];
    float* out = (float*)d_out;

    float *sv, *modi, *modt, *x, *qkvb, *q, *k, *v, *attn, *x1, *x2, *h1;
    cudaGetSymbolAddress((void**)&sv,     g_silu);
    cudaGetSymbolAddress((void**)&modi,   g_mod_img);
    cudaGetSymbolAddress((void**)&modt,   g_mod_txt);
    cudaGetSymbolAddress((void**)&x,      g_x);
    cudaGetSymbolAddress((void**)&qkvb,   g_qkv);
    cudaGetSymbolAddress((void**)&q,      g_q);
    cudaGetSymbolAddress((void**)&k,      g_k);
    cudaGetSymbolAddress((void**)&v,      g_v);
    cudaGetSymbolAddress((void**)&attn,   g_attn);
    cudaGetSymbolAddress((void**)&x1,     g_x1);
    cudaGetSymbolAddress((void**)&x2,     g_x2);
    cudaGetSymbolAddress((void**)&h1,     g_h1);

    // allow 166KB dynamic smem for flash_attn (idempotent)
    cudaFuncSetAttribute(flash_attn, cudaFuncAttributeMaxDynamicSharedMemorySize,
                         FA_SMEM_BYTES);

    // 1. silu(vec)
    silu_kernel<<<HS / 256, 256>>>(vec, sv);

    // 2. modulation params (split-K GEMV)
    mod_gemv2<<<(6 * HS) / 64, 256>>>(sv, img_mod_w, img_mod_b, modi);
    mod_gemv2<<<(6 * HS) / 64, 256>>>(sv, txt_mod_w, txt_mod_b, modt);

    // 3. LN + modulate (txt rows 0..511, img rows 512..2559)
    ln_mod<<<LTXT, 256>>>(txt, x,                       modt + 0 * HS, modt + 1 * HS);
    ln_mod<<<LIMG, 256>>>(img, x + (size_t)LTXT * HS,   modi + 0 * HS, modi + 1 * HS);

    // 4. QKV GEMMs
    launch_gemm(0, false, x, txt_qkv_w, txt_qkv_b, qkvb,
                LTXT, QKVW, HS, HS, QKVW, QKVW, 1, 0, 0, 0);
    launch_gemm(0, false, x + (size_t)LTXT * HS, img_qkv_w, img_qkv_b,
                qkvb + (size_t)LTXT * QKVW,
                LIMG, QKVW, HS, HS, QKVW, QKVW, 1, 0, 0, 0);

    // 5. RMS norm + RoPE + head-major scatter
    rms_rope<<<LTOT, 256>>>(qkvb, pe, txt_q_s, txt_k_s, img_q_s, img_k_s, q, k, v);

    // 6-8. fused flash attention -> attn [l][h*HD+d]
    {
        dim3 fgrid(LTOT / 128, NH);
        flash_attn<<<fgrid, 256, FA_SMEM_BYTES>>>(q, k, v, attn);
    }

    // 9. proj + gated residual  -> x1
    launch_gemm(2, false, attn, txt_proj_w, txt_proj_b, x1,
                LTXT, HS, HS, HS, HS, HS, 1, 0, 0, 0,
                modt + 2 * HS, txt, HS);
    launch_gemm(2, false, attn + (size_t)LTXT * HS, img_proj_w, img_proj_b,
                x1 + (size_t)LTXT * HS,
                LIMG, HS, HS, HS, HS, HS, 1, 0, 0, 0,
                modi + 2 * HS, img, HS);

    // 10. second LN + modulate -> x2
    ln_mod<<<LTXT, 256>>>(x1, x2,                                   modt + 3 * HS, modt + 4 * HS);
    ln_mod<<<LIMG, 256>>>(x1 + (size_t)LTXT * HS, x2 + (size_t)LTXT * HS, modi + 3 * HS, modi + 4 * HS);

    // 11. MLP1 with fused GELU -> h1
    launch_gemm(1, false, x2, txt_mlp_w1, txt_mlp_b1, h1,
                LTXT, MLPD, HS, HS, MLPD, MLPD, 1, 0, 0, 0);
    launch_gemm(1, false, x2 + (size_t)LTXT * HS, img_mlp_w1, img_mlp_b1,
                h1 + (size_t)LTXT * MLPD,
                LIMG, MLPD, HS, HS, MLPD, MLPD, 1, 0, 0, 0);

    // 12. MLP2 with fused gated residual, written straight to d_out
    //     output layout: img (2048*3072) then txt (512*3072)
    launch_gemm(2, false, h1, txt_mlp_w2, txt_mlp_b2,
                out + (size_t)LIMG * HS,
                LTXT, HS, MLPD, MLPD, HS, HS, 1, 0, 0, 0,
                modt + 5 * HS, x1, HS);
    launch_gemm(2, false, h1 + (size_t)LTXT * MLPD, img_mlp_w2, img_mlp_b2,
                out,
                LIMG, HS, MLPD, MLPD, HS, HS, 1, 0, 0, 0,
                modi + 5 * HS, x1 + (size_t)LTXT * HS, HS);
}

// round 8
// speedup vs baseline: 3.7787x; 1.5228x over previous
#include <cuda_runtime.h>
#include <cuda_bf16.h>
#include <math.h>
#include <stdint.h>

#define HS    3072
#define MLPD  12288
#define NH    24
#define HD    128
#define LTXT  512
#define LIMG  2048
#define LTOT  2560
#define QKVW  9216

#if defined(__CUDA_ARCH__)
#if defined(__CUDA_ARCH_FEAT_SM103_ALL) || \
    (defined(__CUDA_ARCH_SPECIFIC__) && (__CUDA_ARCH_SPECIFIC__ >= 1000))
#define HAS_TCGEN05 1
#else
#define HAS_TCGEN05 0
#endif
#else
#define HAS_TCGEN05 0
#endif

// ---------------------------------------------------------------------------
// Static device scratch
// ---------------------------------------------------------------------------
__device__ float g_silu[HS];
__device__ float g_mod_img[6 * HS];
__device__ float g_mod_txt[6 * HS];
__device__ float g_x   [(size_t)LTOT * HS];
__device__ float g_qkv [(size_t)LTOT * QKVW];
__device__ float g_q   [(size_t)NH * LTOT * HD];
__device__ float g_k   [(size_t)NH * LTOT * HD];
__device__ float g_v   [(size_t)NH * LTOT * HD];
__device__ float g_attn[(size_t)LTOT * HS];
__device__ float g_x1  [(size_t)LTOT * HS];
__device__ float g_x2  [(size_t)LTOT * HS];
__device__ float g_h1  [(size_t)LTOT * MLPD];

// ---------------------------------------------------------------------------
// Elementwise kernels
// ---------------------------------------------------------------------------
__global__ void silu_kernel(const float* __restrict__ v, float* __restrict__ o) {
    int i = blockIdx.x * 256 + threadIdx.x;
    if (i < HS) { float x = v[i]; o[i] = x / (1.0f + expf(-x)); }
}

__global__ void mod_gemv2(const float* __restrict__ sv, const float* __restrict__ w,
                          const float* __restrict__ b, float* __restrict__ out) {
    __shared__ float ssv[HS];
    __shared__ float red[4][64];
    for (int i = threadIdx.x; i < HS; i += 256) ssv[i] = sv[i];
    __syncthreads();
    const int jl = threadIdx.x & 63, kq = threadIdx.x >> 6;
    const int j = blockIdx.x * 64 + jl;
    const int i0 = kq * (HS / 4);
    float acc = 0.0f;
    #pragma unroll 8
    for (int i = 0; i < HS / 4; i++)
        acc += ssv[i0 + i] * w[(size_t)(i0 + i) * (6 * HS) + j];
    red[kq][jl] = acc;
    __syncthreads();
    if (threadIdx.x < 64) {
        int jj = blockIdx.x * 64 + threadIdx.x;
        out[jj] = red[0][threadIdx.x] + red[1][threadIdx.x] +
                  red[2][threadIdx.x] + red[3][threadIdx.x] + b[jj];
    }
}

__global__ void ln_mod(const float* __restrict__ x, float* __restrict__ dst,
                       const float* __restrict__ shift, const float* __restrict__ scale) {
    int row = blockIdx.x;
    int t = threadIdx.x;
    const float* xr = x + (size_t)row * HS;
    float v[12];
    float s = 0.0f;
    #pragma unroll
    for (int i = 0; i < 12; i++) { v[i] = xr[t + i * 256]; s += v[i]; }
    __shared__ float red[256];
    red[t] = s; __syncthreads();
    for (int o = 128; o > 0; o >>= 1) { if (t < o) red[t] += red[t + o]; __syncthreads(); }
    float mean = red[0] * (1.0f / HS);
    __syncthreads();
    float s2 = 0.0f;
    #pragma unroll
    for (int i = 0; i < 12; i++) { float d = v[i] - mean; s2 += d * d; }
    red[t] = s2; __syncthreads();
    for (int o = 128; o > 0; o >>= 1) { if (t < o) red[t] += red[t + o]; __syncthreads(); }
    float inv = rsqrtf(red[0] * (1.0f / HS) + 1e-6f);
    float* dr = dst + (size_t)row * HS;
    #pragma unroll
    for (int i = 0; i < 12; i++) {
        int c = t + i * 256;
        dr[c] = shift[c] + (1.0f + scale[c]) * (v[i] - mean) * inv;
    }
}

__global__ void rms_rope(const float* __restrict__ qkv, const float* __restrict__ pe,
                         const float* __restrict__ tqs, const float* __restrict__ tks,
                         const float* __restrict__ iqs, const float* __restrict__ iks,
                         float* __restrict__ Q, float* __restrict__ Kp, float* __restrict__ Vp) {
    int l = blockIdx.x;
    int w = threadIdx.x >> 5, lane = threadIdx.x & 31;
    const float* qs = (l < LTXT) ? tqs : iqs;
    const float* ks = (l < LTXT) ? tks : iks;
    const float* row = qkv + (size_t)l * QKVW;
    const float* peb = pe + (size_t)l * 256 + lane * 8;
    float4 p0 = *(const float4*)(peb);
    float4 p1 = *(const float4*)(peb + 4);
    int d0 = lane * 4;
    float4 scq = *(const float4*)(qs + d0);
    float4 sck = *(const float4*)(ks + d0);

    for (int h = w; h < NH; h += 8) {
        float4 xq = *(const float4*)(row + h * HD + d0);
        float ss = xq.x*xq.x + xq.y*xq.y + xq.z*xq.z + xq.w*xq.w;
        #pragma unroll
        for (int o = 16; o > 0; o >>= 1) ss += __shfl_xor_sync(0xffffffffu, ss, o);
        float r = rsqrtf(ss * (1.0f / HD) + 1e-6f);
        float x0 = xq.x * r * scq.x, x1 = xq.y * r * scq.y;
        float x2 = xq.z * r * scq.z, x3 = xq.w * r * scq.w;
        float4 oq;
        oq.x = p0.x * x0 + p0.y * x1;
        oq.y = p0.z * x0 + p0.w * x1;
        oq.z = p1.x * x2 + p1.y * x3;
        oq.w = p1.z * x2 + p1.w * x3;
        *(float4*)(Q + ((size_t)h * LTOT + l) * HD + d0) = oq;
        float4 xk = *(const float4*)(row + HS + h * HD + d0);
        float sk = xk.x*xk.x + xk.y*xk.y + xk.z*xk.z + xk.w*xk.w;
        #pragma unroll
        for (int o = 16; o > 0; o >>= 1) sk += __shfl_xor_sync(0xffffffffu, sk, o);
        float rk = rsqrtf(sk * (1.0f / HD) + 1e-6f);
        float y0 = xk.x * rk * sck.x, y1 = xk.y * rk * sck.y;
        float y2 = xk.z * rk * sck.z, y3 = xk.w * rk * sck.w;
        float4 ok;
        ok.x = p0.x * y0 + p0.y * y1;
        ok.y = p0.z * y0 + p0.w * y1;
        ok.z = p1.x * y2 + p1.y * y3;
        ok.w = p1.z * y2 + p1.w * y3;
        *(float4*)(Kp + ((size_t)h * LTOT + l) * HD + d0) = ok;
        float4 xv = *(const float4*)(row + 2 * HS + h * HD + d0);
        *(float4*)(Vp + ((size_t)h * LTOT + l) * HD + d0) = xv;
    }
}

// ---------------------------------------------------------------------------
// Helpers
// ---------------------------------------------------------------------------
__device__ __forceinline__ float gelu_tanh(float x) {
    float x3 = x * x * x;
    return 0.5f * x * (1.0f + tanhf(0.7978845608028654f * (x + 0.044715f * x3)));
}
__device__ __forceinline__ float to_tf32(float x) {
    unsigned int u;
    asm("cvt.rna.tf32.f32 %0, %1;" : "=r"(u) : "f"(x));
    return __uint_as_float(u);
}
__device__ __forceinline__ unsigned int tf32u(float x) {
    unsigned int u;
    asm("cvt.rna.tf32.f32 %0, %1;" : "=r"(u) : "f"(x));
    return u;
}
__device__ __forceinline__ void mma_tf32(float c[4], const unsigned int a[4],
                                         const unsigned int b[2]) {
    asm volatile(
        "mma.sync.aligned.m16n8k8.row.col.f32.tf32.tf32.f32 "
        "{%0,%1,%2,%3}, {%4,%5,%6,%7}, {%8,%9}, {%0,%1,%2,%3};"
        : "+f"(c[0]), "+f"(c[1]), "+f"(c[2]), "+f"(c[3])
        : "r"(a[0]), "r"(a[1]), "r"(a[2]), "r"(a[3]), "r"(b[0]), "r"(b[1]));
}
__device__ __forceinline__ uint32_t smem_u32(const void* p) {
    uint32_t a;
    asm("{ .reg .u64 t; cvta.to.shared.u64 t, %1; cvt.u32.u64 %0, t; }" : "=r"(a) : "l"(p));
    return a;
}

#define TCG_SMEM_BYTES 90112

#if HAS_TCGEN05
__device__ __forceinline__ uint32_t elect_one() {
    uint32_t pred;
    asm volatile("{\n\t.reg .pred p;\n\telect.sync _|p, 0xFFFFFFFF;\n\t"
                 "selp.b32 %0, 1, 0, p;\n\t}" : "=r"(pred));
    return pred;
}
__device__ __forceinline__ void mbar_wait(uint32_t mbar, uint32_t parity) {
    asm volatile(
        "{\n\t.reg .pred P1;\n\t"
        "W_%=:\n\t"
        "mbarrier.try_wait.parity.acquire.cta.shared::cta.b64 P1, [%0], %1, 0x989680;\n\t"
        "@P1 bra.uni D_%=;\n\t"
        "bra.uni W_%=;\n\t"
        "D_%=:\n\t}"
        :: "r"(mbar), "r"(parity) : "memory");
}
__device__ __forceinline__ uint64_t make_desc(uint32_t addr) {
    const uint64_t base =
        (uint64_t(2) << 61) | (uint64_t(1) << 46) | (uint64_t(64) << 32) | (uint64_t(1) << 16);
    return base | ((uint64_t)(addr >> 4) & 0x3FFF);
}
__device__ __forceinline__ void tc_mma(uint32_t d, uint64_t ad, uint64_t bd,
                                       uint32_t idesc, uint32_t en) {
    asm volatile(
        "{\n\t.reg .pred p;\n\t"
        "setp.ne.u32 p, %4, 0;\n\t"
        "tcgen05.mma.cta_group::1.kind::tf32 [%0], %1, %2, %3, {%5,%5,%5,%5}, p;\n\t}"
        :: "r"(d), "l"(ad), "l"(bd), "r"(idesc), "r"(en), "r"(0u) : "memory");
}
#define TCG_IDESC ((1u<<4)|(2u<<7)|(2u<<10)|((256u/8)<<17)|((128u/16)<<24))
#endif

// ---------------------------------------------------------------------------
// tf32 GEMM, CTA tile 128(M) x 256(N). Grid 1D m-fastest.
//   tcgen05 path (sm_103a pass): K-chunk 32 -> TMEM accumulator.
//   fallback (compute_103 pass): two 128x128 mma.sync sub-tiles.
// A [M,K] rm, B [K,N] rm, C rm. EPI: 0 bias; 1 gelu; 2 resid+gate.
// M%128==0, N%256==0, K%32==0.
// ---------------------------------------------------------------------------
template <int EPI>
__global__ void __launch_bounds__(256)
tc_gemm(const float* __restrict__ A, const float* __restrict__ B,
        const float* __restrict__ bias, float* __restrict__ C,
        int K, int lda, int ldb, int ldc, int nM,
        const float* __restrict__ gate, const float* __restrict__ resid, int ldres) {
    extern __shared__ char smem[];
    const int t = threadIdx.x;
    const int wid = t >> 5, lane = t & 31;
    const int m0 = (blockIdx.x % nM) * 128;
    const int n0 = (blockIdx.x / nM) * 256;

#if HAS_TCGEN05
    const uint32_t smem_base = smem_u32(smem);
    const uint32_t sA = (smem_base + 64 + 1023) & ~1023u;
    const uint32_t sB = sA + 16384;
    const uint32_t mbar = smem_base + 16;
    float* sEp = (float*)(smem + (sA - smem_base));

    if (wid == 0) {
        asm volatile("tcgen05.alloc.cta_group::1.sync.aligned.shared::cta.b32 [%0], %1;"
                     :: "r"(smem_base), "r"(256u) : "memory");
    }
    if (t == 0)
        asm volatile("mbarrier.init.shared.b64 [%0], 1;" :: "r"(mbar) : "memory");
    __syncthreads();
    uint32_t tmem;
    asm volatile("ld.shared.b32 %0, [%1];" : "=r"(tmem) : "r"(smem_base));

    const int nc = K / 32;
    const int ar = t >> 1, af = t & 1;
    const float* Ab = A + (size_t)(m0 + ar) * lda;
    const float* Bb = B + n0 + t;

    float4 ra[4];
    float rb[32];
    #pragma unroll
    for (int i = 0; i < 4; i++) ra[i] = *(const float4*)(Ab + (af + 2 * i) * 4);
    #pragma unroll
    for (int g = 0; g < 8; g++)
        #pragma unroll
        for (int i = 0; i < 4; i++) rb[g * 4 + i] = Bb[(size_t)(g * 4 + i) * ldb];

    for (int c = 0; c < nc; c++) {
        if (c > 0) mbar_wait(mbar, (c - 1) & 1);
        #pragma unroll
        for (int i = 0; i < 4; i++) {
            uint32_t bo = (uint32_t)ar * 128 + (af + 2 * i) * 16;
            uint32_t ad = sA + (bo ^ ((bo >> 3) & 0x70));
            asm volatile("st.shared.v4.b32 [%0], {%1,%2,%3,%4};"
                         :: "r"(ad), "r"(tf32u(ra[i].x)), "r"(tf32u(ra[i].y)),
                            "r"(tf32u(ra[i].z)), "r"(tf32u(ra[i].w)));
        }
        #pragma unroll
        for (int g = 0; g < 8; g++) {
            uint32_t bo = (uint32_t)t * 128 + g * 16;
            uint32_t ad = sB + (bo ^ ((bo >> 3) & 0x70));
            asm volatile("st.shared.v4.b32 [%0], {%1,%2,%3,%4};"
                         :: "r"(ad), "r"(tf32u(rb[g*4+0])), "r"(tf32u(rb[g*4+1])),
                            "r"(tf32u(rb[g*4+2])), "r"(tf32u(rb[g*4+3])));
        }
        asm volatile("fence.proxy.async.shared::cta;" ::: "memory");
        __syncthreads();

        if (wid == 0) {
            asm volatile("tcgen05.fence::after_thread_sync;" ::: "memory");
            if (elect_one()) {
                uint64_t ad = make_desc(sA);
                uint64_t bd = make_desc(sB);
                #pragma unroll
                for (int ks = 0; ks < 4; ks++)
                    tc_mma(tmem, ad + 2 * ks, bd + 2 * ks, TCG_IDESC,
                           (uint32_t)((c > 0) | (ks > 0)));
                asm volatile(
                    "tcgen05.commit.cta_group::1.mbarrier::arrive::one.shared::cluster.b64 [%0];"
                    :: "r"(mbar) : "memory");
            }
        }
        if (c + 1 < nc) {
            const float* Ac = Ab + (size_t)(c + 1) * 32;
            #pragma unroll
            for (int i = 0; i < 4; i++) ra[i] = *(const float4*)(Ac + (af + 2 * i) * 4);
            const float* Bc = Bb + (size_t)(c + 1) * 32 * ldb;
            #pragma unroll
            for (int g = 0; g < 8; g++)
                #pragma unroll
                for (int i = 0; i < 4; i++) rb[g * 4 + i] = Bc[(size_t)(g * 4 + i) * ldb];
        }
    }
    mbar_wait(mbar, (nc - 1) & 1);
    asm volatile("tcgen05.fence::after_thread_sync;" ::: "memory");
    __syncthreads();

    const int half = wid >> 2;
    const int rrow = (wid & 3) * 32 + lane;
    const int f = t & 15, rg = t >> 4;
    for (int cb = 0; cb < 4; cb++) {
        uint32_t r_[32];
        asm volatile(
            "tcgen05.ld.sync.aligned.32x32b.x32.b32 "
            "{%0,%1,%2,%3,%4,%5,%6,%7,%8,%9,%10,%11,%12,%13,%14,%15,"
            "%16,%17,%18,%19,%20,%21,%22,%23,%24,%25,%26,%27,%28,%29,%30,%31}, [%32];"
            : "=r"(r_[0]),"=r"(r_[1]),"=r"(r_[2]),"=r"(r_[3]),
              "=r"(r_[4]),"=r"(r_[5]),"=r"(r_[6]),"=r"(r_[7]),
              "=r"(r_[8]),"=r"(r_[9]),"=r"(r_[10]),"=r"(r_[11]),
              "=r"(r_[12]),"=r"(r_[13]),"=r"(r_[14]),"=r"(r_[15]),
              "=r"(r_[16]),"=r"(r_[17]),"=r"(r_[18]),"=r"(r_[19]),
              "=r"(r_[20]),"=r"(r_[21]),"=r"(r_[22]),"=r"(r_[23]),
              "=r"(r_[24]),"=r"(r_[25]),"=r"(r_[26]),"=r"(r_[27]),
              "=r"(r_[28]),"=r"(r_[29]),"=r"(r_[30]),"=r"(r_[31])
            : "r"(tmem + half * 128 + cb * 32));
        asm volatile("tcgen05.wait::ld.sync.aligned;" ::: "memory");
        #pragma unroll
        for (int j = 0; j < 32; j++)
            sEp[rrow * 65 + half * 32 + j] = __uint_as_float(r_[j]);
        __syncthreads();

        const int scol = (f >> 3) * 32 + (f & 7) * 4;
        const int gcol = n0 + (f >> 3) * 128 + cb * 32 + (f & 7) * 4;
        const float4 bv = *(const float4*)(bias + gcol);
        float4 gv = make_float4(0.f, 0.f, 0.f, 0.f);
        if (EPI == 2) gv = *(const float4*)(gate + gcol);
        #pragma unroll
        for (int i = 0; i < 8; i++) {
            int r = rg + 16 * i;
            const float* sp = &sEp[r * 65 + scol];
            float4 v = make_float4(sp[0], sp[1], sp[2], sp[3]);
            v.x += bv.x; v.y += bv.y; v.z += bv.z; v.w += bv.w;
            if (EPI == 1) {
                v.x = gelu_tanh(v.x); v.y = gelu_tanh(v.y);
                v.z = gelu_tanh(v.z); v.w = gelu_tanh(v.w);
            }
            if (EPI == 2) {
                float4 rr = *(const float4*)(resid + (size_t)(m0 + r) * ldres + gcol);
                v.x = rr.x + gv.x * v.x; v.y = rr.y + gv.y * v.y;
                v.z = rr.z + gv.z * v.z; v.w = rr.w + gv.w * v.w;
            }
            *(float4*)(C + (size_t)(m0 + r) * ldc + gcol) = v;
        }
        __syncthreads();
    }
    if (wid == 0) {
        asm volatile("tcgen05.relinquish_alloc_permit.cta_group::1.sync.aligned;");
        asm volatile("tcgen05.dealloc.cta_group::1.sync.aligned.b32 %0, %1;"
                     :: "r"(tmem), "r"(256u));
    }
#else
    // ---------------- fallback: mma.sync, two 128x128 sub-tiles ----------------
    float (*As)[132] = (float(*)[132])smem;                       // [2*16][132]
    float (*Bs)[132] = (float(*)[132])(smem + 2 * 16 * 132 * 4);  // [2*16][132]

    const int wm = wid >> 2, wn = wid & 3;
    const int gid = lane >> 2, tig = lane & 3;
    const int a_m = t >> 1, a_k = (t & 1) * 4;
    const int b_k = t >> 5, b_n = (t & 31) * 4;
    const int nk = K / 16;

    for (int nh = 0; nh < 2; nh++) {
        const int nb0 = n0 + nh * 128;
        const float* Ap = A + (size_t)(m0 + a_m) * lda + a_k;
        const float* Bp = B + (size_t)b_k * ldb + nb0 + b_n;

        float c[4][4][4];
        #pragma unroll
        for (int i = 0; i < 4; i++)
            #pragma unroll
            for (int j = 0; j < 4; j++)
                #pragma unroll
                for (int r = 0; r < 4; r++) c[i][j][r] = 0.0f;

        float4 pa0, pa1, pb0, pb1;
        pa0 = *(const float4*)(Ap);
        pa1 = *(const float4*)(Ap + 8);
        pb0 = *(const float4*)(Bp);
        pb1 = *(const float4*)(Bp + (size_t)8 * ldb);
        {
            As[a_k + 0][a_m] = to_tf32(pa0.x); As[a_k + 1][a_m] = to_tf32(pa0.y);
            As[a_k + 2][a_m] = to_tf32(pa0.z); As[a_k + 3][a_m] = to_tf32(pa0.w);
            As[a_k + 8][a_m] = to_tf32(pa1.x); As[a_k + 9][a_m] = to_tf32(pa1.y);
            As[a_k +10][a_m] = to_tf32(pa1.z); As[a_k +11][a_m] = to_tf32(pa1.w);
            float4 q0 = make_float4(to_tf32(pb0.x), to_tf32(pb0.y), to_tf32(pb0.z), to_tf32(pb0.w));
            float4 q1 = make_float4(to_tf32(pb1.x), to_tf32(pb1.y), to_tf32(pb1.z), to_tf32(pb1.w));
            *(float4*)(&Bs[b_k][b_n])     = q0;
            *(float4*)(&Bs[b_k + 8][b_n]) = q1;
        }
        __syncthreads();

        for (int kt = 0; kt < nk; kt++) {
            const int buf = kt & 1;
            const bool has_next = (kt + 1 < nk);
            if (has_next) {
                const int off = (kt + 1) * 16;
                pa0 = *(const float4*)(Ap + off);
                pa1 = *(const float4*)(Ap + off + 8);
                pb0 = *(const float4*)(Bp + (size_t)off * ldb);
                pb1 = *(const float4*)(Bp + (size_t)(off + 8) * ldb);
            }
            #pragma unroll
            for (int ks = 0; ks < 2; ks++) {
                const int kb = buf * 16 + ks * 8;
                unsigned int afr[4][4], bfr[4][2];
                #pragma unroll
                for (int mt = 0; mt < 4; mt++) {
                    const int bm = wm * 64 + mt * 16 + gid;
                    afr[mt][0] = __float_as_uint(As[kb + tig    ][bm]);
                    afr[mt][1] = __float_as_uint(As[kb + tig    ][bm + 8]);
                    afr[mt][2] = __float_as_uint(As[kb + tig + 4][bm]);
                    afr[mt][3] = __float_as_uint(As[kb + tig + 4][bm + 8]);
                }
                #pragma unroll
                for (int nt = 0; nt < 4; nt++) {
                    const int bn = wn * 32 + nt * 8 + gid;
                    bfr[nt][0] = __float_as_uint(Bs[kb + tig    ][bn]);
                    bfr[nt][1] = __float_as_uint(Bs[kb + tig + 4][bn]);
                }
                #pragma unroll
                for (int mt = 0; mt < 4; mt++)
                    #pragma unroll
                    for (int nt = 0; nt < 4; nt++)
                        mma_tf32(c[mt][nt], afr[mt], bfr[nt]);
            }
            if (has_next) {
                const int nb = (buf ^ 1) * 16;
                As[nb + a_k + 0][a_m] = to_tf32(pa0.x); As[nb + a_k + 1][a_m] = to_tf32(pa0.y);
                As[nb + a_k + 2][a_m] = to_tf32(pa0.z); As[nb + a_k + 3][a_m] = to_tf32(pa0.w);
                As[nb + a_k + 8][a_m] = to_tf32(pa1.x); As[nb + a_k + 9][a_m] = to_tf32(pa1.y);
                As[nb + a_k +10][a_m] = to_tf32(pa1.z); As[nb + a_k +11][a_m] = to_tf32(pa1.w);
                float4 q0 = make_float4(to_tf32(pb0.x), to_tf32(pb0.y), to_tf32(pb0.z), to_tf32(pb0.w));
                float4 q1 = make_float4(to_tf32(pb1.x), to_tf32(pb1.y), to_tf32(pb1.z), to_tf32(pb1.w));
                *(float4*)(&Bs[nb + b_k][b_n])     = q0;
                *(float4*)(&Bs[nb + b_k + 8][b_n]) = q1;
            }
            __syncthreads();
        }

        #pragma unroll
        for (int nt = 0; nt < 4; nt++) {
            const int col = nb0 + wn * 32 + nt * 8 + tig * 2;
            const float bv0 = bias[col], bv1 = bias[col + 1];
            float gv0 = 0.0f, gv1 = 0.0f;
            if (EPI == 2) { gv0 = gate[col]; gv1 = gate[col + 1]; }
            #pragma unroll
            for (int mt = 0; mt < 4; mt++) {
                const int row0 = m0 + wm * 64 + mt * 16 + gid;
                #pragma unroll
                for (int hh = 0; hh < 2; hh++) {
                    const int row = row0 + hh * 8;
                    float v0 = c[mt][nt][hh * 2 + 0] + bv0;
                    float v1 = c[mt][nt][hh * 2 + 1] + bv1;
                    if (EPI == 1) { v0 = gelu_tanh(v0); v1 = gelu_tanh(v1); }
                    if (EPI == 2) {
                        const float* Rr = resid + (size_t)row * ldres + col;
                        v0 = Rr[0] + gv0 * v0;
                        v1 = Rr[1] + gv1 * v1;
                    }
                    *(float2*)(C + (size_t)row * ldc + col) = make_float2(v0, v1);
                }
            }
        }
        __syncthreads();
    }
#endif
}

// ---------------------------------------------------------------------------
// Flash attention (unchanged, known good)
// ---------------------------------------------------------------------------
#define FA_SCALE 0.08838834764831845f
#define SQ_PITCH 132
#define SK_PITCH 68
#define SV_PITCH 132
#define SP_PITCH 132
#define SQ_OFF 0
#define SK_OFF (128 * SQ_PITCH)
#define SV_OFF (SK_OFF + 128 * SK_PITCH)
#define SP_OFF (SV_OFF + 64 * SV_PITCH)
#define FA_SMEM_FLOATS (SP_OFF + 64 * SP_PITCH)
#define FA_SMEM_BYTES (FA_SMEM_FLOATS * 4)

__global__ void __launch_bounds__(256, 1)
flash_attn(const float* __restrict__ Q, const float* __restrict__ K,
           const float* __restrict__ V, float* __restrict__ O) {
    extern __shared__ float sm[];
    float* sQ = sm + SQ_OFF;
    float* sK = sm + SK_OFF;
    float* sV = sm + SV_OFF;
    float* sP = sm + SP_OFF;

    const int t = threadIdx.x;
    const int wid = t >> 5, lane = t & 31;
    const int gid = lane >> 2, tig = lane & 3;
    const int h = blockIdx.y;
    const int q0 = blockIdx.x * 128;
    const int m0 = wid * 16;

    const float* Qh = Q + ((size_t)h * LTOT + q0) * HD;
    const float* Kh = K + (size_t)h * LTOT * HD;
    const float* Vh = V + (size_t)h * LTOT * HD;

    {
        int r = t >> 1;
        int dseg = (t & 1) * 64;
        const float* qr = Qh + (size_t)r * HD + dseg;
        #pragma unroll
        for (int i = 0; i < 16; i++) {
            float4 v4 = *(const float4*)(qr + i * 4);
            int d = dseg + i * 4;
            sQ[(d + 0) * SQ_PITCH + r] = to_tf32(v4.x * FA_SCALE);
            sQ[(d + 1) * SQ_PITCH + r] = to_tf32(v4.y * FA_SCALE);
            sQ[(d + 2) * SQ_PITCH + r] = to_tf32(v4.z * FA_SCALE);
            sQ[(d + 3) * SQ_PITCH + r] = to_tf32(v4.w * FA_SCALE);
        }
    }
    __syncthreads();

    unsigned int qf[16][4];
    #pragma unroll
    for (int kt = 0; kt < 16; kt++) {
        int kb = kt * 8;
        qf[kt][0] = __float_as_uint(sQ[(kb + tig)     * SQ_PITCH + m0 + gid]);
        qf[kt][1] = __float_as_uint(sQ[(kb + tig)     * SQ_PITCH + m0 + gid + 8]);
        qf[kt][2] = __float_as_uint(sQ[(kb + tig + 4) * SQ_PITCH + m0 + gid]);
        qf[kt][3] = __float_as_uint(sQ[(kb + tig + 4) * SQ_PITCH + m0 + gid + 8]);
    }

    float co[16][4];
    #pragma unroll
    for (int i = 0; i < 16; i++)
        #pragma unroll
        for (int j = 0; j < 4; j++) co[i][j] = 0.0f;
    float mrow0 = -1e30f, mrow1 = -1e30f, lrow0 = 0.0f, lrow1 = 0.0f;

    for (int kv = 0; kv < LTOT; kv += 64) {
        __syncthreads();
        {
            int c = t >> 2;
            int dseg = (t & 3) * 32;
            const float* kr = Kh + (size_t)(kv + c) * HD + dseg;
            #pragma unroll
            for (int i = 0; i < 8; i++) {
                float4 v4 = *(const float4*)(kr + i * 4);
                int d = dseg + i * 4;
                sK[(d + 0) * SK_PITCH + c] = to_tf32(v4.x);
                sK[(d + 1) * SK_PITCH + c] = to_tf32(v4.y);
                sK[(d + 2) * SK_PITCH + c] = to_tf32(v4.z);
                sK[(d + 3) * SK_PITCH + c] = to_tf32(v4.w);
            }
        }
        {
            int c = t >> 2;
            int dseg = (t & 3) * 32;
            const float* vr = Vh + (size_t)(kv + c) * HD + dseg;
            #pragma unroll
            for (int i = 0; i < 8; i++) {
                float4 v4 = *(const float4*)(vr + i * 4);
                float4 q4 = make_float4(to_tf32(v4.x), to_tf32(v4.y),
                                        to_tf32(v4.z), to_tf32(v4.w));
                *(float4*)(sV + c * SV_PITCH + dseg + i * 4) = q4;
            }
        }
        __syncthreads();

        float cs[8][4];
        #pragma unroll
        for (int i = 0; i < 8; i++)
            #pragma unroll
            for (int j = 0; j < 4; j++) cs[i][j] = 0.0f;
        #pragma unroll
        for (int kt = 0; kt < 16; kt++) {
            int kb = kt * 8;
            #pragma unroll
            for (int nt = 0; nt < 8; nt++) {
                unsigned int bf[2];
                bf[0] = __float_as_uint(sK[(kb + tig)     * SK_PITCH + nt * 8 + gid]);
                bf[1] = __float_as_uint(sK[(kb + tig + 4) * SK_PITCH + nt * 8 + gid]);
                mma_tf32(cs[nt], qf[kt], bf);
            }
        }

        float rmax0 = -1e30f, rmax1 = -1e30f;
        #pragma unroll
        for (int nt = 0; nt < 8; nt++) {
            rmax0 = fmaxf(rmax0, fmaxf(cs[nt][0], cs[nt][1]));
            rmax1 = fmaxf(rmax1, fmaxf(cs[nt][2], cs[nt][3]));
        }
        rmax0 = fmaxf(rmax0, __shfl_xor_sync(0xffffffffu, rmax0, 1));
        rmax0 = fmaxf(rmax0, __shfl_xor_sync(0xffffffffu, rmax0, 2));
        rmax1 = fmaxf(rmax1, __shfl_xor_sync(0xffffffffu, rmax1, 1));
        rmax1 = fmaxf(rmax1, __shfl_xor_sync(0xffffffffu, rmax1, 2));
        float mn0 = fmaxf(mrow0, rmax0);
        float mn1 = fmaxf(mrow1, rmax1);
        float corr0 = __expf(mrow0 - mn0);
        float corr1 = __expf(mrow1 - mn1);
        mrow0 = mn0; mrow1 = mn1;

        float rs0 = 0.0f, rs1 = 0.0f;
        #pragma unroll
        for (int nt = 0; nt < 8; nt++) {
            cs[nt][0] = __expf(cs[nt][0] - mn0);
            cs[nt][1] = __expf(cs[nt][1] - mn0);
            cs[nt][2] = __expf(cs[nt][2] - mn1);
            cs[nt][3] = __expf(cs[nt][3] - mn1);
            rs0 += cs[nt][0] + cs[nt][1];
            rs1 += cs[nt][2] + cs[nt][3];
        }
        rs0 += __shfl_xor_sync(0xffffffffu, rs0, 1);
        rs0 += __shfl_xor_sync(0xffffffffu, rs0, 2);
        rs1 += __shfl_xor_sync(0xffffffffu, rs1, 1);
        rs1 += __shfl_xor_sync(0xffffffffu, rs1, 2);
        lrow0 = lrow0 * corr0 + rs0;
        lrow1 = lrow1 * corr1 + rs1;

        #pragma unroll
        for (int nt = 0; nt < 16; nt++) {
            co[nt][0] *= corr0; co[nt][1] *= corr0;
            co[nt][2] *= corr1; co[nt][3] *= corr1;
        }

        #pragma unroll
        for (int nt = 0; nt < 8; nt++) {
            int cb = nt * 8 + tig * 2;
            sP[(cb + 0) * SP_PITCH + m0 + gid]     = to_tf32(cs[nt][0]);
            sP[(cb + 1) * SP_PITCH + m0 + gid]     = to_tf32(cs[nt][1]);
            sP[(cb + 0) * SP_PITCH + m0 + gid + 8] = to_tf32(cs[nt][2]);
            sP[(cb + 1) * SP_PITCH + m0 + gid + 8] = to_tf32(cs[nt][3]);
        }
        __syncwarp();

        #pragma unroll
        for (int kt = 0; kt < 8; kt++) {
            int kb = kt * 8;
            unsigned int af[4];
            af[0] = __float_as_uint(sP[(kb + tig)     * SP_PITCH + m0 + gid]);
            af[1] = __float_as_uint(sP[(kb + tig)     * SP_PITCH + m0 + gid + 8]);
            af[2] = __float_as_uint(sP[(kb + tig + 4) * SP_PITCH + m0 + gid]);
            af[3] = __float_as_uint(sP[(kb + tig + 4) * SP_PITCH + m0 + gid + 8]);
            #pragma unroll
            for (int nt = 0; nt < 16; nt++) {
                unsigned int bf[2];
                bf[0] = __float_as_uint(sV[(kb + tig)     * SV_PITCH + nt * 8 + gid]);
                bf[1] = __float_as_uint(sV[(kb + tig + 4) * SV_PITCH + nt * 8 + gid]);
                mma_tf32(co[nt], af, bf);
            }
        }
    }

    float inv0 = 1.0f / lrow0;
    float inv1 = 1.0f / lrow1;
    int row0 = q0 + m0 + gid;
    #pragma unroll
    for (int nt = 0; nt < 16; nt++) {
        int col = h * HD + nt * 8 + tig * 2;
        *(float2*)(O + (size_t)row0 * HS + col) =
            make_float2(co[nt][0] * inv0, co[nt][1] * inv0);
        *(float2*)(O + (size_t)(row0 + 8) * HS + col) =
            make_float2(co[nt][2] * inv1, co[nt][3] * inv1);
    }
}

// ---------------------------------------------------------------------------
// Host launcher
// ---------------------------------------------------------------------------
static void tc_launch(int epi, const float* A, const float* B, const float* bias,
                      float* C, int M, int N, int K, int lda, int ldb, int ldc,
                      const float* gate = nullptr, const float* resid = nullptr,
                      int ldres = 0) {
    int nM = M / 128, nN = N / 256;
    dim3 grid(nM * nN);
    if (epi == 0)
        tc_gemm<0><<<grid, 256, TCG_SMEM_BYTES>>>(A, B, bias, C, K, lda, ldb, ldc, nM, gate, resid, ldres);
    else if (epi == 1)
        tc_gemm<1><<<grid, 256, TCG_SMEM_BYTES>>>(A, B, bias, C, K, lda, ldb, ldc, nM, gate, resid, ldres);
    else
        tc_gemm<2><<<grid, 256, TCG_SMEM_BYTES>>>(A, B, bias, C, K, lda, ldb, ldc, nM, gate, resid, ldres);
}

extern "C" void kernel_launch(void* const* d_in, const int* in_sizes, int n_in,
                              void* d_out, int out_size) {
    const float* img        = (const float*)d_in[0];
    const float* txt        = (const float*)d_in[1];
    const float* vec        = (const float*)d_in[2];
    const float* pe         = (const float*)d_in[3];
    const float* img_mod_w  = (const float*)d_in[4];
    const float* img_mod_b  = (const float*)d_in[5];
    const float* img_qkv_w  = (const float*)d_in[6];
    const float* img_qkv_b  = (const float*)d_in[7];
    const float* img_q_s    = (const float*)d_in[8];
    const float* img_k_s    = (const float*)d_in[9];
    const float* img_proj_w = (const float*)d_in[10];
    const float* img_proj_b = (const float*)d_in[11];
    const float* img_mlp_w1 = (const float*)d_in[12];
    const float* img_mlp_b1 = (const float*)d_in[13];
    const float* img_mlp_w2 = (const float*)d_in[14];
    const float* img_mlp_b2 = (const float*)d_in[15];
    const float* txt_mod_w  = (const float*)d_in[16];
    const float* txt_mod_b  = (const float*)d_in[17];
    const float* txt_qkv_w  = (const float*)d_in[18];
    const float* txt_qkv_b  = (const float*)d_in[19];
    const float* txt_q_s    = (const float*)d_in[20];
    const float* txt_k_s    = (const float*)d_in[21];
    const float* txt_proj_w = (const float*)d_in[22];
    const float* txt_proj_b = (const float*)d_in[23];
    const float* txt_mlp_w1 = (const float*)d_in[24];
    const float* txt_mlp_b1 = (const float*)d_in[25];
    const float* txt_mlp_w2 = (const float*)d_in[26];
    const float* txt_mlp_b2 = (const float*)d_in[27];
    float* out = (float*)d_out;

    float *sv, *modi, *modt, *x, *qkvb, *q, *k, *v, *attn, *x1, *x2, *h1;
    cudaGetSymbolAddress((void**)&sv,   g_silu);
    cudaGetSymbolAddress((void**)&modi, g_mod_img);
    cudaGetSymbolAddress((void**)&modt, g_mod_txt);
    cudaGetSymbolAddress((void**)&x,    g_x);
    cudaGetSymbolAddress((void**)&qkvb, g_qkv);
    cudaGetSymbolAddress((void**)&q,    g_q);
    cudaGetSymbolAddress((void**)&k,    g_k);
    cudaGetSymbolAddress((void**)&v,    g_v);
    cudaGetSymbolAddress((void**)&attn, g_attn);
    cudaGetSymbolAddress((void**)&x1,   g_x1);
    cudaGetSymbolAddress((void**)&x2,   g_x2);
    cudaGetSymbolAddress((void**)&h1,   g_h1);

    cudaFuncSetAttribute(flash_attn, cudaFuncAttributeMaxDynamicSharedMemorySize, FA_SMEM_BYTES);
    cudaFuncSetAttribute(tc_gemm<0>, cudaFuncAttributeMaxDynamicSharedMemorySize, TCG_SMEM_BYTES);
    cudaFuncSetAttribute(tc_gemm<1>, cudaFuncAttributeMaxDynamicSharedMemorySize, TCG_SMEM_BYTES);
    cudaFuncSetAttribute(tc_gemm<2>, cudaFuncAttributeMaxDynamicSharedMemorySize, TCG_SMEM_BYTES);

    silu_kernel<<<HS / 256, 256>>>(vec, sv);
    mod_gemv2<<<(6 * HS) / 64, 256>>>(sv, img_mod_w, img_mod_b, modi);
    mod_gemv2<<<(6 * HS) / 64, 256>>>(sv, txt_mod_w, txt_mod_b, modt);

    ln_mod<<<LTXT, 256>>>(txt, x,                     modt + 0 * HS, modt + 1 * HS);
    ln_mod<<<LIMG, 256>>>(img, x + (size_t)LTXT * HS, modi + 0 * HS, modi + 1 * HS);

    tc_launch(0, x, txt_qkv_w, txt_qkv_b, qkvb, LTXT, QKVW, HS, HS, QKVW, QKVW);
    tc_launch(0, x + (size_t)LTXT * HS, img_qkv_w, img_qkv_b,
              qkvb + (size_t)LTXT * QKVW, LIMG, QKVW, HS, HS, QKVW, QKVW);

    rms_rope<<<LTOT, 256>>>(qkvb, pe, txt_q_s, txt_k_s, img_q_s, img_k_s, q, k, v);

    {
        dim3 fgrid(LTOT / 128, NH);
        flash_attn<<<fgrid, 256, FA_SMEM_BYTES>>>(q, k, v, attn);
    }

    tc_launch(2, attn, txt_proj_w, txt_proj_b, x1, LTXT, HS, HS, HS, HS, HS,
              modt + 2 * HS, txt, HS);
    tc_launch(2, attn + (size_t)LTXT * HS, img_proj_w, img_proj_b,
              x1 + (size_t)LTXT * HS, LIMG, HS, HS, HS, HS, HS,
              modi + 2 * HS, img, HS);

    ln_mod<<<LTXT, 256>>>(x1, x2,                                         modt + 3 * HS, modt + 4 * HS);
    ln_mod<<<LIMG, 256>>>(x1 + (size_t)LTXT * HS, x2 + (size_t)LTXT * HS, modi + 3 * HS, modi + 4 * HS);

    tc_launch(1, x2, txt_mlp_w1, txt_mlp_b1, h1, LTXT, MLPD, HS, HS, MLPD, MLPD);
    tc_launch(1, x2 + (size_t)LTXT * HS, img_mlp_w1, img_mlp_b1,
              h1 + (size_t)LTXT * MLPD, LIMG, MLPD, HS, HS, MLPD, MLPD);

    tc_launch(2, h1, txt_mlp_w2, txt_mlp_b2, out + (size_t)LIMG * HS,
              LTXT, HS, MLPD, MLPD, HS, HS, modt + 5 * HS, x1, HS);
    tc_launch(2, h1 + (size_t)LTXT * MLPD, img_mlp_w2, img_mlp_b2, out,
              LIMG, HS, MLPD, MLPD, HS, HS, modi + 5 * HS, x1 + (size_t)LTXT * HS, HS);
}

// round 9
// speedup vs baseline: 4.8325x; 1.2789x over previous
#include <cuda_runtime.h>
#include <cuda_bf16.h>
#include <math.h>
#include <stdint.h>

#define HS    3072
#define MLPD  12288
#define NH    24
#define HD    128
#define LTXT  512
#define LIMG  2048
#define LTOT  2560
#define QKVW  9216

#if defined(__CUDA_ARCH__)
#if defined(__CUDA_ARCH_FEAT_SM103_ALL) || \
    (defined(__CUDA_ARCH_SPECIFIC__) && (__CUDA_ARCH_SPECIFIC__ >= 1000))
#define HAS_TCGEN05 1
#else
#define HAS_TCGEN05 0
#endif
#else
#define HAS_TCGEN05 0
#endif

// ---------------------------------------------------------------------------
// Static device scratch
// ---------------------------------------------------------------------------
__device__ float g_silu[HS];
__device__ float g_mod_img[6 * HS];
__device__ float g_mod_txt[6 * HS];
__device__ float g_x   [(size_t)LTOT * HS];
__device__ float g_qkv [(size_t)LTOT * QKVW];
__device__ float g_q   [(size_t)NH * LTOT * HD];
__device__ float g_k   [(size_t)NH * LTOT * HD];
__device__ float g_v   [(size_t)NH * LTOT * HD];
__device__ float g_attn[(size_t)LTOT * HS];
__device__ float g_x1  [(size_t)LTOT * HS];
__device__ float g_x2  [(size_t)LTOT * HS];
__device__ float g_h1  [(size_t)LTOT * MLPD];

// ---------------------------------------------------------------------------
// Elementwise kernels
// ---------------------------------------------------------------------------
__global__ void silu_kernel(const float* __restrict__ v, float* __restrict__ o) {
    int i = blockIdx.x * 256 + threadIdx.x;
    if (i < HS) { float x = v[i]; o[i] = x / (1.0f + expf(-x)); }
}

__global__ void mod_gemv2(const float* __restrict__ sv, const float* __restrict__ w,
                          const float* __restrict__ b, float* __restrict__ out) {
    __shared__ float ssv[HS];
    __shared__ float red[4][64];
    for (int i = threadIdx.x; i < HS; i += 256) ssv[i] = sv[i];
    __syncthreads();
    const int jl = threadIdx.x & 63, kq = threadIdx.x >> 6;
    const int j = blockIdx.x * 64 + jl;
    const int i0 = kq * (HS / 4);
    float acc = 0.0f;
    #pragma unroll 8
    for (int i = 0; i < HS / 4; i++)
        acc += ssv[i0 + i] * w[(size_t)(i0 + i) * (6 * HS) + j];
    red[kq][jl] = acc;
    __syncthreads();
    if (threadIdx.x < 64) {
        int jj = blockIdx.x * 64 + threadIdx.x;
        out[jj] = red[0][threadIdx.x] + red[1][threadIdx.x] +
                  red[2][threadIdx.x] + red[3][threadIdx.x] + b[jj];
    }
}

__global__ void ln_mod(const float* __restrict__ x, float* __restrict__ dst,
                       const float* __restrict__ shift, const float* __restrict__ scale) {
    int row = blockIdx.x;
    int t = threadIdx.x;
    const float* xr = x + (size_t)row * HS;
    float v[12];
    float s = 0.0f;
    #pragma unroll
    for (int i = 0; i < 12; i++) { v[i] = xr[t + i * 256]; s += v[i]; }
    __shared__ float red[256];
    red[t] = s; __syncthreads();
    for (int o = 128; o > 0; o >>= 1) { if (t < o) red[t] += red[t + o]; __syncthreads(); }
    float mean = red[0] * (1.0f / HS);
    __syncthreads();
    float s2 = 0.0f;
    #pragma unroll
    for (int i = 0; i < 12; i++) { float d = v[i] - mean; s2 += d * d; }
    red[t] = s2; __syncthreads();
    for (int o = 128; o > 0; o >>= 1) { if (t < o) red[t] += red[t + o]; __syncthreads(); }
    float inv = rsqrtf(red[0] * (1.0f / HS) + 1e-6f);
    float* dr = dst + (size_t)row * HS;
    #pragma unroll
    for (int i = 0; i < 12; i++) {
        int c = t + i * 256;
        dr[c] = shift[c] + (1.0f + scale[c]) * (v[i] - mean) * inv;
    }
}

__global__ void rms_rope(const float* __restrict__ qkv, const float* __restrict__ pe,
                         const float* __restrict__ tqs, const float* __restrict__ tks,
                         const float* __restrict__ iqs, const float* __restrict__ iks,
                         float* __restrict__ Q, float* __restrict__ Kp, float* __restrict__ Vp) {
    int l = blockIdx.x;
    int w = threadIdx.x >> 5, lane = threadIdx.x & 31;
    const float* qs = (l < LTXT) ? tqs : iqs;
    const float* ks = (l < LTXT) ? tks : iks;
    const float* row = qkv + (size_t)l * QKVW;
    const float* peb = pe + (size_t)l * 256 + lane * 8;
    float4 p0 = *(const float4*)(peb);
    float4 p1 = *(const float4*)(peb + 4);
    int d0 = lane * 4;
    float4 scq = *(const float4*)(qs + d0);
    float4 sck = *(const float4*)(ks + d0);

    for (int h = w; h < NH; h += 8) {
        float4 xq = *(const float4*)(row + h * HD + d0);
        float ss = xq.x*xq.x + xq.y*xq.y + xq.z*xq.z + xq.w*xq.w;
        #pragma unroll
        for (int o = 16; o > 0; o >>= 1) ss += __shfl_xor_sync(0xffffffffu, ss, o);
        float r = rsqrtf(ss * (1.0f / HD) + 1e-6f);
        float x0 = xq.x * r * scq.x, x1 = xq.y * r * scq.y;
        float x2 = xq.z * r * scq.z, x3 = xq.w * r * scq.w;
        float4 oq;
        oq.x = p0.x * x0 + p0.y * x1;
        oq.y = p0.z * x0 + p0.w * x1;
        oq.z = p1.x * x2 + p1.y * x3;
        oq.w = p1.z * x2 + p1.w * x3;
        *(float4*)(Q + ((size_t)h * LTOT + l) * HD + d0) = oq;
        float4 xk = *(const float4*)(row + HS + h * HD + d0);
        float sk = xk.x*xk.x + xk.y*xk.y + xk.z*xk.z + xk.w*xk.w;
        #pragma unroll
        for (int o = 16; o > 0; o >>= 1) sk += __shfl_xor_sync(0xffffffffu, sk, o);
        float rk = rsqrtf(sk * (1.0f / HD) + 1e-6f);
        float y0 = xk.x * rk * sck.x, y1 = xk.y * rk * sck.y;
        float y2 = xk.z * rk * sck.z, y3 = xk.w * rk * sck.w;
        float4 ok;
        ok.x = p0.x * y0 + p0.y * y1;
        ok.y = p0.z * y0 + p0.w * y1;
        ok.z = p1.x * y2 + p1.y * y3;
        ok.w = p1.z * y2 + p1.w * y3;
        *(float4*)(Kp + ((size_t)h * LTOT + l) * HD + d0) = ok;
        float4 xv = *(const float4*)(row + 2 * HS + h * HD + d0);
        *(float4*)(Vp + ((size_t)h * LTOT + l) * HD + d0) = xv;
    }
}

// ---------------------------------------------------------------------------
// Helpers
// ---------------------------------------------------------------------------
__device__ __forceinline__ float gelu_tanh(float x) {
    float x3 = x * x * x;
    return 0.5f * x * (1.0f + tanhf(0.7978845608028654f * (x + 0.044715f * x3)));
}
__device__ __forceinline__ float to_tf32(float x) {
    unsigned int u;
    asm("cvt.rna.tf32.f32 %0, %1;" : "=r"(u) : "f"(x));
    return __uint_as_float(u);
}
__device__ __forceinline__ unsigned int tf32u(float x) {
    unsigned int u;
    asm("cvt.rna.tf32.f32 %0, %1;" : "=r"(u) : "f"(x));
    return u;
}
__device__ __forceinline__ void mma_tf32(float c[4], const unsigned int a[4],
                                         const unsigned int b[2]) {
    asm volatile(
        "mma.sync.aligned.m16n8k8.row.col.f32.tf32.tf32.f32 "
        "{%0,%1,%2,%3}, {%4,%5,%6,%7}, {%8,%9}, {%0,%1,%2,%3};"
        : "+f"(c[0]), "+f"(c[1]), "+f"(c[2]), "+f"(c[3])
        : "r"(a[0]), "r"(a[1]), "r"(a[2]), "r"(a[3]), "r"(b[0]), "r"(b[1]));
}
__device__ __forceinline__ uint32_t smem_u32(const void* p) {
    uint32_t a;
    asm("{ .reg .u64 t; cvta.to.shared.u64 t, %1; cvt.u32.u64 %0, t; }" : "=r"(a) : "l"(p));
    return a;
}

#define TCG_SMEM_BYTES (1024 + 2 * 49152)   // 2 stages of (16KB A + 32KB B)

#if HAS_TCGEN05
__device__ __forceinline__ uint32_t elect_one() {
    uint32_t pred;
    asm volatile("{\n\t.reg .pred p;\n\telect.sync _|p, 0xFFFFFFFF;\n\t"
                 "selp.b32 %0, 1, 0, p;\n\t}" : "=r"(pred));
    return pred;
}
__device__ __forceinline__ void mbar_wait(uint32_t mbar, uint32_t parity) {
    asm volatile(
        "{\n\t.reg .pred P1;\n\t"
        "W_%=:\n\t"
        "mbarrier.try_wait.parity.acquire.cta.shared::cta.b64 P1, [%0], %1, 0x989680;\n\t"
        "@P1 bra.uni D_%=;\n\t"
        "bra.uni W_%=;\n\t"
        "D_%=:\n\t}"
        :: "r"(mbar), "r"(parity) : "memory");
}
__device__ __forceinline__ uint64_t make_desc(uint32_t addr) {
    const uint64_t base =
        (uint64_t(2) << 61) | (uint64_t(1) << 46) | (uint64_t(64) << 32) | (uint64_t(1) << 16);
    return base | ((uint64_t)(addr >> 4) & 0x3FFF);
}
__device__ __forceinline__ void tc_mma(uint32_t d, uint64_t ad, uint64_t bd,
                                       uint32_t idesc, uint32_t en) {
    asm volatile(
        "{\n\t.reg .pred p;\n\t"
        "setp.ne.u32 p, %4, 0;\n\t"
        "tcgen05.mma.cta_group::1.kind::tf32 [%0], %1, %2, %3, {%5,%5,%5,%5}, p;\n\t}"
        :: "r"(d), "l"(ad), "l"(bd), "r"(idesc), "r"(en), "r"(0u) : "memory");
}
#define TCG_IDESC ((1u<<4)|(2u<<7)|(2u<<10)|((256u/8)<<17)|((128u/16)<<24))
#endif

// ---------------------------------------------------------------------------
// tf32 GEMM, CTA tile 128(M) x 256(N). Grid 1D m-fastest.
//   tcgen05 path: 2-stage double-buffered smem, TMEM accumulator.
//   fallback (compute_103 pass): two 128x128 mma.sync sub-tiles.
// A [M,K] rm, B [K,N] rm, C rm. EPI: 0 bias; 1 gelu; 2 resid+gate.
// M%128==0, N%256==0, K%32==0 (and K/32 >= 2).
// ---------------------------------------------------------------------------
template <int EPI>
__global__ void __launch_bounds__(256)
tc_gemm(const float* __restrict__ A, const float* __restrict__ B,
        const float* __restrict__ bias, float* __restrict__ C,
        int K, int lda, int ldb, int ldc, int nM,
        const float* __restrict__ gate, const float* __restrict__ resid, int ldres) {
    extern __shared__ char smem[];
    const int t = threadIdx.x;
    const int wid = t >> 5, lane = t & 31;
    const int m0 = (blockIdx.x % nM) * 128;
    const int n0 = (blockIdx.x / nM) * 256;

#if HAS_TCGEN05
    const uint32_t smem_base = smem_u32(smem);
    const uint32_t sA0 = (smem_base + 64 + 1023) & ~1023u;
    const uint32_t sB0 = sA0 + 16384;
    const uint32_t sA1 = sB0 + 32768;
    const uint32_t sB1 = sA1 + 16384;
    const uint32_t mb0 = smem_base + 16;
    const uint32_t mb1 = smem_base + 24;
    float* sEp = (float*)(smem + (sA0 - smem_base));

    if (wid == 0) {
        asm volatile("tcgen05.alloc.cta_group::1.sync.aligned.shared::cta.b32 [%0], %1;"
                     :: "r"(smem_base), "r"(256u) : "memory");
        asm volatile("tcgen05.relinquish_alloc_permit.cta_group::1.sync.aligned;");
    }
    if (t == 0) {
        asm volatile("mbarrier.init.shared.b64 [%0], 1;" :: "r"(mb0) : "memory");
        asm volatile("mbarrier.init.shared.b64 [%0], 1;" :: "r"(mb1) : "memory");
    }
    __syncthreads();
    uint32_t tmem;
    asm volatile("ld.shared.b32 %0, [%1];" : "=r"(tmem) : "r"(smem_base));

    const int nc = K / 32;
    const int ar = t >> 1, af = t & 1;
    const float* Ab = A + (size_t)(m0 + ar) * lda;
    const float* Bb = B + n0 + t;

    float4 ra[4];
    float rb[32];
    // prefetch chunk 0
    #pragma unroll
    for (int i = 0; i < 4; i++) ra[i] = *(const float4*)(Ab + (af + 2 * i) * 4);
    #pragma unroll
    for (int g = 0; g < 8; g++)
        #pragma unroll
        for (int i = 0; i < 4; i++) rb[g * 4 + i] = Bb[(size_t)(g * 4 + i) * ldb];

    int ph0 = 0, ph1 = 0;
    for (int c = 0; c < nc; c++) {
        const int s = c & 1;
        const uint32_t sAc = s ? sA1 : sA0;
        const uint32_t sBc = s ? sB1 : sB0;
        const uint32_t mbc = s ? mb1 : mb0;
        // buffer s was last used by chunk c-2; wait its MMA completion
        if (c >= 2) {
            if (s == 0) { mbar_wait(mb0, ph0); ph0 ^= 1; }
            else        { mbar_wait(mb1, ph1); ph1 ^= 1; }
        }
        // STS chunk c into stage s (tf32-rounded, SW128 swizzle)
        #pragma unroll
        for (int i = 0; i < 4; i++) {
            uint32_t bo = (uint32_t)ar * 128 + (af + 2 * i) * 16;
            uint32_t ad = sAc + (bo ^ ((bo >> 3) & 0x70));
            asm volatile("st.shared.v4.b32 [%0], {%1,%2,%3,%4};"
                         :: "r"(ad), "r"(tf32u(ra[i].x)), "r"(tf32u(ra[i].y)),
                            "r"(tf32u(ra[i].z)), "r"(tf32u(ra[i].w)));
        }
        #pragma unroll
        for (int g = 0; g < 8; g++) {
            uint32_t bo = (uint32_t)t * 128 + g * 16;
            uint32_t ad = sBc + (bo ^ ((bo >> 3) & 0x70));
            asm volatile("st.shared.v4.b32 [%0], {%1,%2,%3,%4};"
                         :: "r"(ad), "r"(tf32u(rb[g*4+0])), "r"(tf32u(rb[g*4+1])),
                            "r"(tf32u(rb[g*4+2])), "r"(tf32u(rb[g*4+3])));
        }
        asm volatile("fence.proxy.async.shared::cta;" ::: "memory");
        __syncthreads();

        if (wid == 0) {
            asm volatile("tcgen05.fence::after_thread_sync;" ::: "memory");
            if (elect_one()) {
                uint64_t ad = make_desc(sAc);
                uint64_t bd = make_desc(sBc);
                #pragma unroll
                for (int ks = 0; ks < 4; ks++)
                    tc_mma(tmem, ad + 2 * ks, bd + 2 * ks, TCG_IDESC,
                           (uint32_t)((c > 0) | (ks > 0)));
                asm volatile(
                    "tcgen05.commit.cta_group::1.mbarrier::arrive::one.shared::cluster.b64 [%0];"
                    :: "r"(mbc) : "memory");
            }
        }
        // prefetch chunk c+1 while MMA(c) runs
        if (c + 1 < nc) {
            const float* Ac = Ab + (size_t)(c + 1) * 32;
            #pragma unroll
            for (int i = 0; i < 4; i++) ra[i] = *(const float4*)(Ac + (af + 2 * i) * 4);
            const float* Bc = Bb + (size_t)(c + 1) * 32 * ldb;
            #pragma unroll
            for (int g = 0; g < 8; g++)
                #pragma unroll
                for (int i = 0; i < 4; i++) rb[g * 4 + i] = Bc[(size_t)(g * 4 + i) * ldb];
        }
    }
    // wait for the last chunk's MMAs (in-order queue => covers all)
    {
        const int s = (nc - 1) & 1;
        if (s == 0) mbar_wait(mb0, ph0);
        else        mbar_wait(mb1, ph1);
    }
    asm volatile("tcgen05.fence::after_thread_sync;" ::: "memory");
    __syncthreads();

    // ---- epilogue: TMEM -> smem bounce (pitch 65) -> coalesced STG ----
    const int half = wid >> 2;
    const int rrow = (wid & 3) * 32 + lane;
    const int f = t & 15, rg = t >> 4;
    for (int cb = 0; cb < 4; cb++) {
        uint32_t r_[32];
        asm volatile(
            "tcgen05.ld.sync.aligned.32x32b.x32.b32 "
            "{%0,%1,%2,%3,%4,%5,%6,%7,%8,%9,%10,%11,%12,%13,%14,%15,"
            "%16,%17,%18,%19,%20,%21,%22,%23,%24,%25,%26,%27,%28,%29,%30,%31}, [%32];"
            : "=r"(r_[0]),"=r"(r_[1]),"=r"(r_[2]),"=r"(r_[3]),
              "=r"(r_[4]),"=r"(r_[5]),"=r"(r_[6]),"=r"(r_[7]),
              "=r"(r_[8]),"=r"(r_[9]),"=r"(r_[10]),"=r"(r_[11]),
              "=r"(r_[12]),"=r"(r_[13]),"=r"(r_[14]),"=r"(r_[15]),
              "=r"(r_[16]),"=r"(r_[17]),"=r"(r_[18]),"=r"(r_[19]),
              "=r"(r_[20]),"=r"(r_[21]),"=r"(r_[22]),"=r"(r_[23]),
              "=r"(r_[24]),"=r"(r_[25]),"=r"(r_[26]),"=r"(r_[27]),
              "=r"(r_[28]),"=r"(r_[29]),"=r"(r_[30]),"=r"(r_[31])
            : "r"(tmem + half * 128 + cb * 32));
        asm volatile("tcgen05.wait::ld.sync.aligned;" ::: "memory");
        #pragma unroll
        for (int j = 0; j < 32; j++)
            sEp[rrow * 65 + half * 32 + j] = __uint_as_float(r_[j]);
        __syncthreads();

        const int scol = (f >> 3) * 32 + (f & 7) * 4;
        const int gcol = n0 + (f >> 3) * 128 + cb * 32 + (f & 7) * 4;
        const float4 bv = *(const float4*)(bias + gcol);
        float4 gv = make_float4(0.f, 0.f, 0.f, 0.f);
        if (EPI == 2) gv = *(const float4*)(gate + gcol);
        #pragma unroll
        for (int i = 0; i < 8; i++) {
            int r = rg + 16 * i;
            const float* sp = &sEp[r * 65 + scol];
            float4 v = make_float4(sp[0], sp[1], sp[2], sp[3]);
            v.x += bv.x; v.y += bv.y; v.z += bv.z; v.w += bv.w;
            if (EPI == 1) {
                v.x = gelu_tanh(v.x); v.y = gelu_tanh(v.y);
                v.z = gelu_tanh(v.z); v.w = gelu_tanh(v.w);
            }
            if (EPI == 2) {
                float4 rr = *(const float4*)(resid + (size_t)(m0 + r) * ldres + gcol);
                v.x = rr.x + gv.x * v.x; v.y = rr.y + gv.y * v.y;
                v.z = rr.z + gv.z * v.z; v.w = rr.w + gv.w * v.w;
            }
            *(float4*)(C + (size_t)(m0 + r) * ldc + gcol) = v;
        }
        __syncthreads();
    }
    if (wid == 0) {
        asm volatile("tcgen05.dealloc.cta_group::1.sync.aligned.b32 %0, %1;"
                     :: "r"(tmem), "r"(256u));
    }
#else
    // ---------------- fallback: mma.sync, two 128x128 sub-tiles ----------------
    float (*As)[132] = (float(*)[132])smem;                       // [2*16][132]
    float (*Bs)[132] = (float(*)[132])(smem + 2 * 16 * 132 * 4);  // [2*16][132]

    const int wm = wid >> 2, wn = wid & 3;
    const int gid = lane >> 2, tig = lane & 3;
    const int a_m = t >> 1, a_k = (t & 1) * 4;
    const int b_k = t >> 5, b_n = (t & 31) * 4;
    const int nk = K / 16;

    for (int nh = 0; nh < 2; nh++) {
        const int nb0 = n0 + nh * 128;
        const float* Ap = A + (size_t)(m0 + a_m) * lda + a_k;
        const float* Bp = B + (size_t)b_k * ldb + nb0 + b_n;

        float c[4][4][4];
        #pragma unroll
        for (int i = 0; i < 4; i++)
            #pragma unroll
            for (int j = 0; j < 4; j++)
                #pragma unroll
                for (int r = 0; r < 4; r++) c[i][j][r] = 0.0f;

        float4 pa0, pa1, pb0, pb1;
        pa0 = *(const float4*)(Ap);
        pa1 = *(const float4*)(Ap + 8);
        pb0 = *(const float4*)(Bp);
        pb1 = *(const float4*)(Bp + (size_t)8 * ldb);
        {
            As[a_k + 0][a_m] = to_tf32(pa0.x); As[a_k + 1][a_m] = to_tf32(pa0.y);
            As[a_k + 2][a_m] = to_tf32(pa0.z); As[a_k + 3][a_m] = to_tf32(pa0.w);
            As[a_k + 8][a_m] = to_tf32(pa1.x); As[a_k + 9][a_m] = to_tf32(pa1.y);
            As[a_k +10][a_m] = to_tf32(pa1.z); As[a_k +11][a_m] = to_tf32(pa1.w);
            float4 q0 = make_float4(to_tf32(pb0.x), to_tf32(pb0.y), to_tf32(pb0.z), to_tf32(pb0.w));
            float4 q1 = make_float4(to_tf32(pb1.x), to_tf32(pb1.y), to_tf32(pb1.z), to_tf32(pb1.w));
            *(float4*)(&Bs[b_k][b_n])     = q0;
            *(float4*)(&Bs[b_k + 8][b_n]) = q1;
        }
        __syncthreads();

        for (int kt = 0; kt < nk; kt++) {
            const int buf = kt & 1;
            const bool has_next = (kt + 1 < nk);
            if (has_next) {
                const int off = (kt + 1) * 16;
                pa0 = *(const float4*)(Ap + off);
                pa1 = *(const float4*)(Ap + off + 8);
                pb0 = *(const float4*)(Bp + (size_t)off * ldb);
                pb1 = *(const float4*)(Bp + (size_t)(off + 8) * ldb);
            }
            #pragma unroll
            for (int ks = 0; ks < 2; ks++) {
                const int kb = buf * 16 + ks * 8;
                unsigned int afr[4][4], bfr[4][2];
                #pragma unroll
                for (int mt = 0; mt < 4; mt++) {
                    const int bm = wm * 64 + mt * 16 + gid;
                    afr[mt][0] = __float_as_uint(As[kb + tig    ][bm]);
                    afr[mt][1] = __float_as_uint(As[kb + tig    ][bm + 8]);
                    afr[mt][2] = __float_as_uint(As[kb + tig + 4][bm]);
                    afr[mt][3] = __float_as_uint(As[kb + tig + 4][bm + 8]);
                }
                #pragma unroll
                for (int nt = 0; nt < 4; nt++) {
                    const int bn = wn * 32 + nt * 8 + gid;
                    bfr[nt][0] = __float_as_uint(Bs[kb + tig    ][bn]);
                    bfr[nt][1] = __float_as_uint(Bs[kb + tig + 4][bn]);
                }
                #pragma unroll
                for (int mt = 0; mt < 4; mt++)
                    #pragma unroll
                    for (int nt = 0; nt < 4; nt++)
                        mma_tf32(c[mt][nt], afr[mt], bfr[nt]);
            }
            if (has_next) {
                const int nb = (buf ^ 1) * 16;
                As[nb + a_k + 0][a_m] = to_tf32(pa0.x); As[nb + a_k + 1][a_m] = to_tf32(pa0.y);
                As[nb + a_k + 2][a_m] = to_tf32(pa0.z); As[nb + a_k + 3][a_m] = to_tf32(pa0.w);
                As[nb + a_k + 8][a_m] = to_tf32(pa1.x); As[nb + a_k + 9][a_m] = to_tf32(pa1.y);
                As[nb + a_k +10][a_m] = to_tf32(pa1.z); As[nb + a_k +11][a_m] = to_tf32(pa1.w);
                float4 q0 = make_float4(to_tf32(pb0.x), to_tf32(pb0.y), to_tf32(pb0.z), to_tf32(pb0.w));
                float4 q1 = make_float4(to_tf32(pb1.x), to_tf32(pb1.y), to_tf32(pb1.z), to_tf32(pb1.w));
                *(float4*)(&Bs[nb + b_k][b_n])     = q0;
                *(float4*)(&Bs[nb + b_k + 8][b_n]) = q1;
            }
            __syncthreads();
        }

        #pragma unroll
        for (int nt = 0; nt < 4; nt++) {
            const int col = nb0 + wn * 32 + nt * 8 + tig * 2;
            const float bv0 = bias[col], bv1 = bias[col + 1];
            float gv0 = 0.0f, gv1 = 0.0f;
            if (EPI == 2) { gv0 = gate[col]; gv1 = gate[col + 1]; }
            #pragma unroll
            for (int mt = 0; mt < 4; mt++) {
                const int row0 = m0 + wm * 64 + mt * 16 + gid;
                #pragma unroll
                for (int hh = 0; hh < 2; hh++) {
                    const int row = row0 + hh * 8;
                    float v0 = c[mt][nt][hh * 2 + 0] + bv0;
                    float v1 = c[mt][nt][hh * 2 + 1] + bv1;
                    if (EPI == 1) { v0 = gelu_tanh(v0); v1 = gelu_tanh(v1); }
                    if (EPI == 2) {
                        const float* Rr = resid + (size_t)row * ldres + col;
                        v0 = Rr[0] + gv0 * v0;
                        v1 = Rr[1] + gv1 * v1;
                    }
                    *(float2*)(C + (size_t)row * ldc + col) = make_float2(v0, v1);
                }
            }
        }
        __syncthreads();
    }
#endif
}

// ---------------------------------------------------------------------------
// Flash attention (unchanged, known good)
// ---------------------------------------------------------------------------
#define FA_SCALE 0.08838834764831845f
#define SQ_PITCH 132
#define SK_PITCH 68
#define SV_PITCH 132
#define SP_PITCH 132
#define SQ_OFF 0
#define SK_OFF (128 * SQ_PITCH)
#define SV_OFF (SK_OFF + 128 * SK_PITCH)
#define SP_OFF (SV_OFF + 64 * SV_PITCH)
#define FA_SMEM_FLOATS (SP_OFF + 64 * SP_PITCH)
#define FA_SMEM_BYTES (FA_SMEM_FLOATS * 4)

__global__ void __launch_bounds__(256, 1)
flash_attn(const float* __restrict__ Q, const float* __restrict__ K,
           const float* __restrict__ V, float* __restrict__ O) {
    extern __shared__ float sm[];
    float* sQ = sm + SQ_OFF;
    float* sK = sm + SK_OFF;
    float* sV = sm + SV_OFF;
    float* sP = sm + SP_OFF;

    const int t = threadIdx.x;
    const int wid = t >> 5, lane = t & 31;
    const int gid = lane >> 2, tig = lane & 3;
    const int h = blockIdx.y;
    const int q0 = blockIdx.x * 128;
    const int m0 = wid * 16;

    const float* Qh = Q + ((size_t)h * LTOT + q0) * HD;
    const float* Kh = K + (size_t)h * LTOT * HD;
    const float* Vh = V + (size_t)h * LTOT * HD;

    {
        int r = t >> 1;
        int dseg = (t & 1) * 64;
        const float* qr = Qh + (size_t)r * HD + dseg;
        #pragma unroll
        for (int i = 0; i < 16; i++) {
            float4 v4 = *(const float4*)(qr + i * 4);
            int d = dseg + i * 4;
            sQ[(d + 0) * SQ_PITCH + r] = to_tf32(v4.x * FA_SCALE);
            sQ[(d + 1) * SQ_PITCH + r] = to_tf32(v4.y * FA_SCALE);
            sQ[(d + 2) * SQ_PITCH + r] = to_tf32(v4.z * FA_SCALE);
            sQ[(d + 3) * SQ_PITCH + r] = to_tf32(v4.w * FA_SCALE);
        }
    }
    __syncthreads();

    unsigned int qf[16][4];
    #pragma unroll
    for (int kt = 0; kt < 16; kt++) {
        int kb = kt * 8;
        qf[kt][0] = __float_as_uint(sQ[(kb + tig)     * SQ_PITCH + m0 + gid]);
        qf[kt][1] = __float_as_uint(sQ[(kb + tig)     * SQ_PITCH + m0 + gid + 8]);
        qf[kt][2] = __float_as_uint(sQ[(kb + tig + 4) * SQ_PITCH + m0 + gid]);
        qf[kt][3] = __float_as_uint(sQ[(kb + tig + 4) * SQ_PITCH + m0 + gid + 8]);
    }

    float co[16][4];
    #pragma unroll
    for (int i = 0; i < 16; i++)
        #pragma unroll
        for (int j = 0; j < 4; j++) co[i][j] = 0.0f;
    float mrow0 = -1e30f, mrow1 = -1e30f, lrow0 = 0.0f, lrow1 = 0.0f;

    for (int kv = 0; kv < LTOT; kv += 64) {
        __syncthreads();
        {
            int c = t >> 2;
            int dseg = (t & 3) * 32;
            const float* kr = Kh + (size_t)(kv + c) * HD + dseg;
            #pragma unroll
            for (int i = 0; i < 8; i++) {
                float4 v4 = *(const float4*)(kr + i * 4);
                int d = dseg + i * 4;
                sK[(d + 0) * SK_PITCH + c] = to_tf32(v4.x);
                sK[(d + 1) * SK_PITCH + c] = to_tf32(v4.y);
                sK[(d + 2) * SK_PITCH + c] = to_tf32(v4.z);
                sK[(d + 3) * SK_PITCH + c] = to_tf32(v4.w);
            }
        }
        {
            int c = t >> 2;
            int dseg = (t & 3) * 32;
            const float* vr = Vh + (size_t)(kv + c) * HD + dseg;
            #pragma unroll
            for (int i = 0; i < 8; i++) {
                float4 v4 = *(const float4*)(vr + i * 4);
                float4 q4 = make_float4(to_tf32(v4.x), to_tf32(v4.y),
                                        to_tf32(v4.z), to_tf32(v4.w));
                *(float4*)(sV + c * SV_PITCH + dseg + i * 4) = q4;
            }
        }
        __syncthreads();

        float cs[8][4];
        #pragma unroll
        for (int i = 0; i < 8; i++)
            #pragma unroll
            for (int j = 0; j < 4; j++) cs[i][j] = 0.0f;
        #pragma unroll
        for (int kt = 0; kt < 16; kt++) {
            int kb = kt * 8;
            #pragma unroll
            for (int nt = 0; nt < 8; nt++) {
                unsigned int bf[2];
                bf[0] = __float_as_uint(sK[(kb + tig)     * SK_PITCH + nt * 8 + gid]);
                bf[1] = __float_as_uint(sK[(kb + tig + 4) * SK_PITCH + nt * 8 + gid]);
                mma_tf32(cs[nt], qf[kt], bf);
            }
        }

        float rmax0 = -1e30f, rmax1 = -1e30f;
        #pragma unroll
        for (int nt = 0; nt < 8; nt++) {
            rmax0 = fmaxf(rmax0, fmaxf(cs[nt][0], cs[nt][1]));
            rmax1 = fmaxf(rmax1, fmaxf(cs[nt][2], cs[nt][3]));
        }
        rmax0 = fmaxf(rmax0, __shfl_xor_sync(0xffffffffu, rmax0, 1));
        rmax0 = fmaxf(rmax0, __shfl_xor_sync(0xffffffffu, rmax0, 2));
        rmax1 = fmaxf(rmax1, __shfl_xor_sync(0xffffffffu, rmax1, 1));
        rmax1 = fmaxf(rmax1, __shfl_xor_sync(0xffffffffu, rmax1, 2));
        float mn0 = fmaxf(mrow0, rmax0);
        float mn1 = fmaxf(mrow1, rmax1);
        float corr0 = __expf(mrow0 - mn0);
        float corr1 = __expf(mrow1 - mn1);
        mrow0 = mn0; mrow1 = mn1;

        float rs0 = 0.0f, rs1 = 0.0f;
        #pragma unroll
        for (int nt = 0; nt < 8; nt++) {
            cs[nt][0] = __expf(cs[nt][0] - mn0);
            cs[nt][1] = __expf(cs[nt][1] - mn0);
            cs[nt][2] = __expf(cs[nt][2] - mn1);
            cs[nt][3] = __expf(cs[nt][3] - mn1);
            rs0 += cs[nt][0] + cs[nt][1];
            rs1 += cs[nt][2] + cs[nt][3];
        }
        rs0 += __shfl_xor_sync(0xffffffffu, rs0, 1);
        rs0 += __shfl_xor_sync(0xffffffffu, rs0, 2);
        rs1 += __shfl_xor_sync(0xffffffffu, rs1, 1);
        rs1 += __shfl_xor_sync(0xffffffffu, rs1, 2);
        lrow0 = lrow0 * corr0 + rs0;
        lrow1 = lrow1 * corr1 + rs1;

        #pragma unroll
        for (int nt = 0; nt < 16; nt++) {
            co[nt][0] *= corr0; co[nt][1] *= corr0;
            co[nt][2] *= corr1; co[nt][3] *= corr1;
        }

        #pragma unroll
        for (int nt = 0; nt < 8; nt++) {
            int cb = nt * 8 + tig * 2;
            sP[(cb + 0) * SP_PITCH + m0 + gid]     = to_tf32(cs[nt][0]);
            sP[(cb + 1) * SP_PITCH + m0 + gid]     = to_tf32(cs[nt][1]);
            sP[(cb + 0) * SP_PITCH + m0 + gid + 8] = to_tf32(cs[nt][2]);
            sP[(cb + 1) * SP_PITCH + m0 + gid + 8] = to_tf32(cs[nt][3]);
        }
        __syncwarp();

        #pragma unroll
        for (int kt = 0; kt < 8; kt++) {
            int kb = kt * 8;
            unsigned int af[4];
            af[0] = __float_as_uint(sP[(kb + tig)     * SP_PITCH + m0 + gid]);
            af[1] = __float_as_uint(sP[(kb + tig)     * SP_PITCH + m0 + gid + 8]);
            af[2] = __float_as_uint(sP[(kb + tig + 4) * SP_PITCH + m0 + gid]);
            af[3] = __float_as_uint(sP[(kb + tig + 4) * SP_PITCH + m0 + gid + 8]);
            #pragma unroll
            for (int nt = 0; nt < 16; nt++) {
                unsigned int bf[2];
                bf[0] = __float_as_uint(sV[(kb + tig)     * SV_PITCH + nt * 8 + gid]);
                bf[1] = __float_as_uint(sV[(kb + tig + 4) * SV_PITCH + nt * 8 + gid]);
                mma_tf32(co[nt], af, bf);
            }
        }
    }

    float inv0 = 1.0f / lrow0;
    float inv1 = 1.0f / lrow1;
    int row0 = q0 + m0 + gid;
    #pragma unroll
    for (int nt = 0; nt < 16; nt++) {
        int col = h * HD + nt * 8 + tig * 2;
        *(float2*)(O + (size_t)row0 * HS + col) =
            make_float2(co[nt][0] * inv0, co[nt][1] * inv0);
        *(float2*)(O + (size_t)(row0 + 8) * HS + col) =
            make_float2(co[nt][2] * inv1, co[nt][3] * inv1);
    }
}

// ---------------------------------------------------------------------------
// Host launcher
// ---------------------------------------------------------------------------
static void tc_launch(int epi, const float* A, const float* B, const float* bias,
                      float* C, int M, int N, int K, int lda, int ldb, int ldc,
                      const float* gate = nullptr, const float* resid = nullptr,
                      int ldres = 0) {
    int nM = M / 128, nN = N / 256;
    dim3 grid(nM * nN);
    if (epi == 0)
        tc_gemm<0><<<grid, 256, TCG_SMEM_BYTES>>>(A, B, bias, C, K, lda, ldb, ldc, nM, gate, resid, ldres);
    else if (epi == 1)
        tc_gemm<1><<<grid, 256, TCG_SMEM_BYTES>>>(A, B, bias, C, K, lda, ldb, ldc, nM, gate, resid, ldres);
    else
        tc_gemm<2><<<grid, 256, TCG_SMEM_BYTES>>>(A, B, bias, C, K, lda, ldb, ldc, nM, gate, resid, ldres);
}

extern "C" void kernel_launch(void* const* d_in, const int* in_sizes, int n_in,
                              void* d_out, int out_size) {
    const float* img        = (const float*)d_in[0];
    const float* txt        = (const float*)d_in[1];
    const float* vec        = (const float*)d_in[2];
    const float* pe         = (const float*)d_in[3];
    const float* img_mod_w  = (const float*)d_in[4];
    const float* img_mod_b  = (const float*)d_in[5];
    const float* img_qkv_w  = (const float*)d_in[6];
    const float* img_qkv_b  = (const float*)d_in[7];
    const float* img_q_s    = (const float*)d_in[8];
    const float* img_k_s    = (const float*)d_in[9];
    const float* img_proj_w = (const float*)d_in[10];
    const float* img_proj_b = (const float*)d_in[11];
    const float* img_mlp_w1 = (const float*)d_in[12];
    const float* img_mlp_b1 = (const float*)d_in[13];
    const float* img_mlp_w2 = (const float*)d_in[14];
    const float* img_mlp_b2 = (const float*)d_in[15];
    const float* txt_mod_w  = (const float*)d_in[16];
    const float* txt_mod_b  = (const float*)d_in[17];
    const float* txt_qkv_w  = (const float*)d_in[18];
    const float* txt_qkv_b  = (const float*)d_in[19];
    const float* txt_q_s    = (const float*)d_in[20];
    const float* txt_k_s    = (const float*)d_in[21];
    const float* txt_proj_w = (const float*)d_in[22];
    const float* txt_proj_b = (const float*)d_in[23];
    const float* txt_mlp_w1 = (const float*)d_in[24];
    const float* txt_mlp_b1 = (const float*)d_in[25];
    const float* txt_mlp_w2 = (const float*)d_in[26];
    const float* txt_mlp_b2 = (const float*)d_in[27];
    float* out = (float*)d_out;

    float *sv, *modi, *modt, *x, *qkvb, *q, *k, *v, *attn, *x1, *x2, *h1;
    cudaGetSymbolAddress((void**)&sv,   g_silu);
    cudaGetSymbolAddress((void**)&modi, g_mod_img);
    cudaGetSymbolAddress((void**)&modt, g_mod_txt);
    cudaGetSymbolAddress((void**)&x,    g_x);
    cudaGetSymbolAddress((void**)&qkvb, g_qkv);
    cudaGetSymbolAddress((void**)&q,    g_q);
    cudaGetSymbolAddress((void**)&k,    g_k);
    cudaGetSymbolAddress((void**)&v,    g_v);
    cudaGetSymbolAddress((void**)&attn, g_attn);
    cudaGetSymbolAddress((void**)&x1,   g_x1);
    cudaGetSymbolAddress((void**)&x2,   g_x2);
    cudaGetSymbolAddress((void**)&h1,   g_h1);

    cudaFuncSetAttribute(flash_attn, cudaFuncAttributeMaxDynamicSharedMemorySize, FA_SMEM_BYTES);
    cudaFuncSetAttribute(tc_gemm<0>, cudaFuncAttributeMaxDynamicSharedMemorySize, TCG_SMEM_BYTES);
    cudaFuncSetAttribute(tc_gemm<1>, cudaFuncAttributeMaxDynamicSharedMemorySize, TCG_SMEM_BYTES);
    cudaFuncSetAttribute(tc_gemm<2>, cudaFuncAttributeMaxDynamicSharedMemorySize, TCG_SMEM_BYTES);

    silu_kernel<<<HS / 256, 256>>>(vec, sv);
    mod_gemv2<<<(6 * HS) / 64, 256>>>(sv, img_mod_w, img_mod_b, modi);
    mod_gemv2<<<(6 * HS) / 64, 256>>>(sv, txt_mod_w, txt_mod_b, modt);

    ln_mod<<<LTXT, 256>>>(txt, x,                     modt + 0 * HS, modt + 1 * HS);
    ln_mod<<<LIMG, 256>>>(img, x + (size_t)LTXT * HS, modi + 0 * HS, modi + 1 * HS);

    tc_launch(0, x, txt_qkv_w, txt_qkv_b, qkvb, LTXT, QKVW, HS, HS, QKVW, QKVW);
    tc_launch(0, x + (size_t)LTXT * HS, img_qkv_w, img_qkv_b,
              qkvb + (size_t)LTXT * QKVW, LIMG, QKVW, HS, HS, QKVW, QKVW);

    rms_rope<<<LTOT, 256>>>(qkvb, pe, txt_q_s, txt_k_s, img_q_s, img_k_s, q, k, v);

    {
        dim3 fgrid(LTOT / 128, NH);
        flash_attn<<<fgrid, 256, FA_SMEM_BYTES>>>(q, k, v, attn);
    }

    tc_launch(2, attn, txt_proj_w, txt_proj_b, x1, LTXT, HS, HS, HS, HS, HS,
              modt + 2 * HS, txt, HS);
    tc_launch(2, attn + (size_t)LTXT * HS, img_proj_w, img_proj_b,
              x1 + (size_t)LTXT * HS, LIMG, HS, HS, HS, HS, HS,
              modi + 2 * HS, img, HS);

    ln_mod<<<LTXT, 256>>>(x1, x2,                                         modt + 3 * HS, modt + 4 * HS);
    ln_mod<<<LIMG, 256>>>(x1 + (size_t)LTXT * HS, x2 + (size_t)LTXT * HS, modi + 3 * HS, modi + 4 * HS);

    tc_launch(1, x2, txt_mlp_w1, txt_mlp_b1, h1, LTXT, MLPD, HS, HS, MLPD, MLPD);
    tc_launch(1, x2 + (size_t)LTXT * HS, img_mlp_w1, img_mlp_b1,
              h1 + (size_t)LTXT * MLPD, LIMG, MLPD, HS, HS, MLPD, MLPD);

    tc_launch(2, h1, txt_mlp_w2, txt_mlp_b2, out + (size_t)LIMG * HS,
              LTXT, HS, MLPD, MLPD, HS, HS, modt + 5 * HS, x1, HS);
    tc_launch(2, h1 + (size_t)LTXT * MLPD, img_mlp_w2, img_mlp_b2, out,
              LIMG, HS, MLPD, MLPD, HS, HS, modi + 5 * HS, x1 + (size_t)LTXT * HS, HS);
}

// round 10
// speedup vs baseline: 4.8730x; 1.0084x over previous
#include <cuda_runtime.h>
#include <cuda_bf16.h>
#include <math.h>
#include <stdint.h>

#define HS    3072
#define MLPD  12288
#define NH    24
#define HD    128
#define LTXT  512
#define LIMG  2048
#define LTOT  2560
#define QKVW  9216
#define NMT   4      // txt M-tiles (512/128)
#define NMALL 20     // total M-tiles (2560/128)

#if defined(__CUDA_ARCH__)
#if defined(__CUDA_ARCH_FEAT_SM103_ALL) || \
    (defined(__CUDA_ARCH_SPECIFIC__) && (__CUDA_ARCH_SPECIFIC__ >= 1000))
#define HAS_TCGEN05 1
#else
#define HAS_TCGEN05 0
#endif
#else
#define HAS_TCGEN05 0
#endif

// ---------------------------------------------------------------------------
// Static device scratch
// ---------------------------------------------------------------------------
__device__ float g_silu[HS];
__device__ float g_mod_img[6 * HS];
__device__ float g_mod_txt[6 * HS];
__device__ float g_x   [(size_t)LTOT * HS];
__device__ float g_qkv [(size_t)LTOT * QKVW];
__device__ float g_q   [(size_t)NH * LTOT * HD];
__device__ float g_k   [(size_t)NH * LTOT * HD];
__device__ float g_v   [(size_t)NH * LTOT * HD];
__device__ float g_attn[(size_t)LTOT * HS];
__device__ float g_x1  [(size_t)LTOT * HS];
__device__ float g_x2  [(size_t)LTOT * HS];
__device__ float g_h1  [(size_t)LTOT * MLPD];

// ---------------------------------------------------------------------------
// Elementwise kernels
// ---------------------------------------------------------------------------
__global__ void silu_kernel(const float* __restrict__ v, float* __restrict__ o) {
    int i = blockIdx.x * 256 + threadIdx.x;
    if (i < HS) { float x = v[i]; o[i] = x / (1.0f + expf(-x)); }
}

__global__ void mod_gemv2(const float* __restrict__ sv, const float* __restrict__ w,
                          const float* __restrict__ b, float* __restrict__ out) {
    __shared__ float ssv[HS];
    __shared__ float red[4][64];
    for (int i = threadIdx.x; i < HS; i += 256) ssv[i] = sv[i];
    __syncthreads();
    const int jl = threadIdx.x & 63, kq = threadIdx.x >> 6;
    const int j = blockIdx.x * 64 + jl;
    const int i0 = kq * (HS / 4);
    float acc = 0.0f;
    #pragma unroll 8
    for (int i = 0; i < HS / 4; i++)
        acc += ssv[i0 + i] * w[(size_t)(i0 + i) * (6 * HS) + j];
    red[kq][jl] = acc;
    __syncthreads();
    if (threadIdx.x < 64) {
        int jj = blockIdx.x * 64 + threadIdx.x;
        out[jj] = red[0][threadIdx.x] + red[1][threadIdx.x] +
                  red[2][threadIdx.x] + red[3][threadIdx.x] + b[jj];
    }
}

__global__ void ln_mod(const float* __restrict__ x, float* __restrict__ dst,
                       const float* __restrict__ shift, const float* __restrict__ scale) {
    int row = blockIdx.x;
    int t = threadIdx.x;
    const float* xr = x + (size_t)row * HS;
    float v[12];
    float s = 0.0f;
    #pragma unroll
    for (int i = 0; i < 12; i++) { v[i] = xr[t + i * 256]; s += v[i]; }
    __shared__ float red[256];
    red[t] = s; __syncthreads();
    for (int o = 128; o > 0; o >>= 1) { if (t < o) red[t] += red[t + o]; __syncthreads(); }
    float mean = red[0] * (1.0f / HS);
    __syncthreads();
    float s2 = 0.0f;
    #pragma unroll
    for (int i = 0; i < 12; i++) { float d = v[i] - mean; s2 += d * d; }
    red[t] = s2; __syncthreads();
    for (int o = 128; o > 0; o >>= 1) { if (t < o) red[t] += red[t + o]; __syncthreads(); }
    float inv = rsqrtf(red[0] * (1.0f / HS) + 1e-6f);
    float* dr = dst + (size_t)row * HS;
    #pragma unroll
    for (int i = 0; i < 12; i++) {
        int c = t + i * 256;
        dr[c] = shift[c] + (1.0f + scale[c]) * (v[i] - mean) * inv;
    }
}

__global__ void rms_rope(const float* __restrict__ qkv, const float* __restrict__ pe,
                         const float* __restrict__ tqs, const float* __restrict__ tks,
                         const float* __restrict__ iqs, const float* __restrict__ iks,
                         float* __restrict__ Q, float* __restrict__ Kp, float* __restrict__ Vp) {
    int l = blockIdx.x;
    int w = threadIdx.x >> 5, lane = threadIdx.x & 31;
    const float* qs = (l < LTXT) ? tqs : iqs;
    const float* ks = (l < LTXT) ? tks : iks;
    const float* row = qkv + (size_t)l * QKVW;
    const float* peb = pe + (size_t)l * 256 + lane * 8;
    float4 p0 = *(const float4*)(peb);
    float4 p1 = *(const float4*)(peb + 4);
    int d0 = lane * 4;
    float4 scq = *(const float4*)(qs + d0);
    float4 sck = *(const float4*)(ks + d0);

    for (int h = w; h < NH; h += 8) {
        float4 xq = *(const float4*)(row + h * HD + d0);
        float ss = xq.x*xq.x + xq.y*xq.y + xq.z*xq.z + xq.w*xq.w;
        #pragma unroll
        for (int o = 16; o > 0; o >>= 1) ss += __shfl_xor_sync(0xffffffffu, ss, o);
        float r = rsqrtf(ss * (1.0f / HD) + 1e-6f);
        float x0 = xq.x * r * scq.x, x1 = xq.y * r * scq.y;
        float x2 = xq.z * r * scq.z, x3 = xq.w * r * scq.w;
        float4 oq;
        oq.x = p0.x * x0 + p0.y * x1;
        oq.y = p0.z * x0 + p0.w * x1;
        oq.z = p1.x * x2 + p1.y * x3;
        oq.w = p1.z * x2 + p1.w * x3;
        *(float4*)(Q + ((size_t)h * LTOT + l) * HD + d0) = oq;
        float4 xk = *(const float4*)(row + HS + h * HD + d0);
        float sk = xk.x*xk.x + xk.y*xk.y + xk.z*xk.z + xk.w*xk.w;
        #pragma unroll
        for (int o = 16; o > 0; o >>= 1) sk += __shfl_xor_sync(0xffffffffu, sk, o);
        float rk = rsqrtf(sk * (1.0f / HD) + 1e-6f);
        float y0 = xk.x * rk * sck.x, y1 = xk.y * rk * sck.y;
        float y2 = xk.z * rk * sck.z, y3 = xk.w * rk * sck.w;
        float4 ok;
        ok.x = p0.x * y0 + p0.y * y1;
        ok.y = p0.z * y0 + p0.w * y1;
        ok.z = p1.x * y2 + p1.y * y3;
        ok.w = p1.z * y2 + p1.w * y3;
        *(float4*)(Kp + ((size_t)h * LTOT + l) * HD + d0) = ok;
        float4 xv = *(const float4*)(row + 2 * HS + h * HD + d0);
        *(float4*)(Vp + ((size_t)h * LTOT + l) * HD + d0) = xv;
    }
}

// ---------------------------------------------------------------------------
// Helpers
// ---------------------------------------------------------------------------
__device__ __forceinline__ float gelu_tanh(float x) {
    float x3 = x * x * x;
    return 0.5f * x * (1.0f + tanhf(0.7978845608028654f * (x + 0.044715f * x3)));
}
__device__ __forceinline__ float to_tf32(float x) {
    unsigned int u;
    asm("cvt.rna.tf32.f32 %0, %1;" : "=r"(u) : "f"(x));
    return __uint_as_float(u);
}
__device__ __forceinline__ unsigned int tf32u(float x) {
    unsigned int u;
    asm("cvt.rna.tf32.f32 %0, %1;" : "=r"(u) : "f"(x));
    return u;
}
__device__ __forceinline__ void mma_tf32(float c[4], const unsigned int a[4],
                                         const unsigned int b[2]) {
    asm volatile(
        "mma.sync.aligned.m16n8k8.row.col.f32.tf32.tf32.f32 "
        "{%0,%1,%2,%3}, {%4,%5,%6,%7}, {%8,%9}, {%0,%1,%2,%3};"
        : "+f"(c[0]), "+f"(c[1]), "+f"(c[2]), "+f"(c[3])
        : "r"(a[0]), "r"(a[1]), "r"(a[2]), "r"(a[3]), "r"(b[0]), "r"(b[1]));
}
__device__ __forceinline__ uint32_t smem_u32(const void* p) {
    uint32_t a;
    asm("{ .reg .u64 t; cvta.to.shared.u64 t, %1; cvt.u32.u64 %0, t; }" : "=r"(a) : "l"(p));
    return a;
}

#define TCG_SMEM_BYTES (1024 + 2 * 49152)   // 2 stages of (16KB A + 32KB B)

#if HAS_TCGEN05
__device__ __forceinline__ uint32_t elect_one() {
    uint32_t pred;
    asm volatile("{\n\t.reg .pred p;\n\telect.sync _|p, 0xFFFFFFFF;\n\t"
                 "selp.b32 %0, 1, 0, p;\n\t}" : "=r"(pred));
    return pred;
}
__device__ __forceinline__ void mbar_wait(uint32_t mbar, uint32_t parity) {
    asm volatile(
        "{\n\t.reg .pred P1;\n\t"
        "W_%=:\n\t"
        "mbarrier.try_wait.parity.acquire.cta.shared::cta.b64 P1, [%0], %1, 0x989680;\n\t"
        "@P1 bra.uni D_%=;\n\t"
        "bra.uni W_%=;\n\t"
        "D_%=:\n\t}"
        :: "r"(mbar), "r"(parity) : "memory");
}
__device__ __forceinline__ uint64_t make_desc(uint32_t addr) {
    const uint64_t base =
        (uint64_t(2) << 61) | (uint64_t(1) << 46) | (uint64_t(64) << 32) | (uint64_t(1) << 16);
    return base | ((uint64_t)(addr >> 4) & 0x3FFF);
}
__device__ __forceinline__ void tc_mma(uint32_t d, uint64_t ad, uint64_t bd,
                                       uint32_t idesc, uint32_t en) {
    asm volatile(
        "{\n\t.reg .pred p;\n\t"
        "setp.ne.u32 p, %4, 0;\n\t"
        "tcgen05.mma.cta_group::1.kind::tf32 [%0], %1, %2, %3, {%5,%5,%5,%5}, p;\n\t}"
        :: "r"(d), "l"(ad), "l"(bd), "r"(idesc), "r"(en), "r"(0u) : "memory");
}
#define TCG_IDESC ((1u<<4)|(2u<<7)|(2u<<10)|((256u/8)<<17)|((128u/16)<<24))
#endif

// ---------------------------------------------------------------------------
// Merged txt/img tf32 GEMM, CTA tile 128(M) x 256(N). Grid 1D m-fastest,
// M fixed = 2560 (txt tiles m<4, img tiles m>=4). Region selects B/bias/gate/
// resid/C-base. tcgen05 path: double-buffered, LDG.128 B loads. Fallback:
// mma.sync 2x128x128.
// ---------------------------------------------------------------------------
template <int EPI>
__global__ void __launch_bounds__(256)
tc_gemm(const float* __restrict__ A,
        const float* __restrict__ Bt, const float* __restrict__ Bi,
        const float* __restrict__ biast, const float* __restrict__ biasi,
        float* __restrict__ Ct, float* __restrict__ Ci,
        int K, int lda, int ldb, int ldc,
        const float* __restrict__ gatet, const float* __restrict__ gatei,
        const float* __restrict__ residt, const float* __restrict__ residi,
        int ldres) {
    extern __shared__ char smem[];
    const int t = threadIdx.x;
    const int wid = t >> 5, lane = t & 31;
    const int mi = blockIdx.x % NMALL;
    const int m0 = mi * 128;
    const int n0 = (blockIdx.x / NMALL) * 256;
    const bool is_txt = (mi < NMT);
    const float* B     = is_txt ? Bt : Bi;
    const float* bias  = is_txt ? biast : biasi;
    const float* gate  = is_txt ? gatet : gatei;
    const float* resid = is_txt ? residt : residi;
    float* C           = is_txt ? Ct : Ci;

#if HAS_TCGEN05
    const uint32_t smem_base = smem_u32(smem);
    const uint32_t sA0 = (smem_base + 64 + 1023) & ~1023u;
    const uint32_t sB0 = sA0 + 16384;
    const uint32_t sA1 = sB0 + 32768;
    const uint32_t sB1 = sA1 + 16384;
    const uint32_t mb0 = smem_base + 16;
    const uint32_t mb1 = smem_base + 24;
    float* sEp = (float*)(smem + (sA0 - smem_base));

    if (wid == 0) {
        asm volatile("tcgen05.alloc.cta_group::1.sync.aligned.shared::cta.b32 [%0], %1;"
                     :: "r"(smem_base), "r"(256u) : "memory");
        asm volatile("tcgen05.relinquish_alloc_permit.cta_group::1.sync.aligned;");
    }
    if (t == 0) {
        asm volatile("mbarrier.init.shared.b64 [%0], 1;" :: "r"(mb0) : "memory");
        asm volatile("mbarrier.init.shared.b64 [%0], 1;" :: "r"(mb1) : "memory");
    }
    __syncthreads();
    uint32_t tmem;
    asm volatile("ld.shared.b32 %0, [%1];" : "=r"(tmem) : "r"(smem_base));

    const int nc = K / 32;
    // A: thread t loads row ar, 4 float4 at k-offsets (af + 2i)*4
    const int ar = t >> 1, af = t & 1;
    const float* Ab = A + (size_t)(m0 + ar) * lda;
    // B: thread t covers n-quad n4 = t&63, k-rows kq*8..kq*8+7 (kq = t>>6)
    const int n4 = t & 63, kq = t >> 6;
    const float* Bb = B + n0 + n4 * 4;

    float4 ra[4];
    float4 rbv[8];
    // prefetch chunk 0
    #pragma unroll
    for (int i = 0; i < 4; i++) ra[i] = *(const float4*)(Ab + (af + 2 * i) * 4);
    {
        const float* Bc = Bb + (size_t)(kq * 8) * ldb;
        #pragma unroll
        for (int p = 0; p < 8; p++) rbv[p] = *(const float4*)(Bc + (size_t)p * ldb);
    }

    int ph0 = 0, ph1 = 0;
    for (int c = 0; c < nc; c++) {
        const int s = c & 1;
        const uint32_t sAc = s ? sA1 : sA0;
        const uint32_t sBc = s ? sB1 : sB0;
        const uint32_t mbc = s ? mb1 : mb0;
        if (c >= 2) {
            if (s == 0) { mbar_wait(mb0, ph0); ph0 ^= 1; }
            else        { mbar_wait(mb1, ph1); ph1 ^= 1; }
        }
        // STS A (tf32, SW128 swizzle)
        #pragma unroll
        for (int i = 0; i < 4; i++) {
            uint32_t bo = (uint32_t)ar * 128 + (af + 2 * i) * 16;
            uint32_t ad = sAc + (bo ^ ((bo >> 3) & 0x70));
            asm volatile("st.shared.v4.b32 [%0], {%1,%2,%3,%4};"
                         :: "r"(ad), "r"(tf32u(ra[i].x)), "r"(tf32u(ra[i].y)),
                            "r"(tf32u(ra[i].z)), "r"(tf32u(ra[i].w)));
        }
        // STS B transposed: row n = n4*4+j holds 32 k-floats (128B)
        const float* rbf = (const float*)rbv;
        #pragma unroll
        for (int j = 0; j < 3 + 1; j++) {
            #pragma unroll
            for (int q = 0; q < 2; q++) {
                uint32_t bo = (uint32_t)(n4 * 4 + j) * 128 + kq * 32 + q * 16;
                uint32_t ad = sBc + (bo ^ ((bo >> 3) & 0x70));
                asm volatile("st.shared.v4.b32 [%0], {%1,%2,%3,%4};"
                             :: "r"(ad),
                                "r"(tf32u(rbf[(4*q+0)*4 + j])),
                                "r"(tf32u(rbf[(4*q+1)*4 + j])),
                                "r"(tf32u(rbf[(4*q+2)*4 + j])),
                                "r"(tf32u(rbf[(4*q+3)*4 + j])));
            }
        }
        asm volatile("fence.proxy.async.shared::cta;" ::: "memory");
        __syncthreads();

        if (wid == 0) {
            asm volatile("tcgen05.fence::after_thread_sync;" ::: "memory");
            if (elect_one()) {
                uint64_t ad = make_desc(sAc);
                uint64_t bd = make_desc(sBc);
                #pragma unroll
                for (int ks = 0; ks < 4; ks++)
                    tc_mma(tmem, ad + 2 * ks, bd + 2 * ks, TCG_IDESC,
                           (uint32_t)((c > 0) | (ks > 0)));
                asm volatile(
                    "tcgen05.commit.cta_group::1.mbarrier::arrive::one.shared::cluster.b64 [%0];"
                    :: "r"(mbc) : "memory");
            }
        }
        if (c + 1 < nc) {   // prefetch next chunk (overlaps async MMA)
            const float* Ac = Ab + (size_t)(c + 1) * 32;
            #pragma unroll
            for (int i = 0; i < 4; i++) ra[i] = *(const float4*)(Ac + (af + 2 * i) * 4);
            const float* Bc = Bb + (size_t)((c + 1) * 32 + kq * 8) * ldb;
            #pragma unroll
            for (int p = 0; p < 8; p++) rbv[p] = *(const float4*)(Bc + (size_t)p * ldb);
        }
    }
    {
        const int s = (nc - 1) & 1;
        if (s == 0) mbar_wait(mb0, ph0);
        else        mbar_wait(mb1, ph1);
    }
    asm volatile("tcgen05.fence::after_thread_sync;" ::: "memory");
    __syncthreads();

    // ---- epilogue: TMEM -> smem bounce (pitch 65) -> coalesced STG ----
    const int half = wid >> 2;
    const int rrow = (wid & 3) * 32 + lane;
    const int f = t & 15, rg = t >> 4;
    for (int cb = 0; cb < 4; cb++) {
        uint32_t r_[32];
        asm volatile(
            "tcgen05.ld.sync.aligned.32x32b.x32.b32 "
            "{%0,%1,%2,%3,%4,%5,%6,%7,%8,%9,%10,%11,%12,%13,%14,%15,"
            "%16,%17,%18,%19,%20,%21,%22,%23,%24,%25,%26,%27,%28,%29,%30,%31}, [%32];"
            : "=r"(r_[0]),"=r"(r_[1]),"=r"(r_[2]),"=r"(r_[3]),
              "=r"(r_[4]),"=r"(r_[5]),"=r"(r_[6]),"=r"(r_[7]),
              "=r"(r_[8]),"=r"(r_[9]),"=r"(r_[10]),"=r"(r_[11]),
              "=r"(r_[12]),"=r"(r_[13]),"=r"(r_[14]),"=r"(r_[15]),
              "=r"(r_[16]),"=r"(r_[17]),"=r"(r_[18]),"=r"(r_[19]),
              "=r"(r_[20]),"=r"(r_[21]),"=r"(r_[22]),"=r"(r_[23]),
              "=r"(r_[24]),"=r"(r_[25]),"=r"(r_[26]),"=r"(r_[27]),
              "=r"(r_[28]),"=r"(r_[29]),"=r"(r_[30]),"=r"(r_[31])
            : "r"(tmem + half * 128 + cb * 32));
        asm volatile("tcgen05.wait::ld.sync.aligned;" ::: "memory");
        #pragma unroll
        for (int j = 0; j < 32; j++)
            sEp[rrow * 65 + half * 32 + j] = __uint_as_float(r_[j]);
        __syncthreads();

        const int scol = (f >> 3) * 32 + (f & 7) * 4;
        const int gcol = n0 + (f >> 3) * 128 + cb * 32 + (f & 7) * 4;
        const float4 bv = *(const float4*)(bias + gcol);
        float4 gv = make_float4(0.f, 0.f, 0.f, 0.f);
        if (EPI == 2) gv = *(const float4*)(gate + gcol);
        #pragma unroll
        for (int i = 0; i < 8; i++) {
            int r = rg + 16 * i;
            const float* sp = &sEp[r * 65 + scol];
            float4 v = make_float4(sp[0], sp[1], sp[2], sp[3]);
            v.x += bv.x; v.y += bv.y; v.z += bv.z; v.w += bv.w;
            if (EPI == 1) {
                v.x = gelu_tanh(v.x); v.y = gelu_tanh(v.y);
                v.z = gelu_tanh(v.z); v.w = gelu_tanh(v.w);
            }
            if (EPI == 2) {
                float4 rr = *(const float4*)(resid + (size_t)(m0 + r) * ldres + gcol);
                v.x = rr.x + gv.x * v.x; v.y = rr.y + gv.y * v.y;
                v.z = rr.z + gv.z * v.z; v.w = rr.w + gv.w * v.w;
            }
            *(float4*)(C + (size_t)(m0 + r) * ldc + gcol) = v;
        }
        __syncthreads();
    }
    if (wid == 0) {
        asm volatile("tcgen05.dealloc.cta_group::1.sync.aligned.b32 %0, %1;"
                     :: "r"(tmem), "r"(256u));
    }
#else
    // ---------------- fallback: mma.sync, two 128x128 sub-tiles ----------------
    float (*As)[132] = (float(*)[132])smem;
    float (*Bs)[132] = (float(*)[132])(smem + 2 * 16 * 132 * 4);

    const int wm = wid >> 2, wn = wid & 3;
    const int gid = lane >> 2, tig = lane & 3;
    const int a_m = t >> 1, a_k = (t & 1) * 4;
    const int b_k = t >> 5, b_n = (t & 31) * 4;
    const int nk = K / 16;

    for (int nh = 0; nh < 2; nh++) {
        const int nb0 = n0 + nh * 128;
        const float* Ap = A + (size_t)(m0 + a_m) * lda + a_k;
        const float* Bp = B + (size_t)b_k * ldb + nb0 + b_n;

        float c[4][4][4];
        #pragma unroll
        for (int i = 0; i < 4; i++)
            #pragma unroll
            for (int j = 0; j < 4; j++)
                #pragma unroll
                for (int r = 0; r < 4; r++) c[i][j][r] = 0.0f;

        float4 pa0, pa1, pb0, pb1;
        pa0 = *(const float4*)(Ap);
        pa1 = *(const float4*)(Ap + 8);
        pb0 = *(const float4*)(Bp);
        pb1 = *(const float4*)(Bp + (size_t)8 * ldb);
        {
            As[a_k + 0][a_m] = to_tf32(pa0.x); As[a_k + 1][a_m] = to_tf32(pa0.y);
            As[a_k + 2][a_m] = to_tf32(pa0.z); As[a_k + 3][a_m] = to_tf32(pa0.w);
            As[a_k + 8][a_m] = to_tf32(pa1.x); As[a_k + 9][a_m] = to_tf32(pa1.y);
            As[a_k +10][a_m] = to_tf32(pa1.z); As[a_k +11][a_m] = to_tf32(pa1.w);
            float4 q0 = make_float4(to_tf32(pb0.x), to_tf32(pb0.y), to_tf32(pb0.z), to_tf32(pb0.w));
            float4 q1 = make_float4(to_tf32(pb1.x), to_tf32(pb1.y), to_tf32(pb1.z), to_tf32(pb1.w));
            *(float4*)(&Bs[b_k][b_n])     = q0;
            *(float4*)(&Bs[b_k + 8][b_n]) = q1;
        }
        __syncthreads();

        for (int kt = 0; kt < nk; kt++) {
            const int buf = kt & 1;
            const bool has_next = (kt + 1 < nk);
            if (has_next) {
                const int off = (kt + 1) * 16;
                pa0 = *(const float4*)(Ap + off);
                pa1 = *(const float4*)(Ap + off + 8);
                pb0 = *(const float4*)(Bp + (size_t)off * ldb);
                pb1 = *(const float4*)(Bp + (size_t)(off + 8) * ldb);
            }
            #pragma unroll
            for (int ks = 0; ks < 2; ks++) {
                const int kb = buf * 16 + ks * 8;
                unsigned int afr[4][4], bfr[4][2];
                #pragma unroll
                for (int mt = 0; mt < 4; mt++) {
                    const int bm = wm * 64 + mt * 16 + gid;
                    afr[mt][0] = __float_as_uint(As[kb + tig    ][bm]);
                    afr[mt][1] = __float_as_uint(As[kb + tig    ][bm + 8]);
                    afr[mt][2] = __float_as_uint(As[kb + tig + 4][bm]);
                    afr[mt][3] = __float_as_uint(As[kb + tig + 4][bm + 8]);
                }
                #pragma unroll
                for (int nt = 0; nt < 4; nt++) {
                    const int bn = wn * 32 + nt * 8 + gid;
                    bfr[nt][0] = __float_as_uint(Bs[kb + tig    ][bn]);
                    bfr[nt][1] = __float_as_uint(Bs[kb + tig + 4][bn]);
                }
                #pragma unroll
                for (int mt = 0; mt < 4; mt++)
                    #pragma unroll
                    for (int nt = 0; nt < 4; nt++)
                        mma_tf32(c[mt][nt], afr[mt], bfr[nt]);
            }
            if (has_next) {
                const int nb = (buf ^ 1) * 16;
                As[nb + a_k + 0][a_m] = to_tf32(pa0.x); As[nb + a_k + 1][a_m] = to_tf32(pa0.y);
                As[nb + a_k + 2][a_m] = to_tf32(pa0.z); As[nb + a_k + 3][a_m] = to_tf32(pa0.w);
                As[nb + a_k + 8][a_m] = to_tf32(pa1.x); As[nb + a_k + 9][a_m] = to_tf32(pa1.y);
                As[nb + a_k +10][a_m] = to_tf32(pa1.z); As[nb + a_k +11][a_m] = to_tf32(pa1.w);
                float4 q0 = make_float4(to_tf32(pb0.x), to_tf32(pb0.y), to_tf32(pb0.z), to_tf32(pb0.w));
                float4 q1 = make_float4(to_tf32(pb1.x), to_tf32(pb1.y), to_tf32(pb1.z), to_tf32(pb1.w));
                *(float4*)(&Bs[nb + b_k][b_n])     = q0;
                *(float4*)(&Bs[nb + b_k + 8][b_n]) = q1;
            }
            __syncthreads();
        }

        #pragma unroll
        for (int nt = 0; nt < 4; nt++) {
            const int col = nb0 + wn * 32 + nt * 8 + tig * 2;
            const float bv0 = bias[col], bv1 = bias[col + 1];
            float gv0 = 0.0f, gv1 = 0.0f;
            if (EPI == 2) { gv0 = gate[col]; gv1 = gate[col + 1]; }
            #pragma unroll
            for (int mt = 0; mt < 4; mt++) {
                const int row0 = m0 + wm * 64 + mt * 16 + gid;
                #pragma unroll
                for (int hh = 0; hh < 2; hh++) {
                    const int row = row0 + hh * 8;
                    float v0 = c[mt][nt][hh * 2 + 0] + bv0;
                    float v1 = c[mt][nt][hh * 2 + 1] + bv1;
                    if (EPI == 1) { v0 = gelu_tanh(v0); v1 = gelu_tanh(v1); }
                    if (EPI == 2) {
                        const float* Rr = resid + (size_t)row * ldres + col;
                        v0 = Rr[0] + gv0 * v0;
                        v1 = Rr[1] + gv1 * v1;
                    }
                    *(float2*)(C + (size_t)row * ldc + col) = make_float2(v0, v1);
                }
            }
        }
        __syncthreads();
    }
#endif
}

// ---------------------------------------------------------------------------
// Flash attention (unchanged, known good)
// ---------------------------------------------------------------------------
#define FA_SCALE 0.08838834764831845f
#define SQ_PITCH 132
#define SK_PITCH 68
#define SV_PITCH 132
#define SP_PITCH 132
#define SQ_OFF 0
#define SK_OFF (128 * SQ_PITCH)
#define SV_OFF (SK_OFF + 128 * SK_PITCH)
#define SP_OFF (SV_OFF + 64 * SV_PITCH)
#define FA_SMEM_FLOATS (SP_OFF + 64 * SP_PITCH)
#define FA_SMEM_BYTES (FA_SMEM_FLOATS * 4)

__global__ void __launch_bounds__(256, 1)
flash_attn(const float* __restrict__ Q, const float* __restrict__ K,
           const float* __restrict__ V, float* __restrict__ O) {
    extern __shared__ float sm[];
    float* sQ = sm + SQ_OFF;
    float* sK = sm + SK_OFF;
    float* sV = sm + SV_OFF;
    float* sP = sm + SP_OFF;

    const int t = threadIdx.x;
    const int wid = t >> 5, lane = t & 31;
    const int gid = lane >> 2, tig = lane & 3;
    const int h = blockIdx.y;
    const int q0 = blockIdx.x * 128;
    const int m0 = wid * 16;

    const float* Qh = Q + ((size_t)h * LTOT + q0) * HD;
    const float* Kh = K + (size_t)h * LTOT * HD;
    const float* Vh = V + (size_t)h * LTOT * HD;

    {
        int r = t >> 1;
        int dseg = (t & 1) * 64;
        const float* qr = Qh + (size_t)r * HD + dseg;
        #pragma unroll
        for (int i = 0; i < 16; i++) {
            float4 v4 = *(const float4*)(qr + i * 4);
            int d = dseg + i * 4;
            sQ[(d + 0) * SQ_PITCH + r] = to_tf32(v4.x * FA_SCALE);
            sQ[(d + 1) * SQ_PITCH + r] = to_tf32(v4.y * FA_SCALE);
            sQ[(d + 2) * SQ_PITCH + r] = to_tf32(v4.z * FA_SCALE);
            sQ[(d + 3) * SQ_PITCH + r] = to_tf32(v4.w * FA_SCALE);
        }
    }
    __syncthreads();

    unsigned int qf[16][4];
    #pragma unroll
    for (int kt = 0; kt < 16; kt++) {
        int kb = kt * 8;
        qf[kt][0] = __float_as_uint(sQ[(kb + tig)     * SQ_PITCH + m0 + gid]);
        qf[kt][1] = __float_as_uint(sQ[(kb + tig)     * SQ_PITCH + m0 + gid + 8]);
        qf[kt][2] = __float_as_uint(sQ[(kb + tig + 4) * SQ_PITCH + m0 + gid]);
        qf[kt][3] = __float_as_uint(sQ[(kb + tig + 4) * SQ_PITCH + m0 + gid + 8]);
    }

    float co[16][4];
    #pragma unroll
    for (int i = 0; i < 16; i++)
        #pragma unroll
        for (int j = 0; j < 4; j++) co[i][j] = 0.0f;
    float mrow0 = -1e30f, mrow1 = -1e30f, lrow0 = 0.0f, lrow1 = 0.0f;

    for (int kv = 0; kv < LTOT; kv += 64) {
        __syncthreads();
        {
            int c = t >> 2;
            int dseg = (t & 3) * 32;
            const float* kr = Kh + (size_t)(kv + c) * HD + dseg;
            #pragma unroll
            for (int i = 0; i < 8; i++) {
                float4 v4 = *(const float4*)(kr + i * 4);
                int d = dseg + i * 4;
                sK[(d + 0) * SK_PITCH + c] = to_tf32(v4.x);
                sK[(d + 1) * SK_PITCH + c] = to_tf32(v4.y);
                sK[(d + 2) * SK_PITCH + c] = to_tf32(v4.z);
                sK[(d + 3) * SK_PITCH + c] = to_tf32(v4.w);
            }
        }
        {
            int c = t >> 2;
            int dseg = (t & 3) * 32;
            const float* vr = Vh + (size_t)(kv + c) * HD + dseg;
            #pragma unroll
            for (int i = 0; i < 8; i++) {
                float4 v4 = *(const float4*)(vr + i * 4);
                float4 q4 = make_float4(to_tf32(v4.x), to_tf32(v4.y),
                                        to_tf32(v4.z), to_tf32(v4.w));
                *(float4*)(sV + c * SV_PITCH + dseg + i * 4) = q4;
            }
        }
        __syncthreads();

        float cs[8][4];
        #pragma unroll
        for (int i = 0; i < 8; i++)
            #pragma unroll
            for (int j = 0; j < 4; j++) cs[i][j] = 0.0f;
        #pragma unroll
        for (int kt = 0; kt < 16; kt++) {
            int kb = kt * 8;
            #pragma unroll
            for (int nt = 0; nt < 8; nt++) {
                unsigned int bf[2];
                bf[0] = __float_as_uint(sK[(kb + tig)     * SK_PITCH + nt * 8 + gid]);
                bf[1] = __float_as_uint(sK[(kb + tig + 4) * SK_PITCH + nt * 8 + gid]);
                mma_tf32(cs[nt], qf[kt], bf);
            }
        }

        float rmax0 = -1e30f, rmax1 = -1e30f;
        #pragma unroll
        for (int nt = 0; nt < 8; nt++) {
            rmax0 = fmaxf(rmax0, fmaxf(cs[nt][0], cs[nt][1]));
            rmax1 = fmaxf(rmax1, fmaxf(cs[nt][2], cs[nt][3]));
        }
        rmax0 = fmaxf(rmax0, __shfl_xor_sync(0xffffffffu, rmax0, 1));
        rmax0 = fmaxf(rmax0, __shfl_xor_sync(0xffffffffu, rmax0, 2));
        rmax1 = fmaxf(rmax1, __shfl_xor_sync(0xffffffffu, rmax1, 1));
        rmax1 = fmaxf(rmax1, __shfl_xor_sync(0xffffffffu, rmax1, 2));
        float mn0 = fmaxf(mrow0, rmax0);
        float mn1 = fmaxf(mrow1, rmax1);
        float corr0 = __expf(mrow0 - mn0);
        float corr1 = __expf(mrow1 - mn1);
        mrow0 = mn0; mrow1 = mn1;

        float rs0 = 0.0f, rs1 = 0.0f;
        #pragma unroll
        for (int nt = 0; nt < 8; nt++) {
            cs[nt][0] = __expf(cs[nt][0] - mn0);
            cs[nt][1] = __expf(cs[nt][1] - mn0);
            cs[nt][2] = __expf(cs[nt][2] - mn1);
            cs[nt][3] = __expf(cs[nt][3] - mn1);
            rs0 += cs[nt][0] + cs[nt][1];
            rs1 += cs[nt][2] + cs[nt][3];
        }
        rs0 += __shfl_xor_sync(0xffffffffu, rs0, 1);
        rs0 += __shfl_xor_sync(0xffffffffu, rs0, 2);
        rs1 += __shfl_xor_sync(0xffffffffu, rs1, 1);
        rs1 += __shfl_xor_sync(0xffffffffu, rs1, 2);
        lrow0 = lrow0 * corr0 + rs0;
        lrow1 = lrow1 * corr1 + rs1;

        #pragma unroll
        for (int nt = 0; nt < 16; nt++) {
            co[nt][0] *= corr0; co[nt][1] *= corr0;
            co[nt][2] *= corr1; co[nt][3] *= corr1;
        }

        #pragma unroll
        for (int nt = 0; nt < 8; nt++) {
            int cb = nt * 8 + tig * 2;
            sP[(cb + 0) * SP_PITCH + m0 + gid]     = to_tf32(cs[nt][0]);
            sP[(cb + 1) * SP_PITCH + m0 + gid]     = to_tf32(cs[nt][1]);
            sP[(cb + 0) * SP_PITCH + m0 + gid + 8] = to_tf32(cs[nt][2]);
            sP[(cb + 1) * SP_PITCH + m0 + gid + 8] = to_tf32(cs[nt][3]);
        }
        __syncwarp();

        #pragma unroll
        for (int kt = 0; kt < 8; kt++) {
            int kb = kt * 8;
            unsigned int af[4];
            af[0] = __float_as_uint(sP[(kb + tig)     * SP_PITCH + m0 + gid]);
            af[1] = __float_as_uint(sP[(kb + tig)     * SP_PITCH + m0 + gid + 8]);
            af[2] = __float_as_uint(sP[(kb + tig + 4) * SP_PITCH + m0 + gid]);
            af[3] = __float_as_uint(sP[(kb + tig + 4) * SP_PITCH + m0 + gid + 8]);
            #pragma unroll
            for (int nt = 0; nt < 16; nt++) {
                unsigned int bf[2];
                bf[0] = __float_as_uint(sV[(kb + tig)     * SV_PITCH + nt * 8 + gid]);
                bf[1] = __float_as_uint(sV[(kb + tig + 4) * SV_PITCH + nt * 8 + gid]);
                mma_tf32(co[nt], af, bf);
            }
        }
    }

    float inv0 = 1.0f / lrow0;
    float inv1 = 1.0f / lrow1;
    int row0 = q0 + m0 + gid;
    #pragma unroll
    for (int nt = 0; nt < 16; nt++) {
        int col = h * HD + nt * 8 + tig * 2;
        *(float2*)(O + (size_t)row0 * HS + col) =
            make_float2(co[nt][0] * inv0, co[nt][1] * inv0);
        *(float2*)(O + (size_t)(row0 + 8) * HS + col) =
            make_float2(co[nt][2] * inv1, co[nt][3] * inv1);
    }
}

// ---------------------------------------------------------------------------
// Host launcher: merged txt/img GEMM
// ---------------------------------------------------------------------------
static void tc_launch(int epi, const float* A,
                      const float* Bt, const float* Bi,
                      const float* biast, const float* biasi,
                      float* Ct, float* Ci,
                      int N, int K, int lda, int ldb, int ldc,
                      const float* gatet = nullptr, const float* gatei = nullptr,
                      const float* residt = nullptr, const float* residi = nullptr,
                      int ldres = 0) {
    dim3 grid(NMALL * (N / 256));
    if (epi == 0)
        tc_gemm<0><<<grid, 256, TCG_SMEM_BYTES>>>(A, Bt, Bi, biast, biasi, Ct, Ci,
                                                  K, lda, ldb, ldc, gatet, gatei, residt, residi, ldres);
    else if (epi == 1)
        tc_gemm<1><<<grid, 256, TCG_SMEM_BYTES>>>(A, Bt, Bi, biast, biasi, Ct, Ci,
                                                  K, lda, ldb, ldc, gatet, gatei, residt, residi, ldres);
    else
        tc_gemm<2><<<grid, 256, TCG_SMEM_BYTES>>>(A, Bt, Bi, biast, biasi, Ct, Ci,
                                                  K, lda, ldb, ldc, gatet, gatei, residt, residi, ldres);
}

extern "C" void kernel_launch(void* const* d_in, const int* in_sizes, int n_in,
                              void* d_out, int out_size) {
    const float* img        = (const float*)d_in[0];
    const float* txt        = (const float*)d_in[1];
    const float* vec        = (const float*)d_in[2];
    const float* pe         = (const float*)d_in[3];
    const float* img_mod_w  = (const float*)d_in[4];
    const float* img_mod_b  = (const float*)d_in[5];
    const float* img_qkv_w  = (const float*)d_in[6];
    const float* img_qkv_b  = (const float*)d_in[7];
    const float* img_q_s    = (const float*)d_in[8];
    const float* img_k_s    = (const float*)d_in[9];
    const float* img_proj_w = (const float*)d_in[10];
    const float* img_proj_b = (const float*)d_in[11];
    const float* img_mlp_w1 = (const float*)d_in[12];
    const float* img_mlp_b1 = (const float*)d_in[13];
    const float* img_mlp_w2 = (const float*)d_in[14];
    const float* img_mlp_b2 = (const float*)d_in[15];
    const float* txt_mod_w  = (const float*)d_in[16];
    const float* txt_mod_b  = (const float*)d_in[17];
    const float* txt_qkv_w  = (const float*)d_in[18];
    const float* txt_qkv_b  = (const float*)d_in[19];
    const float* txt_q_s    = (const float*)d_in[20];
    const float* txt_k_s    = (const float*)d_in[21];
    const float* txt_proj_w = (const float*)d_in[22];
    const float* txt_proj_b = (const float*)d_in[23];
    const float* txt_mlp_w1 = (const float*)d_in[24];
    const float* txt_mlp_b1 = (const float*)d_in[25];
    const float* txt_mlp_w2 = (const float*)d_in[26];
    const float* txt_mlp_b2 = (const float*)d_in[27];
    float* out = (float*)d_out;

    float *sv, *modi, *modt, *x, *qkvb, *q, *k, *v, *attn, *x1, *x2, *h1;
    cudaGetSymbolAddress((void**)&sv,   g_silu);
    cudaGetSymbolAddress((void**)&modi, g_mod_img);
    cudaGetSymbolAddress((void**)&modt, g_mod_txt);
    cudaGetSymbolAddress((void**)&x,    g_x);
    cudaGetSymbolAddress((void**)&qkvb, g_qkv);
    cudaGetSymbolAddress((void**)&q,    g_q);
    cudaGetSymbolAddress((void**)&k,    g_k);
    cudaGetSymbolAddress((void**)&v,    g_v);
    cudaGetSymbolAddress((void**)&attn, g_attn);
    cudaGetSymbolAddress((void**)&x1,   g_x1);
    cudaGetSymbolAddress((void**)&x2,   g_x2);
    cudaGetSymbolAddress((void**)&h1,   g_h1);

    cudaFuncSetAttribute(flash_attn, cudaFuncAttributeMaxDynamicSharedMemorySize, FA_SMEM_BYTES);
    cudaFuncSetAttribute(tc_gemm<0>, cudaFuncAttributeMaxDynamicSharedMemorySize, TCG_SMEM_BYTES);
    cudaFuncSetAttribute(tc_gemm<1>, cudaFuncAttributeMaxDynamicSharedMemorySize, TCG_SMEM_BYTES);
    cudaFuncSetAttribute(tc_gemm<2>, cudaFuncAttributeMaxDynamicSharedMemorySize, TCG_SMEM_BYTES);

    silu_kernel<<<HS / 256, 256>>>(vec, sv);
    mod_gemv2<<<(6 * HS) / 64, 256>>>(sv, img_mod_w, img_mod_b, modi);
    mod_gemv2<<<(6 * HS) / 64, 256>>>(sv, txt_mod_w, txt_mod_b, modt);

    ln_mod<<<LTXT, 256>>>(txt, x,                     modt + 0 * HS, modt + 1 * HS);
    ln_mod<<<LIMG, 256>>>(img, x + (size_t)LTXT * HS, modi + 0 * HS, modi + 1 * HS);

    // QKV (merged txt/img)
    tc_launch(0, x, txt_qkv_w, img_qkv_w, txt_qkv_b, img_qkv_b,
              qkvb, qkvb, QKVW, HS, HS, QKVW, QKVW);

    rms_rope<<<LTOT, 256>>>(qkvb, pe, txt_q_s, txt_k_s, img_q_s, img_k_s, q, k, v);

    {
        dim3 fgrid(LTOT / 128, NH);
        flash_attn<<<fgrid, 256, FA_SMEM_BYTES>>>(q, k, v, attn);
    }

    // proj + gated residual (merged); img resid rows indexed by m-512
    tc_launch(2, attn, txt_proj_w, img_proj_w, txt_proj_b, img_proj_b,
              x1, x1, HS, HS, HS, HS, HS,
              modt + 2 * HS, modi + 2 * HS,
              txt, img - (size_t)LTXT * HS, HS);

    ln_mod<<<LTXT, 256>>>(x1, x2,                                         modt + 3 * HS, modt + 4 * HS);
    ln_mod<<<LIMG, 256>>>(x1 + (size_t)LTXT * HS, x2 + (size_t)LTXT * HS, modi + 3 * HS, modi + 4 * HS);

    // MLP1 (+GELU, merged)
    tc_launch(1, x2, txt_mlp_w1, img_mlp_w1, txt_mlp_b1, img_mlp_b1,
              h1, h1, MLPD, HS, HS, MLPD, MLPD);

    // MLP2 (+gated residual, merged) -> d_out (img first, then txt)
    tc_launch(2, h1, txt_mlp_w2, img_mlp_w2, txt_mlp_b2, img_mlp_b2,
              out + (size_t)LIMG * HS,            // txt rows m -> out + LIMG*HS + m*HS
              out - (size_t)LTXT * HS,            // img rows m -> out + (m-512)*HS
              HS, MLPD, MLPD, HS, HS,
              modt + 5 * HS, modi + 5 * HS,
              x1, x1, HS);
}

// round 11
// speedup vs baseline: 7.6692x; 1.5738x over previous
#include <cuda_runtime.h>
#include <cuda_bf16.h>
#include <math.h>
#include <stdint.h>

#define HS    3072
#define MLPD  12288
#define NH    24
#define HD    128
#define LTXT  512
#define LIMG  2048
#define LTOT  2560
#define QKVW  9216
#define NMT   4      // txt M-tiles (512/128)
#define NMALL 20     // total M-tiles (2560/128)

#if defined(__CUDA_ARCH__)
#if defined(__CUDA_ARCH_FEAT_SM103_ALL) || \
    (defined(__CUDA_ARCH_SPECIFIC__) && (__CUDA_ARCH_SPECIFIC__ >= 1000))
#define HAS_TCGEN05 1
#else
#define HAS_TCGEN05 0
#endif
#else
#define HAS_TCGEN05 0
#endif

// ---------------------------------------------------------------------------
// Static device scratch
// ---------------------------------------------------------------------------
__device__ float g_silu[HS];
__device__ float g_mod_img[6 * HS];
__device__ float g_mod_txt[6 * HS];
// A-operand buffers: chunk-major tf32 layout [K/32][LTOT][32], pre-swizzled
__device__ __align__(1024) float g_x   [(size_t)LTOT * HS];
__device__ __align__(1024) float g_attn[(size_t)LTOT * HS];
__device__ __align__(1024) float g_x2  [(size_t)LTOT * HS];
__device__ __align__(1024) float g_h1  [(size_t)LTOT * MLPD];
// row-major fp32 buffers
__device__ float g_qkv [(size_t)LTOT * QKVW];
__device__ float g_q   [(size_t)NH * LTOT * HD];
__device__ float g_k   [(size_t)NH * LTOT * HD];
__device__ float g_v   [(size_t)NH * LTOT * HD];
__device__ float g_x1  [(size_t)LTOT * HS];
// converted weights: chunk-major tf32, pre-swizzled [K/32][N][32]
#define OFF_QKV_T  0u
#define OFF_QKV_I  28311552u
#define OFF_PROJ_T 56623104u
#define OFF_PROJ_I 66060288u
#define OFF_MLP1_T 75497472u
#define OFF_MLP1_I 113246208u
#define OFF_MLP2_T 150994944u
#define OFF_MLP2_I 188743680u
__device__ __align__(1024) float g_w[226492416];

// ---------------------------------------------------------------------------
// Helpers
// ---------------------------------------------------------------------------
__device__ __forceinline__ float gelu_tanh(float x) {
    float x3 = x * x * x;
    return 0.5f * x * (1.0f + tanhf(0.7978845608028654f * (x + 0.044715f * x3)));
}
__device__ __forceinline__ float to_tf32(float x) {
    unsigned int u;
    asm("cvt.rna.tf32.f32 %0, %1;" : "=r"(u) : "f"(x));
    return __uint_as_float(u);
}
__device__ __forceinline__ void mma_tf32(float c[4], const unsigned int a[4],
                                         const unsigned int b[2]) {
    asm volatile(
        "mma.sync.aligned.m16n8k8.row.col.f32.tf32.tf32.f32 "
        "{%0,%1,%2,%3}, {%4,%5,%6,%7}, {%8,%9}, {%0,%1,%2,%3};"
        : "+f"(c[0]), "+f"(c[1]), "+f"(c[2]), "+f"(c[3])
        : "r"(a[0]), "r"(a[1]), "r"(a[2]), "r"(a[3]), "r"(b[0]), "r"(b[1]));
}
__device__ __forceinline__ uint32_t smem_u32(const void* p) {
    uint32_t a;
    asm("{ .reg .u64 t; cvta.to.shared.u64 t, %1; cvt.u32.u64 %0, t; }" : "=r"(a) : "l"(p));
    return a;
}
// A/B-operand layout: element (row, k) of a [rows x K] operand, chunk-major +
// per-row SW128 pre-swizzle (16B chunk q -> q ^ (row%8)).
__device__ __forceinline__ size_t aoff(int row, int k, int rows) {
    int q = (k >> 2) & 7;
    return ((size_t)(k >> 5) * rows + row) * 32 + (((q ^ (row & 7)) << 2) + (k & 3));
}

// ---------------------------------------------------------------------------
// Elementwise kernels
// ---------------------------------------------------------------------------
__global__ void silu_kernel(const float* __restrict__ v, float* __restrict__ o) {
    int i = blockIdx.x * 256 + threadIdx.x;
    if (i < HS) { float x = v[i]; o[i] = x / (1.0f + expf(-x)); }
}

__global__ void mod_gemv2(const float* __restrict__ sv, const float* __restrict__ w,
                          const float* __restrict__ b, float* __restrict__ out) {
    __shared__ float ssv[HS];
    __shared__ float red[4][64];
    for (int i = threadIdx.x; i < HS; i += 256) ssv[i] = sv[i];
    __syncthreads();
    const int jl = threadIdx.x & 63, kq = threadIdx.x >> 6;
    const int j = blockIdx.x * 64 + jl;
    const int i0 = kq * (HS / 4);
    float acc = 0.0f;
    #pragma unroll 8
    for (int i = 0; i < HS / 4; i++)
        acc += ssv[i0 + i] * w[(size_t)(i0 + i) * (6 * HS) + j];
    red[kq][jl] = acc;
    __syncthreads();
    if (threadIdx.x < 64) {
        int jj = blockIdx.x * 64 + threadIdx.x;
        out[jj] = red[0][threadIdx.x] + red[1][threadIdx.x] +
                  red[2][threadIdx.x] + red[3][threadIdx.x] + b[jj];
    }
}

// weight conversion: W [K,N] row-major fp32 -> chunk-major tf32 pre-swizzled
__global__ void conv_w(const float* __restrict__ W, float* __restrict__ Wc, int N) {
    const int n = blockIdx.x * 256 + threadIdx.x;
    const int c = blockIdx.y;
    const float* src = W + (size_t)(c * 32) * N + n;
    float* dst = Wc + ((size_t)c * N + n) * 32;
    const int p = (n & 7) << 2;
    #pragma unroll
    for (int j = 0; j < 32; j += 4) {
        float4 v;
        v.x = to_tf32(src[(size_t)(j + 0) * N]);
        v.y = to_tf32(src[(size_t)(j + 1) * N]);
        v.z = to_tf32(src[(size_t)(j + 2) * N]);
        v.w = to_tf32(src[(size_t)(j + 3) * N]);
        *(float4*)(dst + (j ^ p)) = v;
    }
}

// LayerNorm + modulate -> A-layout tf32 output (global row = row0 + blockIdx.x)
__global__ void ln_mod(const float* __restrict__ x, float* __restrict__ dst,
                       const float* __restrict__ shift, const float* __restrict__ scale,
                       int row0) {
    const int row = row0 + blockIdx.x;
    const int t = threadIdx.x;
    const float* xr = x + (size_t)blockIdx.x * HS;
    float v[12];
    float s = 0.0f;
    #pragma unroll
    for (int i = 0; i < 12; i++) { v[i] = xr[t + i * 256]; s += v[i]; }
    __shared__ float red[256];
    red[t] = s; __syncthreads();
    for (int o = 128; o > 0; o >>= 1) { if (t < o) red[t] += red[t + o]; __syncthreads(); }
    float mean = red[0] * (1.0f / HS);
    __syncthreads();
    float s2 = 0.0f;
    #pragma unroll
    for (int i = 0; i < 12; i++) { float d = v[i] - mean; s2 += d * d; }
    red[t] = s2; __syncthreads();
    for (int o = 128; o > 0; o >>= 1) { if (t < o) red[t] += red[t + o]; __syncthreads(); }
    float inv = rsqrtf(red[0] * (1.0f / HS) + 1e-6f);
    #pragma unroll
    for (int i = 0; i < 12; i++) {
        int c = t + i * 256;
        float val = shift[c] + (1.0f + scale[c]) * (v[i] - mean) * inv;
        dst[aoff(row, c, LTOT)] = to_tf32(val);
    }
}

__global__ void rms_rope(const float* __restrict__ qkv, const float* __restrict__ pe,
                         const float* __restrict__ tqs, const float* __restrict__ tks,
                         const float* __restrict__ iqs, const float* __restrict__ iks,
                         float* __restrict__ Q, float* __restrict__ Kp, float* __restrict__ Vp) {
    int l = blockIdx.x;
    int w = threadIdx.x >> 5, lane = threadIdx.x & 31;
    const float* qs = (l < LTXT) ? tqs : iqs;
    const float* ks = (l < LTXT) ? tks : iks;
    const float* row = qkv + (size_t)l * QKVW;
    const float* peb = pe + (size_t)l * 256 + lane * 8;
    float4 p0 = *(const float4*)(peb);
    float4 p1 = *(const float4*)(peb + 4);
    int d0 = lane * 4;
    float4 scq = *(const float4*)(qs + d0);
    float4 sck = *(const float4*)(ks + d0);

    for (int h = w; h < NH; h += 8) {
        float4 xq = *(const float4*)(row + h * HD + d0);
        float ss = xq.x*xq.x + xq.y*xq.y + xq.z*xq.z + xq.w*xq.w;
        #pragma unroll
        for (int o = 16; o > 0; o >>= 1) ss += __shfl_xor_sync(0xffffffffu, ss, o);
        float r = rsqrtf(ss * (1.0f / HD) + 1e-6f);
        float x0 = xq.x * r * scq.x, x1 = xq.y * r * scq.y;
        float x2 = xq.z * r * scq.z, x3 = xq.w * r * scq.w;
        float4 oq;
        oq.x = p0.x * x0 + p0.y * x1;
        oq.y = p0.z * x0 + p0.w * x1;
        oq.z = p1.x * x2 + p1.y * x3;
        oq.w = p1.z * x2 + p1.w * x3;
        *(float4*)(Q + ((size_t)h * LTOT + l) * HD + d0) = oq;
        float4 xk = *(const float4*)(row + HS + h * HD + d0);
        float sk = xk.x*xk.x + xk.y*xk.y + xk.z*xk.z + xk.w*xk.w;
        #pragma unroll
        for (int o = 16; o > 0; o >>= 1) sk += __shfl_xor_sync(0xffffffffu, sk, o);
        float rk = rsqrtf(sk * (1.0f / HD) + 1e-6f);
        float y0 = xk.x * rk * sck.x, y1 = xk.y * rk * sck.y;
        float y2 = xk.z * rk * sck.z, y3 = xk.w * rk * sck.w;
        float4 ok;
        ok.x = p0.x * y0 + p0.y * y1;
        ok.y = p0.z * y0 + p0.w * y1;
        ok.z = p1.x * y2 + p1.y * y3;
        ok.w = p1.z * y2 + p1.w * y3;
        *(float4*)(Kp + ((size_t)h * LTOT + l) * HD + d0) = ok;
        float4 xv = *(const float4*)(row + 2 * HS + h * HD + d0);
        *(float4*)(Vp + ((size_t)h * LTOT + l) * HD + d0) = xv;
    }
}

#define TCG_SMEM_BYTES (1024 + 2 * 49152)

#if HAS_TCGEN05
__device__ __forceinline__ uint32_t elect_one() {
    uint32_t pred;
    asm volatile("{\n\t.reg .pred p;\n\telect.sync _|p, 0xFFFFFFFF;\n\t"
                 "selp.b32 %0, 1, 0, p;\n\t}" : "=r"(pred));
    return pred;
}
__device__ __forceinline__ void mbar_wait(uint32_t mbar, uint32_t parity) {
    asm volatile(
        "{\n\t.reg .pred P1;\n\t"
        "W_%=:\n\t"
        "mbarrier.try_wait.parity.acquire.cta.shared::cta.b64 P1, [%0], %1, 0x989680;\n\t"
        "@P1 bra.uni D_%=;\n\t"
        "bra.uni W_%=;\n\t"
        "D_%=:\n\t}"
        :: "r"(mbar), "r"(parity) : "memory");
}
__device__ __forceinline__ uint64_t make_desc(uint32_t addr) {
    const uint64_t base =
        (uint64_t(2) << 61) | (uint64_t(1) << 46) | (uint64_t(64) << 32) | (uint64_t(1) << 16);
    return base | ((uint64_t)(addr >> 4) & 0x3FFF);
}
__device__ __forceinline__ void tc_mma(uint32_t d, uint64_t ad, uint64_t bd,
                                       uint32_t idesc, uint32_t en) {
    asm volatile(
        "{\n\t.reg .pred p;\n\t"
        "setp.ne.u32 p, %4, 0;\n\t"
        "tcgen05.mma.cta_group::1.kind::tf32 [%0], %1, %2, %3, {%5,%5,%5,%5}, p;\n\t}"
        :: "r"(d), "l"(ad), "l"(bd), "r"(idesc), "r"(en), "r"(0u) : "memory");
}
#define TCG_IDESC ((1u<<4)|(2u<<7)|(2u<<10)|((256u/8)<<17)|((128u/16)<<24))
#define EXPECT_TX(mbar, bytes) \
    asm volatile("mbarrier.arrive.expect_tx.shared.b64 _, [%0], %1;" \
                 :: "r"(mbar), "r"(bytes) : "memory")
#define BULK_CP(dst, src, bytes, mbar) \
    asm volatile("cp.async.bulk.shared::cluster.global.mbarrier::complete_tx::bytes " \
                 "[%0], [%1], %2, [%3];" \
                 :: "r"(dst), "l"(src), "r"(bytes), "r"(mbar) : "memory")
#endif

// ---------------------------------------------------------------------------
// Merged txt/img tf32 GEMM, CTA 128(M)x256(N), chunk-major pre-formatted
// operands, bulk-DMA pipeline (2 stages), TMEM accumulator.
// A: [K/32][lda rows][32] (lda = LTOT). B: [K/32][ldb cols][32].
// EPI: 0 bias row-major out; 1 gelu(bias) -> A-layout tf32 out (rows=LTOT);
//      2 resid + gate*(bias) row-major out.
// ---------------------------------------------------------------------------
template <int EPI>
__global__ void __launch_bounds__(256)
tc_gemm(const float* __restrict__ A,
        const float* __restrict__ Bt, const float* __restrict__ Bi,
        const float* __restrict__ biast, const float* __restrict__ biasi,
        float* __restrict__ Ct, float* __restrict__ Ci,
        int K, int lda, int ldb, int ldc,
        const float* __restrict__ gatet, const float* __restrict__ gatei,
        const float* __restrict__ residt, const float* __restrict__ residi,
        int ldres) {
    extern __shared__ char smem[];
    const int t = threadIdx.x;
    const int wid = t >> 5, lane = t & 31;
    const int mi = blockIdx.x % NMALL;
    const int m0 = mi * 128;
    const int n0 = (blockIdx.x / NMALL) * 256;
    const bool is_txt = (mi < NMT);
    const float* B     = is_txt ? Bt : Bi;
    const float* bias  = is_txt ? biast : biasi;
    const float* gate  = is_txt ? gatet : gatei;
    const float* resid = is_txt ? residt : residi;
    float* C           = is_txt ? Ct : Ci;
    const int nc = K / 32;

#if HAS_TCGEN05
    const uint32_t smem_base = smem_u32(smem);
    const uint32_t sA0 = (smem_base + 64 + 1023) & ~1023u;
    const uint32_t sB0 = sA0 + 16384;
    const uint32_t sA1 = sB0 + 32768;
    const uint32_t sB1 = sA1 + 16384;
    const uint32_t tx0 = smem_base + 16, tx1 = smem_base + 24;
    const uint32_t mm0 = smem_base + 32, mm1 = smem_base + 40;
    const uint32_t dn  = smem_base + 48;
    float* sEp = (float*)(smem + (sA0 - smem_base));

    if (wid == 0) {
        asm volatile("tcgen05.alloc.cta_group::1.sync.aligned.shared::cta.b32 [%0], %1;"
                     :: "r"(smem_base), "r"(256u) : "memory");
        asm volatile("tcgen05.relinquish_alloc_permit.cta_group::1.sync.aligned;");
    }
    if (t == 0) {
        asm volatile("mbarrier.init.shared.b64 [%0], 1;" :: "r"(tx0) : "memory");
        asm volatile("mbarrier.init.shared.b64 [%0], 1;" :: "r"(tx1) : "memory");
        asm volatile("mbarrier.init.shared.b64 [%0], 1;" :: "r"(mm0) : "memory");
        asm volatile("mbarrier.init.shared.b64 [%0], 1;" :: "r"(mm1) : "memory");
        asm volatile("mbarrier.init.shared.b64 [%0], 1;" :: "r"(dn)  : "memory");
    }
    __syncthreads();
    uint32_t tmem;
    asm volatile("ld.shared.b32 %0, [%1];" : "=r"(tmem) : "r"(smem_base));

    if (wid == 0 && elect_one()) {
        const float* Ab = A + (size_t)m0 * 32;
        const float* Bb = B + (size_t)n0 * 32;
        // prologue: chunks 0 and 1
        EXPECT_TX(tx0, 49152u);
        BULK_CP(sA0, Ab, 16384u, tx0);
        BULK_CP(sB0, Bb, 32768u, tx0);
        EXPECT_TX(tx1, 49152u);
        BULK_CP(sA1, Ab + (size_t)lda * 32, 16384u, tx1);
        BULK_CP(sB1, Bb + (size_t)ldb * 32, 32768u, tx1);
        asm volatile("tcgen05.fence::after_thread_sync;" ::: "memory");

        int phtx0 = 0, phtx1 = 0, phmm0 = 0, phmm1 = 0;
        for (int c = 0; c < nc; c++) {
            const int s = c & 1;
            if (s == 0) { mbar_wait(tx0, phtx0); phtx0 ^= 1; }
            else        { mbar_wait(tx1, phtx1); phtx1 ^= 1; }
            uint64_t ad = make_desc(s ? sA1 : sA0);
            uint64_t bd = make_desc(s ? sB1 : sB0);
            #pragma unroll
            for (int ks = 0; ks < 4; ks++)
                tc_mma(tmem, ad + 2 * ks, bd + 2 * ks, TCG_IDESC,
                       (uint32_t)((c > 0) | (ks > 0)));
            asm volatile(
                "tcgen05.commit.cta_group::1.mbarrier::arrive::one.shared::cluster.b64 [%0];"
                :: "r"(s ? mm1 : mm0) : "memory");
            if (c == nc - 1) {
                asm volatile(
                    "tcgen05.commit.cta_group::1.mbarrier::arrive::one.shared::cluster.b64 [%0];"
                    :: "r"(dn) : "memory");
            }
            if (c + 2 < nc) {
                if (s == 0) { mbar_wait(mm0, phmm0); phmm0 ^= 1; }
                else        { mbar_wait(mm1, phmm1); phmm1 ^= 1; }
                const uint32_t txm = s ? tx1 : tx0;
                EXPECT_TX(txm, 49152u);
                BULK_CP(s ? sA1 : sA0, Ab + (size_t)(c + 2) * lda * 32, 16384u, txm);
                BULK_CP(s ? sB1 : sB0, Bb + (size_t)(c + 2) * ldb * 32, 32768u, txm);
            }
        }
    }
    // all threads: wait for the single 'done' commit (no parity aliasing)
    mbar_wait(dn, 0);
    asm volatile("tcgen05.fence::after_thread_sync;" ::: "memory");
    __syncthreads();

    // ---- epilogue: TMEM -> smem bounce (pitch 65) -> coalesced STG ----
    const int half = wid >> 2;
    const int rrow = (wid & 3) * 32 + lane;
    const int f = t & 15, rg = t >> 4;
    for (int cb = 0; cb < 4; cb++) {
        uint32_t r_[32];
        asm volatile(
            "tcgen05.ld.sync.aligned.32x32b.x32.b32 "
            "{%0,%1,%2,%3,%4,%5,%6,%7,%8,%9,%10,%11,%12,%13,%14,%15,"
            "%16,%17,%18,%19,%20,%21,%22,%23,%24,%25,%26,%27,%28,%29,%30,%31}, [%32];"
            : "=r"(r_[0]),"=r"(r_[1]),"=r"(r_[2]),"=r"(r_[3]),
              "=r"(r_[4]),"=r"(r_[5]),"=r"(r_[6]),"=r"(r_[7]),
              "=r"(r_[8]),"=r"(r_[9]),"=r"(r_[10]),"=r"(r_[11]),
              "=r"(r_[12]),"=r"(r_[13]),"=r"(r_[14]),"=r"(r_[15]),
              "=r"(r_[16]),"=r"(r_[17]),"=r"(r_[18]),"=r"(r_[19]),
              "=r"(r_[20]),"=r"(r_[21]),"=r"(r_[22]),"=r"(r_[23]),
              "=r"(r_[24]),"=r"(r_[25]),"=r"(r_[26]),"=r"(r_[27]),
              "=r"(r_[28]),"=r"(r_[29]),"=r"(r_[30]),"=r"(r_[31])
            : "r"(tmem + half * 128 + cb * 32));
        asm volatile("tcgen05.wait::ld.sync.aligned;" ::: "memory");
        #pragma unroll
        for (int j = 0; j < 32; j++)
            sEp[rrow * 65 + half * 32 + j] = __uint_as_float(r_[j]);
        __syncthreads();

        const int scol = (f >> 3) * 32 + (f & 7) * 4;
        const int gcol = n0 + (f >> 3) * 128 + cb * 32 + (f & 7) * 4;
        const float4 bv = *(const float4*)(bias + gcol);
        float4 gv = make_float4(0.f, 0.f, 0.f, 0.f);
        if (EPI == 2) gv = *(const float4*)(gate + gcol);
        #pragma unroll
        for (int i = 0; i < 8; i++) {
            int r = rg + 16 * i;
            int m = m0 + r;
            const float* sp = &sEp[r * 65 + scol];
            float4 v = make_float4(sp[0], sp[1], sp[2], sp[3]);
            v.x += bv.x; v.y += bv.y; v.z += bv.z; v.w += bv.w;
            if (EPI == 1) {
                v.x = gelu_tanh(v.x); v.y = gelu_tanh(v.y);
                v.z = gelu_tanh(v.z); v.w = gelu_tanh(v.w);
                // A-layout tf32 store (rows = LTOT)
                size_t ad2 = ((size_t)(gcol >> 5) * LTOT + m) * 32 +
                             ((((gcol >> 2) & 7) ^ (m & 7)) << 2);
                float4 w = make_float4(to_tf32(v.x), to_tf32(v.y),
                                       to_tf32(v.z), to_tf32(v.w));
                *(float4*)(C + ad2) = w;
            } else {
                if (EPI == 2) {
                    float4 rr = *(const float4*)(resid + (size_t)m * ldres + gcol);
                    v.x = rr.x + gv.x * v.x; v.y = rr.y + gv.y * v.y;
                    v.z = rr.z + gv.z * v.z; v.w = rr.w + gv.w * v.w;
                }
                *(float4*)(C + (size_t)m * ldc + gcol) = v;
            }
        }
        __syncthreads();
    }
    if (wid == 0) {
        asm volatile("tcgen05.dealloc.cta_group::1.sync.aligned.b32 %0, %1;"
                     :: "r"(tmem), "r"(256u));
    }
#else
    // naive fallback (never executed on sm_103a builds; reads same layouts)
    for (int e = t; e < 128 * 256; e += 256) {
        int r = e >> 8, j = e & 255;
        int m = m0 + r, n = n0 + j;
        float acc = 0.f;
        for (int k = 0; k < K; k++) {
            float a = A[((size_t)(k >> 5) * lda + m) * 32 +
                        ((((k >> 2) & 7) ^ (m & 7)) << 2) + (k & 3)];
            float b = B[((size_t)(k >> 5) * ldb + n) * 32 +
                        ((((k >> 2) & 7) ^ (n & 7)) << 2) + (k & 3)];
            acc += a * b;
        }
        acc += bias[n];
        if (EPI == 1) {
            acc = gelu_tanh(acc);
            C[((size_t)(n >> 5) * LTOT + m) * 32 +
              ((((n >> 2) & 7) ^ (m & 7)) << 2) + (n & 3)] = to_tf32(acc);
        } else {
            if (EPI == 2) acc = resid[(size_t)m * ldres + n] + gate[n] * acc;
            C[(size_t)m * ldc + n] = acc;
        }
    }
#endif
}

// ---------------------------------------------------------------------------
// Flash attention (core unchanged; output now A-layout tf32)
// ---------------------------------------------------------------------------
#define FA_SCALE 0.08838834764831845f
#define SQ_PITCH 132
#define SK_PITCH 68
#define SV_PITCH 132
#define SP_PITCH 132
#define SQ_OFF 0
#define SK_OFF (128 * SQ_PITCH)
#define SV_OFF (SK_OFF + 128 * SK_PITCH)
#define SP_OFF (SV_OFF + 64 * SV_PITCH)
#define FA_SMEM_FLOATS (SP_OFF + 64 * SP_PITCH)
#define FA_SMEM_BYTES (FA_SMEM_FLOATS * 4)

__global__ void __launch_bounds__(256, 1)
flash_attn(const float* __restrict__ Q, const float* __restrict__ K,
           const float* __restrict__ V, float* __restrict__ O) {
    extern __shared__ float sm[];
    float* sQ = sm + SQ_OFF;
    float* sK = sm + SK_OFF;
    float* sV = sm + SV_OFF;
    float* sP = sm + SP_OFF;

    const int t = threadIdx.x;
    const int wid = t >> 5, lane = t & 31;
    const int gid = lane >> 2, tig = lane & 3;
    const int h = blockIdx.y;
    const int q0 = blockIdx.x * 128;
    const int m0 = wid * 16;

    const float* Qh = Q + ((size_t)h * LTOT + q0) * HD;
    const float* Kh = K + (size_t)h * LTOT * HD;
    const float* Vh = V + (size_t)h * LTOT * HD;

    {
        int r = t >> 1;
        int dseg = (t & 1) * 64;
        const float* qr = Qh + (size_t)r * HD + dseg;
        #pragma unroll
        for (int i = 0; i < 16; i++) {
            float4 v4 = *(const float4*)(qr + i * 4);
            int d = dseg + i * 4;
            sQ[(d + 0) * SQ_PITCH + r] = to_tf32(v4.x * FA_SCALE);
            sQ[(d + 1) * SQ_PITCH + r] = to_tf32(v4.y * FA_SCALE);
            sQ[(d + 2) * SQ_PITCH + r] = to_tf32(v4.z * FA_SCALE);
            sQ[(d + 3) * SQ_PITCH + r] = to_tf32(v4.w * FA_SCALE);
        }
    }
    __syncthreads();

    unsigned int qf[16][4];
    #pragma unroll
    for (int kt = 0; kt < 16; kt++) {
        int kb = kt * 8;
        qf[kt][0] = __float_as_uint(sQ[(kb + tig)     * SQ_PITCH + m0 + gid]);
        qf[kt][1] = __float_as_uint(sQ[(kb + tig)     * SQ_PITCH + m0 + gid + 8]);
        qf[kt][2] = __float_as_uint(sQ[(kb + tig + 4) * SQ_PITCH + m0 + gid]);
        qf[kt][3] = __float_as_uint(sQ[(kb + tig + 4) * SQ_PITCH + m0 + gid + 8]);
    }

    float co[16][4];
    #pragma unroll
    for (int i = 0; i < 16; i++)
        #pragma unroll
        for (int j = 0; j < 4; j++) co[i][j] = 0.0f;
    float mrow0 = -1e30f, mrow1 = -1e30f, lrow0 = 0.0f, lrow1 = 0.0f;

    for (int kv = 0; kv < LTOT; kv += 64) {
        __syncthreads();
        {
            int c = t >> 2;
            int dseg = (t & 3) * 32;
            const float* kr = Kh + (size_t)(kv + c) * HD + dseg;
            #pragma unroll
            for (int i = 0; i < 8; i++) {
                float4 v4 = *(const float4*)(kr + i * 4);
                int d = dseg + i * 4;
                sK[(d + 0) * SK_PITCH + c] = to_tf32(v4.x);
                sK[(d + 1) * SK_PITCH + c] = to_tf32(v4.y);
                sK[(d + 2) * SK_PITCH + c] = to_tf32(v4.z);
                sK[(d + 3) * SK_PITCH + c] = to_tf32(v4.w);
            }
        }
        {
            int c = t >> 2;
            int dseg = (t & 3) * 32;
            const float* vr = Vh + (size_t)(kv + c) * HD + dseg;
            #pragma unroll
            for (int i = 0; i < 8; i++) {
                float4 v4 = *(const float4*)(vr + i * 4);
                float4 q4 = make_float4(to_tf32(v4.x), to_tf32(v4.y),
                                        to_tf32(v4.z), to_tf32(v4.w));
                *(float4*)(sV + c * SV_PITCH + dseg + i * 4) = q4;
            }
        }
        __syncthreads();

        float cs[8][4];
        #pragma unroll
        for (int i = 0; i < 8; i++)
            #pragma unroll
            for (int j = 0; j < 4; j++) cs[i][j] = 0.0f;
        #pragma unroll
        for (int kt = 0; kt < 16; kt++) {
            int kb = kt * 8;
            #pragma unroll
            for (int nt = 0; nt < 8; nt++) {
                unsigned int bf[2];
                bf[0] = __float_as_uint(sK[(kb + tig)     * SK_PITCH + nt * 8 + gid]);
                bf[1] = __float_as_uint(sK[(kb + tig + 4) * SK_PITCH + nt * 8 + gid]);
                mma_tf32(cs[nt], qf[kt], bf);
            }
        }

        float rmax0 = -1e30f, rmax1 = -1e30f;
        #pragma unroll
        for (int nt = 0; nt < 8; nt++) {
            rmax0 = fmaxf(rmax0, fmaxf(cs[nt][0], cs[nt][1]));
            rmax1 = fmaxf(rmax1, fmaxf(cs[nt][2], cs[nt][3]));
        }
        rmax0 = fmaxf(rmax0, __shfl_xor_sync(0xffffffffu, rmax0, 1));
        rmax0 = fmaxf(rmax0, __shfl_xor_sync(0xffffffffu, rmax0, 2));
        rmax1 = fmaxf(rmax1, __shfl_xor_sync(0xffffffffu, rmax1, 1));
        rmax1 = fmaxf(rmax1, __shfl_xor_sync(0xffffffffu, rmax1, 2));
        float mn0 = fmaxf(mrow0, rmax0);
        float mn1 = fmaxf(mrow1, rmax1);
        float corr0 = __expf(mrow0 - mn0);
        float corr1 = __expf(mrow1 - mn1);
        mrow0 = mn0; mrow1 = mn1;

        float rs0 = 0.0f, rs1 = 0.0f;
        #pragma unroll
        for (int nt = 0; nt < 8; nt++) {
            cs[nt][0] = __expf(cs[nt][0] - mn0);
            cs[nt][1] = __expf(cs[nt][1] - mn0);
            cs[nt][2] = __expf(cs[nt][2] - mn1);
            cs[nt][3] = __expf(cs[nt][3] - mn1);
            rs0 += cs[nt][0] + cs[nt][1];
            rs1 += cs[nt][2] + cs[nt][3];
        }
        rs0 += __shfl_xor_sync(0xffffffffu, rs0, 1);
        rs0 += __shfl_xor_sync(0xffffffffu, rs0, 2);
        rs1 += __shfl_xor_sync(0xffffffffu, rs1, 1);
        rs1 += __shfl_xor_sync(0xffffffffu, rs1, 2);
        lrow0 = lrow0 * corr0 + rs0;
        lrow1 = lrow1 * corr1 + rs1;

        #pragma unroll
        for (int nt = 0; nt < 16; nt++) {
            co[nt][0] *= corr0; co[nt][1] *= corr0;
            co[nt][2] *= corr1; co[nt][3] *= corr1;
        }

        #pragma unroll
        for (int nt = 0; nt < 8; nt++) {
            int cb = nt * 8 + tig * 2;
            sP[(cb + 0) * SP_PITCH + m0 + gid]     = to_tf32(cs[nt][0]);
            sP[(cb + 1) * SP_PITCH + m0 + gid]     = to_tf32(cs[nt][1]);
            sP[(cb + 0) * SP_PITCH + m0 + gid + 8] = to_tf32(cs[nt][2]);
            sP[(cb + 1) * SP_PITCH + m0 + gid + 8] = to_tf32(cs[nt][3]);
        }
        __syncwarp();

        #pragma unroll
        for (int kt = 0; kt < 8; kt++) {
            int kb = kt * 8;
            unsigned int af[4];
            af[0] = __float_as_uint(sP[(kb + tig)     * SP_PITCH + m0 + gid]);
            af[1] = __float_as_uint(sP[(kb + tig)     * SP_PITCH + m0 + gid + 8]);
            af[2] = __float_as_uint(sP[(kb + tig + 4) * SP_PITCH + m0 + gid]);
            af[3] = __float_as_uint(sP[(kb + tig + 4) * SP_PITCH + m0 + gid + 8]);
            #pragma unroll
            for (int nt = 0; nt < 16; nt++) {
                unsigned int bf[2];
                bf[0] = __float_as_uint(sV[(kb + tig)     * SV_PITCH + nt * 8 + gid]);
                bf[1] = __float_as_uint(sV[(kb + tig + 4) * SV_PITCH + nt * 8 + gid]);
                mma_tf32(co[nt], af, bf);
            }
        }
    }

    // epilogue: O /= l, write A-layout tf32 (rows = LTOT)
    float inv0 = 1.0f / lrow0;
    float inv1 = 1.0f / lrow1;
    int ra = q0 + m0 + gid;
    int rb = ra + 8;
    #pragma unroll
    for (int nt = 0; nt < 16; nt++) {
        int col = h * HD + nt * 8 + tig * 2;
        int q = (col >> 2) & 7, e = col & 3;
        size_t base = (size_t)(col >> 5) * LTOT * 32;
        float2 va = make_float2(to_tf32(co[nt][0] * inv0), to_tf32(co[nt][1] * inv0));
        float2 vb = make_float2(to_tf32(co[nt][2] * inv1), to_tf32(co[nt][3] * inv1));
        *(float2*)(O + base + (size_t)ra * 32 + ((q ^ (ra & 7)) << 2) + e) = va;
        *(float2*)(O + base + (size_t)rb * 32 + ((q ^ (rb & 7)) << 2) + e) = vb;
    }
}

// ---------------------------------------------------------------------------
// Host launcher
// ---------------------------------------------------------------------------
static void tc_launch(int epi, const float* A,
                      const float* Bt, const float* Bi,
                      const float* biast, const float* biasi,
                      float* Ct, float* Ci,
                      int N, int K, int lda, int ldb, int ldc,
                      const float* gatet = nullptr, const float* gatei = nullptr,
                      const float* residt = nullptr, const float* residi = nullptr,
                      int ldres = 0) {
    dim3 grid(NMALL * (N / 256));
    if (epi == 0)
        tc_gemm<0><<<grid, 256, TCG_SMEM_BYTES>>>(A, Bt, Bi, biast, biasi, Ct, Ci,
                                                  K, lda, ldb, ldc, gatet, gatei, residt, residi, ldres);
    else if (epi == 1)
        tc_gemm<1><<<grid, 256, TCG_SMEM_BYTES>>>(A, Bt, Bi, biast, biasi, Ct, Ci,
                                                  K, lda, ldb, ldc, gatet, gatei, residt, residi, ldres);
    else
        tc_gemm<2><<<grid, 256, TCG_SMEM_BYTES>>>(A, Bt, Bi, biast, biasi, Ct, Ci,
                                                  K, lda, ldb, ldc, gatet, gatei, residt, residi, ldres);
}

extern "C" void kernel_launch(void* const* d_in, const int* in_sizes, int n_in,
                              void* d_out, int out_size) {
    const float* img        = (const float*)d_in[0];
    const float* txt        = (const float*)d_in[1];
    const float* vec        = (const float*)d_in[2];
    const float* pe         = (const float*)d_in[3];
    const float* img_mod_w  = (const float*)d_in[4];
    const float* img_mod_b  = (const float*)d_in[5];
    const float* img_qkv_w  = (const float*)d_in[6];
    const float* img_qkv_b  = (const float*)d_in[7];
    const float* img_q_s    = (const float*)d_in[8];
    const float* img_k_s    = (const float*)d_in[9];
    const float* img_proj_w = (const float*)d_in[10];
    const float* img_proj_b = (const float*)d_in[11];
    const float* img_mlp_w1 = (const float*)d_in[12];
    const float* img_mlp_b1 = (const float*)d_in[13];
    const float* img_mlp_w2 = (const float*)d_in[14];
    const float* img_mlp_b2 = (const float*)d_in[15];
    const float* txt_mod_w  = (const float*)d_in[16];
    const float* txt_mod_b  = (const float*)d_in[17];
    const float* txt_qkv_w  = (const float*)d_in[18];
    const float* txt_qkv_b  = (const float*)d_in[19];
    const float* txt_q_s    = (const float*)d_in[20];
    const float* txt_k_s    = (const float*)d_in[21];
    const float* txt_proj_w = (const float*)d_in[22];
    const float* txt_proj_b = (const float*)d_in[23];
    const float* txt_mlp_w1 = (const float*)d_in[24];
    const float* txt_mlp_b1 = (const float*)d_in[25];
    const float* txt_mlp_w2 = (const float*)d_in[26];
    const float* txt_mlp_b2 = (const float*)d_in[27];
    float* out = (float*)d_out;

    float *sv, *modi, *modt, *x, *qkvb, *q, *k, *v, *attn, *x1, *x2, *h1, *w;
    cudaGetSymbolAddress((void**)&sv,   g_silu);
    cudaGetSymbolAddress((void**)&modi, g_mod_img);
    cudaGetSymbolAddress((void**)&modt, g_mod_txt);
    cudaGetSymbolAddress((void**)&x,    g_x);
    cudaGetSymbolAddress((void**)&qkvb, g_qkv);
    cudaGetSymbolAddress((void**)&q,    g_q);
    cudaGetSymbolAddress((void**)&k,    g_k);
    cudaGetSymbolAddress((void**)&v,    g_v);
    cudaGetSymbolAddress((void**)&attn, g_attn);
    cudaGetSymbolAddress((void**)&x1,   g_x1);
    cudaGetSymbolAddress((void**)&x2,   g_x2);
    cudaGetSymbolAddress((void**)&h1,   g_h1);
    cudaGetSymbolAddress((void**)&w,    g_w);

    cudaFuncSetAttribute(flash_attn, cudaFuncAttributeMaxDynamicSharedMemorySize, FA_SMEM_BYTES);
    cudaFuncSetAttribute(tc_gemm<0>, cudaFuncAttributeMaxDynamicSharedMemorySize, TCG_SMEM_BYTES);
    cudaFuncSetAttribute(tc_gemm<1>, cudaFuncAttributeMaxDynamicSharedMemorySize, TCG_SMEM_BYTES);
    cudaFuncSetAttribute(tc_gemm<2>, cudaFuncAttributeMaxDynamicSharedMemorySize, TCG_SMEM_BYTES);

    // weight conversion (chunk-major tf32, pre-swizzled)
    conv_w<<<dim3(QKVW / 256, HS / 32),  256>>>(txt_qkv_w,  w + OFF_QKV_T,  QKVW);
    conv_w<<<dim3(QKVW / 256, HS / 32),  256>>>(img_qkv_w,  w + OFF_QKV_I,  QKVW);
    conv_w<<<dim3(HS / 256,   HS / 32),  256>>>(txt_proj_w, w + OFF_PROJ_T, HS);
    conv_w<<<dim3(HS / 256,   HS / 32),  256>>>(img_proj_w, w + OFF_PROJ_I, HS);
    conv_w<<<dim3(MLPD / 256, HS / 32),  256>>>(txt_mlp_w1, w + OFF_MLP1_T, MLPD);
    conv_w<<<dim3(MLPD / 256, HS / 32),  256>>>(img_mlp_w1, w + OFF_MLP1_I, MLPD);
    conv_w<<<dim3(HS / 256,   MLPD / 32),256>>>(txt_mlp_w2, w + OFF_MLP2_T, HS);
    conv_w<<<dim3(HS / 256,   MLPD / 32),256>>>(img_mlp_w2, w + OFF_MLP2_I, HS);

    silu_kernel<<<HS / 256, 256>>>(vec, sv);
    mod_gemv2<<<(6 * HS) / 64, 256>>>(sv, img_mod_w, img_mod_b, modi);
    mod_gemv2<<<(6 * HS) / 64, 256>>>(sv, txt_mod_w, txt_mod_b, modt);

    ln_mod<<<LTXT, 256>>>(txt, x, modt + 0 * HS, modt + 1 * HS, 0);
    ln_mod<<<LIMG, 256>>>(img, x, modi + 0 * HS, modi + 1 * HS, LTXT);

    // QKV (merged txt/img) -> row-major qkvb
    tc_launch(0, x, w + OFF_QKV_T, w + OFF_QKV_I, txt_qkv_b, img_qkv_b,
              qkvb, qkvb, QKVW, HS, LTOT, QKVW, QKVW);

    rms_rope<<<LTOT, 256>>>(qkvb, pe, txt_q_s, txt_k_s, img_q_s, img_k_s, q, k, v);

    {
        dim3 fgrid(LTOT / 128, NH);
        flash_attn<<<fgrid, 256, FA_SMEM_BYTES>>>(q, k, v, attn);
    }

    // proj + gated residual (merged) -> row-major x1
    tc_launch(2, attn, w + OFF_PROJ_T, w + OFF_PROJ_I, txt_proj_b, img_proj_b,
              x1, x1, HS, HS, LTOT, HS, HS,
              modt + 2 * HS, modi + 2 * HS,
              txt, img - (size_t)LTXT * HS, HS);

    ln_mod<<<LTXT, 256>>>(x1, x2,                     modt + 3 * HS, modt + 4 * HS, 0);
    ln_mod<<<LIMG, 256>>>(x1 + (size_t)LTXT * HS, x2, modi + 3 * HS, modi + 4 * HS, LTXT);

    // MLP1 (+GELU, merged) -> A-layout h1
    tc_launch(1, x2, w + OFF_MLP1_T, w + OFF_MLP1_I, txt_mlp_b1, img_mlp_b1,
              h1, h1, MLPD, HS, LTOT, MLPD, MLPD);

    // MLP2 (+gated residual, merged) -> d_out (img first, then txt)
    tc_launch(2, h1, w + OFF_MLP2_T, w + OFF_MLP2_I, txt_mlp_b2, img_mlp_b2,
              out + (size_t)LIMG * HS,
              out - (size_t)LTXT * HS,
              HS, MLPD, LTOT, HS, HS,
              modt + 5 * HS, modi + 5 * HS,
              x1, x1, HS);
}

// round 12
// speedup vs baseline: 9.1529x; 1.1935x over previous
#include <cuda_runtime.h>
#include <cuda_bf16.h>
#include <cuda_fp16.h>
#include <math.h>
#include <stdint.h>

#define HS    3072
#define MLPD  12288
#define NH    24
#define HD    128
#define LTXT  512
#define LIMG  2048
#define LTOT  2560
#define QKVW  9216
#define NMT   4
#define NMALL 20

#if defined(__CUDA_ARCH__)
#if defined(__CUDA_ARCH_FEAT_SM103_ALL) || \
    (defined(__CUDA_ARCH_SPECIFIC__) && (__CUDA_ARCH_SPECIFIC__ >= 1000))
#define HAS_TCGEN05 1
#else
#define HAS_TCGEN05 0
#endif
#else
#define HAS_TCGEN05 0
#endif

// ---------------------------------------------------------------------------
// Static device scratch
// ---------------------------------------------------------------------------
__device__ float g_silu[HS];
__device__ float g_mod_img[6 * HS];
__device__ float g_mod_txt[6 * HS];
// A-operand buffers: chunk-major fp16 layout [K/64][LTOT][64], pre-swizzled
__device__ __align__(1024) __half g_x   [(size_t)LTOT * HS];
__device__ __align__(1024) __half g_attn[(size_t)LTOT * HS];
__device__ __align__(1024) __half g_x2  [(size_t)LTOT * HS];
__device__ __align__(1024) __half g_h1  [(size_t)LTOT * MLPD];
// row-major fp32 buffers
__device__ float g_qkv [(size_t)LTOT * QKVW];
__device__ float g_q   [(size_t)NH * LTOT * HD];
__device__ float g_k   [(size_t)NH * LTOT * HD];
__device__ float g_v   [(size_t)NH * LTOT * HD];
__device__ float g_x1  [(size_t)LTOT * HS];
// converted weights: chunk-major fp16, pre-swizzled [K/64][N][64]
#define OFF_QKV_T  0u
#define OFF_QKV_I  28311552u
#define OFF_PROJ_T 56623104u
#define OFF_PROJ_I 66060288u
#define OFF_MLP1_T 75497472u
#define OFF_MLP1_I 113246208u
#define OFF_MLP2_T 150994944u
#define OFF_MLP2_I 188743680u
__device__ __align__(1024) __half g_w[226492416];

// ---------------------------------------------------------------------------
// Helpers
// ---------------------------------------------------------------------------
__device__ __forceinline__ float gelu_tanh(float x) {
    float x3 = x * x * x;
    return 0.5f * x * (1.0f + tanhf(0.7978845608028654f * (x + 0.044715f * x3)));
}
__device__ __forceinline__ float to_tf32(float x) {
    unsigned int u;
    asm("cvt.rna.tf32.f32 %0, %1;" : "=r"(u) : "f"(x));
    return __uint_as_float(u);
}
__device__ __forceinline__ void mma_tf32(float c[4], const unsigned int a[4],
                                         const unsigned int b[2]) {
    asm volatile(
        "mma.sync.aligned.m16n8k8.row.col.f32.tf32.tf32.f32 "
        "{%0,%1,%2,%3}, {%4,%5,%6,%7}, {%8,%9}, {%0,%1,%2,%3};"
        : "+f"(c[0]), "+f"(c[1]), "+f"(c[2]), "+f"(c[3])
        : "r"(a[0]), "r"(a[1]), "r"(a[2]), "r"(a[3]), "r"(b[0]), "r"(b[1]));
}
__device__ __forceinline__ uint32_t smem_u32(const void* p) {
    uint32_t a;
    asm("{ .reg .u64 t; cvta.to.shared.u64 t, %1; cvt.u32.u64 %0, t; }" : "=r"(a) : "l"(p));
    return a;
}
// fp16 operand layout: element (row, k), chunk-major [K/64][rows][64] with
// SW128 pre-swizzle on 16B units (8 halves): q = (k>>3)&7, q ^= row&7.
__device__ __forceinline__ size_t aoff16(int row, int k, int rows) {
    int q = (k >> 3) & 7;
    return ((size_t)(k >> 6) * rows + row) * 64 + (((q ^ (row & 7)) << 3) + (k & 7));
}

// ---------------------------------------------------------------------------
// Elementwise kernels
// ---------------------------------------------------------------------------
__global__ void silu_kernel(const float* __restrict__ v, float* __restrict__ o) {
    int i = blockIdx.x * 256 + threadIdx.x;
    if (i < HS) { float x = v[i]; o[i] = x / (1.0f + expf(-x)); }
}

__global__ void mod_gemv2(const float* __restrict__ sv, const float* __restrict__ w,
                          const float* __restrict__ b, float* __restrict__ out) {
    __shared__ float ssv[HS];
    __shared__ float red[4][64];
    for (int i = threadIdx.x; i < HS; i += 256) ssv[i] = sv[i];
    __syncthreads();
    const int jl = threadIdx.x & 63, kq = threadIdx.x >> 6;
    const int j = blockIdx.x * 64 + jl;
    const int i0 = kq * (HS / 4);
    float acc = 0.0f;
    #pragma unroll 8
    for (int i = 0; i < HS / 4; i++)
        acc += ssv[i0 + i] * w[(size_t)(i0 + i) * (6 * HS) + j];
    red[kq][jl] = acc;
    __syncthreads();
    if (threadIdx.x < 64) {
        int jj = blockIdx.x * 64 + threadIdx.x;
        out[jj] = red[0][threadIdx.x] + red[1][threadIdx.x] +
                  red[2][threadIdx.x] + red[3][threadIdx.x] + b[jj];
    }
}

// weight conversion: W [K,N] row-major fp32 -> chunk-major fp16 pre-swizzled
__global__ void conv_w(const float* __restrict__ W, __half* __restrict__ Wc, int N) {
    const int n = blockIdx.x * 256 + threadIdx.x;
    const int c = blockIdx.y;
    const float* src = W + (size_t)(c * 64) * N + n;
    __half* dst = Wc + ((size_t)c * N + n) * 64;
    const int p = n & 7;
    #pragma unroll
    for (int j = 0; j < 64; j += 8) {
        __half2 h0 = __floats2half2_rn(src[(size_t)(j + 0) * N], src[(size_t)(j + 1) * N]);
        __half2 h1 = __floats2half2_rn(src[(size_t)(j + 2) * N], src[(size_t)(j + 3) * N]);
        __half2 h2 = __floats2half2_rn(src[(size_t)(j + 4) * N], src[(size_t)(j + 5) * N]);
        __half2 h3 = __floats2half2_rn(src[(size_t)(j + 6) * N], src[(size_t)(j + 7) * N]);
        uint4 v = make_uint4(*(unsigned int*)&h0, *(unsigned int*)&h1,
                             *(unsigned int*)&h2, *(unsigned int*)&h3);
        *(uint4*)(dst + (((j >> 3) ^ p) << 3)) = v;
    }
}

// LayerNorm + modulate -> fp16 A-layout output (global row = row0 + blockIdx.x)
__global__ void ln_mod(const float* __restrict__ x, __half* __restrict__ dst,
                       const float* __restrict__ shift, const float* __restrict__ scale,
                       int row0) {
    const int row = row0 + blockIdx.x;
    const int t = threadIdx.x;
    const float* xr = x + (size_t)blockIdx.x * HS;
    float v[12];
    float s = 0.0f;
    #pragma unroll
    for (int i = 0; i < 12; i++) { v[i] = xr[t + i * 256]; s += v[i]; }
    __shared__ float red[256];
    red[t] = s; __syncthreads();
    for (int o = 128; o > 0; o >>= 1) { if (t < o) red[t] += red[t + o]; __syncthreads(); }
    float mean = red[0] * (1.0f / HS);
    __syncthreads();
    float s2 = 0.0f;
    #pragma unroll
    for (int i = 0; i < 12; i++) { float d = v[i] - mean; s2 += d * d; }
    red[t] = s2; __syncthreads();
    for (int o = 128; o > 0; o >>= 1) { if (t < o) red[t] += red[t + o]; __syncthreads(); }
    float inv = rsqrtf(red[0] * (1.0f / HS) + 1e-6f);
    #pragma unroll
    for (int i = 0; i < 12; i++) {
        int c = t + i * 256;
        float val = shift[c] + (1.0f + scale[c]) * (v[i] - mean) * inv;
        dst[aoff16(row, c, LTOT)] = __float2half_rn(val);
    }
}

__global__ void rms_rope(const float* __restrict__ qkv, const float* __restrict__ pe,
                         const float* __restrict__ tqs, const float* __restrict__ tks,
                         const float* __restrict__ iqs, const float* __restrict__ iks,
                         float* __restrict__ Q, float* __restrict__ Kp, float* __restrict__ Vp) {
    int l = blockIdx.x;
    int w = threadIdx.x >> 5, lane = threadIdx.x & 31;
    const float* qs = (l < LTXT) ? tqs : iqs;
    const float* ks = (l < LTXT) ? tks : iks;
    const float* row = qkv + (size_t)l * QKVW;
    const float* peb = pe + (size_t)l * 256 + lane * 8;
    float4 p0 = *(const float4*)(peb);
    float4 p1 = *(const float4*)(peb + 4);
    int d0 = lane * 4;
    float4 scq = *(const float4*)(qs + d0);
    float4 sck = *(const float4*)(ks + d0);

    for (int h = w; h < NH; h += 8) {
        float4 xq = *(const float4*)(row + h * HD + d0);
        float ss = xq.x*xq.x + xq.y*xq.y + xq.z*xq.z + xq.w*xq.w;
        #pragma unroll
        for (int o = 16; o > 0; o >>= 1) ss += __shfl_xor_sync(0xffffffffu, ss, o);
        float r = rsqrtf(ss * (1.0f / HD) + 1e-6f);
        float x0 = xq.x * r * scq.x, x1 = xq.y * r * scq.y;
        float x2 = xq.z * r * scq.z, x3 = xq.w * r * scq.w;
        float4 oq;
        oq.x = p0.x * x0 + p0.y * x1;
        oq.y = p0.z * x0 + p0.w * x1;
        oq.z = p1.x * x2 + p1.y * x3;
        oq.w = p1.z * x2 + p1.w * x3;
        *(float4*)(Q + ((size_t)h * LTOT + l) * HD + d0) = oq;
        float4 xk = *(const float4*)(row + HS + h * HD + d0);
        float sk = xk.x*xk.x + xk.y*xk.y + xk.z*xk.z + xk.w*xk.w;
        #pragma unroll
        for (int o = 16; o > 0; o >>= 1) sk += __shfl_xor_sync(0xffffffffu, sk, o);
        float rk = rsqrtf(sk * (1.0f / HD) + 1e-6f);
        float y0 = xk.x * rk * sck.x, y1 = xk.y * rk * sck.y;
        float y2 = xk.z * rk * sck.z, y3 = xk.w * rk * sck.w;
        float4 ok;
        ok.x = p0.x * y0 + p0.y * y1;
        ok.y = p0.z * y0 + p0.w * y1;
        ok.z = p1.x * y2 + p1.y * y3;
        ok.w = p1.z * y2 + p1.w * y3;
        *(float4*)(Kp + ((size_t)h * LTOT + l) * HD + d0) = ok;
        float4 xv = *(const float4*)(row + 2 * HS + h * HD + d0);
        *(float4*)(Vp + ((size_t)h * LTOT + l) * HD + d0) = xv;
    }
}

#define TCG_SMEM_BYTES (1024 + 2 * 49152)

#if HAS_TCGEN05
__device__ __forceinline__ uint32_t elect_one() {
    uint32_t pred;
    asm volatile("{\n\t.reg .pred p;\n\telect.sync _|p, 0xFFFFFFFF;\n\t"
                 "selp.b32 %0, 1, 0, p;\n\t}" : "=r"(pred));
    return pred;
}
__device__ __forceinline__ void mbar_wait(uint32_t mbar, uint32_t parity) {
    asm volatile(
        "{\n\t.reg .pred P1;\n\t"
        "W_%=:\n\t"
        "mbarrier.try_wait.parity.acquire.cta.shared::cta.b64 P1, [%0], %1, 0x989680;\n\t"
        "@P1 bra.uni D_%=;\n\t"
        "bra.uni W_%=;\n\t"
        "D_%=:\n\t}"
        :: "r"(mbar), "r"(parity) : "memory");
}
__device__ __forceinline__ uint64_t make_desc(uint32_t addr) {
    const uint64_t base =
        (uint64_t(2) << 61) | (uint64_t(1) << 46) | (uint64_t(64) << 32) | (uint64_t(1) << 16);
    return base | ((uint64_t)(addr >> 4) & 0x3FFF);
}
// kind::f16 MMA (fp16 inputs, fp32 accum), K=16 per dispatch
__device__ __forceinline__ void tc_mma_f16(uint32_t d, uint64_t ad, uint64_t bd,
                                           uint32_t idesc, uint32_t en) {
    asm volatile(
        "{\n\t.reg .pred p;\n\t"
        "setp.ne.u32 p, %4, 0;\n\t"
        "tcgen05.mma.cta_group::1.kind::f16 [%0], %1, %2, %3, {%5,%5,%5,%5}, p;\n\t}"
        :: "r"(d), "l"(ad), "l"(bd), "r"(idesc), "r"(en), "r"(0u) : "memory");
}
// dtype=F32(1)<<4, atype=btype=F16(0), N/8<<17, M/16<<24
#define TCG_IDESC ((1u<<4)|((256u/8)<<17)|((128u/16)<<24))
#define EXPECT_TX(mbar, bytes) \
    asm volatile("mbarrier.arrive.expect_tx.shared.b64 _, [%0], %1;" \
                 :: "r"(mbar), "r"(bytes) : "memory")
#define BULK_CP(dst, src, bytes, mbar) \
    asm volatile("cp.async.bulk.shared::cluster.global.mbarrier::complete_tx::bytes " \
                 "[%0], [%1], %2, [%3];" \
                 :: "r"(dst), "l"(src), "r"(bytes), "r"(mbar) : "memory")
#endif

// ---------------------------------------------------------------------------
// Merged txt/img fp16 GEMM, CTA 128(M)x256(N), chunk-major pre-formatted
// operands (64-k chunks), bulk-DMA pipeline (2 stages), TMEM accumulator.
// A: [K/64][lda rows][64] halves. B: [K/64][ldb cols][64] halves.
// EPI: 0 bias -> row-major fp32; 1 gelu(bias) -> fp16 A-layout (rows=LTOT);
//      2 resid + gate*(bias) -> row-major fp32.
// ---------------------------------------------------------------------------
template <int EPI>
__global__ void __launch_bounds__(256)
tc_gemm(const __half* __restrict__ A,
        const __half* __restrict__ Bt, const __half* __restrict__ Bi,
        const float* __restrict__ biast, const float* __restrict__ biasi,
        float* __restrict__ Ct, float* __restrict__ Ci, __half* __restrict__ Ch,
        int K, int lda, int ldb, int ldc,
        const float* __restrict__ gatet, const float* __restrict__ gatei,
        const float* __restrict__ residt, const float* __restrict__ residi,
        int ldres) {
    extern __shared__ char smem[];
    const int t = threadIdx.x;
    const int wid = t >> 5, lane = t & 31;
    const int mi = blockIdx.x % NMALL;
    const int m0 = mi * 128;
    const int n0 = (blockIdx.x / NMALL) * 256;
    const bool is_txt = (mi < NMT);
    const __half* B    = is_txt ? Bt : Bi;
    const float* bias  = is_txt ? biast : biasi;
    const float* gate  = is_txt ? gatet : gatei;
    const float* resid = is_txt ? residt : residi;
    float* C           = is_txt ? Ct : Ci;
    const int nc = K / 64;

#if HAS_TCGEN05
    const uint32_t smem_base = smem_u32(smem);
    const uint32_t sA0 = (smem_base + 64 + 1023) & ~1023u;
    const uint32_t sB0 = sA0 + 16384;
    const uint32_t sA1 = sB0 + 32768;
    const uint32_t sB1 = sA1 + 16384;
    const uint32_t tx0 = smem_base + 16, tx1 = smem_base + 24;
    const uint32_t mm0 = smem_base + 32, mm1 = smem_base + 40;
    const uint32_t dn  = smem_base + 48;
    float* sEp = (float*)(smem + (sA0 - smem_base));

    if (wid == 0) {
        asm volatile("tcgen05.alloc.cta_group::1.sync.aligned.shared::cta.b32 [%0], %1;"
                     :: "r"(smem_base), "r"(256u) : "memory");
        asm volatile("tcgen05.relinquish_alloc_permit.cta_group::1.sync.aligned;");
    }
    if (t == 0) {
        asm volatile("mbarrier.init.shared.b64 [%0], 1;" :: "r"(tx0) : "memory");
        asm volatile("mbarrier.init.shared.b64 [%0], 1;" :: "r"(tx1) : "memory");
        asm volatile("mbarrier.init.shared.b64 [%0], 1;" :: "r"(mm0) : "memory");
        asm volatile("mbarrier.init.shared.b64 [%0], 1;" :: "r"(mm1) : "memory");
        asm volatile("mbarrier.init.shared.b64 [%0], 1;" :: "r"(dn)  : "memory");
    }
    __syncthreads();
    uint32_t tmem;
    asm volatile("ld.shared.b32 %0, [%1];" : "=r"(tmem) : "r"(smem_base));

    if (wid == 0 && elect_one()) {
        const __half* Ab = A + (size_t)m0 * 64;
        const __half* Bb = B + (size_t)n0 * 64;
        EXPECT_TX(tx0, 49152u);
        BULK_CP(sA0, Ab, 16384u, tx0);
        BULK_CP(sB0, Bb, 32768u, tx0);
        EXPECT_TX(tx1, 49152u);
        BULK_CP(sA1, Ab + (size_t)lda * 64, 16384u, tx1);
        BULK_CP(sB1, Bb + (size_t)ldb * 64, 32768u, tx1);
        asm volatile("tcgen05.fence::after_thread_sync;" ::: "memory");

        int phtx0 = 0, phtx1 = 0, phmm0 = 0, phmm1 = 0;
        for (int c = 0; c < nc; c++) {
            const int s = c & 1;
            if (s == 0) { mbar_wait(tx0, phtx0); phtx0 ^= 1; }
            else        { mbar_wait(tx1, phtx1); phtx1 ^= 1; }
            uint64_t ad = make_desc(s ? sA1 : sA0);
            uint64_t bd = make_desc(s ? sB1 : sB0);
            #pragma unroll
            for (int ks = 0; ks < 4; ks++)   // 4 x K=16 = 64
                tc_mma_f16(tmem, ad + 2 * ks, bd + 2 * ks, TCG_IDESC,
                           (uint32_t)((c > 0) | (ks > 0)));
            asm volatile(
                "tcgen05.commit.cta_group::1.mbarrier::arrive::one.shared::cluster.b64 [%0];"
                :: "r"(s ? mm1 : mm0) : "memory");
            if (c == nc - 1) {
                asm volatile(
                    "tcgen05.commit.cta_group::1.mbarrier::arrive::one.shared::cluster.b64 [%0];"
                    :: "r"(dn) : "memory");
            }
            if (c + 2 < nc) {
                if (s == 0) { mbar_wait(mm0, phmm0); phmm0 ^= 1; }
                else        { mbar_wait(mm1, phmm1); phmm1 ^= 1; }
                const uint32_t txm = s ? tx1 : tx0;
                EXPECT_TX(txm, 49152u);
                BULK_CP(s ? sA1 : sA0, Ab + (size_t)(c + 2) * lda * 64, 16384u, txm);
                BULK_CP(s ? sB1 : sB0, Bb + (size_t)(c + 2) * ldb * 64, 32768u, txm);
            }
        }
    }
    mbar_wait(dn, 0);
    asm volatile("tcgen05.fence::after_thread_sync;" ::: "memory");
    __syncthreads();

    // ---- epilogue: TMEM -> smem bounce (pitch 65) -> coalesced stores ----
    const int half = wid >> 2;
    const int rrow = (wid & 3) * 32 + lane;
    const int f = t & 15, rg = t >> 4;
    for (int cb = 0; cb < 4; cb++) {
        uint32_t r_[32];
        asm volatile(
            "tcgen05.ld.sync.aligned.32x32b.x32.b32 "
            "{%0,%1,%2,%3,%4,%5,%6,%7,%8,%9,%10,%11,%12,%13,%14,%15,"
            "%16,%17,%18,%19,%20,%21,%22,%23,%24,%25,%26,%27,%28,%29,%30,%31}, [%32];"
            : "=r"(r_[0]),"=r"(r_[1]),"=r"(r_[2]),"=r"(r_[3]),
              "=r"(r_[4]),"=r"(r_[5]),"=r"(r_[6]),"=r"(r_[7]),
              "=r"(r_[8]),"=r"(r_[9]),"=r"(r_[10]),"=r"(r_[11]),
              "=r"(r_[12]),"=r"(r_[13]),"=r"(r_[14]),"=r"(r_[15]),
              "=r"(r_[16]),"=r"(r_[17]),"=r"(r_[18]),"=r"(r_[19]),
              "=r"(r_[20]),"=r"(r_[21]),"=r"(r_[22]),"=r"(r_[23]),
              "=r"(r_[24]),"=r"(r_[25]),"=r"(r_[26]),"=r"(r_[27]),
              "=r"(r_[28]),"=r"(r_[29]),"=r"(r_[30]),"=r"(r_[31])
            : "r"(tmem + half * 128 + cb * 32));
        asm volatile("tcgen05.wait::ld.sync.aligned;" ::: "memory");
        #pragma unroll
        for (int j = 0; j < 32; j++)
            sEp[rrow * 65 + half * 32 + j] = __uint_as_float(r_[j]);
        __syncthreads();

        const int scol = (f >> 3) * 32 + (f & 7) * 4;
        const int gcol = n0 + (f >> 3) * 128 + cb * 32 + (f & 7) * 4;
        const float4 bv = *(const float4*)(bias + gcol);
        float4 gv = make_float4(0.f, 0.f, 0.f, 0.f);
        if (EPI == 2) gv = *(const float4*)(gate + gcol);
        #pragma unroll
        for (int i = 0; i < 8; i++) {
            int r = rg + 16 * i;
            int m = m0 + r;
            const float* sp = &sEp[r * 65 + scol];
            float4 v = make_float4(sp[0], sp[1], sp[2], sp[3]);
            v.x += bv.x; v.y += bv.y; v.z += bv.z; v.w += bv.w;
            if (EPI == 1) {
                v.x = gelu_tanh(v.x); v.y = gelu_tanh(v.y);
                v.z = gelu_tanh(v.z); v.w = gelu_tanh(v.w);
                size_t ad2 = ((size_t)(gcol >> 6) * LTOT + m) * 64 +
                             (((((gcol >> 3) & 7) ^ (m & 7)) << 3) + (gcol & 7));
                __half2 ha = __floats2half2_rn(v.x, v.y);
                __half2 hb = __floats2half2_rn(v.z, v.w);
                *(uint2*)(Ch + ad2) = make_uint2(*(unsigned int*)&ha, *(unsigned int*)&hb);
            } else {
                if (EPI == 2) {
                    float4 rr = *(const float4*)(resid + (size_t)m * ldres + gcol);
                    v.x = rr.x + gv.x * v.x; v.y = rr.y + gv.y * v.y;
                    v.z = rr.z + gv.z * v.z; v.w = rr.w + gv.w * v.w;
                }
                *(float4*)(C + (size_t)m * ldc + gcol) = v;
            }
        }
        __syncthreads();
    }
    if (wid == 0) {
        asm volatile("tcgen05.dealloc.cta_group::1.sync.aligned.b32 %0, %1;"
                     :: "r"(tmem), "r"(256u));
    }
#else
    // naive fallback (compiles for compute_103 pass; never runs on sm_103a)
    for (int e = t; e < 128 * 256; e += 256) {
        int r = e >> 8, j = e & 255;
        int m = m0 + r, n = n0 + j;
        float acc = 0.f;
        for (int k = 0; k < K; k++) {
            float a = __half2float(A[aoff16(m, k, lda)]);
            float b = __half2float(B[aoff16(n, k, ldb)]);
            acc += a * b;
        }
        acc += bias[n];
        if (EPI == 1) {
            acc = gelu_tanh(acc);
            Ch[aoff16(m, n, LTOT)] = __float2half_rn(acc);
        } else {
            if (EPI == 2) acc = resid[(size_t)m * ldres + n] + gate[n] * acc;
            C[(size_t)m * ldc + n] = acc;
        }
    }
#endif
}

// ---------------------------------------------------------------------------
// Flash attention (tf32 core unchanged; output fp16 A-layout)
// ---------------------------------------------------------------------------
#define FA_SCALE 0.08838834764831845f
#define SQ_PITCH 132
#define SK_PITCH 68
#define SV_PITCH 132
#define SP_PITCH 132
#define SQ_OFF 0
#define SK_OFF (128 * SQ_PITCH)
#define SV_OFF (SK_OFF + 128 * SK_PITCH)
#define SP_OFF (SV_OFF + 64 * SV_PITCH)
#define FA_SMEM_FLOATS (SP_OFF + 64 * SP_PITCH)
#define FA_SMEM_BYTES (FA_SMEM_FLOATS * 4)

__global__ void __launch_bounds__(256, 1)
flash_attn(const float* __restrict__ Q, const float* __restrict__ K,
           const float* __restrict__ V, __half* __restrict__ O) {
    extern __shared__ float sm[];
    float* sQ = sm + SQ_OFF;
    float* sK = sm + SK_OFF;
    float* sV = sm + SV_OFF;
    float* sP = sm + SP_OFF;

    const int t = threadIdx.x;
    const int wid = t >> 5, lane = t & 31;
    const int gid = lane >> 2, tig = lane & 3;
    const int h = blockIdx.y;
    const int q0 = blockIdx.x * 128;
    const int m0 = wid * 16;

    const float* Qh = Q + ((size_t)h * LTOT + q0) * HD;
    const float* Kh = K + (size_t)h * LTOT * HD;
    const float* Vh = V + (size_t)h * LTOT * HD;

    {
        int r = t >> 1;
        int dseg = (t & 1) * 64;
        const float* qr = Qh + (size_t)r * HD + dseg;
        #pragma unroll
        for (int i = 0; i < 16; i++) {
            float4 v4 = *(const float4*)(qr + i * 4);
            int d = dseg + i * 4;
            sQ[(d + 0) * SQ_PITCH + r] = to_tf32(v4.x * FA_SCALE);
            sQ[(d + 1) * SQ_PITCH + r] = to_tf32(v4.y * FA_SCALE);
            sQ[(d + 2) * SQ_PITCH + r] = to_tf32(v4.z * FA_SCALE);
            sQ[(d + 3) * SQ_PITCH + r] = to_tf32(v4.w * FA_SCALE);
        }
    }
    __syncthreads();

    unsigned int qf[16][4];
    #pragma unroll
    for (int kt = 0; kt < 16; kt++) {
        int kb = kt * 8;
        qf[kt][0] = __float_as_uint(sQ[(kb + tig)     * SQ_PITCH + m0 + gid]);
        qf[kt][1] = __float_as_uint(sQ[(kb + tig)     * SQ_PITCH + m0 + gid + 8]);
        qf[kt][2] = __float_as_uint(sQ[(kb + tig + 4) * SQ_PITCH + m0 + gid]);
        qf[kt][3] = __float_as_uint(sQ[(kb + tig + 4) * SQ_PITCH + m0 + gid + 8]);
    }

    float co[16][4];
    #pragma unroll
    for (int i = 0; i < 16; i++)
        #pragma unroll
        for (int j = 0; j < 4; j++) co[i][j] = 0.0f;
    float mrow0 = -1e30f, mrow1 = -1e30f, lrow0 = 0.0f, lrow1 = 0.0f;

    for (int kv = 0; kv < LTOT; kv += 64) {
        __syncthreads();
        {
            int c = t >> 2;
            int dseg = (t & 3) * 32;
            const float* kr = Kh + (size_t)(kv + c) * HD + dseg;
            #pragma unroll
            for (int i = 0; i < 8; i++) {
                float4 v4 = *(const float4*)(kr + i * 4);
                int d = dseg + i * 4;
                sK[(d + 0) * SK_PITCH + c] = to_tf32(v4.x);
                sK[(d + 1) * SK_PITCH + c] = to_tf32(v4.y);
                sK[(d + 2) * SK_PITCH + c] = to_tf32(v4.z);
                sK[(d + 3) * SK_PITCH + c] = to_tf32(v4.w);
            }
        }
        {
            int c = t >> 2;
            int dseg = (t & 3) * 32;
            const float* vr = Vh + (size_t)(kv + c) * HD + dseg;
            #pragma unroll
            for (int i = 0; i < 8; i++) {
                float4 v4 = *(const float4*)(vr + i * 4);
                float4 q4 = make_float4(to_tf32(v4.x), to_tf32(v4.y),
                                        to_tf32(v4.z), to_tf32(v4.w));
                *(float4*)(sV + c * SV_PITCH + dseg + i * 4) = q4;
            }
        }
        __syncthreads();

        float cs[8][4];
        #pragma unroll
        for (int i = 0; i < 8; i++)
            #pragma unroll
            for (int j = 0; j < 4; j++) cs[i][j] = 0.0f;
        #pragma unroll
        for (int kt = 0; kt < 16; kt++) {
            int kb = kt * 8;
            #pragma unroll
            for (int nt = 0; nt < 8; nt++) {
                unsigned int bf[2];
                bf[0] = __float_as_uint(sK[(kb + tig)     * SK_PITCH + nt * 8 + gid]);
                bf[1] = __float_as_uint(sK[(kb + tig + 4) * SK_PITCH + nt * 8 + gid]);
                mma_tf32(cs[nt], qf[kt], bf);
            }
        }

        float rmax0 = -1e30f, rmax1 = -1e30f;
        #pragma unroll
        for (int nt = 0; nt < 8; nt++) {
            rmax0 = fmaxf(rmax0, fmaxf(cs[nt][0], cs[nt][1]));
            rmax1 = fmaxf(rmax1, fmaxf(cs[nt][2], cs[nt][3]));
        }
        rmax0 = fmaxf(rmax0, __shfl_xor_sync(0xffffffffu, rmax0, 1));
        rmax0 = fmaxf(rmax0, __shfl_xor_sync(0xffffffffu, rmax0, 2));
        rmax1 = fmaxf(rmax1, __shfl_xor_sync(0xffffffffu, rmax1, 1));
        rmax1 = fmaxf(rmax1, __shfl_xor_sync(0xffffffffu, rmax1, 2));
        float mn0 = fmaxf(mrow0, rmax0);
        float mn1 = fmaxf(mrow1, rmax1);
        float corr0 = __expf(mrow0 - mn0);
        float corr1 = __expf(mrow1 - mn1);
        mrow0 = mn0; mrow1 = mn1;

        float rs0 = 0.0f, rs1 = 0.0f;
        #pragma unroll
        for (int nt = 0; nt < 8; nt++) {
            cs[nt][0] = __expf(cs[nt][0] - mn0);
            cs[nt][1] = __expf(cs[nt][1] - mn0);
            cs[nt][2] = __expf(cs[nt][2] - mn1);
            cs[nt][3] = __expf(cs[nt][3] - mn1);
            rs0 += cs[nt][0] + cs[nt][1];
            rs1 += cs[nt][2] + cs[nt][3];
        }
        rs0 += __shfl_xor_sync(0xffffffffu, rs0, 1);
        rs0 += __shfl_xor_sync(0xffffffffu, rs0, 2);
        rs1 += __shfl_xor_sync(0xffffffffu, rs1, 1);
        rs1 += __shfl_xor_sync(0xffffffffu, rs1, 2);
        lrow0 = lrow0 * corr0 + rs0;
        lrow1 = lrow1 * corr1 + rs1;

        #pragma unroll
        for (int nt = 0; nt < 16; nt++) {
            co[nt][0] *= corr0; co[nt][1] *= corr0;
            co[nt][2] *= corr1; co[nt][3] *= corr1;
        }

        #pragma unroll
        for (int nt = 0; nt < 8; nt++) {
            int cb = nt * 8 + tig * 2;
            sP[(cb + 0) * SP_PITCH + m0 + gid]     = to_tf32(cs[nt][0]);
            sP[(cb + 1) * SP_PITCH + m0 + gid]     = to_tf32(cs[nt][1]);
            sP[(cb + 0) * SP_PITCH + m0 + gid + 8] = to_tf32(cs[nt][2]);
            sP[(cb + 1) * SP_PITCH + m0 + gid + 8] = to_tf32(cs[nt][3]);
        }
        __syncwarp();

        #pragma unroll
        for (int kt = 0; kt < 8; kt++) {
            int kb = kt * 8;
            unsigned int af[4];
            af[0] = __float_as_uint(sP[(kb + tig)     * SP_PITCH + m0 + gid]);
            af[1] = __float_as_uint(sP[(kb + tig)     * SP_PITCH + m0 + gid + 8]);
            af[2] = __float_as_uint(sP[(kb + tig + 4) * SP_PITCH + m0 + gid]);
            af[3] = __float_as_uint(sP[(kb + tig + 4) * SP_PITCH + m0 + gid + 8]);
            #pragma unroll
            for (int nt = 0; nt < 16; nt++) {
                unsigned int bf[2];
                bf[0] = __float_as_uint(sV[(kb + tig)     * SV_PITCH + nt * 8 + gid]);
                bf[1] = __float_as_uint(sV[(kb + tig + 4) * SV_PITCH + nt * 8 + gid]);
                mma_tf32(co[nt], af, bf);
            }
        }
    }

    // epilogue: O /= l, write fp16 A-layout (rows = LTOT)
    float inv0 = 1.0f / lrow0;
    float inv1 = 1.0f / lrow1;
    int ra = q0 + m0 + gid;
    int rb = ra + 8;
    #pragma unroll
    for (int nt = 0; nt < 16; nt++) {
        int col = h * HD + nt * 8 + tig * 2;
        int q = (col >> 3) & 7, e = col & 7;
        size_t base = (size_t)(col >> 6) * LTOT * 64;
        __half2 va = __floats2half2_rn(co[nt][0] * inv0, co[nt][1] * inv0);
        __half2 vb = __floats2half2_rn(co[nt][2] * inv1, co[nt][3] * inv1);
        *(unsigned int*)(O + base + (size_t)ra * 64 + ((q ^ (ra & 7)) << 3) + e) =
            *(unsigned int*)&va;
        *(unsigned int*)(O + base + (size_t)rb * 64 + ((q ^ (rb & 7)) << 3) + e) =
            *(unsigned int*)&vb;
    }
}

// ---------------------------------------------------------------------------
// Host launcher
// ---------------------------------------------------------------------------
static void tc_launch(int epi, const __half* A,
                      const __half* Bt, const __half* Bi,
                      const float* biast, const float* biasi,
                      float* Ct, float* Ci, __half* Ch,
                      int N, int K, int lda, int ldb, int ldc,
                      const float* gatet = nullptr, const float* gatei = nullptr,
                      const float* residt = nullptr, const float* residi = nullptr,
                      int ldres = 0) {
    dim3 grid(NMALL * (N / 256));
    if (epi == 0)
        tc_gemm<0><<<grid, 256, TCG_SMEM_BYTES>>>(A, Bt, Bi, biast, biasi, Ct, Ci, Ch,
                                                  K, lda, ldb, ldc, gatet, gatei, residt, residi, ldres);
    else if (epi == 1)
        tc_gemm<1><<<grid, 256, TCG_SMEM_BYTES>>>(A, Bt, Bi, biast, biasi, Ct, Ci, Ch,
                                                  K, lda, ldb, ldc, gatet, gatei, residt, residi, ldres);
    else
        tc_gemm<2><<<grid, 256, TCG_SMEM_BYTES>>>(A, Bt, Bi, biast, biasi, Ct, Ci, Ch,
                                                  K, lda, ldb, ldc, gatet, gatei, residt, residi, ldres);
}

extern "C" void kernel_launch(void* const* d_in, const int* in_sizes, int n_in,
                              void* d_out, int out_size) {
    const float* img        = (const float*)d_in[0];
    const float* txt        = (const float*)d_in[1];
    const float* vec        = (const float*)d_in[2];
    const float* pe         = (const float*)d_in[3];
    const float* img_mod_w  = (const float*)d_in[4];
    const float* img_mod_b  = (const float*)d_in[5];
    const float* img_qkv_w  = (const float*)d_in[6];
    const float* img_qkv_b  = (const float*)d_in[7];
    const float* img_q_s    = (const float*)d_in[8];
    const float* img_k_s    = (const float*)d_in[9];
    const float* img_proj_w = (const float*)d_in[10];
    const float* img_proj_b = (const float*)d_in[11];
    const float* img_mlp_w1 = (const float*)d_in[12];
    const float* img_mlp_b1 = (const float*)d_in[13];
    const float* img_mlp_w2 = (const float*)d_in[14];
    const float* img_mlp_b2 = (const float*)d_in[15];
    const float* txt_mod_w  = (const float*)d_in[16];
    const float* txt_mod_b  = (const float*)d_in[17];
    const float* txt_qkv_w  = (const float*)d_in[18];
    const float* txt_qkv_b  = (const float*)d_in[19];
    const float* txt_q_s    = (const float*)d_in[20];
    const float* txt_k_s    = (const float*)d_in[21];
    const float* txt_proj_w = (const float*)d_in[22];
    const float* txt_proj_b = (const float*)d_in[23];
    const float* txt_mlp_w1 = (const float*)d_in[24];
    const float* txt_mlp_b1 = (const float*)d_in[25];
    const float* txt_mlp_w2 = (const float*)d_in[26];
    const float* txt_mlp_b2 = (const float*)d_in[27];
    float* out = (float*)d_out;

    float *sv, *modi, *modt, *qkvb, *q, *k, *v, *x1;
    __half *x, *attn, *x2, *h1, *w;
    cudaGetSymbolAddress((void**)&sv,   g_silu);
    cudaGetSymbolAddress((void**)&modi, g_mod_img);
    cudaGetSymbolAddress((void**)&modt, g_mod_txt);
    cudaGetSymbolAddress((void**)&x,    g_x);
    cudaGetSymbolAddress((void**)&qkvb, g_qkv);
    cudaGetSymbolAddress((void**)&q,    g_q);
    cudaGetSymbolAddress((void**)&k,    g_k);
    cudaGetSymbolAddress((void**)&v,    g_v);
    cudaGetSymbolAddress((void**)&attn, g_attn);
    cudaGetSymbolAddress((void**)&x1,   g_x1);
    cudaGetSymbolAddress((void**)&x2,   g_x2);
    cudaGetSymbolAddress((void**)&h1,   g_h1);
    cudaGetSymbolAddress((void**)&w,    g_w);

    cudaFuncSetAttribute(flash_attn, cudaFuncAttributeMaxDynamicSharedMemorySize, FA_SMEM_BYTES);
    cudaFuncSetAttribute(tc_gemm<0>, cudaFuncAttributeMaxDynamicSharedMemorySize, TCG_SMEM_BYTES);
    cudaFuncSetAttribute(tc_gemm<1>, cudaFuncAttributeMaxDynamicSharedMemorySize, TCG_SMEM_BYTES);
    cudaFuncSetAttribute(tc_gemm<2>, cudaFuncAttributeMaxDynamicSharedMemorySize, TCG_SMEM_BYTES);

    // weight conversion (chunk-major fp16, pre-swizzled)
    conv_w<<<dim3(QKVW / 256, HS / 64),   256>>>(txt_qkv_w,  w + OFF_QKV_T,  QKVW);
    conv_w<<<dim3(QKVW / 256, HS / 64),   256>>>(img_qkv_w,  w + OFF_QKV_I,  QKVW);
    conv_w<<<dim3(HS / 256,   HS / 64),   256>>>(txt_proj_w, w + OFF_PROJ_T, HS);
    conv_w<<<dim3(HS / 256,   HS / 64),   256>>>(img_proj_w, w + OFF_PROJ_I, HS);
    conv_w<<<dim3(MLPD / 256, HS / 64),   256>>>(txt_mlp_w1, w + OFF_MLP1_T, MLPD);
    conv_w<<<dim3(MLPD / 256, HS / 64),   256>>>(img_mlp_w1, w + OFF_MLP1_I, MLPD);
    conv_w<<<dim3(HS / 256,   MLPD / 64), 256>>>(txt_mlp_w2, w + OFF_MLP2_T, HS);
    conv_w<<<dim3(HS / 256,   MLPD / 64), 256>>>(img_mlp_w2, w + OFF_MLP2_I, HS);

    silu_kernel<<<HS / 256, 256>>>(vec, sv);
    mod_gemv2<<<(6 * HS) / 64, 256>>>(sv, img_mod_w, img_mod_b, modi);
    mod_gemv2<<<(6 * HS) / 64, 256>>>(sv, txt_mod_w, txt_mod_b, modt);

    ln_mod<<<LTXT, 256>>>(txt, x, modt + 0 * HS, modt + 1 * HS, 0);
    ln_mod<<<LIMG, 256>>>(img, x, modi + 0 * HS, modi + 1 * HS, LTXT);

    // QKV (merged txt/img) -> row-major fp32 qkvb
    tc_launch(0, x, w + OFF_QKV_T, w + OFF_QKV_I, txt_qkv_b, img_qkv_b,
              qkvb, qkvb, nullptr, QKVW, HS, LTOT, QKVW, QKVW);

    rms_rope<<<LTOT, 256>>>(qkvb, pe, txt_q_s, txt_k_s, img_q_s, img_k_s, q, k, v);

    {
        dim3 fgrid(LTOT / 128, NH);
        flash_attn<<<fgrid, 256, FA_SMEM_BYTES>>>(q, k, v, attn);
    }

    // proj + gated residual (merged) -> row-major fp32 x1
    tc_launch(2, attn, w + OFF_PROJ_T, w + OFF_PROJ_I, txt_proj_b, img_proj_b,
              x1, x1, nullptr, HS, HS, LTOT, HS, HS,
              modt + 2 * HS, modi + 2 * HS,
              txt, img - (size_t)LTXT * HS, HS);

    ln_mod<<<LTXT, 256>>>(x1, x2,                     modt + 3 * HS, modt + 4 * HS, 0);
    ln_mod<<<LIMG, 256>>>(x1 + (size_t)LTXT * HS, x2, modi + 3 * HS, modi + 4 * HS, LTXT);

    // MLP1 (+GELU, merged) -> fp16 A-layout h1
    tc_launch(1, x2, w + OFF_MLP1_T, w + OFF_MLP1_I, txt_mlp_b1, img_mlp_b1,
              nullptr, nullptr, h1, MLPD, HS, LTOT, MLPD, MLPD);

    // MLP2 (+gated residual, merged) -> d_out (img first, then txt)
    tc_launch(2, h1, w + OFF_MLP2_T, w + OFF_MLP2_I, txt_mlp_b2, img_mlp_b2,
              out + (size_t)LIMG * HS,
              out - (size_t)LTXT * HS,
              nullptr, HS, MLPD, LTOT, HS, HS,
              modt + 5 * HS, modi + 5 * HS,
              x1, x1, HS);
}

// round 13
// speedup vs baseline: 15.4680x; 1.6900x over previous
#include <cuda_runtime.h>
#include <cuda_bf16.h>
#include <cuda_fp16.h>
#include <math.h>
#include <stdint.h>

#define HS    3072
#define MLPD  12288
#define NH    24
#define HD    128
#define LTXT  512
#define LIMG  2048
#define LTOT  2560
#define QKVW  9216
#define NMT   4
#define NMALL 20

#if defined(__CUDA_ARCH__)
#if defined(__CUDA_ARCH_FEAT_SM103_ALL) || \
    (defined(__CUDA_ARCH_SPECIFIC__) && (__CUDA_ARCH_SPECIFIC__ >= 1000))
#define HAS_TCGEN05 1
#else
#define HAS_TCGEN05 0
#endif
#else
#define HAS_TCGEN05 0
#endif

// ---------------------------------------------------------------------------
// Static device scratch
// ---------------------------------------------------------------------------
__device__ float g_silu[HS];
__device__ float g_mod_img[6 * HS];
__device__ float g_mod_txt[6 * HS];
// A-operand buffers: chunk-major fp16 layout [K/64][LTOT][64], pre-swizzled
__device__ __align__(1024) __half g_x   [(size_t)LTOT * HS];
__device__ __align__(1024) __half g_attn[(size_t)LTOT * HS];
__device__ __align__(1024) __half g_x2  [(size_t)LTOT * HS];
__device__ __align__(1024) __half g_h1  [(size_t)LTOT * MLPD];
// row-major buffers
__device__ float  g_qkv [(size_t)LTOT * QKVW];
__device__ __half g_q   [(size_t)NH * LTOT * HD];   // pre-scaled by FA_SCALE
__device__ __half g_k   [(size_t)NH * LTOT * HD];
__device__ __half g_v   [(size_t)NH * LTOT * HD];
__device__ float  g_x1  [(size_t)LTOT * HS];
// converted weights: chunk-major fp16, pre-swizzled [K/64][N][64]
#define OFF_QKV_T  0u
#define OFF_QKV_I  28311552u
#define OFF_PROJ_T 56623104u
#define OFF_PROJ_I 66060288u
#define OFF_MLP1_T 75497472u
#define OFF_MLP1_I 113246208u
#define OFF_MLP2_T 150994944u
#define OFF_MLP2_I 188743680u
__device__ __align__(1024) __half g_w[226492416];

// ---------------------------------------------------------------------------
// Helpers
// ---------------------------------------------------------------------------
__device__ __forceinline__ float gelu_tanh(float x) {
    float x3 = x * x * x;
    return 0.5f * x * (1.0f + tanhf(0.7978845608028654f * (x + 0.044715f * x3)));
}
__device__ __forceinline__ uint32_t smem_u32(const void* p) {
    uint32_t a;
    asm("{ .reg .u64 t; cvta.to.shared.u64 t, %1; cvt.u32.u64 %0, t; }" : "=r"(a) : "l"(p));
    return a;
}
// fp16 operand layout: element (row, k), chunk-major [K/64][rows][64] with
// SW128 pre-swizzle on 16B units (8 halves): q = (k>>3)&7, q ^= row&7.
__device__ __forceinline__ size_t aoff16(int row, int k, int rows) {
    int q = (k >> 3) & 7;
    return ((size_t)(k >> 6) * rows + row) * 64 + (((q ^ (row & 7)) << 3) + (k & 7));
}
// fp16 mma m16n8k16, fp32 accum
__device__ __forceinline__ void mma_f16(float c[4], const unsigned int a[4],
                                        unsigned int b0, unsigned int b1) {
    asm volatile(
        "mma.sync.aligned.m16n8k16.row.col.f32.f16.f16.f32 "
        "{%0,%1,%2,%3}, {%4,%5,%6,%7}, {%8,%9}, {%0,%1,%2,%3};"
        : "+f"(c[0]), "+f"(c[1]), "+f"(c[2]), "+f"(c[3])
        : "r"(a[0]), "r"(a[1]), "r"(a[2]), "r"(a[3]), "r"(b0), "r"(b1));
}

// ---------------------------------------------------------------------------
// Elementwise kernels
// ---------------------------------------------------------------------------
__global__ void silu_kernel(const float* __restrict__ v, float* __restrict__ o) {
    int i = blockIdx.x * 256 + threadIdx.x;
    if (i < HS) { float x = v[i]; o[i] = x / (1.0f + expf(-x)); }
}

__global__ void mod_gemv2(const float* __restrict__ sv, const float* __restrict__ w,
                          const float* __restrict__ b, float* __restrict__ out) {
    __shared__ float ssv[HS];
    __shared__ float red[4][64];
    for (int i = threadIdx.x; i < HS; i += 256) ssv[i] = sv[i];
    __syncthreads();
    const int jl = threadIdx.x & 63, kq = threadIdx.x >> 6;
    const int j = blockIdx.x * 64 + jl;
    const int i0 = kq * (HS / 4);
    float acc = 0.0f;
    #pragma unroll 8
    for (int i = 0; i < HS / 4; i++)
        acc += ssv[i0 + i] * w[(size_t)(i0 + i) * (6 * HS) + j];
    red[kq][jl] = acc;
    __syncthreads();
    if (threadIdx.x < 64) {
        int jj = blockIdx.x * 64 + threadIdx.x;
        out[jj] = red[0][threadIdx.x] + red[1][threadIdx.x] +
                  red[2][threadIdx.x] + red[3][threadIdx.x] + b[jj];
    }
}

// weight conversion: W [K,N] row-major fp32 -> chunk-major fp16 pre-swizzled.
// Grid (N/256, K/32): each block covers half of a 64-k chunk.
__global__ void conv_w(const float* __restrict__ W, __half* __restrict__ Wc, int N) {
    const int n = blockIdx.x * 256 + threadIdx.x;
    const int c = blockIdx.y >> 1;
    const int jb = (blockIdx.y & 1) * 32;
    const float* src = W + (size_t)(c * 64 + jb) * N + n;
    __half* dst = Wc + ((size_t)c * N + n) * 64;
    const int p = n & 7;
    #pragma unroll
    for (int j = 0; j < 32; j += 8) {
        __half2 h0 = __floats2half2_rn(src[(size_t)(j + 0) * N], src[(size_t)(j + 1) * N]);
        __half2 h1 = __floats2half2_rn(src[(size_t)(j + 2) * N], src[(size_t)(j + 3) * N]);
        __half2 h2 = __floats2half2_rn(src[(size_t)(j + 4) * N], src[(size_t)(j + 5) * N]);
        __half2 h3 = __floats2half2_rn(src[(size_t)(j + 6) * N], src[(size_t)(j + 7) * N]);
        uint4 v = make_uint4(*(unsigned int*)&h0, *(unsigned int*)&h1,
                             *(unsigned int*)&h2, *(unsigned int*)&h3);
        *(uint4*)(dst + ((((j + jb) >> 3) ^ p) << 3)) = v;
    }
}

// LayerNorm + modulate -> fp16 A-layout output
__global__ void ln_mod(const float* __restrict__ x, __half* __restrict__ dst,
                       const float* __restrict__ shift, const float* __restrict__ scale,
                       int row0) {
    const int row = row0 + blockIdx.x;
    const int t = threadIdx.x;
    const float* xr = x + (size_t)blockIdx.x * HS;
    float v[12];
    float s = 0.0f;
    #pragma unroll
    for (int i = 0; i < 12; i++) { v[i] = xr[t + i * 256]; s += v[i]; }
    __shared__ float red[256];
    red[t] = s; __syncthreads();
    for (int o = 128; o > 0; o >>= 1) { if (t < o) red[t] += red[t + o]; __syncthreads(); }
    float mean = red[0] * (1.0f / HS);
    __syncthreads();
    float s2 = 0.0f;
    #pragma unroll
    for (int i = 0; i < 12; i++) { float d = v[i] - mean; s2 += d * d; }
    red[t] = s2; __syncthreads();
    for (int o = 128; o > 0; o >>= 1) { if (t < o) red[t] += red[t + o]; __syncthreads(); }
    float inv = rsqrtf(red[0] * (1.0f / HS) + 1e-6f);
    #pragma unroll
    for (int i = 0; i < 12; i++) {
        int c = t + i * 256;
        float val = shift[c] + (1.0f + scale[c]) * (v[i] - mean) * inv;
        dst[aoff16(row, c, LTOT)] = __float2half_rn(val);
    }
}

#define FA_SCALE 0.08838834764831845f

// RMS-norm + RoPE + head-major scatter; fp16 outputs, Q pre-scaled.
__global__ void rms_rope(const float* __restrict__ qkv, const float* __restrict__ pe,
                         const float* __restrict__ tqs, const float* __restrict__ tks,
                         const float* __restrict__ iqs, const float* __restrict__ iks,
                         __half* __restrict__ Q, __half* __restrict__ Kp,
                         __half* __restrict__ Vp) {
    int l = blockIdx.x;
    int w = threadIdx.x >> 5, lane = threadIdx.x & 31;
    const float* qs = (l < LTXT) ? tqs : iqs;
    const float* ks = (l < LTXT) ? tks : iks;
    const float* row = qkv + (size_t)l * QKVW;
    const float* peb = pe + (size_t)l * 256 + lane * 8;
    float4 p0 = *(const float4*)(peb);
    float4 p1 = *(const float4*)(peb + 4);
    int d0 = lane * 4;
    float4 scq = *(const float4*)(qs + d0);
    float4 sck = *(const float4*)(ks + d0);

    for (int h = w; h < NH; h += 8) {
        float4 xq = *(const float4*)(row + h * HD + d0);
        float ss = xq.x*xq.x + xq.y*xq.y + xq.z*xq.z + xq.w*xq.w;
        #pragma unroll
        for (int o = 16; o > 0; o >>= 1) ss += __shfl_xor_sync(0xffffffffu, ss, o);
        float r = rsqrtf(ss * (1.0f / HD) + 1e-6f);
        float x0 = xq.x * r * scq.x, x1 = xq.y * r * scq.y;
        float x2 = xq.z * r * scq.z, x3 = xq.w * r * scq.w;
        float q0 = (p0.x * x0 + p0.y * x1) * FA_SCALE;
        float q1 = (p0.z * x0 + p0.w * x1) * FA_SCALE;
        float q2 = (p1.x * x2 + p1.y * x3) * FA_SCALE;
        float q3 = (p1.z * x2 + p1.w * x3) * FA_SCALE;
        __half2 qa = __floats2half2_rn(q0, q1);
        __half2 qb = __floats2half2_rn(q2, q3);
        *(uint2*)(Q + ((size_t)h * LTOT + l) * HD + d0) =
            make_uint2(*(unsigned int*)&qa, *(unsigned int*)&qb);

        float4 xk = *(const float4*)(row + HS + h * HD + d0);
        float sk = xk.x*xk.x + xk.y*xk.y + xk.z*xk.z + xk.w*xk.w;
        #pragma unroll
        for (int o = 16; o > 0; o >>= 1) sk += __shfl_xor_sync(0xffffffffu, sk, o);
        float rk = rsqrtf(sk * (1.0f / HD) + 1e-6f);
        float y0 = xk.x * rk * sck.x, y1 = xk.y * rk * sck.y;
        float y2 = xk.z * rk * sck.z, y3 = xk.w * rk * sck.w;
        float k0 = p0.x * y0 + p0.y * y1;
        float k1 = p0.z * y0 + p0.w * y1;
        float k2 = p1.x * y2 + p1.y * y3;
        float k3 = p1.z * y2 + p1.w * y3;
        __half2 ka = __floats2half2_rn(k0, k1);
        __half2 kb = __floats2half2_rn(k2, k3);
        *(uint2*)(Kp + ((size_t)h * LTOT + l) * HD + d0) =
            make_uint2(*(unsigned int*)&ka, *(unsigned int*)&kb);

        float4 xv = *(const float4*)(row + 2 * HS + h * HD + d0);
        __half2 va = __floats2half2_rn(xv.x, xv.y);
        __half2 vb = __floats2half2_rn(xv.z, xv.w);
        *(uint2*)(Vp + ((size_t)h * LTOT + l) * HD + d0) =
            make_uint2(*(unsigned int*)&va, *(unsigned int*)&vb);
    }
}

#define TCG_SMEM_BYTES (1024 + 2 * 49152)

#if HAS_TCGEN05
__device__ __forceinline__ uint32_t elect_one() {
    uint32_t pred;
    asm volatile("{\n\t.reg .pred p;\n\telect.sync _|p, 0xFFFFFFFF;\n\t"
                 "selp.b32 %0, 1, 0, p;\n\t}" : "=r"(pred));
    return pred;
}
__device__ __forceinline__ void mbar_wait(uint32_t mbar, uint32_t parity) {
    asm volatile(
        "{\n\t.reg .pred P1;\n\t"
        "W_%=:\n\t"
        "mbarrier.try_wait.parity.acquire.cta.shared::cta.b64 P1, [%0], %1, 0x989680;\n\t"
        "@P1 bra.uni D_%=;\n\t"
        "bra.uni W_%=;\n\t"
        "D_%=:\n\t}"
        :: "r"(mbar), "r"(parity) : "memory");
}
__device__ __forceinline__ uint64_t make_desc(uint32_t addr) {
    const uint64_t base =
        (uint64_t(2) << 61) | (uint64_t(1) << 46) | (uint64_t(64) << 32) | (uint64_t(1) << 16);
    return base | ((uint64_t)(addr >> 4) & 0x3FFF);
}
__device__ __forceinline__ void tc_mma_f16(uint32_t d, uint64_t ad, uint64_t bd,
                                           uint32_t idesc, uint32_t en) {
    asm volatile(
        "{\n\t.reg .pred p;\n\t"
        "setp.ne.u32 p, %4, 0;\n\t"
        "tcgen05.mma.cta_group::1.kind::f16 [%0], %1, %2, %3, {%5,%5,%5,%5}, p;\n\t}"
        :: "r"(d), "l"(ad), "l"(bd), "r"(idesc), "r"(en), "r"(0u) : "memory");
}
#define TCG_IDESC ((1u<<4)|((256u/8)<<17)|((128u/16)<<24))
#define EXPECT_TX(mbar, bytes) \
    asm volatile("mbarrier.arrive.expect_tx.shared.b64 _, [%0], %1;" \
                 :: "r"(mbar), "r"(bytes) : "memory")
#define BULK_CP(dst, src, bytes, mbar) \
    asm volatile("cp.async.bulk.shared::cluster.global.mbarrier::complete_tx::bytes " \
                 "[%0], [%1], %2, [%3];" \
                 :: "r"(dst), "l"(src), "r"(bytes), "r"(mbar) : "memory")
#endif

// ---------------------------------------------------------------------------
// Merged txt/img fp16 GEMM (unchanged from R12)
// ---------------------------------------------------------------------------
template <int EPI>
__global__ void __launch_bounds__(256)
tc_gemm(const __half* __restrict__ A,
        const __half* __restrict__ Bt, const __half* __restrict__ Bi,
        const float* __restrict__ biast, const float* __restrict__ biasi,
        float* __restrict__ Ct, float* __restrict__ Ci, __half* __restrict__ Ch,
        int K, int lda, int ldb, int ldc,
        const float* __restrict__ gatet, const float* __restrict__ gatei,
        const float* __restrict__ residt, const float* __restrict__ residi,
        int ldres) {
    extern __shared__ char smem[];
    const int t = threadIdx.x;
    const int wid = t >> 5, lane = t & 31;
    const int mi = blockIdx.x % NMALL;
    const int m0 = mi * 128;
    const int n0 = (blockIdx.x / NMALL) * 256;
    const bool is_txt = (mi < NMT);
    const __half* B    = is_txt ? Bt : Bi;
    const float* bias  = is_txt ? biast : biasi;
    const float* gate  = is_txt ? gatet : gatei;
    const float* resid = is_txt ? residt : residi;
    float* C           = is_txt ? Ct : Ci;
    const int nc = K / 64;

#if HAS_TCGEN05
    const uint32_t smem_base = smem_u32(smem);
    const uint32_t sA0 = (smem_base + 64 + 1023) & ~1023u;
    const uint32_t sB0 = sA0 + 16384;
    const uint32_t sA1 = sB0 + 32768;
    const uint32_t sB1 = sA1 + 16384;
    const uint32_t tx0 = smem_base + 16, tx1 = smem_base + 24;
    const uint32_t mm0 = smem_base + 32, mm1 = smem_base + 40;
    const uint32_t dn  = smem_base + 48;
    float* sEp = (float*)(smem + (sA0 - smem_base));

    if (wid == 0) {
        asm volatile("tcgen05.alloc.cta_group::1.sync.aligned.shared::cta.b32 [%0], %1;"
                     :: "r"(smem_base), "r"(256u) : "memory");
        asm volatile("tcgen05.relinquish_alloc_permit.cta_group::1.sync.aligned;");
    }
    if (t == 0) {
        asm volatile("mbarrier.init.shared.b64 [%0], 1;" :: "r"(tx0) : "memory");
        asm volatile("mbarrier.init.shared.b64 [%0], 1;" :: "r"(tx1) : "memory");
        asm volatile("mbarrier.init.shared.b64 [%0], 1;" :: "r"(mm0) : "memory");
        asm volatile("mbarrier.init.shared.b64 [%0], 1;" :: "r"(mm1) : "memory");
        asm volatile("mbarrier.init.shared.b64 [%0], 1;" :: "r"(dn)  : "memory");
    }
    __syncthreads();
    uint32_t tmem;
    asm volatile("ld.shared.b32 %0, [%1];" : "=r"(tmem) : "r"(smem_base));

    if (wid == 0 && elect_one()) {
        const __half* Ab = A + (size_t)m0 * 64;
        const __half* Bb = B + (size_t)n0 * 64;
        EXPECT_TX(tx0, 49152u);
        BULK_CP(sA0, Ab, 16384u, tx0);
        BULK_CP(sB0, Bb, 32768u, tx0);
        EXPECT_TX(tx1, 49152u);
        BULK_CP(sA1, Ab + (size_t)lda * 64, 16384u, tx1);
        BULK_CP(sB1, Bb + (size_t)ldb * 64, 32768u, tx1);
        asm volatile("tcgen05.fence::after_thread_sync;" ::: "memory");

        int phtx0 = 0, phtx1 = 0, phmm0 = 0, phmm1 = 0;
        for (int c = 0; c < nc; c++) {
            const int s = c & 1;
            if (s == 0) { mbar_wait(tx0, phtx0); phtx0 ^= 1; }
            else        { mbar_wait(tx1, phtx1); phtx1 ^= 1; }
            uint64_t ad = make_desc(s ? sA1 : sA0);
            uint64_t bd = make_desc(s ? sB1 : sB0);
            #pragma unroll
            for (int ks = 0; ks < 4; ks++)
                tc_mma_f16(tmem, ad + 2 * ks, bd + 2 * ks, TCG_IDESC,
                           (uint32_t)((c > 0) | (ks > 0)));
            asm volatile(
                "tcgen05.commit.cta_group::1.mbarrier::arrive::one.shared::cluster.b64 [%0];"
                :: "r"(s ? mm1 : mm0) : "memory");
            if (c == nc - 1) {
                asm volatile(
                    "tcgen05.commit.cta_group::1.mbarrier::arrive::one.shared::cluster.b64 [%0];"
                    :: "r"(dn) : "memory");
            }
            if (c + 2 < nc) {
                if (s == 0) { mbar_wait(mm0, phmm0); phmm0 ^= 1; }
                else        { mbar_wait(mm1, phmm1); phmm1 ^= 1; }
                const uint32_t txm = s ? tx1 : tx0;
                EXPECT_TX(txm, 49152u);
                BULK_CP(s ? sA1 : sA0, Ab + (size_t)(c + 2) * lda * 64, 16384u, txm);
                BULK_CP(s ? sB1 : sB0, Bb + (size_t)(c + 2) * ldb * 64, 32768u, txm);
            }
        }
    }
    mbar_wait(dn, 0);
    asm volatile("tcgen05.fence::after_thread_sync;" ::: "memory");
    __syncthreads();

    const int half = wid >> 2;
    const int rrow = (wid & 3) * 32 + lane;
    const int f = t & 15, rg = t >> 4;
    for (int cb = 0; cb < 4; cb++) {
        uint32_t r_[32];
        asm volatile(
            "tcgen05.ld.sync.aligned.32x32b.x32.b32 "
            "{%0,%1,%2,%3,%4,%5,%6,%7,%8,%9,%10,%11,%12,%13,%14,%15,"
            "%16,%17,%18,%19,%20,%21,%22,%23,%24,%25,%26,%27,%28,%29,%30,%31}, [%32];"
            : "=r"(r_[0]),"=r"(r_[1]),"=r"(r_[2]),"=r"(r_[3]),
              "=r"(r_[4]),"=r"(r_[5]),"=r"(r_[6]),"=r"(r_[7]),
              "=r"(r_[8]),"=r"(r_[9]),"=r"(r_[10]),"=r"(r_[11]),
              "=r"(r_[12]),"=r"(r_[13]),"=r"(r_[14]),"=r"(r_[15]),
              "=r"(r_[16]),"=r"(r_[17]),"=r"(r_[18]),"=r"(r_[19]),
              "=r"(r_[20]),"=r"(r_[21]),"=r"(r_[22]),"=r"(r_[23]),
              "=r"(r_[24]),"=r"(r_[25]),"=r"(r_[26]),"=r"(r_[27]),
              "=r"(r_[28]),"=r"(r_[29]),"=r"(r_[30]),"=r"(r_[31])
            : "r"(tmem + half * 128 + cb * 32));
        asm volatile("tcgen05.wait::ld.sync.aligned;" ::: "memory");
        #pragma unroll
        for (int j = 0; j < 32; j++)
            sEp[rrow * 65 + half * 32 + j] = __uint_as_float(r_[j]);
        __syncthreads();

        const int scol = (f >> 3) * 32 + (f & 7) * 4;
        const int gcol = n0 + (f >> 3) * 128 + cb * 32 + (f & 7) * 4;
        const float4 bv = *(const float4*)(bias + gcol);
        float4 gv = make_float4(0.f, 0.f, 0.f, 0.f);
        if (EPI == 2) gv = *(const float4*)(gate + gcol);
        #pragma unroll
        for (int i = 0; i < 8; i++) {
            int r = rg + 16 * i;
            int m = m0 + r;
            const float* sp = &sEp[r * 65 + scol];
            float4 v = make_float4(sp[0], sp[1], sp[2], sp[3]);
            v.x += bv.x; v.y += bv.y; v.z += bv.z; v.w += bv.w;
            if (EPI == 1) {
                v.x = gelu_tanh(v.x); v.y = gelu_tanh(v.y);
                v.z = gelu_tanh(v.z); v.w = gelu_tanh(v.w);
                size_t ad2 = ((size_t)(gcol >> 6) * LTOT + m) * 64 +
                             (((((gcol >> 3) & 7) ^ (m & 7)) << 3) + (gcol & 7));
                __half2 ha = __floats2half2_rn(v.x, v.y);
                __half2 hb = __floats2half2_rn(v.z, v.w);
                *(uint2*)(Ch + ad2) = make_uint2(*(unsigned int*)&ha, *(unsigned int*)&hb);
            } else {
                if (EPI == 2) {
                    float4 rr = *(const float4*)(resid + (size_t)m * ldres + gcol);
                    v.x = rr.x + gv.x * v.x; v.y = rr.y + gv.y * v.y;
                    v.z = rr.z + gv.z * v.z; v.w = rr.w + gv.w * v.w;
                }
                *(float4*)(C + (size_t)m * ldc + gcol) = v;
            }
        }
        __syncthreads();
    }
    if (wid == 0) {
        asm volatile("tcgen05.dealloc.cta_group::1.sync.aligned.b32 %0, %1;"
                     :: "r"(tmem), "r"(256u));
    }
#else
    for (int e = t; e < 128 * 256; e += 256) {
        int r = e >> 8, j = e & 255;
        int m = m0 + r, n = n0 + j;
        float acc = 0.f;
        for (int k = 0; k < K; k++) {
            float a = __half2float(A[aoff16(m, k, lda)]);
            float b = __half2float(B[aoff16(n, k, ldb)]);
            acc += a * b;
        }
        acc += bias[n];
        if (EPI == 1) {
            acc = gelu_tanh(acc);
            Ch[aoff16(m, n, LTOT)] = __float2half_rn(acc);
        } else {
            if (EPI == 2) acc = resid[(size_t)m * ldres + n] + gate[n] * acc;
            C[(size_t)m * ldc + n] = acc;
        }
    }
#endif
}

// ---------------------------------------------------------------------------
// fp16 flash attention: 128 Q rows/CTA, 64-wide KV tiles, m16n8k16 mma.
// K staged [c][d] (B frags = direct LDS.32), V staged [c][d] with
// ldmatrix.x4.trans for B frags. Softmax fp32. Output fp16 A-layout.
// ---------------------------------------------------------------------------
#define KPITCH 136
#define PPITCH 72
#define SK_OFF 0
#define SV_OFF (64 * KPITCH)
#define SP_OFF (2 * 64 * KPITCH)
#define FA_SMEM_BYTES ((2 * 64 * KPITCH + 8 * 16 * PPITCH) * 2)

__global__ void __launch_bounds__(256, 1)
flash_attn(const __half* __restrict__ Q, const __half* __restrict__ K,
           const __half* __restrict__ V, __half* __restrict__ O) {
    extern __shared__ __half smh[];
    __half* sK = smh + SK_OFF;
    __half* sV = smh + SV_OFF;
    __half* sP = smh + SP_OFF;

    const int t = threadIdx.x;
    const int wid = t >> 5, lane = t & 31;
    const int gid = lane >> 2, tig = lane & 3;
    const int h = blockIdx.y;
    const int q0 = blockIdx.x * 128;
    const int m0 = wid * 16;
    __half* sPw = sP + wid * 16 * PPITCH;

    const __half* Qh = Q + ((size_t)h * LTOT + q0) * HD;
    const __half* Kh = K + (size_t)h * LTOT * HD;
    const __half* Vh = V + (size_t)h * LTOT * HD;

    // Q fragments straight from gmem (pre-scaled fp16)
    unsigned int qf[8][4];
    #pragma unroll
    for (int kb = 0; kb < 8; kb++) {
        const __half* qr = Qh + (size_t)(m0 + gid) * HD + kb * 16 + 2 * tig;
        qf[kb][0] = *(const unsigned int*)(qr);
        qf[kb][1] = *(const unsigned int*)(qr + 8 * HD);
        qf[kb][2] = *(const unsigned int*)(qr + 8);
        qf[kb][3] = *(const unsigned int*)(qr + 8 * HD + 8);
    }

    float co[16][4];
    #pragma unroll
    for (int i = 0; i < 16; i++)
        #pragma unroll
        for (int j = 0; j < 4; j++) co[i][j] = 0.0f;
    float mrow0 = -1e30f, mrow1 = -1e30f, lrow0 = 0.0f, lrow1 = 0.0f;

    for (int kv = 0; kv < LTOT; kv += 64) {
        __syncthreads();
        {
            const int c = t >> 2;
            const int dseg = (t & 3) * 32;
            const __half* kr = Kh + (size_t)(kv + c) * HD + dseg;
            const __half* vr = Vh + (size_t)(kv + c) * HD + dseg;
            #pragma unroll
            for (int i = 0; i < 4; i++)
                *(uint4*)(sK + c * KPITCH + dseg + i * 8) = *(const uint4*)(kr + i * 8);
            #pragma unroll
            for (int i = 0; i < 4; i++)
                *(uint4*)(sV + c * KPITCH + dseg + i * 8) = *(const uint4*)(vr + i * 8);
        }
        __syncthreads();

        // S = Q @ K^T (16 x 64 per warp)
        float cs[8][4];
        #pragma unroll
        for (int i = 0; i < 8; i++)
            #pragma unroll
            for (int j = 0; j < 4; j++) cs[i][j] = 0.0f;
        #pragma unroll
        for (int kb = 0; kb < 8; kb++) {
            #pragma unroll
            for (int nt = 0; nt < 8; nt++) {
                const __half* kp = sK + (nt * 8 + gid) * KPITCH + kb * 16 + 2 * tig;
                unsigned int b0 = *(const unsigned int*)(kp);
                unsigned int b1 = *(const unsigned int*)(kp + 8);
                mma_f16(cs[nt], qf[kb], b0, b1);
            }
        }

        // online softmax (fp32)
        float rmax0 = -1e30f, rmax1 = -1e30f;
        #pragma unroll
        for (int nt = 0; nt < 8; nt++) {
            rmax0 = fmaxf(rmax0, fmaxf(cs[nt][0], cs[nt][1]));
            rmax1 = fmaxf(rmax1, fmaxf(cs[nt][2], cs[nt][3]));
        }
        rmax0 = fmaxf(rmax0, __shfl_xor_sync(0xffffffffu, rmax0, 1));
        rmax0 = fmaxf(rmax0, __shfl_xor_sync(0xffffffffu, rmax0, 2));
        rmax1 = fmaxf(rmax1, __shfl_xor_sync(0xffffffffu, rmax1, 1));
        rmax1 = fmaxf(rmax1, __shfl_xor_sync(0xffffffffu, rmax1, 2));
        float mn0 = fmaxf(mrow0, rmax0);
        float mn1 = fmaxf(mrow1, rmax1);
        float corr0 = __expf(mrow0 - mn0);
        float corr1 = __expf(mrow1 - mn1);
        mrow0 = mn0; mrow1 = mn1;

        float rs0 = 0.0f, rs1 = 0.0f;
        #pragma unroll
        for (int nt = 0; nt < 8; nt++) {
            cs[nt][0] = __expf(cs[nt][0] - mn0);
            cs[nt][1] = __expf(cs[nt][1] - mn0);
            cs[nt][2] = __expf(cs[nt][2] - mn1);
            cs[nt][3] = __expf(cs[nt][3] - mn1);
            rs0 += cs[nt][0] + cs[nt][1];
            rs1 += cs[nt][2] + cs[nt][3];
        }
        rs0 += __shfl_xor_sync(0xffffffffu, rs0, 1);
        rs0 += __shfl_xor_sync(0xffffffffu, rs0, 2);
        rs1 += __shfl_xor_sync(0xffffffffu, rs1, 1);
        rs1 += __shfl_xor_sync(0xffffffffu, rs1, 2);
        lrow0 = lrow0 * corr0 + rs0;
        lrow1 = lrow1 * corr1 + rs1;

        #pragma unroll
        for (int nt = 0; nt < 16; nt++) {
            co[nt][0] *= corr0; co[nt][1] *= corr0;
            co[nt][2] *= corr1; co[nt][3] *= corr1;
        }

        // P -> per-warp smem (half, row-major 16x64)
        #pragma unroll
        for (int nt = 0; nt < 8; nt++) {
            __half2 p01 = __floats2half2_rn(cs[nt][0], cs[nt][1]);
            __half2 p23 = __floats2half2_rn(cs[nt][2], cs[nt][3]);
            *(unsigned int*)(sPw + gid * PPITCH + nt * 8 + 2 * tig) = *(unsigned int*)&p01;
            *(unsigned int*)(sPw + (gid + 8) * PPITCH + nt * 8 + 2 * tig) = *(unsigned int*)&p23;
        }
        __syncwarp();

        // P fragments
        unsigned int pf[4][4];
        #pragma unroll
        for (int kb = 0; kb < 4; kb++) {
            const __half* pp = sPw + gid * PPITCH + kb * 16 + 2 * tig;
            pf[kb][0] = *(const unsigned int*)(pp);
            pf[kb][1] = *(const unsigned int*)(pp + 8 * PPITCH);
            pf[kb][2] = *(const unsigned int*)(pp + 8);
            pf[kb][3] = *(const unsigned int*)(pp + 8 * PPITCH + 8);
        }

        // O += P @ V ; V b-frags via ldmatrix.x4.trans
        #pragma unroll
        for (int nt = 0; nt < 16; nt++) {
            #pragma unroll
            for (int cb = 0; cb < 2; cb++) {
                uint32_t va = smem_u32(sV + (cb * 32 + lane) * KPITCH + nt * 8);
                unsigned int v0, v1, v2, v3;
                asm volatile(
                    "ldmatrix.sync.aligned.m8n8.x4.trans.shared.b16 {%0,%1,%2,%3}, [%4];"
                    : "=r"(v0), "=r"(v1), "=r"(v2), "=r"(v3) : "r"(va));
                mma_f16(co[nt], pf[cb * 2 + 0], v0, v1);
                mma_f16(co[nt], pf[cb * 2 + 1], v2, v3);
            }
        }
    }

    // epilogue: O /= l, fp16 A-layout (rows = LTOT)
    float inv0 = 1.0f / lrow0;
    float inv1 = 1.0f / lrow1;
    int ra = q0 + m0 + gid;
    int rb = ra + 8;
    #pragma unroll
    for (int nt = 0; nt < 16; nt++) {
        int col = h * HD + nt * 8 + tig * 2;
        int q = (col >> 3) & 7, e = col & 7;
        size_t base = (size_t)(col >> 6) * LTOT * 64;
        __half2 va = __floats2half2_rn(co[nt][0] * inv0, co[nt][1] * inv0);
        __half2 vb = __floats2half2_rn(co[nt][2] * inv1, co[nt][3] * inv1);
        *(unsigned int*)(O + base + (size_t)ra * 64 + ((q ^ (ra & 7)) << 3) + e) =
            *(unsigned int*)&va;
        *(unsigned int*)(O + base + (size_t)rb * 64 + ((q ^ (rb & 7)) << 3) + e) =
            *(unsigned int*)&vb;
    }
}

// ---------------------------------------------------------------------------
// Host launcher
// ---------------------------------------------------------------------------
static void tc_launch(int epi, const __half* A,
                      const __half* Bt, const __half* Bi,
                      const float* biast, const float* biasi,
                      float* Ct, float* Ci, __half* Ch,
                      int N, int K, int lda, int ldb, int ldc,
                      const float* gatet = nullptr, const float* gatei = nullptr,
                      const float* residt = nullptr, const float* residi = nullptr,
                      int ldres = 0) {
    dim3 grid(NMALL * (N / 256));
    if (epi == 0)
        tc_gemm<0><<<grid, 256, TCG_SMEM_BYTES>>>(A, Bt, Bi, biast, biasi, Ct, Ci, Ch,
                                                  K, lda, ldb, ldc, gatet, gatei, residt, residi, ldres);
    else if (epi == 1)
        tc_gemm<1><<<grid, 256, TCG_SMEM_BYTES>>>(A, Bt, Bi, biast, biasi, Ct, Ci, Ch,
                                                  K, lda, ldb, ldc, gatet, gatei, residt, residi, ldres);
    else
        tc_gemm<2><<<grid, 256, TCG_SMEM_BYTES>>>(A, Bt, Bi, biast, biasi, Ct, Ci, Ch,
                                                  K, lda, ldb, ldc, gatet, gatei, residt, residi, ldres);
}

extern "C" void kernel_launch(void* const* d_in, const int* in_sizes, int n_in,
                              void* d_out, int out_size) {
    const float* img        = (const float*)d_in[0];
    const float* txt        = (const float*)d_in[1];
    const float* vec        = (const float*)d_in[2];
    const float* pe         = (const float*)d_in[3];
    const float* img_mod_w  = (const float*)d_in[4];
    const float* img_mod_b  = (const float*)d_in[5];
    const float* img_qkv_w  = (const float*)d_in[6];
    const float* img_qkv_b  = (const float*)d_in[7];
    const float* img_q_s    = (const float*)d_in[8];
    const float* img_k_s    = (const float*)d_in[9];
    const float* img_proj_w = (const float*)d_in[10];
    const float* img_proj_b = (const float*)d_in[11];
    const float* img_mlp_w1 = (const float*)d_in[12];
    const float* img_mlp_b1 = (const float*)d_in[13];
    const float* img_mlp_w2 = (const float*)d_in[14];
    const float* img_mlp_b2 = (const float*)d_in[15];
    const float* txt_mod_w  = (const float*)d_in[16];
    const float* txt_mod_b  = (const float*)d_in[17];
    const float* txt_qkv_w  = (const float*)d_in[18];
    const float* txt_qkv_b  = (const float*)d_in[19];
    const float* txt_q_s    = (const float*)d_in[20];
    const float* txt_k_s    = (const float*)d_in[21];
    const float* txt_proj_w = (const float*)d_in[22];
    const float* txt_proj_b = (const float*)d_in[23];
    const float* txt_mlp_w1 = (const float*)d_in[24];
    const float* txt_mlp_b1 = (const float*)d_in[25];
    const float* txt_mlp_w2 = (const float*)d_in[26];
    const float* txt_mlp_b2 = (const float*)d_in[27];
    float* out = (float*)d_out;

    float *sv, *modi, *modt, *qkvb, *x1;
    __half *x, *attn, *x2, *h1, *w, *q, *k, *v;
    cudaGetSymbolAddress((void**)&sv,   g_silu);
    cudaGetSymbolAddress((void**)&modi, g_mod_img);
    cudaGetSymbolAddress((void**)&modt, g_mod_txt);
    cudaGetSymbolAddress((void**)&x,    g_x);
    cudaGetSymbolAddress((void**)&qkvb, g_qkv);
    cudaGetSymbolAddress((void**)&q,    g_q);
    cudaGetSymbolAddress((void**)&k,    g_k);
    cudaGetSymbolAddress((void**)&v,    g_v);
    cudaGetSymbolAddress((void**)&attn, g_attn);
    cudaGetSymbolAddress((void**)&x1,   g_x1);
    cudaGetSymbolAddress((void**)&x2,   g_x2);
    cudaGetSymbolAddress((void**)&h1,   g_h1);
    cudaGetSymbolAddress((void**)&w,    g_w);

    cudaFuncSetAttribute(flash_attn, cudaFuncAttributeMaxDynamicSharedMemorySize, FA_SMEM_BYTES);
    cudaFuncSetAttribute(tc_gemm<0>, cudaFuncAttributeMaxDynamicSharedMemorySize, TCG_SMEM_BYTES);
    cudaFuncSetAttribute(tc_gemm<1>, cudaFuncAttributeMaxDynamicSharedMemorySize, TCG_SMEM_BYTES);
    cudaFuncSetAttribute(tc_gemm<2>, cudaFuncAttributeMaxDynamicSharedMemorySize, TCG_SMEM_BYTES);

    // weight conversion (chunk-major fp16, pre-swizzled), 2 blocks per chunk
    conv_w<<<dim3(QKVW / 256, HS / 32),   256>>>(txt_qkv_w,  w + OFF_QKV_T,  QKVW);
    conv_w<<<dim3(QKVW / 256, HS / 32),   256>>>(img_qkv_w,  w + OFF_QKV_I,  QKVW);
    conv_w<<<dim3(HS / 256,   HS / 32),   256>>>(txt_proj_w, w + OFF_PROJ_T, HS);
    conv_w<<<dim3(HS / 256,   HS / 32),   256>>>(img_proj_w, w + OFF_PROJ_I, HS);
    conv_w<<<dim3(MLPD / 256, HS / 32),   256>>>(txt_mlp_w1, w + OFF_MLP1_T, MLPD);
    conv_w<<<dim3(MLPD / 256, HS / 32),   256>>>(img_mlp_w1, w + OFF_MLP1_I, MLPD);
    conv_w<<<dim3(HS / 256,   MLPD / 32), 256>>>(txt_mlp_w2, w + OFF_MLP2_T, HS);
    conv_w<<<dim3(HS / 256,   MLPD / 32), 256>>>(img_mlp_w2, w + OFF_MLP2_I, HS);

    silu_kernel<<<HS / 256, 256>>>(vec, sv);
    mod_gemv2<<<(6 * HS) / 64, 256>>>(sv, img_mod_w, img_mod_b, modi);
    mod_gemv2<<<(6 * HS) / 64, 256>>>(sv, txt_mod_w, txt_mod_b, modt);

    ln_mod<<<LTXT, 256>>>(txt, x, modt + 0 * HS, modt + 1 * HS, 0);
    ln_mod<<<LIMG, 256>>>(img, x, modi + 0 * HS, modi + 1 * HS, LTXT);

    // QKV (merged txt/img) -> row-major fp32 qkvb
    tc_launch(0, x, w + OFF_QKV_T, w + OFF_QKV_I, txt_qkv_b, img_qkv_b,
              qkvb, qkvb, nullptr, QKVW, HS, LTOT, QKVW, QKVW);

    rms_rope<<<LTOT, 256>>>(qkvb, pe, txt_q_s, txt_k_s, img_q_s, img_k_s, q, k, v);

    {
        dim3 fgrid(LTOT / 128, NH);
        flash_attn<<<fgrid, 256, FA_SMEM_BYTES>>>(q, k, v, attn);
    }

    // proj + gated residual (merged) -> row-major fp32 x1
    tc_launch(2, attn, w + OFF_PROJ_T, w + OFF_PROJ_I, txt_proj_b, img_proj_b,
              x1, x1, nullptr, HS, HS, LTOT, HS, HS,
              modt + 2 * HS, modi + 2 * HS,
              txt, img - (size_t)LTXT * HS, HS);

    ln_mod<<<LTXT, 256>>>(x1, x2,                     modt + 3 * HS, modt + 4 * HS, 0);
    ln_mod<<<LIMG, 256>>>(x1 + (size_t)LTXT * HS, x2, modi + 3 * HS, modi + 4 * HS, LTXT);

    // MLP1 (+GELU, merged) -> fp16 A-layout h1
    tc_launch(1, x2, w + OFF_MLP1_T, w + OFF_MLP1_I, txt_mlp_b1, img_mlp_b1,
              nullptr, nullptr, h1, MLPD, HS, LTOT, MLPD, MLPD);

    // MLP2 (+gated residual, merged) -> d_out (img first, then txt)
    tc_launch(2, h1, w + OFF_MLP2_T, w + OFF_MLP2_I, txt_mlp_b2, img_mlp_b2,
              out + (size_t)LIMG * HS,
              out - (size_t)LTXT * HS,
              nullptr, HS, MLPD, LTOT, HS, HS,
              modt + 5 * HS, modi + 5 * HS,
              x1, x1, HS);
}